// round 1
// baseline (speedup 1.0000x reference)
#include <cuda_runtime.h>
#include <math.h>

// ---------------- problem constants ----------------
#define D_    3072
#define S_    2048
#define H_    24
#define DH_   128
#define ENC_  512
#define NIP_  64
#define COND_ 1024
#define SL_   2560   // ENC + S
#define SB_   1536   // SL - COND
#define RANK_ 16
#define EPS_  1e-5f
#define SCALE_ 0.08838834764831845f  // 1/sqrt(128)

// ---------------- scratch (device globals; no allocations allowed) ----------------
__device__ float g_qproj[S_ * D_];
__device__ float g_kproj[S_ * D_];
__device__ float g_vproj[S_ * D_];
__device__ float g_eq[ENC_ * D_];
__device__ float g_ek[ENC_ * D_];
__device__ float g_ev[ENC_ * D_];
__device__ float g_kipp[NIP_ * D_];
__device__ float g_vipp[NIP_ * D_];
__device__ float g_Q[H_ * SL_ * DH_];
__device__ float g_K[H_ * SL_ * DH_];
__device__ float g_V[H_ * SL_ * DH_];
__device__ float g_KIP[H_ * NIP_ * DH_];
__device__ float g_VIP[H_ * NIP_ * DH_];
__device__ float g_am[S_ * D_];      // main attention out (+ ip out), token-major
__device__ float g_ae[ENC_ * D_];    // encoder attention out
__device__ float g_lt[COND_ * RANK_]; // lora temp

// ---------------- generic tiled SGEMM: C = A[M,K] @ W[K,N] (+bias) ----------------
// BN=128, BK=8, 256 threads, thread micro-tile TM x 8 where TM = BM/16.
template <int BM>
__global__ void __launch_bounds__(256) sgemm_kernel(
    const float* __restrict__ A, const float* __restrict__ W,
    const float* __restrict__ bias, float* __restrict__ C,
    int M, int N, int K) {
  constexpr int BK = 8, BN = 128, TM = BM / 16;
  __shared__ float As[BK][BM];
  __shared__ float Bs[BK][BN];
  const int tid = threadIdx.x;
  const int m0 = blockIdx.y * BM;
  const int n0 = blockIdx.x * BN;
  const int rf = tid >> 4;    // 0..15 row-fragment
  const int cf = tid & 15;    // 0..15 col-fragment

  float acc[TM][8];
#pragma unroll
  for (int i = 0; i < TM; i++)
#pragma unroll
    for (int j = 0; j < 8; j++) acc[i][j] = 0.f;

  for (int k0 = 0; k0 < K; k0 += BK) {
    // load A tile (BM x 8), stored transposed As[k][m]
    for (int v = tid; v < BM * 2; v += 256) {
      int r = v >> 1, kq = (v & 1) << 2;
      int gr = m0 + r;
      float4 t = make_float4(0.f, 0.f, 0.f, 0.f);
      if (gr < M) t = *(const float4*)(A + (size_t)gr * K + k0 + kq);
      As[kq + 0][r] = t.x; As[kq + 1][r] = t.y;
      As[kq + 2][r] = t.z; As[kq + 3][r] = t.w;
    }
    // load B tile (8 x 128)
    {
      int kk = tid >> 5, c = (tid & 31) << 2;
      float4 t = *(const float4*)(W + (size_t)(k0 + kk) * N + n0 + c);
      *(float4*)&Bs[kk][c] = t;
    }
    __syncthreads();
#pragma unroll
    for (int kk = 0; kk < BK; kk++) {
      float b[8];
      *(float4*)&b[0] = *(const float4*)&Bs[kk][cf * 8];
      *(float4*)&b[4] = *(const float4*)&Bs[kk][cf * 8 + 4];
      float a[TM];
#pragma unroll
      for (int i = 0; i < TM; i++) a[i] = As[kk][rf * TM + i];
#pragma unroll
      for (int i = 0; i < TM; i++)
#pragma unroll
        for (int j = 0; j < 8; j++) acc[i][j] = fmaf(a[i], b[j], acc[i][j]);
    }
    __syncthreads();
  }
#pragma unroll
  for (int i = 0; i < TM; i++) {
    int gr = m0 + rf * TM + i;
    if (gr >= M) continue;
#pragma unroll
    for (int j = 0; j < 8; j++) {
      int gc = n0 + cf * 8 + j;
      float o = acc[i][j];
      if (bias) o += bias[gc];
      C[(size_t)gr * N + gc] = o;
    }
  }
}

// ---------------- LoRA: t[COND,16] = A[COND,D] @ dn[D,16] ----------------
__global__ void lora_dn_kernel(const float* __restrict__ A,
                               const float* __restrict__ dn,
                               float* __restrict__ t) {
  int idx = blockIdx.x * blockDim.x + threadIdx.x;  // COND*RANK threads
  if (idx >= COND_ * RANK_) return;
  int r = idx >> 4, c = idx & 15;
  const float* a = A + (size_t)r * D_;
  float s = 0.f;
#pragma unroll 4
  for (int k = 0; k < D_; k++) s = fmaf(a[k], dn[k * RANK_ + c], s);
  t[idx] = s;
}

// C[COND,D] += t[COND,16] @ up[16,D]   (ALPHA/RANK * LW == 1.0)
__global__ void lora_up_add_kernel(const float* __restrict__ t,
                                   const float* __restrict__ up,
                                   float* __restrict__ C) {
  int idx = blockIdx.x * blockDim.x + threadIdx.x;  // COND*D threads
  if (idx >= COND_ * D_) return;
  int r = idx / D_, c = idx - r * D_;
  float s = 0.f;
#pragma unroll
  for (int i = 0; i < RANK_; i++) s = fmaf(t[r * RANK_ + i], up[(size_t)i * D_ + c], s);
  C[(size_t)r * D_ + c] += s;
}

// ---------------- to_heads (+ optional per-head RMS): one warp per (s,h) row ----------------
__global__ void heads_kernel(const float* __restrict__ proj, float* __restrict__ out,
                             int M, int outSeq, int rowOff, int doRMS) {
  int gw = (blockIdx.x * blockDim.x + threadIdx.x) >> 5;
  int lane = threadIdx.x & 31;
  if (gw >= M * H_) return;
  int s2 = gw / H_, h = gw - s2 * H_;
  float4 v = *(const float4*)(proj + (size_t)s2 * D_ + h * DH_ + lane * 4);
  if (doRMS) {
    float ss = v.x * v.x + v.y * v.y + v.z * v.z + v.w * v.w;
#pragma unroll
    for (int o = 16; o; o >>= 1) ss += __shfl_xor_sync(0xffffffffu, ss, o);
    float r = rsqrtf(ss * (1.f / DH_) + EPS_);
    v.x *= r; v.y *= r; v.z *= r; v.w *= r;
  }
  *(float4*)(out + ((size_t)h * outSeq + rowOff + s2) * DH_ + lane * 4) = v;
}

// ---------------- main joint attention (flash-style, fp32) ----------------
// grid: (SL/64, H). block 256. Tile 64q x 64k, online softmax.
// Rows >= SB attend only keys [SB, SL)  (mask structure exploited exactly).
__global__ void __launch_bounds__(256) attn_kernel(
    const float* __restrict__ Q, const float* __restrict__ K,
    const float* __restrict__ V, float* __restrict__ outE,
    float* __restrict__ outM) {
  extern __shared__ float sm[];
  float* Qs  = sm;                 // 64 x 128
  float* KVs = sm + 64 * 128;      // 64 x 129 (padded; K then V)
  float* Ps  = KVs + 64 * 129;     // 64 x 65  (padded)
  const int tid = threadIdx.x;
  const int h = blockIdx.y;
  const int q0 = blockIdx.x * 64;
  const int ry = tid >> 4;   // 0..15 -> rows ry*4..ry*4+3
  const int cx = tid & 15;   // 0..15 -> cols j*16+cx

  // load Q tile
  {
    const float* Qg = Q + ((size_t)h * SL_ + q0) * DH_;
    for (int v = tid; v < 64 * 32; v += 256) {
      int r = v >> 5, c4 = (v & 31) << 2;
      *(float4*)(Qs + r * 128 + c4) = *(const float4*)(Qg + r * DH_ + c4);
    }
  }
  float m_i[4], l_i[4], acc[4][8];
#pragma unroll
  for (int i = 0; i < 4; i++) {
    m_i[i] = -1e30f; l_i[i] = 0.f;
#pragma unroll
    for (int j = 0; j < 8; j++) acc[i][j] = 0.f;
  }
  const int kt0 = (q0 >= SB_) ? (SB_ / 64) : 0;
  const float* Kg = K + (size_t)h * SL_ * DH_;
  const float* Vg = V + (size_t)h * SL_ * DH_;

  for (int kt = kt0; kt < SL_ / 64; kt++) {
    __syncthreads();  // protect KVs/Ps from previous-iteration readers; makes Qs visible (1st iter)
    // load K tile
    {
      const float* Kt = Kg + (size_t)kt * 64 * DH_;
      for (int v = tid; v < 64 * 32; v += 256) {
        int r = v >> 5, c4 = (v & 31) << 2;
        float4 t = *(const float4*)(Kt + r * DH_ + c4);
        KVs[r * 129 + c4 + 0] = t.x; KVs[r * 129 + c4 + 1] = t.y;
        KVs[r * 129 + c4 + 2] = t.z; KVs[r * 129 + c4 + 3] = t.w;
      }
    }
    __syncthreads();
    // S = Q @ K^T (thread owns rows ry*4+i, cols j*16+cx)
    float s[4][4];
#pragma unroll
    for (int i = 0; i < 4; i++)
#pragma unroll
      for (int j = 0; j < 4; j++) s[i][j] = 0.f;
#pragma unroll 4
    for (int kk = 0; kk < 128; kk++) {
      float qv[4], kv[4];
#pragma unroll
      for (int i = 0; i < 4; i++) qv[i] = Qs[(ry * 4 + i) * 128 + kk];
#pragma unroll
      for (int j = 0; j < 4; j++) kv[j] = KVs[(j * 16 + cx) * 129 + kk];
#pragma unroll
      for (int i = 0; i < 4; i++)
#pragma unroll
        for (int j = 0; j < 4; j++) s[i][j] = fmaf(qv[i], kv[j], s[i][j]);
    }
    // online softmax update (row stats reduced over cx = lane bits 0..3)
#pragma unroll
    for (int i = 0; i < 4; i++) {
      float rm = -1e30f;
#pragma unroll
      for (int j = 0; j < 4; j++) { s[i][j] *= SCALE_; rm = fmaxf(rm, s[i][j]); }
#pragma unroll
      for (int o = 1; o < 16; o <<= 1) rm = fmaxf(rm, __shfl_xor_sync(0xffffffffu, rm, o));
      float mn = fmaxf(m_i[i], rm);
      float rs = 0.f;
#pragma unroll
      for (int j = 0; j < 4; j++) {
        float p = __expf(s[i][j] - mn);
        s[i][j] = p; rs += p;
      }
#pragma unroll
      for (int o = 1; o < 16; o <<= 1) rs += __shfl_xor_sync(0xffffffffu, rs, o);
      float corr = __expf(m_i[i] - mn);
      l_i[i] = l_i[i] * corr + rs;
      m_i[i] = mn;
#pragma unroll
      for (int j = 0; j < 8; j++) acc[i][j] *= corr;
#pragma unroll
      for (int j = 0; j < 4; j++) Ps[(ry * 4 + i) * 65 + j * 16 + cx] = s[i][j];
    }
    __syncthreads();
    // load V tile into the same buffer (K no longer needed)
    {
      const float* Vt = Vg + (size_t)kt * 64 * DH_;
      for (int v = tid; v < 64 * 32; v += 256) {
        int r = v >> 5, c4 = (v & 31) << 2;
        float4 t = *(const float4*)(Vt + r * DH_ + c4);
        KVs[r * 129 + c4 + 0] = t.x; KVs[r * 129 + c4 + 1] = t.y;
        KVs[r * 129 + c4 + 2] = t.z; KVs[r * 129 + c4 + 3] = t.w;
      }
    }
    __syncthreads();
    // acc += P @ V  (thread owns d-cols j*16+cx)
#pragma unroll 2
    for (int kk = 0; kk < 64; kk++) {
      float pv[4];
#pragma unroll
      for (int i = 0; i < 4; i++) pv[i] = Ps[(ry * 4 + i) * 65 + kk];
      float vv[8];
#pragma unroll
      for (int j = 0; j < 8; j++) vv[j] = KVs[kk * 129 + j * 16 + cx];
#pragma unroll
      for (int i = 0; i < 4; i++)
#pragma unroll
        for (int j = 0; j < 8; j++) acc[i][j] = fmaf(pv[i], vv[j], acc[i][j]);
    }
  }
  // epilogue: normalize, scatter to token-major buffers (from_heads layout)
#pragma unroll
  for (int i = 0; i < 4; i++) {
    int gr = q0 + ry * 4 + i;
    float inv = 1.f / l_i[i];
#pragma unroll
    for (int j = 0; j < 8; j++) {
      float o = acc[i][j] * inv;
      int col = h * DH_ + j * 16 + cx;
      if (gr < ENC_) outE[(size_t)gr * D_ + col] = o;
      else outM[(size_t)(gr - ENC_) * D_ + col] = o;
    }
  }
}

// ---------------- IP attention (64 keys, no mask): one warp per (h, s); += into g_am ----------------
__global__ void ip_attn_kernel(const float* __restrict__ Q, const float* __restrict__ KIP,
                               const float* __restrict__ VIP, float* __restrict__ am) {
  int gw = (blockIdx.x * blockDim.x + threadIdx.x) >> 5;
  int lane = threadIdx.x & 31;
  if (gw >= H_ * S_) return;
  int h = gw / S_, s = gw - h * S_;
  float4 q4 = *(const float4*)(Q + ((size_t)h * SL_ + ENC_ + s) * DH_ + lane * 4);
  float sc0 = 0.f, sc1 = 0.f;
#pragma unroll 8
  for (int k = 0; k < NIP_; k++) {
    float4 k4 = *(const float4*)(KIP + ((size_t)h * NIP_ + k) * DH_ + lane * 4);
    float d = q4.x * k4.x + q4.y * k4.y + q4.z * k4.z + q4.w * k4.w;
#pragma unroll
    for (int o = 16; o; o >>= 1) d += __shfl_xor_sync(0xffffffffu, d, o);
    d *= SCALE_;
    if ((k & 31) == lane) { if (k < 32) sc0 = d; else sc1 = d; }
  }
  float mx = fmaxf(sc0, sc1);
#pragma unroll
  for (int o = 16; o; o >>= 1) mx = fmaxf(mx, __shfl_xor_sync(0xffffffffu, mx, o));
  float e0 = __expf(sc0 - mx), e1 = __expf(sc1 - mx);
  float sum = e0 + e1;
#pragma unroll
  for (int o = 16; o; o >>= 1) sum += __shfl_xor_sync(0xffffffffu, sum, o);
  float inv = 1.f / sum;
  float4 a = make_float4(0.f, 0.f, 0.f, 0.f);
#pragma unroll 8
  for (int k = 0; k < NIP_; k++) {
    float p = __shfl_sync(0xffffffffu, (k < 32) ? e0 : e1, k & 31);
    float4 v4 = *(const float4*)(VIP + ((size_t)h * NIP_ + k) * DH_ + lane * 4);
    a.x = fmaf(p, v4.x, a.x); a.y = fmaf(p, v4.y, a.y);
    a.z = fmaf(p, v4.z, a.z); a.w = fmaf(p, v4.w, a.w);
  }
  float* dst = am + (size_t)s * D_ + h * DH_ + lane * 4;
  float4 cur = *(float4*)dst;
  cur.x += a.x * inv; cur.y += a.y * inv; cur.z += a.z * inv; cur.w += a.w * inv;
  *(float4*)dst = cur;
}

// ---------------- launch ----------------
extern "C" void kernel_launch(void* const* d_in, const int* in_sizes, int n_in,
                              void* d_out, int out_size) {
  const float* hs   = (const float*)d_in[0];
  const float* ehs  = (const float*)d_in[1];
  const float* img  = (const float*)d_in[2];
  const float* Wq   = (const float*)d_in[3];  const float* bq  = (const float*)d_in[4];
  const float* Wk   = (const float*)d_in[5];  const float* bk  = (const float*)d_in[6];
  const float* Wv   = (const float*)d_in[7];  const float* bv  = (const float*)d_in[8];
  const float* Waq  = (const float*)d_in[9];  const float* baq = (const float*)d_in[10];
  const float* Wak  = (const float*)d_in[11]; const float* bak = (const float*)d_in[12];
  const float* Wav  = (const float*)d_in[13]; const float* bav = (const float*)d_in[14];
  const float* Wo   = (const float*)d_in[15]; const float* bo  = (const float*)d_in[16];
  const float* Wao  = (const float*)d_in[17]; const float* bao = (const float*)d_in[18];
  const float* Wkip = (const float*)d_in[19]; const float* Wvip = (const float*)d_in[20];
  const float* lq_dn = (const float*)d_in[21]; const float* lq_up = (const float*)d_in[22];
  const float* lk_dn = (const float*)d_in[23]; const float* lk_up = (const float*)d_in[24];
  const float* lv_dn = (const float*)d_in[25]; const float* lv_up = (const float*)d_in[26];
  const float* lp_dn = (const float*)d_in[27]; const float* lp_up = (const float*)d_in[28];
  float* out = (float*)d_out;

  float *qproj, *kproj, *vproj, *eq, *ek, *ev, *kipp, *vipp;
  float *Q, *K, *V, *KIP, *VIP, *am, *ae, *lt;
  cudaGetSymbolAddress((void**)&qproj, g_qproj);
  cudaGetSymbolAddress((void**)&kproj, g_kproj);
  cudaGetSymbolAddress((void**)&vproj, g_vproj);
  cudaGetSymbolAddress((void**)&eq, g_eq);
  cudaGetSymbolAddress((void**)&ek, g_ek);
  cudaGetSymbolAddress((void**)&ev, g_ev);
  cudaGetSymbolAddress((void**)&kipp, g_kipp);
  cudaGetSymbolAddress((void**)&vipp, g_vipp);
  cudaGetSymbolAddress((void**)&Q, g_Q);
  cudaGetSymbolAddress((void**)&K, g_K);
  cudaGetSymbolAddress((void**)&V, g_V);
  cudaGetSymbolAddress((void**)&KIP, g_KIP);
  cudaGetSymbolAddress((void**)&VIP, g_VIP);
  cudaGetSymbolAddress((void**)&am, g_am);
  cudaGetSymbolAddress((void**)&ae, g_ae);
  cudaGetSymbolAddress((void**)&lt, g_lt);

  const int ATTN_SMEM = (64 * 128 + 64 * 129 + 64 * 65) * (int)sizeof(float);  // 82432
  cudaFuncSetAttribute(attn_kernel, cudaFuncAttributeMaxDynamicSharedMemorySize, ATTN_SMEM);

  // --- main projections (q,k,v) + LoRA on the last COND rows ---
  sgemm_kernel<128><<<dim3(24, 16), 256>>>(hs, Wq, bq, qproj, S_, D_, D_);
  sgemm_kernel<128><<<dim3(24, 16), 256>>>(hs, Wk, bk, kproj, S_, D_, D_);
  sgemm_kernel<128><<<dim3(24, 16), 256>>>(hs, Wv, bv, vproj, S_, D_, D_);
  const float* hsC = hs + (size_t)(S_ - COND_) * D_;
  lora_dn_kernel<<<64, 256>>>(hsC, lq_dn, lt);
  lora_up_add_kernel<<<COND_ * D_ / 256, 256>>>(lt, lq_up, qproj + (size_t)(S_ - COND_) * D_);
  lora_dn_kernel<<<64, 256>>>(hsC, lk_dn, lt);
  lora_up_add_kernel<<<COND_ * D_ / 256, 256>>>(lt, lk_up, kproj + (size_t)(S_ - COND_) * D_);
  lora_dn_kernel<<<64, 256>>>(hsC, lv_dn, lt);
  lora_up_add_kernel<<<COND_ * D_ / 256, 256>>>(lt, lv_up, vproj + (size_t)(S_ - COND_) * D_);

  // --- encoder + IP projections ---
  sgemm_kernel<64><<<dim3(24, 8), 256>>>(ehs, Waq, baq, eq, ENC_, D_, D_);
  sgemm_kernel<64><<<dim3(24, 8), 256>>>(ehs, Wak, bak, ek, ENC_, D_, D_);
  sgemm_kernel<64><<<dim3(24, 8), 256>>>(ehs, Wav, bav, ev, ENC_, D_, D_);
  sgemm_kernel<16><<<dim3(24, 4), 256>>>(img, Wkip, nullptr, kipp, NIP_, D_, D_);
  sgemm_kernel<16><<<dim3(24, 4), 256>>>(img, Wvip, nullptr, vipp, NIP_, D_, D_);

  // --- to_heads + RMS; build concatenated head-major Q/K/V ---
  heads_kernel<<<ENC_ * H_ / 8, 256>>>(eq, Q, ENC_, SL_, 0, 1);
  heads_kernel<<<S_ * H_ / 8, 256>>>(qproj, Q, S_, SL_, ENC_, 1);
  heads_kernel<<<ENC_ * H_ / 8, 256>>>(ek, K, ENC_, SL_, 0, 1);
  heads_kernel<<<S_ * H_ / 8, 256>>>(kproj, K, S_, SL_, ENC_, 1);
  heads_kernel<<<ENC_ * H_ / 8, 256>>>(ev, V, ENC_, SL_, 0, 0);
  heads_kernel<<<S_ * H_ / 8, 256>>>(vproj, V, S_, SL_, ENC_, 0);
  heads_kernel<<<NIP_ * H_ / 8, 256>>>(kipp, KIP, NIP_, NIP_, 0, 1);
  heads_kernel<<<NIP_ * H_ / 8, 256>>>(vipp, VIP, NIP_, NIP_, 0, 0);

  // --- attention: main joint attention writes, IP attention accumulates ---
  attn_kernel<<<dim3(SL_ / 64, H_), 256, ATTN_SMEM>>>(Q, K, V, ae, am);
  ip_attn_kernel<<<H_ * S_ / 8, 256>>>(Q, KIP, VIP, am);

  // --- output projections + output LoRA ---
  float* outMain = out + (size_t)ENC_ * D_;
  sgemm_kernel<128><<<dim3(24, 16), 256>>>(am, Wo, bo, outMain, S_, D_, D_);
  sgemm_kernel<64><<<dim3(24, 8), 256>>>(ae, Wao, bao, out, ENC_, D_, D_);
  float* outCond = outMain + (size_t)(S_ - COND_) * D_;
  lora_dn_kernel<<<64, 256>>>(outCond, lp_dn, lt);
  lora_up_add_kernel<<<COND_ * D_ / 256, 256>>>(lt, lp_up, outCond);
}

// round 2
// speedup vs baseline: 1.0019x; 1.0019x over previous
#include <cuda_runtime.h>
#include <math.h>

// ---------------- problem constants ----------------
#define D_    3072
#define S_    2048
#define H_    24
#define DH_   128
#define ENC_  512
#define NIP_  64
#define COND_ 1024
#define SL_   2560   // ENC + S
#define SB_   1536   // SL - COND
#define RANK_ 16
#define EPS_  1e-5f
#define SCALE_ 0.08838834764831845f  // 1/sqrt(128)

// ---------------- scratch (device globals; no allocations allowed) ----------------
__device__ float g_qproj[S_ * D_];
__device__ float g_kproj[S_ * D_];
__device__ float g_vproj[S_ * D_];
__device__ float g_eq[ENC_ * D_];
__device__ float g_ek[ENC_ * D_];
__device__ float g_ev[ENC_ * D_];
__device__ float g_kipp[NIP_ * D_];
__device__ float g_vipp[NIP_ * D_];
__device__ float g_Q[H_ * SL_ * DH_];
__device__ float g_K[H_ * SL_ * DH_];
__device__ float g_V[H_ * SL_ * DH_];
__device__ float g_KIP[H_ * NIP_ * DH_];
__device__ float g_VIP[H_ * NIP_ * DH_];
__device__ float g_am[S_ * D_];      // main attention out (+ ip out), token-major
__device__ float g_ae[ENC_ * D_];    // encoder attention out
__device__ float g_lt[COND_ * RANK_]; // lora temp

// ---------------- generic tiled SGEMM: C = A[M,K] @ W[K,N] (+bias) ----------------
// BN=128, BK=8, 256 threads, thread micro-tile TM x 8 where TM = BM/16.
template <int BM>
__global__ void __launch_bounds__(256) sgemm_kernel(
    const float* __restrict__ A, const float* __restrict__ W,
    const float* __restrict__ bias, float* __restrict__ C,
    int M, int N, int K) {
  constexpr int BK = 8, BN = 128, TM = BM / 16;
  __shared__ float As[BK][BM];
  __shared__ float Bs[BK][BN];
  const int tid = threadIdx.x;
  const int m0 = blockIdx.y * BM;
  const int n0 = blockIdx.x * BN;
  const int rf = tid >> 4;    // 0..15 row-fragment
  const int cf = tid & 15;    // 0..15 col-fragment

  float acc[TM][8];
#pragma unroll
  for (int i = 0; i < TM; i++)
#pragma unroll
    for (int j = 0; j < 8; j++) acc[i][j] = 0.f;

  for (int k0 = 0; k0 < K; k0 += BK) {
    // load A tile (BM x 8), stored transposed As[k][m]
    for (int v = tid; v < BM * 2; v += 256) {
      int r = v >> 1, kq = (v & 1) << 2;
      int gr = m0 + r;
      float4 t = make_float4(0.f, 0.f, 0.f, 0.f);
      if (gr < M) t = *(const float4*)(A + (size_t)gr * K + k0 + kq);
      As[kq + 0][r] = t.x; As[kq + 1][r] = t.y;
      As[kq + 2][r] = t.z; As[kq + 3][r] = t.w;
    }
    // load B tile (8 x 128)
    {
      int kk = tid >> 5, c = (tid & 31) << 2;
      float4 t = *(const float4*)(W + (size_t)(k0 + kk) * N + n0 + c);
      *(float4*)&Bs[kk][c] = t;
    }
    __syncthreads();
#pragma unroll
    for (int kk = 0; kk < BK; kk++) {
      float b[8];
      *(float4*)&b[0] = *(const float4*)&Bs[kk][cf * 8];
      *(float4*)&b[4] = *(const float4*)&Bs[kk][cf * 8 + 4];
      float a[TM];
#pragma unroll
      for (int i = 0; i < TM; i++) a[i] = As[kk][rf * TM + i];
#pragma unroll
      for (int i = 0; i < TM; i++)
#pragma unroll
        for (int j = 0; j < 8; j++) acc[i][j] = fmaf(a[i], b[j], acc[i][j]);
    }
    __syncthreads();
  }
#pragma unroll
  for (int i = 0; i < TM; i++) {
    int gr = m0 + rf * TM + i;
    if (gr >= M) continue;
#pragma unroll
    for (int j = 0; j < 8; j++) {
      int gc = n0 + cf * 8 + j;
      float o = acc[i][j];
      if (bias) o += bias[gc];
      C[(size_t)gr * N + gc] = o;
    }
  }
}

// ---------------- LoRA: t[COND,16] = A[COND,D] @ dn[D,16] ----------------
__global__ void lora_dn_kernel(const float* __restrict__ A,
                               const float* __restrict__ dn,
                               float* __restrict__ t) {
  int idx = blockIdx.x * blockDim.x + threadIdx.x;  // COND*RANK threads
  if (idx >= COND_ * RANK_) return;
  int r = idx >> 4, c = idx & 15;
  const float* a = A + (size_t)r * D_;
  float s = 0.f;
#pragma unroll 4
  for (int k = 0; k < D_; k++) s = fmaf(a[k], dn[k * RANK_ + c], s);
  t[idx] = s;
}

// C[COND,D] += t[COND,16] @ up[16,D]   (ALPHA/RANK * LW == 1.0)
__global__ void lora_up_add_kernel(const float* __restrict__ t,
                                   const float* __restrict__ up,
                                   float* __restrict__ C) {
  int idx = blockIdx.x * blockDim.x + threadIdx.x;  // COND*D threads
  if (idx >= COND_ * D_) return;
  int r = idx / D_, c = idx - r * D_;
  float s = 0.f;
#pragma unroll
  for (int i = 0; i < RANK_; i++) s = fmaf(t[r * RANK_ + i], up[(size_t)i * D_ + c], s);
  C[(size_t)r * D_ + c] += s;
}

// ---------------- to_heads (+ optional per-head RMS): one warp per (s,h) row ----------------
__global__ void heads_kernel(const float* __restrict__ proj, float* __restrict__ out,
                             int M, int outSeq, int rowOff, int doRMS) {
  int gw = (blockIdx.x * blockDim.x + threadIdx.x) >> 5;
  int lane = threadIdx.x & 31;
  if (gw >= M * H_) return;
  int s2 = gw / H_, h = gw - s2 * H_;
  float4 v = *(const float4*)(proj + (size_t)s2 * D_ + h * DH_ + lane * 4);
  if (doRMS) {
    float ss = v.x * v.x + v.y * v.y + v.z * v.z + v.w * v.w;
#pragma unroll
    for (int o = 16; o; o >>= 1) ss += __shfl_xor_sync(0xffffffffu, ss, o);
    float r = rsqrtf(ss * (1.f / DH_) + EPS_);
    v.x *= r; v.y *= r; v.z *= r; v.w *= r;
  }
  *(float4*)(out + ((size_t)h * outSeq + rowOff + s2) * DH_ + lane * 4) = v;
}

// ---------------- main joint attention (flash-style, fp32) ----------------
// grid: (SL/64, H). block 256. Tile 64q x 64k, online softmax.
// Rows >= SB attend only keys [SB, SL)  (mask structure exploited exactly).
__global__ void __launch_bounds__(256) attn_kernel(
    const float* __restrict__ Q, const float* __restrict__ K,
    const float* __restrict__ V, float* __restrict__ outE,
    float* __restrict__ outM) {
  extern __shared__ float sm[];
  float* Qs  = sm;                 // 64 x 128
  float* KVs = sm + 64 * 128;      // 64 x 129 (padded; K then V)
  float* Ps  = KVs + 64 * 129;     // 64 x 65  (padded)
  const int tid = threadIdx.x;
  const int h = blockIdx.y;
  const int q0 = blockIdx.x * 64;
  const int ry = tid >> 4;   // 0..15 -> rows ry*4..ry*4+3
  const int cx = tid & 15;   // 0..15 -> cols j*16+cx

  // load Q tile
  {
    const float* Qg = Q + ((size_t)h * SL_ + q0) * DH_;
    for (int v = tid; v < 64 * 32; v += 256) {
      int r = v >> 5, c4 = (v & 31) << 2;
      *(float4*)(Qs + r * 128 + c4) = *(const float4*)(Qg + r * DH_ + c4);
    }
  }
  float m_i[4], l_i[4], acc[4][8];
#pragma unroll
  for (int i = 0; i < 4; i++) {
    m_i[i] = -1e30f; l_i[i] = 0.f;
#pragma unroll
    for (int j = 0; j < 8; j++) acc[i][j] = 0.f;
  }
  const int kt0 = (q0 >= SB_) ? (SB_ / 64) : 0;
  const float* Kg = K + (size_t)h * SL_ * DH_;
  const float* Vg = V + (size_t)h * SL_ * DH_;

  for (int kt = kt0; kt < SL_ / 64; kt++) {
    __syncthreads();  // protect KVs/Ps from previous-iteration readers; makes Qs visible (1st iter)
    // load K tile
    {
      const float* Kt = Kg + (size_t)kt * 64 * DH_;
      for (int v = tid; v < 64 * 32; v += 256) {
        int r = v >> 5, c4 = (v & 31) << 2;
        float4 t = *(const float4*)(Kt + r * DH_ + c4);
        KVs[r * 129 + c4 + 0] = t.x; KVs[r * 129 + c4 + 1] = t.y;
        KVs[r * 129 + c4 + 2] = t.z; KVs[r * 129 + c4 + 3] = t.w;
      }
    }
    __syncthreads();
    // S = Q @ K^T (thread owns rows ry*4+i, cols j*16+cx)
    float s[4][4];
#pragma unroll
    for (int i = 0; i < 4; i++)
#pragma unroll
      for (int j = 0; j < 4; j++) s[i][j] = 0.f;
#pragma unroll 4
    for (int kk = 0; kk < 128; kk++) {
      float qv[4], kv[4];
#pragma unroll
      for (int i = 0; i < 4; i++) qv[i] = Qs[(ry * 4 + i) * 128 + kk];
#pragma unroll
      for (int j = 0; j < 4; j++) kv[j] = KVs[(j * 16 + cx) * 129 + kk];
#pragma unroll
      for (int i = 0; i < 4; i++)
#pragma unroll
        for (int j = 0; j < 4; j++) s[i][j] = fmaf(qv[i], kv[j], s[i][j]);
    }
    // online softmax update (row stats reduced over cx = lane bits 0..3)
#pragma unroll
    for (int i = 0; i < 4; i++) {
      float rm = -1e30f;
#pragma unroll
      for (int j = 0; j < 4; j++) { s[i][j] *= SCALE_; rm = fmaxf(rm, s[i][j]); }
#pragma unroll
      for (int o = 1; o < 16; o <<= 1) rm = fmaxf(rm, __shfl_xor_sync(0xffffffffu, rm, o));
      float mn = fmaxf(m_i[i], rm);
      float rs = 0.f;
#pragma unroll
      for (int j = 0; j < 4; j++) {
        float p = __expf(s[i][j] - mn);
        s[i][j] = p; rs += p;
      }
#pragma unroll
      for (int o = 1; o < 16; o <<= 1) rs += __shfl_xor_sync(0xffffffffu, rs, o);
      float corr = __expf(m_i[i] - mn);
      l_i[i] = l_i[i] * corr + rs;
      m_i[i] = mn;
#pragma unroll
      for (int j = 0; j < 8; j++) acc[i][j] *= corr;
#pragma unroll
      for (int j = 0; j < 4; j++) Ps[(ry * 4 + i) * 65 + j * 16 + cx] = s[i][j];
    }
    __syncthreads();
    // load V tile into the same buffer (K no longer needed)
    {
      const float* Vt = Vg + (size_t)kt * 64 * DH_;
      for (int v = tid; v < 64 * 32; v += 256) {
        int r = v >> 5, c4 = (v & 31) << 2;
        float4 t = *(const float4*)(Vt + r * DH_ + c4);
        KVs[r * 129 + c4 + 0] = t.x; KVs[r * 129 + c4 + 1] = t.y;
        KVs[r * 129 + c4 + 2] = t.z; KVs[r * 129 + c4 + 3] = t.w;
      }
    }
    __syncthreads();
    // acc += P @ V  (thread owns d-cols j*16+cx)
#pragma unroll 2
    for (int kk = 0; kk < 64; kk++) {
      float pv[4];
#pragma unroll
      for (int i = 0; i < 4; i++) pv[i] = Ps[(ry * 4 + i) * 65 + kk];
      float vv[8];
#pragma unroll
      for (int j = 0; j < 8; j++) vv[j] = KVs[kk * 129 + j * 16 + cx];
#pragma unroll
      for (int i = 0; i < 4; i++)
#pragma unroll
        for (int j = 0; j < 8; j++) acc[i][j] = fmaf(pv[i], vv[j], acc[i][j]);
    }
  }
  // epilogue: normalize, scatter to token-major buffers (from_heads layout)
#pragma unroll
  for (int i = 0; i < 4; i++) {
    int gr = q0 + ry * 4 + i;
    float inv = 1.f / l_i[i];
#pragma unroll
    for (int j = 0; j < 8; j++) {
      float o = acc[i][j] * inv;
      int col = h * DH_ + j * 16 + cx;
      if (gr < ENC_) outE[(size_t)gr * D_ + col] = o;
      else outM[(size_t)(gr - ENC_) * D_ + col] = o;
    }
  }
}

// ---------------- IP attention (64 keys, no mask): one warp per (h, s); += into g_am ----------------
__global__ void ip_attn_kernel(const float* __restrict__ Q, const float* __restrict__ KIP,
                               const float* __restrict__ VIP, float* __restrict__ am) {
  int gw = (blockIdx.x * blockDim.x + threadIdx.x) >> 5;
  int lane = threadIdx.x & 31;
  if (gw >= H_ * S_) return;
  int h = gw / S_, s = gw - h * S_;
  float4 q4 = *(const float4*)(Q + ((size_t)h * SL_ + ENC_ + s) * DH_ + lane * 4);
  float sc0 = 0.f, sc1 = 0.f;
#pragma unroll 8
  for (int k = 0; k < NIP_; k++) {
    float4 k4 = *(const float4*)(KIP + ((size_t)h * NIP_ + k) * DH_ + lane * 4);
    float d = q4.x * k4.x + q4.y * k4.y + q4.z * k4.z + q4.w * k4.w;
#pragma unroll
    for (int o = 16; o; o >>= 1) d += __shfl_xor_sync(0xffffffffu, d, o);
    d *= SCALE_;
    if ((k & 31) == lane) { if (k < 32) sc0 = d; else sc1 = d; }
  }
  float mx = fmaxf(sc0, sc1);
#pragma unroll
  for (int o = 16; o; o >>= 1) mx = fmaxf(mx, __shfl_xor_sync(0xffffffffu, mx, o));
  float e0 = __expf(sc0 - mx), e1 = __expf(sc1 - mx);
  float sum = e0 + e1;
#pragma unroll
  for (int o = 16; o; o >>= 1) sum += __shfl_xor_sync(0xffffffffu, sum, o);
  float inv = 1.f / sum;
  float4 a = make_float4(0.f, 0.f, 0.f, 0.f);
#pragma unroll 8
  for (int k = 0; k < NIP_; k++) {
    float p = __shfl_sync(0xffffffffu, (k < 32) ? e0 : e1, k & 31);
    float4 v4 = *(const float4*)(VIP + ((size_t)h * NIP_ + k) * DH_ + lane * 4);
    a.x = fmaf(p, v4.x, a.x); a.y = fmaf(p, v4.y, a.y);
    a.z = fmaf(p, v4.z, a.z); a.w = fmaf(p, v4.w, a.w);
  }
  float* dst = am + (size_t)s * D_ + h * DH_ + lane * 4;
  float4 cur = *(float4*)dst;
  cur.x += a.x * inv; cur.y += a.y * inv; cur.z += a.z * inv; cur.w += a.w * inv;
  *(float4*)dst = cur;
}

// ---------------- launch ----------------
extern "C" void kernel_launch(void* const* d_in, const int* in_sizes, int n_in,
                              void* d_out, int out_size) {
  const float* hs   = (const float*)d_in[0];
  const float* ehs  = (const float*)d_in[1];
  const float* img  = (const float*)d_in[2];
  const float* Wq   = (const float*)d_in[3];  const float* bq  = (const float*)d_in[4];
  const float* Wk   = (const float*)d_in[5];  const float* bk  = (const float*)d_in[6];
  const float* Wv   = (const float*)d_in[7];  const float* bv  = (const float*)d_in[8];
  const float* Waq  = (const float*)d_in[9];  const float* baq = (const float*)d_in[10];
  const float* Wak  = (const float*)d_in[11]; const float* bak = (const float*)d_in[12];
  const float* Wav  = (const float*)d_in[13]; const float* bav = (const float*)d_in[14];
  const float* Wo   = (const float*)d_in[15]; const float* bo  = (const float*)d_in[16];
  const float* Wao  = (const float*)d_in[17]; const float* bao = (const float*)d_in[18];
  const float* Wkip = (const float*)d_in[19]; const float* Wvip = (const float*)d_in[20];
  const float* lq_dn = (const float*)d_in[21]; const float* lq_up = (const float*)d_in[22];
  const float* lk_dn = (const float*)d_in[23]; const float* lk_up = (const float*)d_in[24];
  const float* lv_dn = (const float*)d_in[25]; const float* lv_up = (const float*)d_in[26];
  const float* lp_dn = (const float*)d_in[27]; const float* lp_up = (const float*)d_in[28];
  float* out = (float*)d_out;

  float *qproj, *kproj, *vproj, *eq, *ek, *ev, *kipp, *vipp;
  float *Q, *K, *V, *KIP, *VIP, *am, *ae, *lt;
  cudaGetSymbolAddress((void**)&qproj, g_qproj);
  cudaGetSymbolAddress((void**)&kproj, g_kproj);
  cudaGetSymbolAddress((void**)&vproj, g_vproj);
  cudaGetSymbolAddress((void**)&eq, g_eq);
  cudaGetSymbolAddress((void**)&ek, g_ek);
  cudaGetSymbolAddress((void**)&ev, g_ev);
  cudaGetSymbolAddress((void**)&kipp, g_kipp);
  cudaGetSymbolAddress((void**)&vipp, g_vipp);
  cudaGetSymbolAddress((void**)&Q, g_Q);
  cudaGetSymbolAddress((void**)&K, g_K);
  cudaGetSymbolAddress((void**)&V, g_V);
  cudaGetSymbolAddress((void**)&KIP, g_KIP);
  cudaGetSymbolAddress((void**)&VIP, g_VIP);
  cudaGetSymbolAddress((void**)&am, g_am);
  cudaGetSymbolAddress((void**)&ae, g_ae);
  cudaGetSymbolAddress((void**)&lt, g_lt);

  const int ATTN_SMEM = (64 * 128 + 64 * 129 + 64 * 65) * (int)sizeof(float);  // 82432
  cudaFuncSetAttribute(attn_kernel, cudaFuncAttributeMaxDynamicSharedMemorySize, ATTN_SMEM);

  // --- main projections (q,k,v) + LoRA on the last COND rows ---
  sgemm_kernel<128><<<dim3(24, 16), 256>>>(hs, Wq, bq, qproj, S_, D_, D_);
  sgemm_kernel<128><<<dim3(24, 16), 256>>>(hs, Wk, bk, kproj, S_, D_, D_);
  sgemm_kernel<128><<<dim3(24, 16), 256>>>(hs, Wv, bv, vproj, S_, D_, D_);
  const float* hsC = hs + (size_t)(S_ - COND_) * D_;
  lora_dn_kernel<<<64, 256>>>(hsC, lq_dn, lt);
  lora_up_add_kernel<<<COND_ * D_ / 256, 256>>>(lt, lq_up, qproj + (size_t)(S_ - COND_) * D_);
  lora_dn_kernel<<<64, 256>>>(hsC, lk_dn, lt);
  lora_up_add_kernel<<<COND_ * D_ / 256, 256>>>(lt, lk_up, kproj + (size_t)(S_ - COND_) * D_);
  lora_dn_kernel<<<64, 256>>>(hsC, lv_dn, lt);
  lora_up_add_kernel<<<COND_ * D_ / 256, 256>>>(lt, lv_up, vproj + (size_t)(S_ - COND_) * D_);

  // --- encoder + IP projections ---
  sgemm_kernel<64><<<dim3(24, 8), 256>>>(ehs, Waq, baq, eq, ENC_, D_, D_);
  sgemm_kernel<64><<<dim3(24, 8), 256>>>(ehs, Wak, bak, ek, ENC_, D_, D_);
  sgemm_kernel<64><<<dim3(24, 8), 256>>>(ehs, Wav, bav, ev, ENC_, D_, D_);
  sgemm_kernel<16><<<dim3(24, 4), 256>>>(img, Wkip, nullptr, kipp, NIP_, D_, D_);
  sgemm_kernel<16><<<dim3(24, 4), 256>>>(img, Wvip, nullptr, vipp, NIP_, D_, D_);

  // --- to_heads + RMS; build concatenated head-major Q/K/V ---
  heads_kernel<<<ENC_ * H_ / 8, 256>>>(eq, Q, ENC_, SL_, 0, 1);
  heads_kernel<<<S_ * H_ / 8, 256>>>(qproj, Q, S_, SL_, ENC_, 1);
  heads_kernel<<<ENC_ * H_ / 8, 256>>>(ek, K, ENC_, SL_, 0, 1);
  heads_kernel<<<S_ * H_ / 8, 256>>>(kproj, K, S_, SL_, ENC_, 1);
  heads_kernel<<<ENC_ * H_ / 8, 256>>>(ev, V, ENC_, SL_, 0, 0);
  heads_kernel<<<S_ * H_ / 8, 256>>>(vproj, V, S_, SL_, ENC_, 0);
  heads_kernel<<<NIP_ * H_ / 8, 256>>>(kipp, KIP, NIP_, NIP_, 0, 1);
  heads_kernel<<<NIP_ * H_ / 8, 256>>>(vipp, VIP, NIP_, NIP_, 0, 0);

  // --- attention: main joint attention writes, IP attention accumulates ---
  attn_kernel<<<dim3(SL_ / 64, H_), 256, ATTN_SMEM>>>(Q, K, V, ae, am);
  ip_attn_kernel<<<H_ * S_ / 8, 256>>>(Q, KIP, VIP, am);

  // --- output projections + output LoRA ---
  float* outMain = out + (size_t)ENC_ * D_;
  sgemm_kernel<128><<<dim3(24, 16), 256>>>(am, Wo, bo, outMain, S_, D_, D_);
  sgemm_kernel<64><<<dim3(24, 8), 256>>>(ae, Wao, bao, out, ENC_, D_, D_);
  float* outCond = outMain + (size_t)(S_ - COND_) * D_;
  lora_dn_kernel<<<64, 256>>>(outCond, lp_dn, lt);
  lora_up_add_kernel<<<COND_ * D_ / 256, 256>>>(lt, lp_up, outCond);
}

// round 3
// speedup vs baseline: 1.4146x; 1.4120x over previous
#include <cuda_runtime.h>
#include <math.h>
#include <stdint.h>

// ---------------- problem constants ----------------
#define D_    3072
#define S_    2048
#define H_    24
#define DH_   128
#define ENC_  512
#define NIP_  64
#define COND_ 1024
#define SL_   2560   // ENC + S
#define SB_   1536   // SL - COND
#define RANK_ 16
#define EPS_  1e-5f
#define SCALE_ 0.08838834764831845f  // 1/sqrt(128)

// ---------------- scratch (device globals; no allocations allowed) ----------------
__device__ float g_qproj[S_ * D_];
__device__ float g_kproj[S_ * D_];
__device__ float g_vproj[S_ * D_];
__device__ float g_eq[ENC_ * D_];
__device__ float g_ek[ENC_ * D_];
__device__ float g_ev[ENC_ * D_];
__device__ float g_kipp[NIP_ * D_];
__device__ float g_vipp[NIP_ * D_];
__device__ float g_Q[H_ * SL_ * DH_];
__device__ float g_K[H_ * SL_ * DH_];
__device__ float g_V[H_ * SL_ * DH_];
__device__ float g_KIP[H_ * NIP_ * DH_];
__device__ float g_VIP[H_ * NIP_ * DH_];
__device__ float g_am[S_ * D_];      // main attention out (+ ip out), token-major
__device__ float g_ae[ENC_ * D_];    // encoder attention out

// ---------------- tf32 helpers ----------------
__device__ __forceinline__ uint32_t f2tf32(float x) {
  uint32_t r;
  asm("cvt.rna.tf32.f32 %0, %1;" : "=r"(r) : "f"(x));
  return r;
}

__device__ __forceinline__ void mma_tf32(float c[4], const uint32_t a[4], const uint32_t b[2]) {
  asm("mma.sync.aligned.m16n8k8.row.col.f32.tf32.tf32.f32 "
      "{%0,%1,%2,%3}, {%4,%5,%6,%7}, {%8,%9}, {%0,%1,%2,%3};"
      : "+f"(c[0]), "+f"(c[1]), "+f"(c[2]), "+f"(c[3])
      : "r"(a[0]), "r"(a[1]), "r"(a[2]), "r"(a[3]), "r"(b[0]), "r"(b[1]));
}

// ---------------- tf32 tensor-core GEMM: C = A[M,K] @ W[K,N] (+bias) ----------------
// Block tile BM x 128, BK=32, 256 threads (8 warps as 2Mx4N), warp tile (BM/2) x 32.
// Smem holds fragments in mma order: fragment loads are conflict-free LDS.128/LDS.64.
template <int BM>
__global__ void __launch_bounds__(256) mma_gemm(
    const float* __restrict__ A, const float* __restrict__ W,
    const float* __restrict__ bias, float* __restrict__ C,
    int M, int N, int K) {
  constexpr int BN = 128, BK = 32;
  constexpr int MT = BM / 32;           // m16 tiles per warp
  __shared__ uint32_t AsF[(BM / 16) * 4 * 32 * 4];  // [t][ks][lane][4]
  __shared__ uint32_t BsF[16 * 4 * 32 * 2];         // [nt][ks][lane][2]

  const int tid = threadIdx.x;
  const int lane = tid & 31;
  const int wid = tid >> 5;
  const int warpM = wid >> 2;   // 0..1
  const int warpN = wid & 3;    // 0..3
  const int m0 = blockIdx.y * BM;
  const int n0 = blockIdx.x * BN;

  float acc[MT][4][4];
#pragma unroll
  for (int mt = 0; mt < MT; mt++)
#pragma unroll
    for (int nt = 0; nt < 4; nt++)
#pragma unroll
      for (int i = 0; i < 4; i++) acc[mt][nt][i] = 0.f;

  for (int k0 = 0; k0 < K; k0 += BK) {
    __syncthreads();
    // ---- load A tile (BM x 32) into fragment order ----
#pragma unroll
    for (int p = 0; p < BM / 32; p++) {
      int idx = tid + p * 256;
      int r = idx >> 3, c4 = (idx & 7) << 2;
      float4 v = *(const float4*)(A + (size_t)(m0 + r) * K + k0 + c4);
      int t = r >> 4, gid = r & 7, half = (r >> 3) & 1;
      int ks = c4 >> 3, khalf = (c4 >> 2) & 1;
      int slot = half + 2 * khalf;
      uint32_t* base = AsF + ((t * 4 + ks) * 32) * 4 + slot;
      base[(gid * 4 + 0) * 4] = f2tf32(v.x);
      base[(gid * 4 + 1) * 4] = f2tf32(v.y);
      base[(gid * 4 + 2) * 4] = f2tf32(v.z);
      base[(gid * 4 + 3) * 4] = f2tf32(v.w);
    }
    // ---- load B tile (32 x 128) into fragment order ----
#pragma unroll
    for (int p = 0; p < 4; p++) {
      int idx = tid + p * 256;
      int kr = idx >> 5, c4 = (idx & 31) << 2;
      float4 v = *(const float4*)(W + (size_t)(k0 + kr) * N + n0 + c4);
      int ks = kr >> 3, kk = kr & 7, tig = kk & 3, khalf = kk >> 2;
      int nt = c4 >> 3, gg = c4 & 7;
      uint32_t* base = BsF + ((nt * 4 + ks) * 32) * 2 + khalf;
      base[((gg + 0) * 4 + tig) * 2] = f2tf32(v.x);
      base[((gg + 1) * 4 + tig) * 2] = f2tf32(v.y);
      base[((gg + 2) * 4 + tig) * 2] = f2tf32(v.z);
      base[((gg + 3) * 4 + tig) * 2] = f2tf32(v.w);
    }
    __syncthreads();
    // ---- compute ----
#pragma unroll
    for (int ks = 0; ks < 4; ks++) {
      uint32_t a[MT][4];
      uint32_t b[4][2];
#pragma unroll
      for (int mt = 0; mt < MT; mt++) {
        uint4 t4 = *(const uint4*)(AsF + (((warpM * MT + mt) * 4 + ks) * 32 + lane) * 4);
        a[mt][0] = t4.x; a[mt][1] = t4.y; a[mt][2] = t4.z; a[mt][3] = t4.w;
      }
#pragma unroll
      for (int nt = 0; nt < 4; nt++) {
        uint2 t2 = *(const uint2*)(BsF + (((warpN * 4 + nt) * 4 + ks) * 32 + lane) * 2);
        b[nt][0] = t2.x; b[nt][1] = t2.y;
      }
#pragma unroll
      for (int mt = 0; mt < MT; mt++)
#pragma unroll
        for (int nt = 0; nt < 4; nt++) mma_tf32(acc[mt][nt], a[mt], b[nt]);
    }
  }

  // ---- epilogue ----
  const int gid = lane >> 2, tig = lane & 3;
  float bb[4][2];
#pragma unroll
  for (int nt = 0; nt < 4; nt++) {
    int col = n0 + (warpN * 4 + nt) * 8 + tig * 2;
    bb[nt][0] = bias ? bias[col] : 0.f;
    bb[nt][1] = bias ? bias[col + 1] : 0.f;
  }
#pragma unroll
  for (int mt = 0; mt < MT; mt++) {
    int row = m0 + (warpM * MT + mt) * 16 + gid;
#pragma unroll
    for (int nt = 0; nt < 4; nt++) {
      int col = n0 + (warpN * 4 + nt) * 8 + tig * 2;
      float2 lo = make_float2(acc[mt][nt][0] + bb[nt][0], acc[mt][nt][1] + bb[nt][1]);
      float2 hi = make_float2(acc[mt][nt][2] + bb[nt][0], acc[mt][nt][3] + bb[nt][1]);
      *(float2*)(C + (size_t)row * N + col) = lo;
      *(float2*)(C + (size_t)(row + 8) * N + col) = hi;
    }
  }
}

// ---------------- fused LoRA: C[r,:] += (A[r,:] @ dn) @ up  (one block per row) ----------------
__global__ void __launch_bounds__(256) lora_kernel(
    const float* __restrict__ A, const float* __restrict__ dn,
    const float* __restrict__ up, float* __restrict__ C) {
  __shared__ float red[8 * 16];
  __shared__ float st[16];
  const int r = blockIdx.x, tid = threadIdx.x, lane = tid & 31, wid = tid >> 5;
  const float* a = A + (size_t)r * D_;
  float p[16];
#pragma unroll
  for (int i = 0; i < 16; i++) p[i] = 0.f;
  for (int k = tid; k < D_; k += 256) {
    float av = a[k];
    float4 d0 = *(const float4*)(dn + k * 16);
    float4 d1 = *(const float4*)(dn + k * 16 + 4);
    float4 d2 = *(const float4*)(dn + k * 16 + 8);
    float4 d3 = *(const float4*)(dn + k * 16 + 12);
    p[0]  = fmaf(av, d0.x, p[0]);  p[1]  = fmaf(av, d0.y, p[1]);
    p[2]  = fmaf(av, d0.z, p[2]);  p[3]  = fmaf(av, d0.w, p[3]);
    p[4]  = fmaf(av, d1.x, p[4]);  p[5]  = fmaf(av, d1.y, p[5]);
    p[6]  = fmaf(av, d1.z, p[6]);  p[7]  = fmaf(av, d1.w, p[7]);
    p[8]  = fmaf(av, d2.x, p[8]);  p[9]  = fmaf(av, d2.y, p[9]);
    p[10] = fmaf(av, d2.z, p[10]); p[11] = fmaf(av, d2.w, p[11]);
    p[12] = fmaf(av, d3.x, p[12]); p[13] = fmaf(av, d3.y, p[13]);
    p[14] = fmaf(av, d3.z, p[14]); p[15] = fmaf(av, d3.w, p[15]);
  }
#pragma unroll
  for (int o = 16; o; o >>= 1)
#pragma unroll
    for (int i = 0; i < 16; i++) p[i] += __shfl_xor_sync(0xffffffffu, p[i], o);
  if (lane == 0)
#pragma unroll
    for (int i = 0; i < 16; i++) red[wid * 16 + i] = p[i];
  __syncthreads();
  if (tid < 16) {
    float s = 0.f;
#pragma unroll
    for (int w = 0; w < 8; w++) s += red[w * 16 + tid];
    st[tid] = s;
  }
  __syncthreads();
  float t0[16];
#pragma unroll
  for (int i = 0; i < 16; i++) t0[i] = st[i];
  float* crow = C + (size_t)r * D_;
  for (int c = tid; c < D_; c += 256) {
    float s = 0.f;
#pragma unroll
    for (int i = 0; i < 16; i++) s = fmaf(t0[i], up[(size_t)i * D_ + c], s);
    crow[c] += s;
  }
}

// ---------------- to_heads (+ optional per-head RMS): one warp per (s,h) row ----------------
__global__ void heads_kernel(const float* __restrict__ proj, float* __restrict__ out,
                             int M, int outSeq, int rowOff, int doRMS) {
  int gw = (blockIdx.x * blockDim.x + threadIdx.x) >> 5;
  int lane = threadIdx.x & 31;
  if (gw >= M * H_) return;
  int s2 = gw / H_, h = gw - s2 * H_;
  float4 v = *(const float4*)(proj + (size_t)s2 * D_ + h * DH_ + lane * 4);
  if (doRMS) {
    float ss = v.x * v.x + v.y * v.y + v.z * v.z + v.w * v.w;
#pragma unroll
    for (int o = 16; o; o >>= 1) ss += __shfl_xor_sync(0xffffffffu, ss, o);
    float r = rsqrtf(ss * (1.f / DH_) + EPS_);
    v.x *= r; v.y *= r; v.z *= r; v.w *= r;
  }
  *(float4*)(out + ((size_t)h * outSeq + rowOff + s2) * DH_ + lane * 4) = v;
}

// ---------------- main joint attention (flash-style, fp32) ----------------
__global__ void __launch_bounds__(256) attn_kernel(
    const float* __restrict__ Q, const float* __restrict__ K,
    const float* __restrict__ V, float* __restrict__ outE,
    float* __restrict__ outM) {
  extern __shared__ float sm[];
  float* Qs  = sm;                 // 64 x 128
  float* KVs = sm + 64 * 128;      // 64 x 129 (padded; K then V)
  float* Ps  = KVs + 64 * 129;     // 64 x 65  (padded)
  const int tid = threadIdx.x;
  const int h = blockIdx.y;
  const int q0 = blockIdx.x * 64;
  const int ry = tid >> 4;   // 0..15 -> rows ry*4..ry*4+3
  const int cx = tid & 15;   // 0..15 -> cols j*16+cx

  {
    const float* Qg = Q + ((size_t)h * SL_ + q0) * DH_;
    for (int v = tid; v < 64 * 32; v += 256) {
      int r = v >> 5, c4 = (v & 31) << 2;
      *(float4*)(Qs + r * 128 + c4) = *(const float4*)(Qg + r * DH_ + c4);
    }
  }
  float m_i[4], l_i[4], acc[4][8];
#pragma unroll
  for (int i = 0; i < 4; i++) {
    m_i[i] = -1e30f; l_i[i] = 0.f;
#pragma unroll
    for (int j = 0; j < 8; j++) acc[i][j] = 0.f;
  }
  const int kt0 = (q0 >= SB_) ? (SB_ / 64) : 0;
  const float* Kg = K + (size_t)h * SL_ * DH_;
  const float* Vg = V + (size_t)h * SL_ * DH_;

  for (int kt = kt0; kt < SL_ / 64; kt++) {
    __syncthreads();
    {
      const float* Kt = Kg + (size_t)kt * 64 * DH_;
      for (int v = tid; v < 64 * 32; v += 256) {
        int r = v >> 5, c4 = (v & 31) << 2;
        float4 t = *(const float4*)(Kt + r * DH_ + c4);
        KVs[r * 129 + c4 + 0] = t.x; KVs[r * 129 + c4 + 1] = t.y;
        KVs[r * 129 + c4 + 2] = t.z; KVs[r * 129 + c4 + 3] = t.w;
      }
    }
    __syncthreads();
    float s[4][4];
#pragma unroll
    for (int i = 0; i < 4; i++)
#pragma unroll
      for (int j = 0; j < 4; j++) s[i][j] = 0.f;
#pragma unroll 4
    for (int kk = 0; kk < 128; kk++) {
      float qv[4], kv[4];
#pragma unroll
      for (int i = 0; i < 4; i++) qv[i] = Qs[(ry * 4 + i) * 128 + kk];
#pragma unroll
      for (int j = 0; j < 4; j++) kv[j] = KVs[(j * 16 + cx) * 129 + kk];
#pragma unroll
      for (int i = 0; i < 4; i++)
#pragma unroll
        for (int j = 0; j < 4; j++) s[i][j] = fmaf(qv[i], kv[j], s[i][j]);
    }
#pragma unroll
    for (int i = 0; i < 4; i++) {
      float rm = -1e30f;
#pragma unroll
      for (int j = 0; j < 4; j++) { s[i][j] *= SCALE_; rm = fmaxf(rm, s[i][j]); }
#pragma unroll
      for (int o = 1; o < 16; o <<= 1) rm = fmaxf(rm, __shfl_xor_sync(0xffffffffu, rm, o));
      float mn = fmaxf(m_i[i], rm);
      float rs = 0.f;
#pragma unroll
      for (int j = 0; j < 4; j++) {
        float p = __expf(s[i][j] - mn);
        s[i][j] = p; rs += p;
      }
#pragma unroll
      for (int o = 1; o < 16; o <<= 1) rs += __shfl_xor_sync(0xffffffffu, rs, o);
      float corr = __expf(m_i[i] - mn);
      l_i[i] = l_i[i] * corr + rs;
      m_i[i] = mn;
#pragma unroll
      for (int j = 0; j < 8; j++) acc[i][j] *= corr;
#pragma unroll
      for (int j = 0; j < 4; j++) Ps[(ry * 4 + i) * 65 + j * 16 + cx] = s[i][j];
    }
    __syncthreads();
    {
      const float* Vt = Vg + (size_t)kt * 64 * DH_;
      for (int v = tid; v < 64 * 32; v += 256) {
        int r = v >> 5, c4 = (v & 31) << 2;
        float4 t = *(const float4*)(Vt + r * DH_ + c4);
        KVs[r * 129 + c4 + 0] = t.x; KVs[r * 129 + c4 + 1] = t.y;
        KVs[r * 129 + c4 + 2] = t.z; KVs[r * 129 + c4 + 3] = t.w;
      }
    }
    __syncthreads();
#pragma unroll 2
    for (int kk = 0; kk < 64; kk++) {
      float pv[4];
#pragma unroll
      for (int i = 0; i < 4; i++) pv[i] = Ps[(ry * 4 + i) * 65 + kk];
      float vv[8];
#pragma unroll
      for (int j = 0; j < 8; j++) vv[j] = KVs[kk * 129 + j * 16 + cx];
#pragma unroll
      for (int i = 0; i < 4; i++)
#pragma unroll
        for (int j = 0; j < 8; j++) acc[i][j] = fmaf(pv[i], vv[j], acc[i][j]);
    }
  }
#pragma unroll
  for (int i = 0; i < 4; i++) {
    int gr = q0 + ry * 4 + i;
    float inv = 1.f / l_i[i];
#pragma unroll
    for (int j = 0; j < 8; j++) {
      float o = acc[i][j] * inv;
      int col = h * DH_ + j * 16 + cx;
      if (gr < ENC_) outE[(size_t)gr * D_ + col] = o;
      else outM[(size_t)(gr - ENC_) * D_ + col] = o;
    }
  }
}

// ---------------- IP attention (64 keys): one warp per (h, s); += into g_am ----------------
__global__ void ip_attn_kernel(const float* __restrict__ Q, const float* __restrict__ KIP,
                               const float* __restrict__ VIP, float* __restrict__ am) {
  int gw = (blockIdx.x * blockDim.x + threadIdx.x) >> 5;
  int lane = threadIdx.x & 31;
  if (gw >= H_ * S_) return;
  int h = gw / S_, s = gw - h * S_;
  float4 q4 = *(const float4*)(Q + ((size_t)h * SL_ + ENC_ + s) * DH_ + lane * 4);
  float sc0 = 0.f, sc1 = 0.f;
#pragma unroll 8
  for (int k = 0; k < NIP_; k++) {
    float4 k4 = *(const float4*)(KIP + ((size_t)h * NIP_ + k) * DH_ + lane * 4);
    float d = q4.x * k4.x + q4.y * k4.y + q4.z * k4.z + q4.w * k4.w;
#pragma unroll
    for (int o = 16; o; o >>= 1) d += __shfl_xor_sync(0xffffffffu, d, o);
    d *= SCALE_;
    if ((k & 31) == lane) { if (k < 32) sc0 = d; else sc1 = d; }
  }
  float mx = fmaxf(sc0, sc1);
#pragma unroll
  for (int o = 16; o; o >>= 1) mx = fmaxf(mx, __shfl_xor_sync(0xffffffffu, mx, o));
  float e0 = __expf(sc0 - mx), e1 = __expf(sc1 - mx);
  float sum = e0 + e1;
#pragma unroll
  for (int o = 16; o; o >>= 1) sum += __shfl_xor_sync(0xffffffffu, sum, o);
  float inv = 1.f / sum;
  float4 a = make_float4(0.f, 0.f, 0.f, 0.f);
#pragma unroll 8
  for (int k = 0; k < NIP_; k++) {
    float p = __shfl_sync(0xffffffffu, (k < 32) ? e0 : e1, k & 31);
    float4 v4 = *(const float4*)(VIP + ((size_t)h * NIP_ + k) * DH_ + lane * 4);
    a.x = fmaf(p, v4.x, a.x); a.y = fmaf(p, v4.y, a.y);
    a.z = fmaf(p, v4.z, a.z); a.w = fmaf(p, v4.w, a.w);
  }
  float* dst = am + (size_t)s * D_ + h * DH_ + lane * 4;
  float4 cur = *(float4*)dst;
  cur.x += a.x * inv; cur.y += a.y * inv; cur.z += a.z * inv; cur.w += a.w * inv;
  *(float4*)dst = cur;
}

// ---------------- launch ----------------
extern "C" void kernel_launch(void* const* d_in, const int* in_sizes, int n_in,
                              void* d_out, int out_size) {
  const float* hs   = (const float*)d_in[0];
  const float* ehs  = (const float*)d_in[1];
  const float* img  = (const float*)d_in[2];
  const float* Wq   = (const float*)d_in[3];  const float* bq  = (const float*)d_in[4];
  const float* Wk   = (const float*)d_in[5];  const float* bk  = (const float*)d_in[6];
  const float* Wv   = (const float*)d_in[7];  const float* bv  = (const float*)d_in[8];
  const float* Waq  = (const float*)d_in[9];  const float* baq = (const float*)d_in[10];
  const float* Wak  = (const float*)d_in[11]; const float* bak = (const float*)d_in[12];
  const float* Wav  = (const float*)d_in[13]; const float* bav = (const float*)d_in[14];
  const float* Wo   = (const float*)d_in[15]; const float* bo  = (const float*)d_in[16];
  const float* Wao  = (const float*)d_in[17]; const float* bao = (const float*)d_in[18];
  const float* Wkip = (const float*)d_in[19]; const float* Wvip = (const float*)d_in[20];
  const float* lq_dn = (const float*)d_in[21]; const float* lq_up = (const float*)d_in[22];
  const float* lk_dn = (const float*)d_in[23]; const float* lk_up = (const float*)d_in[24];
  const float* lv_dn = (const float*)d_in[25]; const float* lv_up = (const float*)d_in[26];
  const float* lp_dn = (const float*)d_in[27]; const float* lp_up = (const float*)d_in[28];
  float* out = (float*)d_out;

  float *qproj, *kproj, *vproj, *eq, *ek, *ev, *kipp, *vipp;
  float *Q, *K, *V, *KIP, *VIP, *am, *ae;
  cudaGetSymbolAddress((void**)&qproj, g_qproj);
  cudaGetSymbolAddress((void**)&kproj, g_kproj);
  cudaGetSymbolAddress((void**)&vproj, g_vproj);
  cudaGetSymbolAddress((void**)&eq, g_eq);
  cudaGetSymbolAddress((void**)&ek, g_ek);
  cudaGetSymbolAddress((void**)&ev, g_ev);
  cudaGetSymbolAddress((void**)&kipp, g_kipp);
  cudaGetSymbolAddress((void**)&vipp, g_vipp);
  cudaGetSymbolAddress((void**)&Q, g_Q);
  cudaGetSymbolAddress((void**)&K, g_K);
  cudaGetSymbolAddress((void**)&V, g_V);
  cudaGetSymbolAddress((void**)&KIP, g_KIP);
  cudaGetSymbolAddress((void**)&VIP, g_VIP);
  cudaGetSymbolAddress((void**)&am, g_am);
  cudaGetSymbolAddress((void**)&ae, g_ae);

  const int ATTN_SMEM = (64 * 128 + 64 * 129 + 64 * 65) * (int)sizeof(float);  // 82432
  cudaFuncSetAttribute(attn_kernel, cudaFuncAttributeMaxDynamicSharedMemorySize, ATTN_SMEM);

  // --- main projections (q,k,v) on tensor cores + fused LoRA on last COND rows ---
  mma_gemm<128><<<dim3(24, 16), 256>>>(hs, Wq, bq, qproj, S_, D_, D_);
  mma_gemm<128><<<dim3(24, 16), 256>>>(hs, Wk, bk, kproj, S_, D_, D_);
  mma_gemm<128><<<dim3(24, 16), 256>>>(hs, Wv, bv, vproj, S_, D_, D_);
  const float* hsC = hs + (size_t)(S_ - COND_) * D_;
  lora_kernel<<<COND_, 256>>>(hsC, lq_dn, lq_up, qproj + (size_t)(S_ - COND_) * D_);
  lora_kernel<<<COND_, 256>>>(hsC, lk_dn, lk_up, kproj + (size_t)(S_ - COND_) * D_);
  lora_kernel<<<COND_, 256>>>(hsC, lv_dn, lv_up, vproj + (size_t)(S_ - COND_) * D_);

  // --- encoder + IP projections ---
  mma_gemm<128><<<dim3(24, 4), 256>>>(ehs, Waq, baq, eq, ENC_, D_, D_);
  mma_gemm<128><<<dim3(24, 4), 256>>>(ehs, Wak, bak, ek, ENC_, D_, D_);
  mma_gemm<128><<<dim3(24, 4), 256>>>(ehs, Wav, bav, ev, ENC_, D_, D_);
  mma_gemm<64><<<dim3(24, 1), 256>>>(img, Wkip, nullptr, kipp, NIP_, D_, D_);
  mma_gemm<64><<<dim3(24, 1), 256>>>(img, Wvip, nullptr, vipp, NIP_, D_, D_);

  // --- to_heads + RMS; build concatenated head-major Q/K/V ---
  heads_kernel<<<ENC_ * H_ / 8, 256>>>(eq, Q, ENC_, SL_, 0, 1);
  heads_kernel<<<S_ * H_ / 8, 256>>>(qproj, Q, S_, SL_, ENC_, 1);
  heads_kernel<<<ENC_ * H_ / 8, 256>>>(ek, K, ENC_, SL_, 0, 1);
  heads_kernel<<<S_ * H_ / 8, 256>>>(kproj, K, S_, SL_, ENC_, 1);
  heads_kernel<<<ENC_ * H_ / 8, 256>>>(ev, V, ENC_, SL_, 0, 0);
  heads_kernel<<<S_ * H_ / 8, 256>>>(vproj, V, S_, SL_, ENC_, 0);
  heads_kernel<<<NIP_ * H_ / 8, 256>>>(kipp, KIP, NIP_, NIP_, 0, 1);
  heads_kernel<<<NIP_ * H_ / 8, 256>>>(vipp, VIP, NIP_, NIP_, 0, 0);

  // --- attention: main joint attention writes, IP attention accumulates ---
  attn_kernel<<<dim3(SL_ / 64, H_), 256, ATTN_SMEM>>>(Q, K, V, ae, am);
  ip_attn_kernel<<<H_ * S_ / 8, 256>>>(Q, KIP, VIP, am);

  // --- output projections + output LoRA ---
  float* outMain = out + (size_t)ENC_ * D_;
  mma_gemm<128><<<dim3(24, 16), 256>>>(am, Wo, bo, outMain, S_, D_, D_);
  mma_gemm<128><<<dim3(24, 4), 256>>>(ae, Wao, bao, out, ENC_, D_, D_);
  float* outCond = outMain + (size_t)(S_ - COND_) * D_;
  lora_kernel<<<COND_, 256>>>(outCond, lp_dn, lp_up, outCond);
}

// round 4
// speedup vs baseline: 2.7951x; 1.9758x over previous
#include <cuda_runtime.h>
#include <math.h>
#include <stdint.h>

// ---------------- problem constants ----------------
#define D_    3072
#define S_    2048
#define H_    24
#define DH_   128
#define ENC_  512
#define NIP_  64
#define COND_ 1024
#define SL_   2560   // ENC + S
#define SB_   1536   // SL - COND
#define RANK_ 16
#define EPS_  1e-5f
#define SCALE_ 0.08838834764831845f  // 1/sqrt(128)

// ---------------- scratch (device globals; no allocations allowed) ----------------
__device__ float g_qproj[S_ * D_];
__device__ float g_kproj[S_ * D_];
__device__ float g_vproj[S_ * D_];
__device__ float g_eq[ENC_ * D_];
__device__ float g_ek[ENC_ * D_];
__device__ float g_ev[ENC_ * D_];
__device__ float g_kipp[NIP_ * D_];
__device__ float g_vipp[NIP_ * D_];
__device__ float g_Q[H_ * SL_ * DH_];
__device__ float g_K[H_ * SL_ * DH_];
__device__ float g_V[H_ * SL_ * DH_];
__device__ float g_KIP[H_ * NIP_ * DH_];
__device__ float g_VIP[H_ * NIP_ * DH_];
__device__ float g_am[S_ * D_];      // main attention out (+ ip out), token-major
__device__ float g_ae[ENC_ * D_];    // encoder attention out

// ---------------- tf32 helpers ----------------
__device__ __forceinline__ uint32_t f2tf32(float x) {
  uint32_t r;
  asm("cvt.rna.tf32.f32 %0, %1;" : "=r"(r) : "f"(x));
  return r;
}

__device__ __forceinline__ void mma_tf32(float c[4], const uint32_t a[4], const uint32_t b[2]) {
  asm("mma.sync.aligned.m16n8k8.row.col.f32.tf32.tf32.f32 "
      "{%0,%1,%2,%3}, {%4,%5,%6,%7}, {%8,%9}, {%0,%1,%2,%3};"
      : "+f"(c[0]), "+f"(c[1]), "+f"(c[2]), "+f"(c[3])
      : "r"(a[0]), "r"(a[1]), "r"(a[2]), "r"(a[3]), "r"(b[0]), "r"(b[1]));
}

// ---------------- batched tf32 tensor-core GEMM: C = A[M,K] @ W[K,N] (+bias) ----------------
// Block tile BM x 128, BK=32, 256 threads (8 warps 2Mx4N). Software pipelined:
// register-prefetch LDG of tile k+1 issued before compute of tile k; double-buffered
// smem fragments; XOR-swizzled staging (A: pos^ks, B: pos^nt) for near-conflict-free STS.
struct GB {
  const float* A[3];
  const float* W[3];
  const float* bias[3];
  float* C[3];
  int M[3];
};

template <int BM>
__global__ void __launch_bounds__(256) mma_gemm(GB gb, int N, int K) {
  constexpr int BK = 32;
  constexpr int MT = BM / 32;                 // m16 tiles per warp (also A-load iters)
  constexpr int ASZ = (BM / 16) * 4 * 32 * 4; // u32 per A stage
  constexpr int BSZ = 16 * 4 * 32 * 2;        // u32 per B stage
  extern __shared__ uint32_t smu[];
  uint32_t* As0 = smu;
  uint32_t* As1 = smu + ASZ;
  uint32_t* Bs0 = smu + 2 * ASZ;
  uint32_t* Bs1 = smu + 2 * ASZ + BSZ;

  const int z = blockIdx.z;
  const float* __restrict__ A = gb.A[z];
  const float* __restrict__ W = gb.W[z];
  const float* __restrict__ bias = gb.bias[z];
  float* __restrict__ C = gb.C[z];
  const int M = gb.M[z];

  const int tid = threadIdx.x;
  const int lane = tid & 31;
  const int wid = tid >> 5;
  const int warpM = wid >> 2;   // 0..1
  const int warpN = wid & 3;    // 0..3
  const int m0 = blockIdx.y * BM;
  const int n0 = blockIdx.x * 128;
  if (m0 >= M) return;

  float4 pa[MT];
  float4 pb[4];

  auto ldg = [&](int k0) {
#pragma unroll
    for (int p = 0; p < MT; p++) {
      int idx = tid + p * 256;
      int r = idx >> 3, c4 = (idx & 7) << 2;
      pa[p] = *(const float4*)(A + (size_t)(m0 + r) * K + k0 + c4);
    }
#pragma unroll
    for (int p = 0; p < 4; p++) {
      int idx = tid + p * 256;
      int kr = idx >> 5, c4 = (idx & 31) << 2;
      pb[p] = *(const float4*)(W + (size_t)(k0 + kr) * N + n0 + c4);
    }
  };

  auto stor = [&](uint32_t* Ad, uint32_t* Bd) {
#pragma unroll
    for (int p = 0; p < MT; p++) {
      int idx = tid + p * 256;
      int r = idx >> 3, c4 = (idx & 7) << 2;
      int t = r >> 4, gid = r & 7, half = (r >> 3) & 1;
      int ks = c4 >> 3, khalf = (c4 >> 2) & 1;
      int slot = half + 2 * khalf;
      uint32_t* base = Ad + (t * 4 + ks) * 32 * 4 + slot;
      float v0 = pa[p].x, v1 = pa[p].y, v2 = pa[p].z, v3 = pa[p].w;
      base[((gid * 4 + 0) ^ ks) * 4] = f2tf32(v0);
      base[((gid * 4 + 1) ^ ks) * 4] = f2tf32(v1);
      base[((gid * 4 + 2) ^ ks) * 4] = f2tf32(v2);
      base[((gid * 4 + 3) ^ ks) * 4] = f2tf32(v3);
    }
#pragma unroll
    for (int p = 0; p < 4; p++) {
      int idx = tid + p * 256;
      int kr = idx >> 5, c4 = (idx & 31) << 2;
      int ks = kr >> 3, kk = kr & 7, tig = kk & 3, khalf = kk >> 2;
      int nt = c4 >> 3, gg = c4 & 7;
      uint32_t* base = Bd + (nt * 4 + ks) * 32 * 2 + khalf;
      float v0 = pb[p].x, v1 = pb[p].y, v2 = pb[p].z, v3 = pb[p].w;
      base[((((gg + 0) * 4 + tig)) ^ nt) * 2] = f2tf32(v0);
      base[((((gg + 1) * 4 + tig)) ^ nt) * 2] = f2tf32(v1);
      base[((((gg + 2) * 4 + tig)) ^ nt) * 2] = f2tf32(v2);
      base[((((gg + 3) * 4 + tig)) ^ nt) * 2] = f2tf32(v3);
    }
  };

  float acc[MT][4][4];
#pragma unroll
  for (int mt = 0; mt < MT; mt++)
#pragma unroll
    for (int nt = 0; nt < 4; nt++)
#pragma unroll
      for (int i = 0; i < 4; i++) acc[mt][nt][i] = 0.f;

  // prologue
  ldg(0);
  stor(As0, Bs0);
  __syncthreads();

  const int NKT = K / BK;
  for (int kt = 0; kt < NKT; kt++) {
    const uint32_t* Ab = (kt & 1) ? As1 : As0;
    const uint32_t* Bb = (kt & 1) ? Bs1 : Bs0;
    const bool more = (kt + 1) < NKT;
    if (more) ldg((kt + 1) * BK);  // LDGs in flight during compute

#pragma unroll
    for (int ks = 0; ks < 4; ks++) {
      uint32_t a[MT][4];
      uint32_t b[4][2];
#pragma unroll
      for (int mt = 0; mt < MT; mt++) {
        uint4 t4 = *(const uint4*)(Ab + (((warpM * MT + mt) * 4 + ks) * 32 + (lane ^ ks)) * 4);
        a[mt][0] = t4.x; a[mt][1] = t4.y; a[mt][2] = t4.z; a[mt][3] = t4.w;
      }
#pragma unroll
      for (int nt = 0; nt < 4; nt++) {
        int ntg = warpN * 4 + nt;
        uint2 t2 = *(const uint2*)(Bb + ((ntg * 4 + ks) * 32 + (lane ^ ntg)) * 2);
        b[nt][0] = t2.x; b[nt][1] = t2.y;
      }
#pragma unroll
      for (int mt = 0; mt < MT; mt++)
#pragma unroll
        for (int nt = 0; nt < 4; nt++) mma_tf32(acc[mt][nt], a[mt], b[nt]);
    }

    if (more) stor((kt & 1) ? As0 : As1, (kt & 1) ? Bs0 : Bs1);
    __syncthreads();
  }

  // ---- epilogue ----
  const int gid = lane >> 2, tig = lane & 3;
  float bb[4][2];
#pragma unroll
  for (int nt = 0; nt < 4; nt++) {
    int col = n0 + (warpN * 4 + nt) * 8 + tig * 2;
    bb[nt][0] = bias ? bias[col] : 0.f;
    bb[nt][1] = bias ? bias[col + 1] : 0.f;
  }
#pragma unroll
  for (int mt = 0; mt < MT; mt++) {
    int row = m0 + (warpM * MT + mt) * 16 + gid;
#pragma unroll
    for (int nt = 0; nt < 4; nt++) {
      int col = n0 + (warpN * 4 + nt) * 8 + tig * 2;
      float2 lo = make_float2(acc[mt][nt][0] + bb[nt][0], acc[mt][nt][1] + bb[nt][1]);
      float2 hi = make_float2(acc[mt][nt][2] + bb[nt][0], acc[mt][nt][3] + bb[nt][1]);
      *(float2*)(C + (size_t)row * N + col) = lo;
      *(float2*)(C + (size_t)(row + 8) * N + col) = hi;
    }
  }
}

// ---------------- fused LoRA: C[r,:] += (A[r,:] @ dn) @ up  (one block per row) ----------------
__global__ void __launch_bounds__(256) lora_kernel(
    const float* __restrict__ A, const float* __restrict__ dn,
    const float* __restrict__ up, float* __restrict__ C) {
  __shared__ float red[8 * 16];
  __shared__ float st[16];
  const int r = blockIdx.x, tid = threadIdx.x, lane = tid & 31, wid = tid >> 5;
  const float* a = A + (size_t)r * D_;
  float p[16];
#pragma unroll
  for (int i = 0; i < 16; i++) p[i] = 0.f;
  for (int k = tid; k < D_; k += 256) {
    float av = a[k];
    float4 d0 = *(const float4*)(dn + k * 16);
    float4 d1 = *(const float4*)(dn + k * 16 + 4);
    float4 d2 = *(const float4*)(dn + k * 16 + 8);
    float4 d3 = *(const float4*)(dn + k * 16 + 12);
    p[0]  = fmaf(av, d0.x, p[0]);  p[1]  = fmaf(av, d0.y, p[1]);
    p[2]  = fmaf(av, d0.z, p[2]);  p[3]  = fmaf(av, d0.w, p[3]);
    p[4]  = fmaf(av, d1.x, p[4]);  p[5]  = fmaf(av, d1.y, p[5]);
    p[6]  = fmaf(av, d1.z, p[6]);  p[7]  = fmaf(av, d1.w, p[7]);
    p[8]  = fmaf(av, d2.x, p[8]);  p[9]  = fmaf(av, d2.y, p[9]);
    p[10] = fmaf(av, d2.z, p[10]); p[11] = fmaf(av, d2.w, p[11]);
    p[12] = fmaf(av, d3.x, p[12]); p[13] = fmaf(av, d3.y, p[13]);
    p[14] = fmaf(av, d3.z, p[14]); p[15] = fmaf(av, d3.w, p[15]);
  }
#pragma unroll
  for (int o = 16; o; o >>= 1)
#pragma unroll
    for (int i = 0; i < 16; i++) p[i] += __shfl_xor_sync(0xffffffffu, p[i], o);
  if (lane == 0)
#pragma unroll
    for (int i = 0; i < 16; i++) red[wid * 16 + i] = p[i];
  __syncthreads();
  if (tid < 16) {
    float s = 0.f;
#pragma unroll
    for (int w = 0; w < 8; w++) s += red[w * 16 + tid];
    st[tid] = s;
  }
  __syncthreads();
  float t0[16];
#pragma unroll
  for (int i = 0; i < 16; i++) t0[i] = st[i];
  float* crow = C + (size_t)r * D_;
  for (int c = tid; c < D_; c += 256) {
    float s = 0.f;
#pragma unroll
    for (int i = 0; i < 16; i++) s = fmaf(t0[i], up[(size_t)i * D_ + c], s);
    crow[c] += s;
  }
}

// ---------------- to_heads (+ optional per-head RMS): one warp per (s,h) row ----------------
__global__ void heads_kernel(const float* __restrict__ proj, float* __restrict__ out,
                             int M, int outSeq, int rowOff, int doRMS) {
  int gw = (blockIdx.x * blockDim.x + threadIdx.x) >> 5;
  int lane = threadIdx.x & 31;
  if (gw >= M * H_) return;
  int s2 = gw / H_, h = gw - s2 * H_;
  float4 v = *(const float4*)(proj + (size_t)s2 * D_ + h * DH_ + lane * 4);
  if (doRMS) {
    float ss = v.x * v.x + v.y * v.y + v.z * v.z + v.w * v.w;
#pragma unroll
    for (int o = 16; o; o >>= 1) ss += __shfl_xor_sync(0xffffffffu, ss, o);
    float r = rsqrtf(ss * (1.f / DH_) + EPS_);
    v.x *= r; v.y *= r; v.z *= r; v.w *= r;
  }
  *(float4*)(out + ((size_t)h * outSeq + rowOff + s2) * DH_ + lane * 4) = v;
}

// ---------------- main joint attention (flash-style, fp32) ----------------
__global__ void __launch_bounds__(256) attn_kernel(
    const float* __restrict__ Q, const float* __restrict__ K,
    const float* __restrict__ V, float* __restrict__ outE,
    float* __restrict__ outM) {
  extern __shared__ float sm[];
  float* Qs  = sm;                 // 64 x 128
  float* KVs = sm + 64 * 128;      // 64 x 129 (padded; K then V)
  float* Ps  = KVs + 64 * 129;     // 64 x 65  (padded)
  const int tid = threadIdx.x;
  const int h = blockIdx.y;
  const int q0 = blockIdx.x * 64;
  const int ry = tid >> 4;   // 0..15 -> rows ry*4..ry*4+3
  const int cx = tid & 15;   // 0..15 -> cols j*16+cx

  {
    const float* Qg = Q + ((size_t)h * SL_ + q0) * DH_;
    for (int v = tid; v < 64 * 32; v += 256) {
      int r = v >> 5, c4 = (v & 31) << 2;
      *(float4*)(Qs + r * 128 + c4) = *(const float4*)(Qg + r * DH_ + c4);
    }
  }
  float m_i[4], l_i[4], acc[4][8];
#pragma unroll
  for (int i = 0; i < 4; i++) {
    m_i[i] = -1e30f; l_i[i] = 0.f;
#pragma unroll
    for (int j = 0; j < 8; j++) acc[i][j] = 0.f;
  }
  const int kt0 = (q0 >= SB_) ? (SB_ / 64) : 0;
  const float* Kg = K + (size_t)h * SL_ * DH_;
  const float* Vg = V + (size_t)h * SL_ * DH_;

  for (int kt = kt0; kt < SL_ / 64; kt++) {
    __syncthreads();
    {
      const float* Kt = Kg + (size_t)kt * 64 * DH_;
      for (int v = tid; v < 64 * 32; v += 256) {
        int r = v >> 5, c4 = (v & 31) << 2;
        float4 t = *(const float4*)(Kt + r * DH_ + c4);
        KVs[r * 129 + c4 + 0] = t.x; KVs[r * 129 + c4 + 1] = t.y;
        KVs[r * 129 + c4 + 2] = t.z; KVs[r * 129 + c4 + 3] = t.w;
      }
    }
    __syncthreads();
    float s[4][4];
#pragma unroll
    for (int i = 0; i < 4; i++)
#pragma unroll
      for (int j = 0; j < 4; j++) s[i][j] = 0.f;
#pragma unroll 4
    for (int kk = 0; kk < 128; kk++) {
      float qv[4], kv[4];
#pragma unroll
      for (int i = 0; i < 4; i++) qv[i] = Qs[(ry * 4 + i) * 128 + kk];
#pragma unroll
      for (int j = 0; j < 4; j++) kv[j] = KVs[(j * 16 + cx) * 129 + kk];
#pragma unroll
      for (int i = 0; i < 4; i++)
#pragma unroll
        for (int j = 0; j < 4; j++) s[i][j] = fmaf(qv[i], kv[j], s[i][j]);
    }
#pragma unroll
    for (int i = 0; i < 4; i++) {
      float rm = -1e30f;
#pragma unroll
      for (int j = 0; j < 4; j++) { s[i][j] *= SCALE_; rm = fmaxf(rm, s[i][j]); }
#pragma unroll
      for (int o = 1; o < 16; o <<= 1) rm = fmaxf(rm, __shfl_xor_sync(0xffffffffu, rm, o));
      float mn = fmaxf(m_i[i], rm);
      float rs = 0.f;
#pragma unroll
      for (int j = 0; j < 4; j++) {
        float p = __expf(s[i][j] - mn);
        s[i][j] = p; rs += p;
      }
#pragma unroll
      for (int o = 1; o < 16; o <<= 1) rs += __shfl_xor_sync(0xffffffffu, rs, o);
      float corr = __expf(m_i[i] - mn);
      l_i[i] = l_i[i] * corr + rs;
      m_i[i] = mn;
#pragma unroll
      for (int j = 0; j < 8; j++) acc[i][j] *= corr;
#pragma unroll
      for (int j = 0; j < 4; j++) Ps[(ry * 4 + i) * 65 + j * 16 + cx] = s[i][j];
    }
    __syncthreads();
    {
      const float* Vt = Vg + (size_t)kt * 64 * DH_;
      for (int v = tid; v < 64 * 32; v += 256) {
        int r = v >> 5, c4 = (v & 31) << 2;
        float4 t = *(const float4*)(Vt + r * DH_ + c4);
        KVs[r * 129 + c4 + 0] = t.x; KVs[r * 129 + c4 + 1] = t.y;
        KVs[r * 129 + c4 + 2] = t.z; KVs[r * 129 + c4 + 3] = t.w;
      }
    }
    __syncthreads();
#pragma unroll 2
    for (int kk = 0; kk < 64; kk++) {
      float pv[4];
#pragma unroll
      for (int i = 0; i < 4; i++) pv[i] = Ps[(ry * 4 + i) * 65 + kk];
      float vv[8];
#pragma unroll
      for (int j = 0; j < 8; j++) vv[j] = KVs[kk * 129 + j * 16 + cx];
#pragma unroll
      for (int i = 0; i < 4; i++)
#pragma unroll
        for (int j = 0; j < 8; j++) acc[i][j] = fmaf(pv[i], vv[j], acc[i][j]);
    }
  }
#pragma unroll
  for (int i = 0; i < 4; i++) {
    int gr = q0 + ry * 4 + i;
    float inv = 1.f / l_i[i];
#pragma unroll
    for (int j = 0; j < 8; j++) {
      float o = acc[i][j] * inv;
      int col = h * DH_ + j * 16 + cx;
      if (gr < ENC_) outE[(size_t)gr * D_ + col] = o;
      else outM[(size_t)(gr - ENC_) * D_ + col] = o;
    }
  }
}

// ---------------- IP attention (64 keys): one warp per (h, s); += into g_am ----------------
__global__ void ip_attn_kernel(const float* __restrict__ Q, const float* __restrict__ KIP,
                               const float* __restrict__ VIP, float* __restrict__ am) {
  int gw = (blockIdx.x * blockDim.x + threadIdx.x) >> 5;
  int lane = threadIdx.x & 31;
  if (gw >= H_ * S_) return;
  int h = gw / S_, s = gw - h * S_;
  float4 q4 = *(const float4*)(Q + ((size_t)h * SL_ + ENC_ + s) * DH_ + lane * 4);
  float sc0 = 0.f, sc1 = 0.f;
#pragma unroll 8
  for (int k = 0; k < NIP_; k++) {
    float4 k4 = *(const float4*)(KIP + ((size_t)h * NIP_ + k) * DH_ + lane * 4);
    float d = q4.x * k4.x + q4.y * k4.y + q4.z * k4.z + q4.w * k4.w;
#pragma unroll
    for (int o = 16; o; o >>= 1) d += __shfl_xor_sync(0xffffffffu, d, o);
    d *= SCALE_;
    if ((k & 31) == lane) { if (k < 32) sc0 = d; else sc1 = d; }
  }
  float mx = fmaxf(sc0, sc1);
#pragma unroll
  for (int o = 16; o; o >>= 1) mx = fmaxf(mx, __shfl_xor_sync(0xffffffffu, mx, o));
  float e0 = __expf(sc0 - mx), e1 = __expf(sc1 - mx);
  float sum = e0 + e1;
#pragma unroll
  for (int o = 16; o; o >>= 1) sum += __shfl_xor_sync(0xffffffffu, sum, o);
  float inv = 1.f / sum;
  float4 a = make_float4(0.f, 0.f, 0.f, 0.f);
#pragma unroll 8
  for (int k = 0; k < NIP_; k++) {
    float p = __shfl_sync(0xffffffffu, (k < 32) ? e0 : e1, k & 31);
    float4 v4 = *(const float4*)(VIP + ((size_t)h * NIP_ + k) * DH_ + lane * 4);
    a.x = fmaf(p, v4.x, a.x); a.y = fmaf(p, v4.y, a.y);
    a.z = fmaf(p, v4.z, a.z); a.w = fmaf(p, v4.w, a.w);
  }
  float* dst = am + (size_t)s * D_ + h * DH_ + lane * 4;
  float4 cur = *(float4*)dst;
  cur.x += a.x * inv; cur.y += a.y * inv; cur.z += a.z * inv; cur.w += a.w * inv;
  *(float4*)dst = cur;
}

// ---------------- launch ----------------
extern "C" void kernel_launch(void* const* d_in, const int* in_sizes, int n_in,
                              void* d_out, int out_size) {
  const float* hs   = (const float*)d_in[0];
  const float* ehs  = (const float*)d_in[1];
  const float* img  = (const float*)d_in[2];
  const float* Wq   = (const float*)d_in[3];  const float* bq  = (const float*)d_in[4];
  const float* Wk   = (const float*)d_in[5];  const float* bk  = (const float*)d_in[6];
  const float* Wv   = (const float*)d_in[7];  const float* bv  = (const float*)d_in[8];
  const float* Waq  = (const float*)d_in[9];  const float* baq = (const float*)d_in[10];
  const float* Wak  = (const float*)d_in[11]; const float* bak = (const float*)d_in[12];
  const float* Wav  = (const float*)d_in[13]; const float* bav = (const float*)d_in[14];
  const float* Wo   = (const float*)d_in[15]; const float* bo  = (const float*)d_in[16];
  const float* Wao  = (const float*)d_in[17]; const float* bao = (const float*)d_in[18];
  const float* Wkip = (const float*)d_in[19]; const float* Wvip = (const float*)d_in[20];
  const float* lq_dn = (const float*)d_in[21]; const float* lq_up = (const float*)d_in[22];
  const float* lk_dn = (const float*)d_in[23]; const float* lk_up = (const float*)d_in[24];
  const float* lv_dn = (const float*)d_in[25]; const float* lv_up = (const float*)d_in[26];
  const float* lp_dn = (const float*)d_in[27]; const float* lp_up = (const float*)d_in[28];
  float* out = (float*)d_out;

  float *qproj, *kproj, *vproj, *eq, *ek, *ev, *kipp, *vipp;
  float *Q, *K, *V, *KIP, *VIP, *am, *ae;
  cudaGetSymbolAddress((void**)&qproj, g_qproj);
  cudaGetSymbolAddress((void**)&kproj, g_kproj);
  cudaGetSymbolAddress((void**)&vproj, g_vproj);
  cudaGetSymbolAddress((void**)&eq, g_eq);
  cudaGetSymbolAddress((void**)&ek, g_ek);
  cudaGetSymbolAddress((void**)&ev, g_ev);
  cudaGetSymbolAddress((void**)&kipp, g_kipp);
  cudaGetSymbolAddress((void**)&vipp, g_vipp);
  cudaGetSymbolAddress((void**)&Q, g_Q);
  cudaGetSymbolAddress((void**)&K, g_K);
  cudaGetSymbolAddress((void**)&V, g_V);
  cudaGetSymbolAddress((void**)&KIP, g_KIP);
  cudaGetSymbolAddress((void**)&VIP, g_VIP);
  cudaGetSymbolAddress((void**)&am, g_am);
  cudaGetSymbolAddress((void**)&ae, g_ae);

  const int ATTN_SMEM = (64 * 128 + 64 * 129 + 64 * 65) * (int)sizeof(float);  // 82432
  cudaFuncSetAttribute(attn_kernel, cudaFuncAttributeMaxDynamicSharedMemorySize, ATTN_SMEM);
  const int G128_SMEM = 65536;  // 2 stages x (16KB A + 16KB B)
  const int G64_SMEM  = 49152;
  cudaFuncSetAttribute(mma_gemm<128>, cudaFuncAttributeMaxDynamicSharedMemorySize, G128_SMEM);
  cudaFuncSetAttribute(mma_gemm<64>,  cudaFuncAttributeMaxDynamicSharedMemorySize, G64_SMEM);

  float* outMain = out + (size_t)ENC_ * D_;

  // --- main projections (q,k,v) batched in one launch + fused LoRA on last COND rows ---
  GB gqkv = {{hs, hs, hs}, {Wq, Wk, Wv}, {bq, bk, bv}, {qproj, kproj, vproj}, {S_, S_, S_}};
  mma_gemm<128><<<dim3(24, 16, 3), 256, G128_SMEM>>>(gqkv, D_, D_);
  const float* hsC = hs + (size_t)(S_ - COND_) * D_;
  lora_kernel<<<COND_, 256>>>(hsC, lq_dn, lq_up, qproj + (size_t)(S_ - COND_) * D_);
  lora_kernel<<<COND_, 256>>>(hsC, lk_dn, lk_up, kproj + (size_t)(S_ - COND_) * D_);
  lora_kernel<<<COND_, 256>>>(hsC, lv_dn, lv_up, vproj + (size_t)(S_ - COND_) * D_);

  // --- encoder projections batched; IP projections batched ---
  GB genc = {{ehs, ehs, ehs}, {Waq, Wak, Wav}, {baq, bak, bav}, {eq, ek, ev}, {ENC_, ENC_, ENC_}};
  mma_gemm<128><<<dim3(24, 4, 3), 256, G128_SMEM>>>(genc, D_, D_);
  GB gip = {{img, img, img}, {Wkip, Wvip, Wvip}, {nullptr, nullptr, nullptr},
            {kipp, vipp, vipp}, {NIP_, NIP_, NIP_}};
  mma_gemm<64><<<dim3(24, 1, 2), 256, G64_SMEM>>>(gip, D_, D_);

  // --- to_heads + RMS; build concatenated head-major Q/K/V ---
  heads_kernel<<<ENC_ * H_ / 8, 256>>>(eq, Q, ENC_, SL_, 0, 1);
  heads_kernel<<<S_ * H_ / 8, 256>>>(qproj, Q, S_, SL_, ENC_, 1);
  heads_kernel<<<ENC_ * H_ / 8, 256>>>(ek, K, ENC_, SL_, 0, 1);
  heads_kernel<<<S_ * H_ / 8, 256>>>(kproj, K, S_, SL_, ENC_, 1);
  heads_kernel<<<ENC_ * H_ / 8, 256>>>(ev, V, ENC_, SL_, 0, 0);
  heads_kernel<<<S_ * H_ / 8, 256>>>(vproj, V, S_, SL_, ENC_, 0);
  heads_kernel<<<NIP_ * H_ / 8, 256>>>(kipp, KIP, NIP_, NIP_, 0, 1);
  heads_kernel<<<NIP_ * H_ / 8, 256>>>(vipp, VIP, NIP_, NIP_, 0, 0);

  // --- attention: main joint attention writes, IP attention accumulates ---
  attn_kernel<<<dim3(SL_ / 64, H_), 256, ATTN_SMEM>>>(Q, K, V, ae, am);
  ip_attn_kernel<<<H_ * S_ / 8, 256>>>(Q, KIP, VIP, am);

  // --- output projections (Wo + Wao batched) + output LoRA ---
  GB gout = {{am, ae, ae}, {Wo, Wao, Wao}, {bo, bao, bao}, {outMain, out, out}, {S_, ENC_, ENC_}};
  mma_gemm<128><<<dim3(24, 16, 2), 256, G128_SMEM>>>(gout, D_, D_);
  float* outCond = outMain + (size_t)(S_ - COND_) * D_;
  lora_kernel<<<COND_, 256>>>(outCond, lp_dn, lp_up, outCond);
}

// round 6
// speedup vs baseline: 3.9796x; 1.4238x over previous
#include <cuda_runtime.h>
#include <math.h>
#include <stdint.h>

// ---------------- problem constants ----------------
#define D_    3072
#define S_    2048
#define H_    24
#define DH_   128
#define ENC_  512
#define NIP_  64
#define COND_ 1024
#define SL_   2560   // ENC + S
#define SB_   1536   // SL - COND
#define RANK_ 16
#define EPS_  1e-5f
#define SCALE_ 0.08838834764831845f  // 1/sqrt(128)

// ---------------- scratch (device globals; no allocations allowed) ----------------
__device__ float g_qproj[S_ * D_];
__device__ float g_kproj[S_ * D_];
__device__ float g_vproj[S_ * D_];
__device__ float g_eq[ENC_ * D_];
__device__ float g_ek[ENC_ * D_];
__device__ float g_ev[ENC_ * D_];
__device__ float g_kipp[NIP_ * D_];
__device__ float g_vipp[NIP_ * D_];
__device__ float g_Q[H_ * SL_ * DH_];
__device__ float g_K[H_ * SL_ * DH_];
__device__ float g_V[H_ * SL_ * DH_];
__device__ float g_KIP[H_ * NIP_ * DH_];
__device__ float g_VIP[H_ * NIP_ * DH_];
__device__ float g_am[S_ * D_];      // main attention out (+ ip out), token-major
__device__ float g_ae[ENC_ * D_];    // encoder attention out

// ---------------- tf32 helpers ----------------
__device__ __forceinline__ uint32_t f2tf32(float x) {
  uint32_t r;
  asm("cvt.rna.tf32.f32 %0, %1;" : "=r"(r) : "f"(x));
  return r;
}

__device__ __forceinline__ void mma_tf32(float c[4], const uint32_t a[4], const uint32_t b[2]) {
  asm("mma.sync.aligned.m16n8k8.row.col.f32.tf32.tf32.f32 "
      "{%0,%1,%2,%3}, {%4,%5,%6,%7}, {%8,%9}, {%0,%1,%2,%3};"
      : "+f"(c[0]), "+f"(c[1]), "+f"(c[2]), "+f"(c[3])
      : "r"(a[0]), "r"(a[1]), "r"(a[2]), "r"(a[3]), "r"(b[0]), "r"(b[1]));
}

// ---------------- batched tf32 tensor-core GEMM ----------------
struct GB {
  const float* A[3];
  const float* W[3];
  const float* bias[3];
  float* C[3];
  int M[3];
};

template <int BM>
__global__ void __launch_bounds__(256) mma_gemm(GB gb, int N, int K) {
  constexpr int BK = 32;
  constexpr int MT = BM / 32;
  constexpr int ASZ = (BM / 16) * 4 * 32 * 4;
  constexpr int BSZ = 16 * 4 * 32 * 2;
  extern __shared__ uint32_t smu[];
  uint32_t* As0 = smu;
  uint32_t* As1 = smu + ASZ;
  uint32_t* Bs0 = smu + 2 * ASZ;
  uint32_t* Bs1 = smu + 2 * ASZ + BSZ;

  const int z = blockIdx.z;
  const float* __restrict__ A = gb.A[z];
  const float* __restrict__ W = gb.W[z];
  const float* __restrict__ bias = gb.bias[z];
  float* __restrict__ C = gb.C[z];
  const int M = gb.M[z];

  const int tid = threadIdx.x;
  const int lane = tid & 31;
  const int wid = tid >> 5;
  const int warpM = wid >> 2;
  const int warpN = wid & 3;
  const int m0 = blockIdx.y * BM;
  const int n0 = blockIdx.x * 128;
  if (m0 >= M) return;

  float4 pa[MT];
  float4 pb[4];

  auto ldg = [&](int k0) {
#pragma unroll
    for (int p = 0; p < MT; p++) {
      int idx = tid + p * 256;
      int r = idx >> 3, c4 = (idx & 7) << 2;
      pa[p] = *(const float4*)(A + (size_t)(m0 + r) * K + k0 + c4);
    }
#pragma unroll
    for (int p = 0; p < 4; p++) {
      int idx = tid + p * 256;
      int kr = idx >> 5, c4 = (idx & 31) << 2;
      pb[p] = *(const float4*)(W + (size_t)(k0 + kr) * N + n0 + c4);
    }
  };

  auto stor = [&](uint32_t* Ad, uint32_t* Bd) {
#pragma unroll
    for (int p = 0; p < MT; p++) {
      int idx = tid + p * 256;
      int r = idx >> 3, c4 = (idx & 7) << 2;
      int t = r >> 4, gid = r & 7, half = (r >> 3) & 1;
      int ks = c4 >> 3, khalf = (c4 >> 2) & 1;
      int slot = half + 2 * khalf;
      uint32_t* base = Ad + (t * 4 + ks) * 32 * 4 + slot;
      base[((gid * 4 + 0) ^ ks) * 4] = f2tf32(pa[p].x);
      base[((gid * 4 + 1) ^ ks) * 4] = f2tf32(pa[p].y);
      base[((gid * 4 + 2) ^ ks) * 4] = f2tf32(pa[p].z);
      base[((gid * 4 + 3) ^ ks) * 4] = f2tf32(pa[p].w);
    }
#pragma unroll
    for (int p = 0; p < 4; p++) {
      int idx = tid + p * 256;
      int kr = idx >> 5, c4 = (idx & 31) << 2;
      int ks = kr >> 3, kk = kr & 7, tig = kk & 3, khalf = kk >> 2;
      int nt = c4 >> 3, gg = c4 & 7;
      uint32_t* base = Bd + (nt * 4 + ks) * 32 * 2 + khalf;
      base[((((gg + 0) * 4 + tig)) ^ nt) * 2] = f2tf32(pb[p].x);
      base[((((gg + 1) * 4 + tig)) ^ nt) * 2] = f2tf32(pb[p].y);
      base[((((gg + 2) * 4 + tig)) ^ nt) * 2] = f2tf32(pb[p].z);
      base[((((gg + 3) * 4 + tig)) ^ nt) * 2] = f2tf32(pb[p].w);
    }
  };

  float acc[MT][4][4];
#pragma unroll
  for (int mt = 0; mt < MT; mt++)
#pragma unroll
    for (int nt = 0; nt < 4; nt++)
#pragma unroll
      for (int i = 0; i < 4; i++) acc[mt][nt][i] = 0.f;

  ldg(0);
  stor(As0, Bs0);
  __syncthreads();

  const int NKT = K / BK;
  for (int kt = 0; kt < NKT; kt++) {
    const uint32_t* Ab = (kt & 1) ? As1 : As0;
    const uint32_t* Bb = (kt & 1) ? Bs1 : Bs0;
    const bool more = (kt + 1) < NKT;
    if (more) ldg((kt + 1) * BK);

#pragma unroll
    for (int ks = 0; ks < 4; ks++) {
      uint32_t a[MT][4];
      uint32_t b[4][2];
#pragma unroll
      for (int mt = 0; mt < MT; mt++) {
        uint4 t4 = *(const uint4*)(Ab + (((warpM * MT + mt) * 4 + ks) * 32 + (lane ^ ks)) * 4);
        a[mt][0] = t4.x; a[mt][1] = t4.y; a[mt][2] = t4.z; a[mt][3] = t4.w;
      }
#pragma unroll
      for (int nt = 0; nt < 4; nt++) {
        int ntg = warpN * 4 + nt;
        uint2 t2 = *(const uint2*)(Bb + ((ntg * 4 + ks) * 32 + (lane ^ ntg)) * 2);
        b[nt][0] = t2.x; b[nt][1] = t2.y;
      }
#pragma unroll
      for (int mt = 0; mt < MT; mt++)
#pragma unroll
        for (int nt = 0; nt < 4; nt++) mma_tf32(acc[mt][nt], a[mt], b[nt]);
    }

    if (more) stor((kt & 1) ? As0 : As1, (kt & 1) ? Bs0 : Bs1);
    __syncthreads();
  }

  const int gid = lane >> 2, tig = lane & 3;
  float bb[4][2];
#pragma unroll
  for (int nt = 0; nt < 4; nt++) {
    int col = n0 + (warpN * 4 + nt) * 8 + tig * 2;
    bb[nt][0] = bias ? bias[col] : 0.f;
    bb[nt][1] = bias ? bias[col + 1] : 0.f;
  }
#pragma unroll
  for (int mt = 0; mt < MT; mt++) {
    int row = m0 + (warpM * MT + mt) * 16 + gid;
#pragma unroll
    for (int nt = 0; nt < 4; nt++) {
      int col = n0 + (warpN * 4 + nt) * 8 + tig * 2;
      float2 lo = make_float2(acc[mt][nt][0] + bb[nt][0], acc[mt][nt][1] + bb[nt][1]);
      float2 hi = make_float2(acc[mt][nt][2] + bb[nt][0], acc[mt][nt][3] + bb[nt][1]);
      *(float2*)(C + (size_t)row * N + col) = lo;
      *(float2*)(C + (size_t)(row + 8) * N + col) = hi;
    }
  }
}

// ---------------- fused triple LoRA: C_t[r,:] += (A[r,:] @ dn_t) @ up_t, t=0..2 ----------------
struct L3 {
  const float* dn[3];
  const float* up[3];
  float* C[3];
};

__global__ void __launch_bounds__(256) lora3_kernel(const float* __restrict__ A, L3 g) {
  __shared__ float red[8 * 48];
  __shared__ float st[48];
  const int r = blockIdx.x, tid = threadIdx.x, lane = tid & 31, wid = tid >> 5;
  const float* a = A + (size_t)r * D_;
  float p[48];
#pragma unroll
  for (int i = 0; i < 48; i++) p[i] = 0.f;
  for (int k = tid; k < D_; k += 256) {
    float av = a[k];
#pragma unroll
    for (int t = 0; t < 3; t++) {
      const float* dk = g.dn[t] + k * 16;
      float4 d0 = *(const float4*)(dk);
      float4 d1 = *(const float4*)(dk + 4);
      float4 d2 = *(const float4*)(dk + 8);
      float4 d3 = *(const float4*)(dk + 12);
      float* pt = p + t * 16;
      pt[0]  = fmaf(av, d0.x, pt[0]);  pt[1]  = fmaf(av, d0.y, pt[1]);
      pt[2]  = fmaf(av, d0.z, pt[2]);  pt[3]  = fmaf(av, d0.w, pt[3]);
      pt[4]  = fmaf(av, d1.x, pt[4]);  pt[5]  = fmaf(av, d1.y, pt[5]);
      pt[6]  = fmaf(av, d1.z, pt[6]);  pt[7]  = fmaf(av, d1.w, pt[7]);
      pt[8]  = fmaf(av, d2.x, pt[8]);  pt[9]  = fmaf(av, d2.y, pt[9]);
      pt[10] = fmaf(av, d2.z, pt[10]); pt[11] = fmaf(av, d2.w, pt[11]);
      pt[12] = fmaf(av, d3.x, pt[12]); pt[13] = fmaf(av, d3.y, pt[13]);
      pt[14] = fmaf(av, d3.z, pt[14]); pt[15] = fmaf(av, d3.w, pt[15]);
    }
  }
#pragma unroll
  for (int o = 16; o; o >>= 1)
#pragma unroll
    for (int i = 0; i < 48; i++) p[i] += __shfl_xor_sync(0xffffffffu, p[i], o);
  if (lane == 0)
#pragma unroll
    for (int i = 0; i < 48; i++) red[wid * 48 + i] = p[i];
  __syncthreads();
  if (tid < 48) {
    float s = 0.f;
#pragma unroll
    for (int w = 0; w < 8; w++) s += red[w * 48 + tid];
    st[tid] = s;
  }
  __syncthreads();
  float t0[48];
#pragma unroll
  for (int i = 0; i < 48; i++) t0[i] = st[i];
  for (int c = tid; c < D_; c += 256) {
#pragma unroll
    for (int t = 0; t < 3; t++) {
      float s = 0.f;
#pragma unroll
      for (int i = 0; i < 16; i++) s = fmaf(t0[t * 16 + i], g.up[t][(size_t)i * D_ + c], s);
      g.C[t][(size_t)r * D_ + c] += s;
    }
  }
}

// single LoRA for the output projection
__global__ void __launch_bounds__(256) lora_kernel(
    const float* __restrict__ A, const float* __restrict__ dn,
    const float* __restrict__ up, float* __restrict__ C) {
  __shared__ float red[8 * 16];
  __shared__ float st[16];
  const int r = blockIdx.x, tid = threadIdx.x, lane = tid & 31, wid = tid >> 5;
  const float* a = A + (size_t)r * D_;
  float p[16];
#pragma unroll
  for (int i = 0; i < 16; i++) p[i] = 0.f;
  for (int k = tid; k < D_; k += 256) {
    float av = a[k];
    float4 d0 = *(const float4*)(dn + k * 16);
    float4 d1 = *(const float4*)(dn + k * 16 + 4);
    float4 d2 = *(const float4*)(dn + k * 16 + 8);
    float4 d3 = *(const float4*)(dn + k * 16 + 12);
    p[0]  = fmaf(av, d0.x, p[0]);  p[1]  = fmaf(av, d0.y, p[1]);
    p[2]  = fmaf(av, d0.z, p[2]);  p[3]  = fmaf(av, d0.w, p[3]);
    p[4]  = fmaf(av, d1.x, p[4]);  p[5]  = fmaf(av, d1.y, p[5]);
    p[6]  = fmaf(av, d1.z, p[6]);  p[7]  = fmaf(av, d1.w, p[7]);
    p[8]  = fmaf(av, d2.x, p[8]);  p[9]  = fmaf(av, d2.y, p[9]);
    p[10] = fmaf(av, d2.z, p[10]); p[11] = fmaf(av, d2.w, p[11]);
    p[12] = fmaf(av, d3.x, p[12]); p[13] = fmaf(av, d3.y, p[13]);
    p[14] = fmaf(av, d3.z, p[14]); p[15] = fmaf(av, d3.w, p[15]);
  }
#pragma unroll
  for (int o = 16; o; o >>= 1)
#pragma unroll
    for (int i = 0; i < 16; i++) p[i] += __shfl_xor_sync(0xffffffffu, p[i], o);
  if (lane == 0)
#pragma unroll
    for (int i = 0; i < 16; i++) red[wid * 16 + i] = p[i];
  __syncthreads();
  if (tid < 16) {
    float s = 0.f;
#pragma unroll
    for (int w = 0; w < 8; w++) s += red[w * 16 + tid];
    st[tid] = s;
  }
  __syncthreads();
  float t0[16];
#pragma unroll
  for (int i = 0; i < 16; i++) t0[i] = st[i];
  float* crow = C + (size_t)r * D_;
  for (int c = tid; c < D_; c += 256) {
    float s = 0.f;
#pragma unroll
    for (int i = 0; i < 16; i++) s = fmaf(t0[i], up[(size_t)i * D_ + c], s);
    crow[c] += s;
  }
}

// ---------------- to_heads (+ optional per-head RMS) ----------------
struct H3 {
  const float* src[3];
  float* dst[3];
  int rms[3];
};

__global__ void heads3_kernel(H3 p, int M, int rowOff) {
  const int z = blockIdx.y;
  const float* proj = p.src[z];
  float* out = p.dst[z];
  const int doRMS = p.rms[z];
  int gw = (blockIdx.x * blockDim.x + threadIdx.x) >> 5;
  int lane = threadIdx.x & 31;
  if (gw >= M * H_) return;
  int s2 = gw / H_, h = gw - s2 * H_;
  float4 v = *(const float4*)(proj + (size_t)s2 * D_ + h * DH_ + lane * 4);
  if (doRMS) {
    float ss = v.x * v.x + v.y * v.y + v.z * v.z + v.w * v.w;
#pragma unroll
    for (int o = 16; o; o >>= 1) ss += __shfl_xor_sync(0xffffffffu, ss, o);
    float r = rsqrtf(ss * (1.f / DH_) + EPS_);
    v.x *= r; v.y *= r; v.z *= r; v.w *= r;
  }
  *(float4*)(out + ((size_t)h * SL_ + rowOff + s2) * DH_ + lane * 4) = v;
}

__global__ void heads_kernel(const float* __restrict__ proj, float* __restrict__ out,
                             int M, int outSeq, int rowOff, int doRMS) {
  int gw = (blockIdx.x * blockDim.x + threadIdx.x) >> 5;
  int lane = threadIdx.x & 31;
  if (gw >= M * H_) return;
  int s2 = gw / H_, h = gw - s2 * H_;
  float4 v = *(const float4*)(proj + (size_t)s2 * D_ + h * DH_ + lane * 4);
  if (doRMS) {
    float ss = v.x * v.x + v.y * v.y + v.z * v.z + v.w * v.w;
#pragma unroll
    for (int o = 16; o; o >>= 1) ss += __shfl_xor_sync(0xffffffffu, ss, o);
    float r = rsqrtf(ss * (1.f / DH_) + EPS_);
    v.x *= r; v.y *= r; v.z *= r; v.w *= r;
  }
  *(float4*)(out + ((size_t)h * outSeq + rowOff + s2) * DH_ + lane * 4) = v;
}

// ---------------- tensor-core flash attention ----------------
// 128q x 64k tiles, 8 warps x 16 q-rows. Q frags in regs (scale folded).
// K stored hi/lo tf32 (2 MMAs removes K truncation); P split hi/lo (removes P
// truncation in PV). Key-permutation within 8-groups makes S C-frags the PV A-frags.
__global__ void __launch_bounds__(256) attn_mma_kernel(
    const float* __restrict__ Q, const float* __restrict__ K,
    const float* __restrict__ V, float* __restrict__ outE,
    float* __restrict__ outM) {
  extern __shared__ uint32_t smA[];
  uint32_t* Ks = smA;            // [(nt*16+ks)*32 + lane^ks]*4 + reg*2 + hilo : 16384 words
  uint32_t* Vs = smA + 16384;    // [(ntd*8+ks)*32 + lane^ntd]*2 + reg : 8192 words
  const int tid = threadIdx.x, lane = tid & 31, w = tid >> 5;
  const int gid = lane >> 2, tig = lane & 3;
  const int h = blockIdx.y, q0 = blockIdx.x * 128;

  // Q fragments (scale folded in before tf32 truncation)
  uint32_t qf[16][4];
  {
    const float* Qg = Q + ((size_t)h * SL_ + q0) * DH_;
    const float* qr0 = Qg + (w * 16 + gid) * DH_;
    const float* qr1 = qr0 + 8 * DH_;
#pragma unroll
    for (int ks = 0; ks < 16; ks++) {
      qf[ks][0] = f2tf32(qr0[ks * 8 + tig] * SCALE_);
      qf[ks][1] = f2tf32(qr1[ks * 8 + tig] * SCALE_);
      qf[ks][2] = f2tf32(qr0[ks * 8 + tig + 4] * SCALE_);
      qf[ks][3] = f2tf32(qr1[ks * 8 + tig + 4] * SCALE_);
    }
  }

  float o[16][4];
#pragma unroll
  for (int i = 0; i < 16; i++) { o[i][0] = o[i][1] = o[i][2] = o[i][3] = 0.f; }
  float m0 = -1e30f, m1 = -1e30f, l0 = 0.f, l1 = 0.f;

  const int kt0 = (q0 >= SB_) ? (SB_ / 64) : 0;
  for (int kt = kt0; kt < SL_ / 64; kt++) {
    __syncthreads();  // previous compute done before overwriting K/V
    // ---- K tile -> hi/lo tf32 fragments (key j placed at n' = pi(j)) ----
    {
      const float* Kt = K + ((size_t)h * SL_ + kt * 64) * DH_;
#pragma unroll
      for (int it = 0; it < 8; it++) {
        int idx = tid + it * 256;
        int r = idx >> 5, c4 = (idx & 31) << 2;
        float4 v = *(const float4*)(Kt + r * DH_ + c4);
        int nt = r >> 3, j = r & 7;
        int nn = ((j & 3) << 1) | (j >> 2);  // pi(j)
        float vv[4] = {v.x, v.y, v.z, v.w};
#pragma unroll
        for (int e = 0; e < 4; e++) {
          int c = c4 + e;
          int ks = c >> 3, reg = (c >> 2) & 1, tg = c & 3;
          int base = ((nt * 16 + ks) * 32 + ((nn * 4 + tg) ^ ks)) * 4 + reg * 2;
          uint32_t hi = f2tf32(vv[e]);
          Ks[base] = hi;
          Ks[base + 1] = f2tf32(vv[e] - __uint_as_float(hi));
        }
      }
    }
    // ---- V tile -> single tf32 fragments (no permutation) ----
    {
      const float* Vt = V + ((size_t)h * SL_ + kt * 64) * DH_;
#pragma unroll
      for (int it = 0; it < 8; it++) {
        int idx = tid + it * 256;
        int k2 = idx >> 5, c4 = (idx & 31) << 2;
        float4 v = *(const float4*)(Vt + k2 * DH_ + c4);
        int ks = k2 >> 3, reg = (k2 >> 2) & 1, tg = k2 & 3;
        float vv[4] = {v.x, v.y, v.z, v.w};
#pragma unroll
        for (int e = 0; e < 4; e++) {
          int c = c4 + e;
          int ntd = c >> 3, n = c & 7;
          Vs[((ntd * 8 + ks) * 32 + ((n * 4 + tg) ^ ntd)) * 2 + reg] = f2tf32(vv[e]);
        }
      }
    }
    __syncthreads();

    // ---- S = Q @ K^T (hi + lo) ----
    float sa[8][4];
#pragma unroll
    for (int nt = 0; nt < 8; nt++) { sa[nt][0] = sa[nt][1] = sa[nt][2] = sa[nt][3] = 0.f; }
#pragma unroll
    for (int ks = 0; ks < 16; ks++) {
#pragma unroll
      for (int nt = 0; nt < 8; nt++) {
        uint4 b4 = *(const uint4*)(Ks + ((nt * 16 + ks) * 32 + (lane ^ ks)) * 4);
        uint32_t bh[2] = {b4.x, b4.z};
        uint32_t bl[2] = {b4.y, b4.w};
        mma_tf32(sa[nt], qf[ks], bh);
        mma_tf32(sa[nt], qf[ks], bl);
      }
    }

    // ---- online softmax (rows gid -> c0,c1; gid+8 -> c2,c3) ----
    float rm0 = -1e30f, rm1 = -1e30f;
#pragma unroll
    for (int nt = 0; nt < 8; nt++) {
      rm0 = fmaxf(rm0, fmaxf(sa[nt][0], sa[nt][1]));
      rm1 = fmaxf(rm1, fmaxf(sa[nt][2], sa[nt][3]));
    }
#pragma unroll
    for (int off = 1; off < 4; off <<= 1) {
      rm0 = fmaxf(rm0, __shfl_xor_sync(0xffffffffu, rm0, off));
      rm1 = fmaxf(rm1, __shfl_xor_sync(0xffffffffu, rm1, off));
    }
    float mn0 = fmaxf(m0, rm0), mn1 = fmaxf(m1, rm1);
    float corr0 = __expf(m0 - mn0), corr1 = __expf(m1 - mn1);
    m0 = mn0; m1 = mn1;
    float rs0 = 0.f, rs1 = 0.f;
#pragma unroll
    for (int nt = 0; nt < 8; nt++) {
      sa[nt][0] = __expf(sa[nt][0] - mn0); rs0 += sa[nt][0];
      sa[nt][1] = __expf(sa[nt][1] - mn0); rs0 += sa[nt][1];
      sa[nt][2] = __expf(sa[nt][2] - mn1); rs1 += sa[nt][2];
      sa[nt][3] = __expf(sa[nt][3] - mn1); rs1 += sa[nt][3];
    }
#pragma unroll
    for (int off = 1; off < 4; off <<= 1) {
      rs0 += __shfl_xor_sync(0xffffffffu, rs0, off);
      rs1 += __shfl_xor_sync(0xffffffffu, rs1, off);
    }
    l0 = l0 * corr0 + rs0;
    l1 = l1 * corr1 + rs1;
#pragma unroll
    for (int i = 0; i < 16; i++) {
      o[i][0] *= corr0; o[i][1] *= corr0; o[i][2] *= corr1; o[i][3] *= corr1;
    }

    // ---- O += P @ V (P split hi/lo; S C-frags ARE the PV A-frags via pi) ----
#pragma unroll
    for (int nt = 0; nt < 8; nt++) {
      float pv0 = sa[nt][0], pv1 = sa[nt][2], pv2 = sa[nt][1], pv3 = sa[nt][3];
      uint32_t phi[4], plo[4];
      phi[0] = f2tf32(pv0); plo[0] = f2tf32(pv0 - __uint_as_float(phi[0]));
      phi[1] = f2tf32(pv1); plo[1] = f2tf32(pv1 - __uint_as_float(phi[1]));
      phi[2] = f2tf32(pv2); plo[2] = f2tf32(pv2 - __uint_as_float(phi[2]));
      phi[3] = f2tf32(pv3); plo[3] = f2tf32(pv3 - __uint_as_float(phi[3]));
#pragma unroll
      for (int ntd = 0; ntd < 16; ntd++) {
        uint2 b2 = *(const uint2*)(Vs + ((ntd * 8 + nt) * 32 + (lane ^ ntd)) * 2);
        uint32_t bb[2] = {b2.x, b2.y};
        mma_tf32(o[ntd], phi, bb);
        mma_tf32(o[ntd], plo, bb);
      }
    }
  }

  // ---- epilogue: normalize, scatter token-major ----
  float inv0 = 1.f / l0, inv1 = 1.f / l1;
  int row0 = q0 + w * 16 + gid, row1 = row0 + 8;
#pragma unroll
  for (int ntd = 0; ntd < 16; ntd++) {
    int col = h * DH_ + ntd * 8 + tig * 2;
    float2 v0 = make_float2(o[ntd][0] * inv0, o[ntd][1] * inv0);
    float2 v1 = make_float2(o[ntd][2] * inv1, o[ntd][3] * inv1);
    if (row0 < ENC_) {
      *(float2*)(outE + (size_t)row0 * D_ + col) = v0;
      *(float2*)(outE + (size_t)row1 * D_ + col) = v1;
    } else {
      *(float2*)(outM + (size_t)(row0 - ENC_) * D_ + col) = v0;
      *(float2*)(outM + (size_t)(row1 - ENC_) * D_ + col) = v1;
    }
  }
}

// ---------------- IP attention (64 keys): one warp per (h, s); += into g_am ----------------
__global__ void ip_attn_kernel(const float* __restrict__ Q, const float* __restrict__ KIP,
                               const float* __restrict__ VIP, float* __restrict__ am) {
  int gw = (blockIdx.x * blockDim.x + threadIdx.x) >> 5;
  int lane = threadIdx.x & 31;
  if (gw >= H_ * S_) return;
  int h = gw / S_, s = gw - h * S_;
  float4 q4 = *(const float4*)(Q + ((size_t)h * SL_ + ENC_ + s) * DH_ + lane * 4);
  float sc0 = 0.f, sc1 = 0.f;
#pragma unroll 8
  for (int k = 0; k < NIP_; k++) {
    float4 k4 = *(const float4*)(KIP + ((size_t)h * NIP_ + k) * DH_ + lane * 4);
    float d = q4.x * k4.x + q4.y * k4.y + q4.z * k4.z + q4.w * k4.w;
#pragma unroll
    for (int o = 16; o; o >>= 1) d += __shfl_xor_sync(0xffffffffu, d, o);
    d *= SCALE_;
    if ((k & 31) == lane) { if (k < 32) sc0 = d; else sc1 = d; }
  }
  float mx = fmaxf(sc0, sc1);
#pragma unroll
  for (int o = 16; o; o >>= 1) mx = fmaxf(mx, __shfl_xor_sync(0xffffffffu, mx, o));
  float e0 = __expf(sc0 - mx), e1 = __expf(sc1 - mx);
  float sum = e0 + e1;
#pragma unroll
  for (int o = 16; o; o >>= 1) sum += __shfl_xor_sync(0xffffffffu, sum, o);
  float inv = 1.f / sum;
  float4 a = make_float4(0.f, 0.f, 0.f, 0.f);
#pragma unroll 8
  for (int k = 0; k < NIP_; k++) {
    float p = __shfl_sync(0xffffffffu, (k < 32) ? e0 : e1, k & 31);
    float4 v4 = *(const float4*)(VIP + ((size_t)h * NIP_ + k) * DH_ + lane * 4);
    a.x = fmaf(p, v4.x, a.x); a.y = fmaf(p, v4.y, a.y);
    a.z = fmaf(p, v4.z, a.z); a.w = fmaf(p, v4.w, a.w);
  }
  float* dst = am + (size_t)s * D_ + h * DH_ + lane * 4;
  float4 cur = *(float4*)dst;
  cur.x += a.x * inv; cur.y += a.y * inv; cur.z += a.z * inv; cur.w += a.w * inv;
  *(float4*)dst = cur;
}

// ---------------- launch ----------------
extern "C" void kernel_launch(void* const* d_in, const int* in_sizes, int n_in,
                              void* d_out, int out_size) {
  const float* hs   = (const float*)d_in[0];
  const float* ehs  = (const float*)d_in[1];
  const float* img  = (const float*)d_in[2];
  const float* Wq   = (const float*)d_in[3];  const float* bq  = (const float*)d_in[4];
  const float* Wk   = (const float*)d_in[5];  const float* bk  = (const float*)d_in[6];
  const float* Wv   = (const float*)d_in[7];  const float* bv  = (const float*)d_in[8];
  const float* Waq  = (const float*)d_in[9];  const float* baq = (const float*)d_in[10];
  const float* Wak  = (const float*)d_in[11]; const float* bak = (const float*)d_in[12];
  const float* Wav  = (const float*)d_in[13]; const float* bav = (const float*)d_in[14];
  const float* Wo   = (const float*)d_in[15]; const float* bo  = (const float*)d_in[16];
  const float* Wao  = (const float*)d_in[17]; const float* bao = (const float*)d_in[18];
  const float* Wkip = (const float*)d_in[19]; const float* Wvip = (const float*)d_in[20];
  const float* lq_dn = (const float*)d_in[21]; const float* lq_up = (const float*)d_in[22];
  const float* lk_dn = (const float*)d_in[23]; const float* lk_up = (const float*)d_in[24];
  const float* lv_dn = (const float*)d_in[25]; const float* lv_up = (const float*)d_in[26];
  const float* lp_dn = (const float*)d_in[27]; const float* lp_up = (const float*)d_in[28];
  float* out = (float*)d_out;

  float *qproj, *kproj, *vproj, *eq, *ek, *ev, *kipp, *vipp;
  float *Q, *K, *V, *KIP, *VIP, *am, *ae;
  cudaGetSymbolAddress((void**)&qproj, g_qproj);
  cudaGetSymbolAddress((void**)&kproj, g_kproj);
  cudaGetSymbolAddress((void**)&vproj, g_vproj);
  cudaGetSymbolAddress((void**)&eq, g_eq);
  cudaGetSymbolAddress((void**)&ek, g_ek);
  cudaGetSymbolAddress((void**)&ev, g_ev);
  cudaGetSymbolAddress((void**)&kipp, g_kipp);
  cudaGetSymbolAddress((void**)&vipp, g_vipp);
  cudaGetSymbolAddress((void**)&Q, g_Q);
  cudaGetSymbolAddress((void**)&K, g_K);
  cudaGetSymbolAddress((void**)&V, g_V);
  cudaGetSymbolAddress((void**)&KIP, g_KIP);
  cudaGetSymbolAddress((void**)&VIP, g_VIP);
  cudaGetSymbolAddress((void**)&am, g_am);
  cudaGetSymbolAddress((void**)&ae, g_ae);

  const int G128_SMEM = 65536;
  const int G64_SMEM  = 49152;
  const int ATTN_SMEM = (16384 + 8192) * 4;  // 98304
  cudaFuncSetAttribute(mma_gemm<128>, cudaFuncAttributeMaxDynamicSharedMemorySize, G128_SMEM);
  cudaFuncSetAttribute(mma_gemm<64>,  cudaFuncAttributeMaxDynamicSharedMemorySize, G64_SMEM);
  cudaFuncSetAttribute(attn_mma_kernel, cudaFuncAttributeMaxDynamicSharedMemorySize, ATTN_SMEM);

  float* outMain = out + (size_t)ENC_ * D_;

  // --- main projections batched + fused triple LoRA on last COND rows ---
  GB gqkv = {{hs, hs, hs}, {Wq, Wk, Wv}, {bq, bk, bv}, {qproj, kproj, vproj}, {S_, S_, S_}};
  mma_gemm<128><<<dim3(24, 16, 3), 256, G128_SMEM>>>(gqkv, D_, D_);
  const float* hsC = hs + (size_t)(S_ - COND_) * D_;
  L3 l3 = {{lq_dn, lk_dn, lv_dn}, {lq_up, lk_up, lv_up},
           {qproj + (size_t)(S_ - COND_) * D_, kproj + (size_t)(S_ - COND_) * D_,
            vproj + (size_t)(S_ - COND_) * D_}};
  lora3_kernel<<<COND_, 256>>>(hsC, l3);

  // --- encoder projections batched; IP projections batched ---
  GB genc = {{ehs, ehs, ehs}, {Waq, Wak, Wav}, {baq, bak, bav}, {eq, ek, ev}, {ENC_, ENC_, ENC_}};
  mma_gemm<128><<<dim3(24, 4, 3), 256, G128_SMEM>>>(genc, D_, D_);
  GB gip = {{img, img, img}, {Wkip, Wvip, Wvip}, {nullptr, nullptr, nullptr},
            {kipp, vipp, vipp}, {NIP_, NIP_, NIP_}};
  mma_gemm<64><<<dim3(24, 1, 2), 256, G64_SMEM>>>(gip, D_, D_);

  // --- to_heads + RMS, batched trios ---
  H3 hmain = {{qproj, kproj, vproj}, {Q, K, V}, {1, 1, 0}};
  heads3_kernel<<<dim3(S_ * H_ / 8, 3), 256>>>(hmain, S_, ENC_);
  H3 henc = {{eq, ek, ev}, {Q, K, V}, {1, 1, 0}};
  heads3_kernel<<<dim3(ENC_ * H_ / 8, 3), 256>>>(henc, ENC_, 0);
  heads_kernel<<<NIP_ * H_ / 8, 256>>>(kipp, KIP, NIP_, NIP_, 0, 1);
  heads_kernel<<<NIP_ * H_ / 8, 256>>>(vipp, VIP, NIP_, NIP_, 0, 0);

  // --- attention: main joint attention writes, IP attention accumulates ---
  attn_mma_kernel<<<dim3(SL_ / 128, H_), 256, ATTN_SMEM>>>(Q, K, V, ae, am);
  ip_attn_kernel<<<H_ * S_ / 8, 256>>>(Q, KIP, VIP, am);

  // --- output projections (Wo + Wao batched) + output LoRA ---
  GB gout = {{am, ae, ae}, {Wo, Wao, Wao}, {bo, bao, bao}, {outMain, out, out}, {S_, ENC_, ENC_}};
  mma_gemm<128><<<dim3(24, 16, 2), 256, G128_SMEM>>>(gout, D_, D_);
  float* outCond = outMain + (size_t)(S_ - COND_) * D_;
  lora_kernel<<<COND_, 256>>>(outCond, lp_dn, lp_up, outCond);
}

// round 7
// speedup vs baseline: 4.3818x; 1.1011x over previous
#include <cuda_runtime.h>
#include <math.h>
#include <stdint.h>

// ---------------- problem constants ----------------
#define D_    3072
#define S_    2048
#define H_    24
#define DH_   128
#define ENC_  512
#define NIP_  64
#define COND_ 1024
#define SL_   2560   // ENC + S
#define SB_   1536   // SL - COND
#define RANK_ 16
#define EPS_  1e-5f
#define SCALE_ 0.08838834764831845f  // 1/sqrt(128)

// ---------------- scratch (device globals; no allocations allowed) ----------------
__device__ float g_Q[H_ * SL_ * DH_];
__device__ float g_K[H_ * SL_ * DH_];
__device__ float g_V[H_ * SL_ * DH_];
__device__ float g_KIP[H_ * NIP_ * DH_];
__device__ float g_VIP[H_ * NIP_ * DH_];
__device__ float g_am[S_ * D_];      // main attention out (+ ip out), token-major
__device__ float g_ae[ENC_ * D_];    // encoder attention out
__device__ float g_T3[3 * COND_ * RANK_];  // lora-down temps for q,k,v

// ---------------- tf32 helpers ----------------
__device__ __forceinline__ uint32_t f2tf32(float x) {
  uint32_t r;
  asm("cvt.rna.tf32.f32 %0, %1;" : "=r"(r) : "f"(x));
  return r;
}

__device__ __forceinline__ void mma_tf32(float c[4], const uint32_t a[4], const uint32_t b[2]) {
  asm("mma.sync.aligned.m16n8k8.row.col.f32.tf32.tf32.f32 "
      "{%0,%1,%2,%3}, {%4,%5,%6,%7}, {%8,%9}, {%0,%1,%2,%3};"
      : "+f"(c[0]), "+f"(c[1]), "+f"(c[2]), "+f"(c[3])
      : "r"(a[0]), "r"(a[1]), "r"(a[2]), "r"(a[3]), "r"(b[0]), "r"(b[1]));
}

// ---------------- lora-down: T[t][r][16] = hsC[r,:] @ dn_t (warp per row) ----------------
struct D3 { const float* dn[3]; };

__global__ void __launch_bounds__(256) lora_dn3(const float* __restrict__ A, D3 g,
                                                float* __restrict__ T) {
  const int tid = threadIdx.x, lane = tid & 31, w = tid >> 5;
  const int row = blockIdx.x * 8 + w;
  const float* a = A + (size_t)row * D_;
  float p[48];
#pragma unroll
  for (int i = 0; i < 48; i++) p[i] = 0.f;
  for (int k = lane; k < D_; k += 32) {
    float av = a[k];
#pragma unroll
    for (int t = 0; t < 3; t++) {
      const float* dk = g.dn[t] + k * 16;
      float4 d0 = *(const float4*)(dk);
      float4 d1 = *(const float4*)(dk + 4);
      float4 d2 = *(const float4*)(dk + 8);
      float4 d3 = *(const float4*)(dk + 12);
      float* pt = p + t * 16;
      pt[0]  = fmaf(av, d0.x, pt[0]);  pt[1]  = fmaf(av, d0.y, pt[1]);
      pt[2]  = fmaf(av, d0.z, pt[2]);  pt[3]  = fmaf(av, d0.w, pt[3]);
      pt[4]  = fmaf(av, d1.x, pt[4]);  pt[5]  = fmaf(av, d1.y, pt[5]);
      pt[6]  = fmaf(av, d1.z, pt[6]);  pt[7]  = fmaf(av, d1.w, pt[7]);
      pt[8]  = fmaf(av, d2.x, pt[8]);  pt[9]  = fmaf(av, d2.y, pt[9]);
      pt[10] = fmaf(av, d2.z, pt[10]); pt[11] = fmaf(av, d2.w, pt[11]);
      pt[12] = fmaf(av, d3.x, pt[12]); pt[13] = fmaf(av, d3.y, pt[13]);
      pt[14] = fmaf(av, d3.z, pt[14]); pt[15] = fmaf(av, d3.w, pt[15]);
    }
  }
#pragma unroll
  for (int off = 16; off; off >>= 1)
#pragma unroll
    for (int i = 0; i < 48; i++) p[i] += __shfl_xor_sync(0xffffffffu, p[i], off);
  if (lane == 0) {
#pragma unroll
    for (int t = 0; t < 3; t++) {
      float* dt = T + ((size_t)t * COND_ + row) * 16;
#pragma unroll
      for (int i = 0; i < 16; i += 4)
        *(float4*)(dt + i) = make_float4(p[t*16+i], p[t*16+i+1], p[t*16+i+2], p[t*16+i+3]);
    }
  }
}

// ---------------- fused tf32 GEMM: C = A@W (+bias) (+loraUp) (+perhead RMS) ----------------
// BM=128 x BN=128, BK=32, 256 threads, software pipelined + XOR-swizzled staging.
// Epilogue: bias add; lora-up add for rows >= M-COND (if up); per-head RMS (N-tile ==
// one head); write head-major dst[(head*seq + rowOff + row)*128 + col] (or row-major if seq==0).
struct GF {
  const float* A[5]; const float* W[5]; const float* bias[5];
  const float* T[5]; const float* up[5];
  float* dst[5];
  int M[5]; int seq[5]; int rowOff[5]; int rms[5];
};

__global__ void __launch_bounds__(256, 2) gemm_f(GF gf, int N, int K) {
  constexpr int BK = 32, MT = 4;
  constexpr int ASZ = 8 * 4 * 32 * 4;
  constexpr int BSZ = 16 * 4 * 32 * 2;
  extern __shared__ uint32_t smu[];
  uint32_t* As0 = smu;
  uint32_t* As1 = smu + ASZ;
  uint32_t* Bs0 = smu + 2 * ASZ;
  uint32_t* Bs1 = smu + 2 * ASZ + BSZ;

  const int z = blockIdx.z;
  const float* __restrict__ A = gf.A[z];
  const float* __restrict__ W = gf.W[z];
  const float* __restrict__ bias = gf.bias[z];
  const int M = gf.M[z];

  const int tid = threadIdx.x;
  const int lane = tid & 31;
  const int wid = tid >> 5;
  const int warpM = wid >> 2;
  const int warpN = wid & 3;
  const int m0 = blockIdx.y * 128;
  const int n0 = blockIdx.x * 128;
  if (m0 >= M) return;

  float4 pa[MT];
  float4 pb[4];

  auto ldg = [&](int k0) {
#pragma unroll
    for (int p = 0; p < MT; p++) {
      int idx = tid + p * 256;
      int r = idx >> 3, c4 = (idx & 7) << 2;
      pa[p] = (m0 + r < M) ? *(const float4*)(A + (size_t)(m0 + r) * K + k0 + c4)
                           : make_float4(0.f, 0.f, 0.f, 0.f);
    }
#pragma unroll
    for (int p = 0; p < 4; p++) {
      int idx = tid + p * 256;
      int kr = idx >> 5, c4 = (idx & 31) << 2;
      pb[p] = *(const float4*)(W + (size_t)(k0 + kr) * N + n0 + c4);
    }
  };

  auto stor = [&](uint32_t* Ad, uint32_t* Bd) {
#pragma unroll
    for (int p = 0; p < MT; p++) {
      int idx = tid + p * 256;
      int r = idx >> 3, c4 = (idx & 7) << 2;
      int t = r >> 4, gid = r & 7, half = (r >> 3) & 1;
      int ks = c4 >> 3, khalf = (c4 >> 2) & 1;
      int slot = half + 2 * khalf;
      uint32_t* base = Ad + (t * 4 + ks) * 32 * 4 + slot;
      base[((gid * 4 + 0) ^ ks) * 4] = f2tf32(pa[p].x);
      base[((gid * 4 + 1) ^ ks) * 4] = f2tf32(pa[p].y);
      base[((gid * 4 + 2) ^ ks) * 4] = f2tf32(pa[p].z);
      base[((gid * 4 + 3) ^ ks) * 4] = f2tf32(pa[p].w);
    }
#pragma unroll
    for (int p = 0; p < 4; p++) {
      int idx = tid + p * 256;
      int kr = idx >> 5, c4 = (idx & 31) << 2;
      int ks = kr >> 3, kk = kr & 7, tig = kk & 3, khalf = kk >> 2;
      int nt = c4 >> 3, gg = c4 & 7;
      uint32_t* base = Bd + (nt * 4 + ks) * 32 * 2 + khalf;
      base[((((gg + 0) * 4 + tig)) ^ nt) * 2] = f2tf32(pb[p].x);
      base[((((gg + 1) * 4 + tig)) ^ nt) * 2] = f2tf32(pb[p].y);
      base[((((gg + 2) * 4 + tig)) ^ nt) * 2] = f2tf32(pb[p].z);
      base[((((gg + 3) * 4 + tig)) ^ nt) * 2] = f2tf32(pb[p].w);
    }
  };

  float acc[MT][4][4];
#pragma unroll
  for (int mt = 0; mt < MT; mt++)
#pragma unroll
    for (int nt = 0; nt < 4; nt++)
#pragma unroll
      for (int i = 0; i < 4; i++) acc[mt][nt][i] = 0.f;

  ldg(0);
  stor(As0, Bs0);
  __syncthreads();

  const int NKT = K / BK;
  for (int kt = 0; kt < NKT; kt++) {
    const uint32_t* Ab = (kt & 1) ? As1 : As0;
    const uint32_t* Bb = (kt & 1) ? Bs1 : Bs0;
    const bool more = (kt + 1) < NKT;
    if (more) ldg((kt + 1) * BK);

#pragma unroll
    for (int ks = 0; ks < 4; ks++) {
      uint32_t a[MT][4];
      uint32_t b[4][2];
#pragma unroll
      for (int mt = 0; mt < MT; mt++) {
        uint4 t4 = *(const uint4*)(Ab + (((warpM * MT + mt) * 4 + ks) * 32 + (lane ^ ks)) * 4);
        a[mt][0] = t4.x; a[mt][1] = t4.y; a[mt][2] = t4.z; a[mt][3] = t4.w;
      }
#pragma unroll
      for (int nt = 0; nt < 4; nt++) {
        int ntg = warpN * 4 + nt;
        uint2 t2 = *(const uint2*)(Bb + ((ntg * 4 + ks) * 32 + (lane ^ ntg)) * 2);
        b[nt][0] = t2.x; b[nt][1] = t2.y;
      }
#pragma unroll
      for (int mt = 0; mt < MT; mt++)
#pragma unroll
        for (int nt = 0; nt < 4; nt++) mma_tf32(acc[mt][nt], a[mt], b[nt]);
    }

    if (more) stor((kt & 1) ? As0 : As1, (kt & 1) ? Bs0 : Bs1);
    __syncthreads();
  }

  // ---- fused epilogue ----
  const int gid = lane >> 2, tig = lane & 3;
  const float* Tz = gf.T[z];
  const float* upz = gf.up[z];
  float* dst = gf.dst[z];
  const int seq = gf.seq[z], rowOff = gf.rowOff[z], doRMS = gf.rms[z];

  float bb0[4], bb1[4];
#pragma unroll
  for (int nt = 0; nt < 4; nt++) {
    int col = n0 + (warpN * 4 + nt) * 8 + tig * 2;
    bb0[nt] = bias ? bias[col] : 0.f;
    bb1[nt] = bias ? bias[col + 1] : 0.f;
  }
#pragma unroll
  for (int mt = 0; mt < MT; mt++) {
    int gr0 = m0 + (warpM * MT + mt) * 16 + gid;
#pragma unroll
    for (int nt = 0; nt < 4; nt++) {
      acc[mt][nt][0] += bb0[nt]; acc[mt][nt][1] += bb1[nt];
      acc[mt][nt][2] += bb0[nt]; acc[mt][nt][3] += bb1[nt];
    }
    if (upz) {
      int l0 = gr0 - (M - COND_);
      int l1 = l0 + 8;
      if (l1 >= 0) {
        bool h0 = (l0 >= 0);
#pragma unroll
        for (int i0 = 0; i0 < 16; i0 += 4) {
          float4 t1q = *(const float4*)(Tz + (size_t)l1 * 16 + i0);
          float4 t0q = h0 ? *(const float4*)(Tz + (size_t)l0 * 16 + i0)
                          : make_float4(0.f, 0.f, 0.f, 0.f);
          float tv0[4] = {t0q.x, t0q.y, t0q.z, t0q.w};
          float tv1[4] = {t1q.x, t1q.y, t1q.z, t1q.w};
#pragma unroll
          for (int j = 0; j < 4; j++) {
#pragma unroll
            for (int nt = 0; nt < 4; nt++) {
              int col = n0 + (warpN * 4 + nt) * 8 + tig * 2;
              float2 u = *(const float2*)(upz + (size_t)(i0 + j) * N + col);
              acc[mt][nt][0] = fmaf(tv0[j], u.x, acc[mt][nt][0]);
              acc[mt][nt][1] = fmaf(tv0[j], u.y, acc[mt][nt][1]);
              acc[mt][nt][2] = fmaf(tv1[j], u.x, acc[mt][nt][2]);
              acc[mt][nt][3] = fmaf(tv1[j], u.y, acc[mt][nt][3]);
            }
          }
        }
      }
    }
  }

  if (doRMS) {
    float* ssm = (float*)smu;  // [128][4], 2KB (mainloop smem is dead now)
#pragma unroll
    for (int mt = 0; mt < MT; mt++) {
      int lr = (warpM * MT + mt) * 16 + gid;
      float ss0 = 0.f, ss1 = 0.f;
#pragma unroll
      for (int nt = 0; nt < 4; nt++) {
        ss0 = fmaf(acc[mt][nt][0], acc[mt][nt][0], ss0);
        ss0 = fmaf(acc[mt][nt][1], acc[mt][nt][1], ss0);
        ss1 = fmaf(acc[mt][nt][2], acc[mt][nt][2], ss1);
        ss1 = fmaf(acc[mt][nt][3], acc[mt][nt][3], ss1);
      }
      ss0 += __shfl_xor_sync(0xffffffffu, ss0, 1);
      ss0 += __shfl_xor_sync(0xffffffffu, ss0, 2);
      ss1 += __shfl_xor_sync(0xffffffffu, ss1, 1);
      ss1 += __shfl_xor_sync(0xffffffffu, ss1, 2);
      if (tig == 0) {
        ssm[lr * 4 + warpN] = ss0;
        ssm[(lr + 8) * 4 + warpN] = ss1;
      }
    }
    __syncthreads();
#pragma unroll
    for (int mt = 0; mt < MT; mt++) {
      int lr = (warpM * MT + mt) * 16 + gid;
      float4 s0 = *(const float4*)&ssm[lr * 4];
      float4 s1 = *(const float4*)&ssm[(lr + 8) * 4];
      float sc0 = rsqrtf((s0.x + s0.y + s0.z + s0.w) * (1.f / 128.f) + EPS_);
      float sc1 = rsqrtf((s1.x + s1.y + s1.z + s1.w) * (1.f / 128.f) + EPS_);
#pragma unroll
      for (int nt = 0; nt < 4; nt++) {
        acc[mt][nt][0] *= sc0; acc[mt][nt][1] *= sc0;
        acc[mt][nt][2] *= sc1; acc[mt][nt][3] *= sc1;
      }
    }
  }

  const int head = n0 >> 7;
#pragma unroll
  for (int mt = 0; mt < MT; mt++) {
    int gr0 = m0 + (warpM * MT + mt) * 16 + gid;
    int gr1 = gr0 + 8;
#pragma unroll
    for (int nt = 0; nt < 4; nt++) {
      int colh = (warpN * 4 + nt) * 8 + tig * 2;
      float2 v0 = make_float2(acc[mt][nt][0], acc[mt][nt][1]);
      float2 v1 = make_float2(acc[mt][nt][2], acc[mt][nt][3]);
      if (seq) {
        float* bp = dst + ((size_t)head * seq + rowOff) * 128 + colh;
        if (gr0 < M) *(float2*)(bp + (size_t)gr0 * 128) = v0;
        if (gr1 < M) *(float2*)(bp + (size_t)gr1 * 128) = v1;
      } else {
        if (gr0 < M) *(float2*)(dst + (size_t)gr0 * N + n0 + colh) = v0;
        if (gr1 < M) *(float2*)(dst + (size_t)gr1 * N + n0 + colh) = v1;
      }
    }
  }
}

// ---------------- single LoRA for the output projection (post-Wo, in-place) ----------------
__global__ void __launch_bounds__(256) lora_kernel(
    const float* __restrict__ A, const float* __restrict__ dn,
    const float* __restrict__ up, float* __restrict__ C) {
  __shared__ float red[8 * 16];
  __shared__ float st[16];
  const int r = blockIdx.x, tid = threadIdx.x, lane = tid & 31, wid = tid >> 5;
  const float* a = A + (size_t)r * D_;
  float p[16];
#pragma unroll
  for (int i = 0; i < 16; i++) p[i] = 0.f;
  for (int k = tid; k < D_; k += 256) {
    float av = a[k];
    float4 d0 = *(const float4*)(dn + k * 16);
    float4 d1 = *(const float4*)(dn + k * 16 + 4);
    float4 d2 = *(const float4*)(dn + k * 16 + 8);
    float4 d3 = *(const float4*)(dn + k * 16 + 12);
    p[0]  = fmaf(av, d0.x, p[0]);  p[1]  = fmaf(av, d0.y, p[1]);
    p[2]  = fmaf(av, d0.z, p[2]);  p[3]  = fmaf(av, d0.w, p[3]);
    p[4]  = fmaf(av, d1.x, p[4]);  p[5]  = fmaf(av, d1.y, p[5]);
    p[6]  = fmaf(av, d1.z, p[6]);  p[7]  = fmaf(av, d1.w, p[7]);
    p[8]  = fmaf(av, d2.x, p[8]);  p[9]  = fmaf(av, d2.y, p[9]);
    p[10] = fmaf(av, d2.z, p[10]); p[11] = fmaf(av, d2.w, p[11]);
    p[12] = fmaf(av, d3.x, p[12]); p[13] = fmaf(av, d3.y, p[13]);
    p[14] = fmaf(av, d3.z, p[14]); p[15] = fmaf(av, d3.w, p[15]);
  }
#pragma unroll
  for (int o = 16; o; o >>= 1)
#pragma unroll
    for (int i = 0; i < 16; i++) p[i] += __shfl_xor_sync(0xffffffffu, p[i], o);
  if (lane == 0)
#pragma unroll
    for (int i = 0; i < 16; i++) red[wid * 16 + i] = p[i];
  __syncthreads();
  if (tid < 16) {
    float s = 0.f;
#pragma unroll
    for (int w = 0; w < 8; w++) s += red[w * 16 + tid];
    st[tid] = s;
  }
  __syncthreads();
  float t0[16];
#pragma unroll
  for (int i = 0; i < 16; i++) t0[i] = st[i];
  float* crow = C + (size_t)r * D_;
  for (int c = tid; c < D_; c += 256) {
    float s = 0.f;
#pragma unroll
    for (int i = 0; i < 16; i++) s = fmaf(t0[i], up[(size_t)i * D_ + c], s);
    crow[c] += s;
  }
}

// ---------------- tensor-core flash attention ----------------
// 128q x 64k tiles, 8 warps x 16 q-rows. Q frags in regs (scale folded).
// K stored hi/lo tf32 (2 MMAs removes K truncation). PV uses single tf32 P
// (key-permutation makes S C-frags the PV A-frags).
__global__ void __launch_bounds__(256) attn_mma_kernel(
    const float* __restrict__ Q, const float* __restrict__ K,
    const float* __restrict__ V, float* __restrict__ outE,
    float* __restrict__ outM) {
  extern __shared__ uint32_t smA[];
  uint32_t* Ks = smA;            // 16384 words
  uint32_t* Vs = smA + 16384;    // 8192 words
  const int tid = threadIdx.x, lane = tid & 31, w = tid >> 5;
  const int gid = lane >> 2, tig = lane & 3;
  const int h = blockIdx.y, q0 = blockIdx.x * 128;

  uint32_t qf[16][4];
  {
    const float* Qg = Q + ((size_t)h * SL_ + q0) * DH_;
    const float* qr0 = Qg + (w * 16 + gid) * DH_;
    const float* qr1 = qr0 + 8 * DH_;
#pragma unroll
    for (int ks = 0; ks < 16; ks++) {
      qf[ks][0] = f2tf32(qr0[ks * 8 + tig] * SCALE_);
      qf[ks][1] = f2tf32(qr1[ks * 8 + tig] * SCALE_);
      qf[ks][2] = f2tf32(qr0[ks * 8 + tig + 4] * SCALE_);
      qf[ks][3] = f2tf32(qr1[ks * 8 + tig + 4] * SCALE_);
    }
  }

  float o[16][4];
#pragma unroll
  for (int i = 0; i < 16; i++) { o[i][0] = o[i][1] = o[i][2] = o[i][3] = 0.f; }
  float m0 = -1e30f, m1 = -1e30f, l0 = 0.f, l1 = 0.f;

  const int kt0 = (q0 >= SB_) ? (SB_ / 64) : 0;
  for (int kt = kt0; kt < SL_ / 64; kt++) {
    __syncthreads();
    {
      const float* Kt = K + ((size_t)h * SL_ + kt * 64) * DH_;
#pragma unroll
      for (int it = 0; it < 8; it++) {
        int idx = tid + it * 256;
        int r = idx >> 5, c4 = (idx & 31) << 2;
        float4 v = *(const float4*)(Kt + r * DH_ + c4);
        int nt = r >> 3, j = r & 7;
        int nn = ((j & 3) << 1) | (j >> 2);  // pi(j)
        float vv[4] = {v.x, v.y, v.z, v.w};
#pragma unroll
        for (int e = 0; e < 4; e++) {
          int c = c4 + e;
          int ks = c >> 3, reg = (c >> 2) & 1, tg = c & 3;
          int base = ((nt * 16 + ks) * 32 + ((nn * 4 + tg) ^ ks)) * 4 + reg * 2;
          uint32_t hi = f2tf32(vv[e]);
          Ks[base] = hi;
          Ks[base + 1] = f2tf32(vv[e] - __uint_as_float(hi));
        }
      }
    }
    {
      const float* Vt = V + ((size_t)h * SL_ + kt * 64) * DH_;
#pragma unroll
      for (int it = 0; it < 8; it++) {
        int idx = tid + it * 256;
        int k2 = idx >> 5, c4 = (idx & 31) << 2;
        float4 v = *(const float4*)(Vt + k2 * DH_ + c4);
        int ks = k2 >> 3, reg = (k2 >> 2) & 1, tg = k2 & 3;
        float vv[4] = {v.x, v.y, v.z, v.w};
#pragma unroll
        for (int e = 0; e < 4; e++) {
          int c = c4 + e;
          int ntd = c >> 3, n = c & 7;
          Vs[((ntd * 8 + ks) * 32 + ((n * 4 + tg) ^ ntd)) * 2 + reg] = f2tf32(vv[e]);
        }
      }
    }
    __syncthreads();

    // ---- S = Q @ K^T (hi + lo) ----
    float sa[8][4];
#pragma unroll
    for (int nt = 0; nt < 8; nt++) { sa[nt][0] = sa[nt][1] = sa[nt][2] = sa[nt][3] = 0.f; }
#pragma unroll
    for (int ks = 0; ks < 16; ks++) {
#pragma unroll
      for (int nt = 0; nt < 8; nt++) {
        uint4 b4 = *(const uint4*)(Ks + ((nt * 16 + ks) * 32 + (lane ^ ks)) * 4);
        uint32_t bh[2] = {b4.x, b4.z};
        uint32_t bl[2] = {b4.y, b4.w};
        mma_tf32(sa[nt], qf[ks], bh);
        mma_tf32(sa[nt], qf[ks], bl);
      }
    }

    // ---- online softmax ----
    float rm0 = -1e30f, rm1 = -1e30f;
#pragma unroll
    for (int nt = 0; nt < 8; nt++) {
      rm0 = fmaxf(rm0, fmaxf(sa[nt][0], sa[nt][1]));
      rm1 = fmaxf(rm1, fmaxf(sa[nt][2], sa[nt][3]));
    }
#pragma unroll
    for (int off = 1; off < 4; off <<= 1) {
      rm0 = fmaxf(rm0, __shfl_xor_sync(0xffffffffu, rm0, off));
      rm1 = fmaxf(rm1, __shfl_xor_sync(0xffffffffu, rm1, off));
    }
    float mn0 = fmaxf(m0, rm0), mn1 = fmaxf(m1, rm1);
    float corr0 = __expf(m0 - mn0), corr1 = __expf(m1 - mn1);
    m0 = mn0; m1 = mn1;
    float rs0 = 0.f, rs1 = 0.f;
#pragma unroll
    for (int nt = 0; nt < 8; nt++) {
      sa[nt][0] = __expf(sa[nt][0] - mn0); rs0 += sa[nt][0];
      sa[nt][1] = __expf(sa[nt][1] - mn0); rs0 += sa[nt][1];
      sa[nt][2] = __expf(sa[nt][2] - mn1); rs1 += sa[nt][2];
      sa[nt][3] = __expf(sa[nt][3] - mn1); rs1 += sa[nt][3];
    }
#pragma unroll
    for (int off = 1; off < 4; off <<= 1) {
      rs0 += __shfl_xor_sync(0xffffffffu, rs0, off);
      rs1 += __shfl_xor_sync(0xffffffffu, rs1, off);
    }
    l0 = l0 * corr0 + rs0;
    l1 = l1 * corr1 + rs1;
#pragma unroll
    for (int i = 0; i < 16; i++) {
      o[i][0] *= corr0; o[i][1] *= corr0; o[i][2] *= corr1; o[i][3] *= corr1;
    }

    // ---- O += P @ V (single tf32 P; S C-frags ARE the PV A-frags via pi) ----
#pragma unroll
    for (int nt = 0; nt < 8; nt++) {
      uint32_t pf[4];
      pf[0] = f2tf32(sa[nt][0]);
      pf[1] = f2tf32(sa[nt][2]);
      pf[2] = f2tf32(sa[nt][1]);
      pf[3] = f2tf32(sa[nt][3]);
#pragma unroll
      for (int ntd = 0; ntd < 16; ntd++) {
        uint2 b2 = *(const uint2*)(Vs + ((ntd * 8 + nt) * 32 + (lane ^ ntd)) * 2);
        uint32_t bb[2] = {b2.x, b2.y};
        mma_tf32(o[ntd], pf, bb);
      }
    }
  }

  // ---- epilogue: normalize, scatter token-major ----
  float inv0 = 1.f / l0, inv1 = 1.f / l1;
  int row0 = q0 + w * 16 + gid, row1 = row0 + 8;
#pragma unroll
  for (int ntd = 0; ntd < 16; ntd++) {
    int col = h * DH_ + ntd * 8 + tig * 2;
    float2 v0 = make_float2(o[ntd][0] * inv0, o[ntd][1] * inv0);
    float2 v1 = make_float2(o[ntd][2] * inv1, o[ntd][3] * inv1);
    if (row0 < ENC_) {
      *(float2*)(outE + (size_t)row0 * D_ + col) = v0;
      *(float2*)(outE + (size_t)row1 * D_ + col) = v1;
    } else {
      *(float2*)(outM + (size_t)(row0 - ENC_) * D_ + col) = v0;
      *(float2*)(outM + (size_t)(row1 - ENC_) * D_ + col) = v1;
    }
  }
}

// ---------------- IP attention (64 keys): one warp per (h, s); += into g_am ----------------
__global__ void ip_attn_kernel(const float* __restrict__ Q, const float* __restrict__ KIP,
                               const float* __restrict__ VIP, float* __restrict__ am) {
  int gw = (blockIdx.x * blockDim.x + threadIdx.x) >> 5;
  int lane = threadIdx.x & 31;
  if (gw >= H_ * S_) return;
  int h = gw / S_, s = gw - h * S_;
  float4 q4 = *(const float4*)(Q + ((size_t)h * SL_ + ENC_ + s) * DH_ + lane * 4);
  float sc0 = 0.f, sc1 = 0.f;
#pragma unroll 8
  for (int k = 0; k < NIP_; k++) {
    float4 k4 = *(const float4*)(KIP + ((size_t)h * NIP_ + k) * DH_ + lane * 4);
    float d = q4.x * k4.x + q4.y * k4.y + q4.z * k4.z + q4.w * k4.w;
#pragma unroll
    for (int o = 16; o; o >>= 1) d += __shfl_xor_sync(0xffffffffu, d, o);
    d *= SCALE_;
    if ((k & 31) == lane) { if (k < 32) sc0 = d; else sc1 = d; }
  }
  float mx = fmaxf(sc0, sc1);
#pragma unroll
  for (int o = 16; o; o >>= 1) mx = fmaxf(mx, __shfl_xor_sync(0xffffffffu, mx, o));
  float e0 = __expf(sc0 - mx), e1 = __expf(sc1 - mx);
  float sum = e0 + e1;
#pragma unroll
  for (int o = 16; o; o >>= 1) sum += __shfl_xor_sync(0xffffffffu, sum, o);
  float inv = 1.f / sum;
  float4 a = make_float4(0.f, 0.f, 0.f, 0.f);
#pragma unroll 8
  for (int k = 0; k < NIP_; k++) {
    float p = __shfl_sync(0xffffffffu, (k < 32) ? e0 : e1, k & 31);
    float4 v4 = *(const float4*)(VIP + ((size_t)h * NIP_ + k) * DH_ + lane * 4);
    a.x = fmaf(p, v4.x, a.x); a.y = fmaf(p, v4.y, a.y);
    a.z = fmaf(p, v4.z, a.z); a.w = fmaf(p, v4.w, a.w);
  }
  float* dst = am + (size_t)s * D_ + h * DH_ + lane * 4;
  float4 cur = *(float4*)dst;
  cur.x += a.x * inv; cur.y += a.y * inv; cur.z += a.z * inv; cur.w += a.w * inv;
  *(float4*)dst = cur;
}

// ---------------- launch ----------------
extern "C" void kernel_launch(void* const* d_in, const int* in_sizes, int n_in,
                              void* d_out, int out_size) {
  const float* hs   = (const float*)d_in[0];
  const float* ehs  = (const float*)d_in[1];
  const float* img  = (const float*)d_in[2];
  const float* Wq   = (const float*)d_in[3];  const float* bq  = (const float*)d_in[4];
  const float* Wk   = (const float*)d_in[5];  const float* bk  = (const float*)d_in[6];
  const float* Wv   = (const float*)d_in[7];  const float* bv  = (const float*)d_in[8];
  const float* Waq  = (const float*)d_in[9];  const float* baq = (const float*)d_in[10];
  const float* Wak  = (const float*)d_in[11]; const float* bak = (const float*)d_in[12];
  const float* Wav  = (const float*)d_in[13]; const float* bav = (const float*)d_in[14];
  const float* Wo   = (const float*)d_in[15]; const float* bo  = (const float*)d_in[16];
  const float* Wao  = (const float*)d_in[17]; const float* bao = (const float*)d_in[18];
  const float* Wkip = (const float*)d_in[19]; const float* Wvip = (const float*)d_in[20];
  const float* lq_dn = (const float*)d_in[21]; const float* lq_up = (const float*)d_in[22];
  const float* lk_dn = (const float*)d_in[23]; const float* lk_up = (const float*)d_in[24];
  const float* lv_dn = (const float*)d_in[25]; const float* lv_up = (const float*)d_in[26];
  const float* lp_dn = (const float*)d_in[27]; const float* lp_up = (const float*)d_in[28];
  float* out = (float*)d_out;

  float *Q, *K, *V, *KIP, *VIP, *am, *ae, *T3;
  cudaGetSymbolAddress((void**)&Q, g_Q);
  cudaGetSymbolAddress((void**)&K, g_K);
  cudaGetSymbolAddress((void**)&V, g_V);
  cudaGetSymbolAddress((void**)&KIP, g_KIP);
  cudaGetSymbolAddress((void**)&VIP, g_VIP);
  cudaGetSymbolAddress((void**)&am, g_am);
  cudaGetSymbolAddress((void**)&ae, g_ae);
  cudaGetSymbolAddress((void**)&T3, g_T3);

  const int G_SMEM = 65536;
  const int ATTN_SMEM = (16384 + 8192) * 4;  // 98304
  cudaFuncSetAttribute(gemm_f, cudaFuncAttributeMaxDynamicSharedMemorySize, G_SMEM);
  cudaFuncSetAttribute(attn_mma_kernel, cudaFuncAttributeMaxDynamicSharedMemorySize, ATTN_SMEM);

  float* outMain = out + (size_t)ENC_ * D_;
  const float* hsC = hs + (size_t)(S_ - COND_) * D_;

  // 1. lora-down temps for q,k,v
  D3 d3 = {{lq_dn, lk_dn, lv_dn}};
  lora_dn3<<<COND_ / 8, 256>>>(hsC, d3, T3);

  // 2. main QKV projections, fully fused (bias + lora-up + RMS + head-major)
  GF gqkv = {
    {hs, hs, hs, 0, 0}, {Wq, Wk, Wv, 0, 0}, {bq, bk, bv, 0, 0},
    {T3, T3 + COND_ * 16, T3 + 2 * COND_ * 16, 0, 0}, {lq_up, lk_up, lv_up, 0, 0},
    {Q, K, V, 0, 0},
    {S_, S_, S_, 1, 1}, {SL_, SL_, SL_, 1, 1}, {ENC_, ENC_, ENC_, 0, 0}, {1, 1, 0, 0, 0}};
  gemm_f<<<dim3(24, 16, 3), 256, G_SMEM>>>(gqkv, D_, D_);

  // 3. encoder + IP projections in one launch (bias/RMS as needed, head-major)
  GF gei = {
    {ehs, ehs, ehs, img, img}, {Waq, Wak, Wav, Wkip, Wvip}, {baq, bak, bav, 0, 0},
    {0, 0, 0, 0, 0}, {0, 0, 0, 0, 0},
    {Q, K, V, KIP, VIP},
    {ENC_, ENC_, ENC_, NIP_, NIP_}, {SL_, SL_, SL_, NIP_, NIP_},
    {0, 0, 0, 0, 0}, {1, 1, 0, 1, 0}};
  gemm_f<<<dim3(24, 4, 5), 256, G_SMEM>>>(gei, D_, D_);

  // 4/5. joint attention + IP attention (accumulates into am)
  attn_mma_kernel<<<dim3(SL_ / 128, H_), 256, ATTN_SMEM>>>(Q, K, V, ae, am);
  ip_attn_kernel<<<H_ * S_ / 8, 256>>>(Q, KIP, VIP, am);

  // 6. output projections (Wo + Wao batched), plain row-major epilogue
  GF gout = {
    {am, ae, 0, 0, 0}, {Wo, Wao, 0, 0, 0}, {bo, bao, 0, 0, 0},
    {0, 0, 0, 0, 0}, {0, 0, 0, 0, 0},
    {outMain, out, 0, 0, 0},
    {S_, ENC_, 1, 1, 1}, {0, 0, 0, 0, 0}, {0, 0, 0, 0, 0}, {0, 0, 0, 0, 0}};
  gemm_f<<<dim3(24, 16, 2), 256, G_SMEM>>>(gout, D_, D_);

  // 7. output LoRA (post-Wo, in-place on last COND rows)
  float* outCond = outMain + (size_t)(S_ - COND_) * D_;
  lora_kernel<<<COND_, 256>>>(outCond, lp_dn, lp_up, outCond);
}

// round 8
// speedup vs baseline: 5.0882x; 1.1612x over previous
#include <cuda_runtime.h>
#include <math.h>
#include <stdint.h>

// ---------------- problem constants ----------------
#define D_    3072
#define S_    2048
#define H_    24
#define DH_   128
#define ENC_  512
#define NIP_  64
#define COND_ 1024
#define SL_   2560   // ENC + S
#define SB_   1536   // SL - COND
#define RANK_ 16
#define EPS_  1e-5f
#define SCALE_ 0.08838834764831845f  // 1/sqrt(128)

// ---------------- scratch (device globals; no allocations allowed) ----------------
__device__ float g_Q[H_ * SL_ * DH_];
__device__ float g_K[H_ * SL_ * DH_];
__device__ float g_V[H_ * SL_ * DH_];
__device__ float g_KIP[H_ * NIP_ * DH_];
__device__ float g_VIP[H_ * NIP_ * DH_];
__device__ float g_am[S_ * D_];      // main attention out (incl. IP), token-major
__device__ float g_ae[ENC_ * D_];    // encoder attention out
__device__ float g_T3[3 * COND_ * RANK_];  // lora-down temps for q,k,v

// ---------------- tf32 helpers ----------------
__device__ __forceinline__ uint32_t f2tf32(float x) {
  uint32_t r;
  asm("cvt.rna.tf32.f32 %0, %1;" : "=r"(r) : "f"(x));
  return r;
}

__device__ __forceinline__ void mma_tf32(float c[4], const uint32_t a[4], const uint32_t b[2]) {
  asm("mma.sync.aligned.m16n8k8.row.col.f32.tf32.tf32.f32 "
      "{%0,%1,%2,%3}, {%4,%5,%6,%7}, {%8,%9}, {%0,%1,%2,%3};"
      : "+f"(c[0]), "+f"(c[1]), "+f"(c[2]), "+f"(c[3])
      : "r"(a[0]), "r"(a[1]), "r"(a[2]), "r"(a[3]), "r"(b[0]), "r"(b[1]));
}

// ---------------- lora-down: T[t][r][16] = hsC[r,:] @ dn_t (warp per row) ----------------
struct D3 { const float* dn[3]; };

__global__ void __launch_bounds__(256) lora_dn3(const float* __restrict__ A, D3 g,
                                                float* __restrict__ T) {
  const int tid = threadIdx.x, lane = tid & 31, w = tid >> 5;
  const int row = blockIdx.x * 8 + w;
  const float* a = A + (size_t)row * D_;
  float p[48];
#pragma unroll
  for (int i = 0; i < 48; i++) p[i] = 0.f;
  for (int k = lane; k < D_; k += 32) {
    float av = a[k];
#pragma unroll
    for (int t = 0; t < 3; t++) {
      const float* dk = g.dn[t] + k * 16;
      float4 d0 = *(const float4*)(dk);
      float4 d1 = *(const float4*)(dk + 4);
      float4 d2 = *(const float4*)(dk + 8);
      float4 d3 = *(const float4*)(dk + 12);
      float* pt = p + t * 16;
      pt[0]  = fmaf(av, d0.x, pt[0]);  pt[1]  = fmaf(av, d0.y, pt[1]);
      pt[2]  = fmaf(av, d0.z, pt[2]);  pt[3]  = fmaf(av, d0.w, pt[3]);
      pt[4]  = fmaf(av, d1.x, pt[4]);  pt[5]  = fmaf(av, d1.y, pt[5]);
      pt[6]  = fmaf(av, d1.z, pt[6]);  pt[7]  = fmaf(av, d1.w, pt[7]);
      pt[8]  = fmaf(av, d2.x, pt[8]);  pt[9]  = fmaf(av, d2.y, pt[9]);
      pt[10] = fmaf(av, d2.z, pt[10]); pt[11] = fmaf(av, d2.w, pt[11]);
      pt[12] = fmaf(av, d3.x, pt[12]); pt[13] = fmaf(av, d3.y, pt[13]);
      pt[14] = fmaf(av, d3.z, pt[14]); pt[15] = fmaf(av, d3.w, pt[15]);
    }
  }
#pragma unroll
  for (int off = 16; off; off >>= 1)
#pragma unroll
    for (int i = 0; i < 48; i++) p[i] += __shfl_xor_sync(0xffffffffu, p[i], off);
  if (lane == 0) {
#pragma unroll
    for (int t = 0; t < 3; t++) {
      float* dt = T + ((size_t)t * COND_ + row) * 16;
#pragma unroll
      for (int i = 0; i < 16; i += 4)
        *(float4*)(dt + i) = make_float4(p[t*16+i], p[t*16+i+1], p[t*16+i+2], p[t*16+i+3]);
    }
  }
}

// ---------------- fused tf32 GEMM: C = A@W (+bias) (+loraUp) (+perhead RMS) ----------------
struct GF {
  const float* A[5]; const float* W[5]; const float* bias[5];
  const float* T[5]; const float* up[5];
  float* dst[5];
  int M[5]; int seq[5]; int rowOff[5]; int rms[5];
};

__global__ void __launch_bounds__(256, 2) gemm_f(GF gf, int N, int K) {
  constexpr int BK = 32, MT = 4;
  constexpr int ASZ = 8 * 4 * 32 * 4;
  constexpr int BSZ = 16 * 4 * 32 * 2;
  extern __shared__ uint32_t smu[];
  uint32_t* As0 = smu;
  uint32_t* As1 = smu + ASZ;
  uint32_t* Bs0 = smu + 2 * ASZ;
  uint32_t* Bs1 = smu + 2 * ASZ + BSZ;

  const int z = blockIdx.z;
  const float* __restrict__ A = gf.A[z];
  const float* __restrict__ W = gf.W[z];
  const float* __restrict__ bias = gf.bias[z];
  const int M = gf.M[z];

  const int tid = threadIdx.x;
  const int lane = tid & 31;
  const int wid = tid >> 5;
  const int warpM = wid >> 2;
  const int warpN = wid & 3;
  const int m0 = blockIdx.y * 128;
  const int n0 = blockIdx.x * 128;
  if (m0 >= M) return;

  float4 pa[MT];
  float4 pb[4];

  auto ldg = [&](int k0) {
#pragma unroll
    for (int p = 0; p < MT; p++) {
      int idx = tid + p * 256;
      int r = idx >> 3, c4 = (idx & 7) << 2;
      pa[p] = (m0 + r < M) ? *(const float4*)(A + (size_t)(m0 + r) * K + k0 + c4)
                           : make_float4(0.f, 0.f, 0.f, 0.f);
    }
#pragma unroll
    for (int p = 0; p < 4; p++) {
      int idx = tid + p * 256;
      int kr = idx >> 5, c4 = (idx & 31) << 2;
      pb[p] = *(const float4*)(W + (size_t)(k0 + kr) * N + n0 + c4);
    }
  };

  auto stor = [&](uint32_t* Ad, uint32_t* Bd) {
#pragma unroll
    for (int p = 0; p < MT; p++) {
      int idx = tid + p * 256;
      int r = idx >> 3, c4 = (idx & 7) << 2;
      int t = r >> 4, gid = r & 7, half = (r >> 3) & 1;
      int ks = c4 >> 3, khalf = (c4 >> 2) & 1;
      int slot = half + 2 * khalf;
      uint32_t* base = Ad + (t * 4 + ks) * 32 * 4 + slot;
      base[((gid * 4 + 0) ^ ks) * 4] = f2tf32(pa[p].x);
      base[((gid * 4 + 1) ^ ks) * 4] = f2tf32(pa[p].y);
      base[((gid * 4 + 2) ^ ks) * 4] = f2tf32(pa[p].z);
      base[((gid * 4 + 3) ^ ks) * 4] = f2tf32(pa[p].w);
    }
#pragma unroll
    for (int p = 0; p < 4; p++) {
      int idx = tid + p * 256;
      int kr = idx >> 5, c4 = (idx & 31) << 2;
      int ks = kr >> 3, kk = kr & 7, tig = kk & 3, khalf = kk >> 2;
      int nt = c4 >> 3, gg = c4 & 7;
      uint32_t* base = Bd + (nt * 4 + ks) * 32 * 2 + khalf;
      base[((((gg + 0) * 4 + tig)) ^ nt) * 2] = f2tf32(pb[p].x);
      base[((((gg + 1) * 4 + tig)) ^ nt) * 2] = f2tf32(pb[p].y);
      base[((((gg + 2) * 4 + tig)) ^ nt) * 2] = f2tf32(pb[p].z);
      base[((((gg + 3) * 4 + tig)) ^ nt) * 2] = f2tf32(pb[p].w);
    }
  };

  float acc[MT][4][4];
#pragma unroll
  for (int mt = 0; mt < MT; mt++)
#pragma unroll
    for (int nt = 0; nt < 4; nt++)
#pragma unroll
      for (int i = 0; i < 4; i++) acc[mt][nt][i] = 0.f;

  ldg(0);
  stor(As0, Bs0);
  __syncthreads();

  const int NKT = K / BK;
  for (int kt = 0; kt < NKT; kt++) {
    const uint32_t* Ab = (kt & 1) ? As1 : As0;
    const uint32_t* Bb = (kt & 1) ? Bs1 : Bs0;
    const bool more = (kt + 1) < NKT;
    if (more) ldg((kt + 1) * BK);

#pragma unroll
    for (int ks = 0; ks < 4; ks++) {
      uint32_t a[MT][4];
      uint32_t b[4][2];
#pragma unroll
      for (int mt = 0; mt < MT; mt++) {
        uint4 t4 = *(const uint4*)(Ab + (((warpM * MT + mt) * 4 + ks) * 32 + (lane ^ ks)) * 4);
        a[mt][0] = t4.x; a[mt][1] = t4.y; a[mt][2] = t4.z; a[mt][3] = t4.w;
      }
#pragma unroll
      for (int nt = 0; nt < 4; nt++) {
        int ntg = warpN * 4 + nt;
        uint2 t2 = *(const uint2*)(Bb + ((ntg * 4 + ks) * 32 + (lane ^ ntg)) * 2);
        b[nt][0] = t2.x; b[nt][1] = t2.y;
      }
#pragma unroll
      for (int mt = 0; mt < MT; mt++)
#pragma unroll
        for (int nt = 0; nt < 4; nt++) mma_tf32(acc[mt][nt], a[mt], b[nt]);
    }

    if (more) stor((kt & 1) ? As0 : As1, (kt & 1) ? Bs0 : Bs1);
    __syncthreads();
  }

  // ---- fused epilogue ----
  const int gid = lane >> 2, tig = lane & 3;
  const float* Tz = gf.T[z];
  const float* upz = gf.up[z];
  float* dst = gf.dst[z];
  const int seq = gf.seq[z], rowOff = gf.rowOff[z], doRMS = gf.rms[z];

  float bb0[4], bb1[4];
#pragma unroll
  for (int nt = 0; nt < 4; nt++) {
    int col = n0 + (warpN * 4 + nt) * 8 + tig * 2;
    bb0[nt] = bias ? bias[col] : 0.f;
    bb1[nt] = bias ? bias[col + 1] : 0.f;
  }
#pragma unroll
  for (int mt = 0; mt < MT; mt++) {
    int gr0 = m0 + (warpM * MT + mt) * 16 + gid;
#pragma unroll
    for (int nt = 0; nt < 4; nt++) {
      acc[mt][nt][0] += bb0[nt]; acc[mt][nt][1] += bb1[nt];
      acc[mt][nt][2] += bb0[nt]; acc[mt][nt][3] += bb1[nt];
    }
    if (upz) {
      int l0 = gr0 - (M - COND_);
      int l1 = l0 + 8;
      if (l1 >= 0) {
        bool h0 = (l0 >= 0);
#pragma unroll
        for (int i0 = 0; i0 < 16; i0 += 4) {
          float4 t1q = *(const float4*)(Tz + (size_t)l1 * 16 + i0);
          float4 t0q = h0 ? *(const float4*)(Tz + (size_t)l0 * 16 + i0)
                          : make_float4(0.f, 0.f, 0.f, 0.f);
          float tv0[4] = {t0q.x, t0q.y, t0q.z, t0q.w};
          float tv1[4] = {t1q.x, t1q.y, t1q.z, t1q.w};
#pragma unroll
          for (int j = 0; j < 4; j++) {
#pragma unroll
            for (int nt = 0; nt < 4; nt++) {
              int col = n0 + (warpN * 4 + nt) * 8 + tig * 2;
              float2 u = *(const float2*)(upz + (size_t)(i0 + j) * N + col);
              acc[mt][nt][0] = fmaf(tv0[j], u.x, acc[mt][nt][0]);
              acc[mt][nt][1] = fmaf(tv0[j], u.y, acc[mt][nt][1]);
              acc[mt][nt][2] = fmaf(tv1[j], u.x, acc[mt][nt][2]);
              acc[mt][nt][3] = fmaf(tv1[j], u.y, acc[mt][nt][3]);
            }
          }
        }
      }
    }
  }

  if (doRMS) {
    float* ssm = (float*)smu;  // [128][4], 2KB (mainloop smem dead now)
#pragma unroll
    for (int mt = 0; mt < MT; mt++) {
      int lr = (warpM * MT + mt) * 16 + gid;
      float ss0 = 0.f, ss1 = 0.f;
#pragma unroll
      for (int nt = 0; nt < 4; nt++) {
        ss0 = fmaf(acc[mt][nt][0], acc[mt][nt][0], ss0);
        ss0 = fmaf(acc[mt][nt][1], acc[mt][nt][1], ss0);
        ss1 = fmaf(acc[mt][nt][2], acc[mt][nt][2], ss1);
        ss1 = fmaf(acc[mt][nt][3], acc[mt][nt][3], ss1);
      }
      ss0 += __shfl_xor_sync(0xffffffffu, ss0, 1);
      ss0 += __shfl_xor_sync(0xffffffffu, ss0, 2);
      ss1 += __shfl_xor_sync(0xffffffffu, ss1, 1);
      ss1 += __shfl_xor_sync(0xffffffffu, ss1, 2);
      if (tig == 0) {
        ssm[lr * 4 + warpN] = ss0;
        ssm[(lr + 8) * 4 + warpN] = ss1;
      }
    }
    __syncthreads();
#pragma unroll
    for (int mt = 0; mt < MT; mt++) {
      int lr = (warpM * MT + mt) * 16 + gid;
      float4 s0 = *(const float4*)&ssm[lr * 4];
      float4 s1 = *(const float4*)&ssm[(lr + 8) * 4];
      float sc0 = rsqrtf((s0.x + s0.y + s0.z + s0.w) * (1.f / 128.f) + EPS_);
      float sc1 = rsqrtf((s1.x + s1.y + s1.z + s1.w) * (1.f / 128.f) + EPS_);
#pragma unroll
      for (int nt = 0; nt < 4; nt++) {
        acc[mt][nt][0] *= sc0; acc[mt][nt][1] *= sc0;
        acc[mt][nt][2] *= sc1; acc[mt][nt][3] *= sc1;
      }
    }
  }

  const int head = n0 >> 7;
#pragma unroll
  for (int mt = 0; mt < MT; mt++) {
    int gr0 = m0 + (warpM * MT + mt) * 16 + gid;
    int gr1 = gr0 + 8;
#pragma unroll
    for (int nt = 0; nt < 4; nt++) {
      int colh = (warpN * 4 + nt) * 8 + tig * 2;
      float2 v0 = make_float2(acc[mt][nt][0], acc[mt][nt][1]);
      float2 v1 = make_float2(acc[mt][nt][2], acc[mt][nt][3]);
      if (seq) {
        float* bp = dst + ((size_t)head * seq + rowOff) * 128 + colh;
        if (gr0 < M) *(float2*)(bp + (size_t)gr0 * 128) = v0;
        if (gr1 < M) *(float2*)(bp + (size_t)gr1 * 128) = v1;
      } else {
        if (gr0 < M) *(float2*)(dst + (size_t)gr0 * N + n0 + colh) = v0;
        if (gr1 < M) *(float2*)(dst + (size_t)gr1 * N + n0 + colh) = v1;
      }
    }
  }
}

// ---------------- single LoRA for the output projection (post-Wo, in-place) ----------------
__global__ void __launch_bounds__(256) lora_kernel(
    const float* __restrict__ A, const float* __restrict__ dn,
    const float* __restrict__ up, float* __restrict__ C) {
  __shared__ float red[8 * 16];
  __shared__ float st[16];
  const int r = blockIdx.x, tid = threadIdx.x, lane = tid & 31, wid = tid >> 5;
  const float* a = A + (size_t)r * D_;
  float p[16];
#pragma unroll
  for (int i = 0; i < 16; i++) p[i] = 0.f;
  for (int k = tid; k < D_; k += 256) {
    float av = a[k];
    float4 d0 = *(const float4*)(dn + k * 16);
    float4 d1 = *(const float4*)(dn + k * 16 + 4);
    float4 d2 = *(const float4*)(dn + k * 16 + 8);
    float4 d3 = *(const float4*)(dn + k * 16 + 12);
    p[0]  = fmaf(av, d0.x, p[0]);  p[1]  = fmaf(av, d0.y, p[1]);
    p[2]  = fmaf(av, d0.z, p[2]);  p[3]  = fmaf(av, d0.w, p[3]);
    p[4]  = fmaf(av, d1.x, p[4]);  p[5]  = fmaf(av, d1.y, p[5]);
    p[6]  = fmaf(av, d1.z, p[6]);  p[7]  = fmaf(av, d1.w, p[7]);
    p[8]  = fmaf(av, d2.x, p[8]);  p[9]  = fmaf(av, d2.y, p[9]);
    p[10] = fmaf(av, d2.z, p[10]); p[11] = fmaf(av, d2.w, p[11]);
    p[12] = fmaf(av, d3.x, p[12]); p[13] = fmaf(av, d3.y, p[13]);
    p[14] = fmaf(av, d3.z, p[14]); p[15] = fmaf(av, d3.w, p[15]);
  }
#pragma unroll
  for (int o = 16; o; o >>= 1)
#pragma unroll
    for (int i = 0; i < 16; i++) p[i] += __shfl_xor_sync(0xffffffffu, p[i], o);
  if (lane == 0)
#pragma unroll
    for (int i = 0; i < 16; i++) red[wid * 16 + i] = p[i];
  __syncthreads();
  if (tid < 16) {
    float s = 0.f;
#pragma unroll
    for (int w = 0; w < 8; w++) s += red[w * 16 + tid];
    st[tid] = s;
  }
  __syncthreads();
  float t0[16];
#pragma unroll
  for (int i = 0; i < 16; i++) t0[i] = st[i];
  float* crow = C + (size_t)r * D_;
  for (int c = tid; c < D_; c += 256) {
    float s = 0.f;
#pragma unroll
    for (int i = 0; i < 16; i++) s = fmaf(t0[i], up[(size_t)i * D_ + c], s);
    crow[c] += s;
  }
}

// ---------------- tensor-core flash attention + fused IP attention ----------------
// 128q x 64k tiles, 8 warps x 16 q-rows. Q frags register-resident (scale folded).
// Single tf32 K (R6 calibration: truncation damped by softmax). K/V register-
// prefetched: all LDGs issued at tile top; V staged after softmax (loads hidden
// behind S MMAs). Blocks with q0>=ENC run one extra 64-key IP tile: complete
// softmax in regs, P pre-normalized, accumulates into the normalized main O.
__global__ void __launch_bounds__(256) attn_mma_kernel(
    const float* __restrict__ Q, const float* __restrict__ K,
    const float* __restrict__ V, const float* __restrict__ KIP,
    const float* __restrict__ VIP, float* __restrict__ outE,
    float* __restrict__ outM) {
  extern __shared__ uint32_t smA[];
  uint32_t* Ks = smA;            // [(nt*16+ks)*32 + lane^ks]*2 + reg : 8192 words
  uint32_t* Vs = smA + 8192;     // [(ntd*8+ks)*32 + lane^ntd]*2 + reg : 8192 words
  const int tid = threadIdx.x, lane = tid & 31, w = tid >> 5;
  const int gid = lane >> 2, tig = lane & 3;
  const int h = blockIdx.y, q0 = blockIdx.x * 128;

  uint32_t qf[16][4];
  {
    const float* Qg = Q + ((size_t)h * SL_ + q0) * DH_;
    const float* qr0 = Qg + (w * 16 + gid) * DH_;
    const float* qr1 = qr0 + 8 * DH_;
#pragma unroll
    for (int ks = 0; ks < 16; ks++) {
      qf[ks][0] = f2tf32(qr0[ks * 8 + tig] * SCALE_);
      qf[ks][1] = f2tf32(qr1[ks * 8 + tig] * SCALE_);
      qf[ks][2] = f2tf32(qr0[ks * 8 + tig + 4] * SCALE_);
      qf[ks][3] = f2tf32(qr1[ks * 8 + tig + 4] * SCALE_);
    }
  }

  float o[16][4];
#pragma unroll
  for (int i = 0; i < 16; i++) { o[i][0] = o[i][1] = o[i][2] = o[i][3] = 0.f; }
  float m0 = -1e30f, m1 = -1e30f, l0 = 0.f, l1 = 0.f;

  // per-thread load coordinates (same for K and V tiles)
  const int lr = tid >> 5;            // +32 per it : row in tile
  const int lc4 = (tid & 31) << 2;    // 4-col group

  const int kt0 = (q0 >= SB_) ? (SB_ / 64) : 0;
  for (int kt = kt0; kt < SL_ / 64; kt++) {
    __syncthreads();  // prior PV complete before overwriting Ks/Vs
    const float* Kt = K + ((size_t)h * SL_ + kt * 64) * DH_;
    const float* Vt = V + ((size_t)h * SL_ + kt * 64) * DH_;
    float4 ka[8], va[8];
#pragma unroll
    for (int it = 0; it < 8; it++) ka[it] = *(const float4*)(Kt + (lr + it * 8) * DH_ + lc4);
#pragma unroll
    for (int it = 0; it < 8; it++) va[it] = *(const float4*)(Vt + (lr + it * 8) * DH_ + lc4);
    // stage K (V loads still in flight)
#pragma unroll
    for (int it = 0; it < 8; it++) {
      int r = lr + it * 8;
      int nt = r >> 3, j = r & 7;
      int nn = ((j & 3) << 1) | (j >> 2);  // pi(j)
      float vv[4] = {ka[it].x, ka[it].y, ka[it].z, ka[it].w};
#pragma unroll
      for (int e = 0; e < 4; e++) {
        int c = lc4 + e;
        int ks = c >> 3, reg = (c >> 2) & 1, tg = c & 3;
        Ks[((nt * 16 + ks) * 32 + ((nn * 4 + tg) ^ ks)) * 2 + reg] = f2tf32(vv[e]);
      }
    }
    __syncthreads();

    // ---- S = Q @ K^T ----
    float sa[8][4];
#pragma unroll
    for (int nt = 0; nt < 8; nt++) { sa[nt][0] = sa[nt][1] = sa[nt][2] = sa[nt][3] = 0.f; }
#pragma unroll
    for (int ks = 0; ks < 16; ks++) {
#pragma unroll
      for (int nt = 0; nt < 8; nt++) {
        uint2 b2 = *(const uint2*)(Ks + ((nt * 16 + ks) * 32 + (lane ^ ks)) * 2);
        uint32_t bb[2] = {b2.x, b2.y};
        mma_tf32(sa[nt], qf[ks], bb);
      }
    }

    // ---- online softmax ----
    float rm0 = -1e30f, rm1 = -1e30f;
#pragma unroll
    for (int nt = 0; nt < 8; nt++) {
      rm0 = fmaxf(rm0, fmaxf(sa[nt][0], sa[nt][1]));
      rm1 = fmaxf(rm1, fmaxf(sa[nt][2], sa[nt][3]));
    }
#pragma unroll
    for (int off = 1; off < 4; off <<= 1) {
      rm0 = fmaxf(rm0, __shfl_xor_sync(0xffffffffu, rm0, off));
      rm1 = fmaxf(rm1, __shfl_xor_sync(0xffffffffu, rm1, off));
    }
    float mn0 = fmaxf(m0, rm0), mn1 = fmaxf(m1, rm1);
    float corr0 = __expf(m0 - mn0), corr1 = __expf(m1 - mn1);
    m0 = mn0; m1 = mn1;
    float rs0 = 0.f, rs1 = 0.f;
#pragma unroll
    for (int nt = 0; nt < 8; nt++) {
      sa[nt][0] = __expf(sa[nt][0] - mn0); rs0 += sa[nt][0];
      sa[nt][1] = __expf(sa[nt][1] - mn0); rs0 += sa[nt][1];
      sa[nt][2] = __expf(sa[nt][2] - mn1); rs1 += sa[nt][2];
      sa[nt][3] = __expf(sa[nt][3] - mn1); rs1 += sa[nt][3];
    }
#pragma unroll
    for (int off = 1; off < 4; off <<= 1) {
      rs0 += __shfl_xor_sync(0xffffffffu, rs0, off);
      rs1 += __shfl_xor_sync(0xffffffffu, rs1, off);
    }
    l0 = l0 * corr0 + rs0;
    l1 = l1 * corr1 + rs1;
#pragma unroll
    for (int i = 0; i < 16; i++) {
      o[i][0] *= corr0; o[i][1] *= corr0; o[i][2] *= corr1; o[i][3] *= corr1;
    }

    // stage V from prefetched regs
#pragma unroll
    for (int it = 0; it < 8; it++) {
      int k2 = lr + it * 8;
      int ks = k2 >> 3, reg = (k2 >> 2) & 1, tg = k2 & 3;
      float vv[4] = {va[it].x, va[it].y, va[it].z, va[it].w};
#pragma unroll
      for (int e = 0; e < 4; e++) {
        int c = lc4 + e;
        int ntd = c >> 3, n = c & 7;
        Vs[((ntd * 8 + ks) * 32 + ((n * 4 + tg) ^ ntd)) * 2 + reg] = f2tf32(vv[e]);
      }
    }
    __syncthreads();

    // ---- O += P @ V (S C-frags ARE the PV A-frags via pi) ----
#pragma unroll
    for (int nt = 0; nt < 8; nt++) {
      uint32_t pf[4];
      pf[0] = f2tf32(sa[nt][0]);
      pf[1] = f2tf32(sa[nt][2]);
      pf[2] = f2tf32(sa[nt][1]);
      pf[3] = f2tf32(sa[nt][3]);
#pragma unroll
      for (int ntd = 0; ntd < 16; ntd++) {
        uint2 b2 = *(const uint2*)(Vs + ((ntd * 8 + nt) * 32 + (lane ^ ntd)) * 2);
        uint32_t bb[2] = {b2.x, b2.y};
        mma_tf32(o[ntd], pf, bb);
      }
    }
  }

  // ---- normalize main result ----
  float inv0 = 1.f / l0, inv1 = 1.f / l1;
#pragma unroll
  for (int i = 0; i < 16; i++) {
    o[i][0] *= inv0; o[i][1] *= inv0; o[i][2] *= inv1; o[i][3] *= inv1;
  }

  // ---- fused IP attention tile (main rows only; one 64-key tile) ----
  if (q0 >= ENC_) {
    __syncthreads();
    const float* Kt = KIP + (size_t)h * NIP_ * DH_;
    const float* Vt = VIP + (size_t)h * NIP_ * DH_;
    float4 ka[8], va[8];
#pragma unroll
    for (int it = 0; it < 8; it++) ka[it] = *(const float4*)(Kt + (lr + it * 8) * DH_ + lc4);
#pragma unroll
    for (int it = 0; it < 8; it++) va[it] = *(const float4*)(Vt + (lr + it * 8) * DH_ + lc4);
#pragma unroll
    for (int it = 0; it < 8; it++) {
      int r = lr + it * 8;
      int nt = r >> 3, j = r & 7;
      int nn = ((j & 3) << 1) | (j >> 2);
      float vv[4] = {ka[it].x, ka[it].y, ka[it].z, ka[it].w};
#pragma unroll
      for (int e = 0; e < 4; e++) {
        int c = lc4 + e;
        int ks = c >> 3, reg = (c >> 2) & 1, tg = c & 3;
        Ks[((nt * 16 + ks) * 32 + ((nn * 4 + tg) ^ ks)) * 2 + reg] = f2tf32(vv[e]);
      }
    }
    __syncthreads();

    float sa[8][4];
#pragma unroll
    for (int nt = 0; nt < 8; nt++) { sa[nt][0] = sa[nt][1] = sa[nt][2] = sa[nt][3] = 0.f; }
#pragma unroll
    for (int ks = 0; ks < 16; ks++) {
#pragma unroll
      for (int nt = 0; nt < 8; nt++) {
        uint2 b2 = *(const uint2*)(Ks + ((nt * 16 + ks) * 32 + (lane ^ ks)) * 2);
        uint32_t bb[2] = {b2.x, b2.y};
        mma_tf32(sa[nt], qf[ks], bb);
      }
    }
    // complete softmax over the single tile
    float rm0 = -1e30f, rm1 = -1e30f;
#pragma unroll
    for (int nt = 0; nt < 8; nt++) {
      rm0 = fmaxf(rm0, fmaxf(sa[nt][0], sa[nt][1]));
      rm1 = fmaxf(rm1, fmaxf(sa[nt][2], sa[nt][3]));
    }
#pragma unroll
    for (int off = 1; off < 4; off <<= 1) {
      rm0 = fmaxf(rm0, __shfl_xor_sync(0xffffffffu, rm0, off));
      rm1 = fmaxf(rm1, __shfl_xor_sync(0xffffffffu, rm1, off));
    }
    float rs0 = 0.f, rs1 = 0.f;
#pragma unroll
    for (int nt = 0; nt < 8; nt++) {
      sa[nt][0] = __expf(sa[nt][0] - rm0); rs0 += sa[nt][0];
      sa[nt][1] = __expf(sa[nt][1] - rm0); rs0 += sa[nt][1];
      sa[nt][2] = __expf(sa[nt][2] - rm1); rs1 += sa[nt][2];
      sa[nt][3] = __expf(sa[nt][3] - rm1); rs1 += sa[nt][3];
    }
#pragma unroll
    for (int off = 1; off < 4; off <<= 1) {
      rs0 += __shfl_xor_sync(0xffffffffu, rs0, off);
      rs1 += __shfl_xor_sync(0xffffffffu, rs1, off);
    }
    float iv0 = 1.f / rs0, iv1 = 1.f / rs1;
    // stage V
#pragma unroll
    for (int it = 0; it < 8; it++) {
      int k2 = lr + it * 8;
      int ks = k2 >> 3, reg = (k2 >> 2) & 1, tg = k2 & 3;
      float vv[4] = {va[it].x, va[it].y, va[it].z, va[it].w};
#pragma unroll
      for (int e = 0; e < 4; e++) {
        int c = lc4 + e;
        int ntd = c >> 3, n = c & 7;
        Vs[((ntd * 8 + ks) * 32 + ((n * 4 + tg) ^ ntd)) * 2 + reg] = f2tf32(vv[e]);
      }
    }
    __syncthreads();
    // accumulate pre-normalized IP P@V straight into the normalized main O
#pragma unroll
    for (int nt = 0; nt < 8; nt++) {
      uint32_t pf[4];
      pf[0] = f2tf32(sa[nt][0] * iv0);
      pf[1] = f2tf32(sa[nt][2] * iv1);
      pf[2] = f2tf32(sa[nt][1] * iv0);
      pf[3] = f2tf32(sa[nt][3] * iv1);
#pragma unroll
      for (int ntd = 0; ntd < 16; ntd++) {
        uint2 b2 = *(const uint2*)(Vs + ((ntd * 8 + nt) * 32 + (lane ^ ntd)) * 2);
        uint32_t bb[2] = {b2.x, b2.y};
        mma_tf32(o[ntd], pf, bb);
      }
    }
  }

  // ---- epilogue: scatter token-major ----
  int row0 = q0 + w * 16 + gid, row1 = row0 + 8;
#pragma unroll
  for (int ntd = 0; ntd < 16; ntd++) {
    int col = h * DH_ + ntd * 8 + tig * 2;
    float2 v0 = make_float2(o[ntd][0], o[ntd][1]);
    float2 v1 = make_float2(o[ntd][2], o[ntd][3]);
    if (row0 < ENC_) {
      *(float2*)(outE + (size_t)row0 * D_ + col) = v0;
      *(float2*)(outE + (size_t)row1 * D_ + col) = v1;
    } else {
      *(float2*)(outM + (size_t)(row0 - ENC_) * D_ + col) = v0;
      *(float2*)(outM + (size_t)(row1 - ENC_) * D_ + col) = v1;
    }
  }
}

// ---------------- launch ----------------
extern "C" void kernel_launch(void* const* d_in, const int* in_sizes, int n_in,
                              void* d_out, int out_size) {
  const float* hs   = (const float*)d_in[0];
  const float* ehs  = (const float*)d_in[1];
  const float* img  = (const float*)d_in[2];
  const float* Wq   = (const float*)d_in[3];  const float* bq  = (const float*)d_in[4];
  const float* Wk   = (const float*)d_in[5];  const float* bk  = (const float*)d_in[6];
  const float* Wv   = (const float*)d_in[7];  const float* bv  = (const float*)d_in[8];
  const float* Waq  = (const float*)d_in[9];  const float* baq = (const float*)d_in[10];
  const float* Wak  = (const float*)d_in[11]; const float* bak = (const float*)d_in[12];
  const float* Wav  = (const float*)d_in[13]; const float* bav = (const float*)d_in[14];
  const float* Wo   = (const float*)d_in[15]; const float* bo  = (const float*)d_in[16];
  const float* Wao  = (const float*)d_in[17]; const float* bao = (const float*)d_in[18];
  const float* Wkip = (const float*)d_in[19]; const float* Wvip = (const float*)d_in[20];
  const float* lq_dn = (const float*)d_in[21]; const float* lq_up = (const float*)d_in[22];
  const float* lk_dn = (const float*)d_in[23]; const float* lk_up = (const float*)d_in[24];
  const float* lv_dn = (const float*)d_in[25]; const float* lv_up = (const float*)d_in[26];
  const float* lp_dn = (const float*)d_in[27]; const float* lp_up = (const float*)d_in[28];
  float* out = (float*)d_out;

  float *Q, *K, *V, *KIP, *VIP, *am, *ae, *T3;
  cudaGetSymbolAddress((void**)&Q, g_Q);
  cudaGetSymbolAddress((void**)&K, g_K);
  cudaGetSymbolAddress((void**)&V, g_V);
  cudaGetSymbolAddress((void**)&KIP, g_KIP);
  cudaGetSymbolAddress((void**)&VIP, g_VIP);
  cudaGetSymbolAddress((void**)&am, g_am);
  cudaGetSymbolAddress((void**)&ae, g_ae);
  cudaGetSymbolAddress((void**)&T3, g_T3);

  const int G_SMEM = 65536;
  const int ATTN_SMEM = (8192 + 8192) * 4;  // 65536
  cudaFuncSetAttribute(gemm_f, cudaFuncAttributeMaxDynamicSharedMemorySize, G_SMEM);
  cudaFuncSetAttribute(attn_mma_kernel, cudaFuncAttributeMaxDynamicSharedMemorySize, ATTN_SMEM);

  float* outMain = out + (size_t)ENC_ * D_;
  const float* hsC = hs + (size_t)(S_ - COND_) * D_;

  // 1. lora-down temps for q,k,v
  D3 d3 = {{lq_dn, lk_dn, lv_dn}};
  lora_dn3<<<COND_ / 8, 256>>>(hsC, d3, T3);

  // 2. main QKV projections, fully fused (bias + lora-up + RMS + head-major)
  GF gqkv = {
    {hs, hs, hs, 0, 0}, {Wq, Wk, Wv, 0, 0}, {bq, bk, bv, 0, 0},
    {T3, T3 + COND_ * 16, T3 + 2 * COND_ * 16, 0, 0}, {lq_up, lk_up, lv_up, 0, 0},
    {Q, K, V, 0, 0},
    {S_, S_, S_, 1, 1}, {SL_, SL_, SL_, 1, 1}, {ENC_, ENC_, ENC_, 0, 0}, {1, 1, 0, 0, 0}};
  gemm_f<<<dim3(24, 16, 3), 256, G_SMEM>>>(gqkv, D_, D_);

  // 3. encoder + IP projections in one launch (bias/RMS as needed, head-major)
  GF gei = {
    {ehs, ehs, ehs, img, img}, {Waq, Wak, Wav, Wkip, Wvip}, {baq, bak, bav, 0, 0},
    {0, 0, 0, 0, 0}, {0, 0, 0, 0, 0},
    {Q, K, V, KIP, VIP},
    {ENC_, ENC_, ENC_, NIP_, NIP_}, {SL_, SL_, SL_, NIP_, NIP_},
    {0, 0, 0, 0, 0}, {1, 1, 0, 1, 0}};
  gemm_f<<<dim3(24, 4, 5), 256, G_SMEM>>>(gei, D_, D_);

  // 4. joint attention with fused IP attention
  attn_mma_kernel<<<dim3(SL_ / 128, H_), 256, ATTN_SMEM>>>(Q, K, V, KIP, VIP, ae, am);

  // 5. output projections (Wo + Wao batched), plain row-major epilogue
  GF gout = {
    {am, ae, 0, 0, 0}, {Wo, Wao, 0, 0, 0}, {bo, bao, 0, 0, 0},
    {0, 0, 0, 0, 0}, {0, 0, 0, 0, 0},
    {outMain, out, 0, 0, 0},
    {S_, ENC_, 1, 1, 1}, {0, 0, 0, 0, 0}, {0, 0, 0, 0, 0}, {0, 0, 0, 0, 0}};
  gemm_f<<<dim3(24, 16, 2), 256, G_SMEM>>>(gout, D_, D_);

  // 6. output LoRA (post-Wo, in-place on last COND rows)
  float* outCond = outMain + (size_t)(S_ - COND_) * D_;
  lora_kernel<<<COND_, 256>>>(outCond, lp_dn, lp_up, outCond);
}

// round 9
// speedup vs baseline: 5.4063x; 1.0625x over previous
#include <cuda_runtime.h>
#include <math.h>
#include <stdint.h>

// ---------------- problem constants ----------------
#define D_    3072
#define S_    2048
#define H_    24
#define DH_   128
#define ENC_  512
#define NIP_  64
#define COND_ 1024
#define SL_   2560   // ENC + S
#define SB_   1536   // SL - COND
#define RANK_ 16
#define EPS_  1e-5f
#define SCALE_ 0.08838834764831845f  // 1/sqrt(128)

// ---------------- scratch (device globals; no allocations allowed) ----------------
__device__ float g_Q[H_ * SL_ * DH_];
__device__ float g_K[H_ * SL_ * DH_];
__device__ float g_V[H_ * SL_ * DH_];
__device__ float g_KIP[H_ * NIP_ * DH_];
__device__ float g_VIP[H_ * NIP_ * DH_];
__device__ float g_am[S_ * D_];      // main attention out (incl. IP), token-major
__device__ float g_ae[ENC_ * D_];    // encoder attention out
__device__ float g_T3[3 * COND_ * RANK_];  // lora-down temps for q,k,v

// ---------------- tf32 helpers ----------------
__device__ __forceinline__ uint32_t f2tf32(float x) {
  uint32_t r;
  asm("cvt.rna.tf32.f32 %0, %1;" : "=r"(r) : "f"(x));
  return r;
}

__device__ __forceinline__ void mma_tf32(float c[4], const uint32_t a[4], const uint32_t b[2]) {
  asm("mma.sync.aligned.m16n8k8.row.col.f32.tf32.tf32.f32 "
      "{%0,%1,%2,%3}, {%4,%5,%6,%7}, {%8,%9}, {%0,%1,%2,%3};"
      : "+f"(c[0]), "+f"(c[1]), "+f"(c[2]), "+f"(c[3])
      : "r"(a[0]), "r"(a[1]), "r"(a[2]), "r"(a[3]), "r"(b[0]), "r"(b[1]));
}

// ---------------- lora-down: T[t][r][16] = hsC[r,:] @ dn_t (warp per row) ----------------
struct D3 { const float* dn[3]; };

__global__ void __launch_bounds__(256) lora_dn3(const float* __restrict__ A, D3 g,
                                                float* __restrict__ T) {
  const int tid = threadIdx.x, lane = tid & 31, w = tid >> 5;
  const int row = blockIdx.x * 8 + w;
  const float* a = A + (size_t)row * D_;
  float p[48];
#pragma unroll
  for (int i = 0; i < 48; i++) p[i] = 0.f;
  for (int k = lane; k < D_; k += 32) {
    float av = a[k];
#pragma unroll
    for (int t = 0; t < 3; t++) {
      const float* dk = g.dn[t] + k * 16;
      float4 d0 = *(const float4*)(dk);
      float4 d1 = *(const float4*)(dk + 4);
      float4 d2 = *(const float4*)(dk + 8);
      float4 d3 = *(const float4*)(dk + 12);
      float* pt = p + t * 16;
      pt[0]  = fmaf(av, d0.x, pt[0]);  pt[1]  = fmaf(av, d0.y, pt[1]);
      pt[2]  = fmaf(av, d0.z, pt[2]);  pt[3]  = fmaf(av, d0.w, pt[3]);
      pt[4]  = fmaf(av, d1.x, pt[4]);  pt[5]  = fmaf(av, d1.y, pt[5]);
      pt[6]  = fmaf(av, d1.z, pt[6]);  pt[7]  = fmaf(av, d1.w, pt[7]);
      pt[8]  = fmaf(av, d2.x, pt[8]);  pt[9]  = fmaf(av, d2.y, pt[9]);
      pt[10] = fmaf(av, d2.z, pt[10]); pt[11] = fmaf(av, d2.w, pt[11]);
      pt[12] = fmaf(av, d3.x, pt[12]); pt[13] = fmaf(av, d3.y, pt[13]);
      pt[14] = fmaf(av, d3.z, pt[14]); pt[15] = fmaf(av, d3.w, pt[15]);
    }
  }
#pragma unroll
  for (int off = 16; off; off >>= 1)
#pragma unroll
    for (int i = 0; i < 48; i++) p[i] += __shfl_xor_sync(0xffffffffu, p[i], off);
  if (lane == 0) {
#pragma unroll
    for (int t = 0; t < 3; t++) {
      float* dt = T + ((size_t)t * COND_ + row) * 16;
#pragma unroll
      for (int i = 0; i < 16; i += 4)
        *(float4*)(dt + i) = make_float4(p[t*16+i], p[t*16+i+1], p[t*16+i+2], p[t*16+i+3]);
    }
  }
}

// ---------------- fused tf32 GEMM: C = A@W (+bias) (+loraUp) (+perhead RMS) ----------------
// BM=256 x BN=128, BK=32, 256 threads, 8 warps as 4M x 2N (warp tile 64x64).
// Fatter warp tiles: fragment-LDS per k-tile = A(32KB)x2 + B(16KB)x4 = 128KB per
// 256x128 output (vs 96KB per 128x128 before) -> ~38% less crossbar per output.
// Software pipelined + XOR-swizzled staging, fused epilogue unchanged in math order.
struct GF {
  const float* A[5]; const float* W[5]; const float* bias[5];
  const float* T[5]; const float* up[5];
  float* dst[5];
  int M[5]; int seq[5]; int rowOff[5]; int rms[5];
};

__global__ void __launch_bounds__(256) gemm_f(GF gf, int N, int K) {
  constexpr int BK = 32;
  constexpr int ASZ = 16 * 4 * 32 * 4;   // 8192 words = 32KB per stage
  constexpr int BSZ = 16 * 4 * 32 * 2;   // 4096 words = 16KB per stage
  extern __shared__ uint32_t smu[];
  uint32_t* As0 = smu;
  uint32_t* As1 = smu + ASZ;
  uint32_t* Bs0 = smu + 2 * ASZ;
  uint32_t* Bs1 = smu + 2 * ASZ + BSZ;

  const int z = blockIdx.z;
  const float* __restrict__ A = gf.A[z];
  const float* __restrict__ W = gf.W[z];
  const float* __restrict__ bias = gf.bias[z];
  const int M = gf.M[z];

  const int tid = threadIdx.x;
  const int lane = tid & 31;
  const int wid = tid >> 5;
  const int warpM = wid >> 1;   // 0..3
  const int warpN = wid & 1;    // 0..1
  const int m0 = blockIdx.y * 256;
  const int n0 = blockIdx.x * 128;
  if (m0 >= M) return;

  float4 pa[8];
  float4 pb[4];

  auto ldg = [&](int k0) {
#pragma unroll
    for (int p = 0; p < 8; p++) {
      int idx = tid + p * 256;
      int r = idx >> 3, c4 = (idx & 7) << 2;
      pa[p] = (m0 + r < M) ? *(const float4*)(A + (size_t)(m0 + r) * K + k0 + c4)
                           : make_float4(0.f, 0.f, 0.f, 0.f);
    }
#pragma unroll
    for (int p = 0; p < 4; p++) {
      int idx = tid + p * 256;
      int kr = idx >> 5, c4 = (idx & 31) << 2;
      pb[p] = *(const float4*)(W + (size_t)(k0 + kr) * N + n0 + c4);
    }
  };

  auto stor = [&](uint32_t* Ad, uint32_t* Bd) {
#pragma unroll
    for (int p = 0; p < 8; p++) {
      int idx = tid + p * 256;
      int r = idx >> 3, c4 = (idx & 7) << 2;
      int t = r >> 4, gid = r & 7, half = (r >> 3) & 1;
      int ks = c4 >> 3, khalf = (c4 >> 2) & 1;
      int slot = half + 2 * khalf;
      uint32_t* base = Ad + (t * 4 + ks) * 32 * 4 + slot;
      base[((gid * 4 + 0) ^ ks) * 4] = f2tf32(pa[p].x);
      base[((gid * 4 + 1) ^ ks) * 4] = f2tf32(pa[p].y);
      base[((gid * 4 + 2) ^ ks) * 4] = f2tf32(pa[p].z);
      base[((gid * 4 + 3) ^ ks) * 4] = f2tf32(pa[p].w);
    }
#pragma unroll
    for (int p = 0; p < 4; p++) {
      int idx = tid + p * 256;
      int kr = idx >> 5, c4 = (idx & 31) << 2;
      int ks = kr >> 3, kk = kr & 7, tig = kk & 3, khalf = kk >> 2;
      int nt = c4 >> 3, gg = c4 & 7;
      uint32_t* base = Bd + (nt * 4 + ks) * 32 * 2 + khalf;
      base[((((gg + 0) * 4 + tig)) ^ nt) * 2] = f2tf32(pb[p].x);
      base[((((gg + 1) * 4 + tig)) ^ nt) * 2] = f2tf32(pb[p].y);
      base[((((gg + 2) * 4 + tig)) ^ nt) * 2] = f2tf32(pb[p].z);
      base[((((gg + 3) * 4 + tig)) ^ nt) * 2] = f2tf32(pb[p].w);
    }
  };

  float acc[4][8][4];
#pragma unroll
  for (int mt = 0; mt < 4; mt++)
#pragma unroll
    for (int nt = 0; nt < 8; nt++)
#pragma unroll
      for (int i = 0; i < 4; i++) acc[mt][nt][i] = 0.f;

  ldg(0);
  stor(As0, Bs0);
  __syncthreads();

  const int NKT = K / BK;
  for (int kt = 0; kt < NKT; kt++) {
    const uint32_t* Ab = (kt & 1) ? As1 : As0;
    const uint32_t* Bb = (kt & 1) ? Bs1 : Bs0;
    const bool more = (kt + 1) < NKT;
    if (more) ldg((kt + 1) * BK);

#pragma unroll
    for (int ks = 0; ks < 4; ks++) {
      uint32_t a[4][4];
      uint32_t b[8][2];
#pragma unroll
      for (int mt = 0; mt < 4; mt++) {
        uint4 t4 = *(const uint4*)(Ab + (((warpM * 4 + mt) * 4 + ks) * 32 + (lane ^ ks)) * 4);
        a[mt][0] = t4.x; a[mt][1] = t4.y; a[mt][2] = t4.z; a[mt][3] = t4.w;
      }
#pragma unroll
      for (int nt = 0; nt < 8; nt++) {
        int ntg = warpN * 8 + nt;
        uint2 t2 = *(const uint2*)(Bb + ((ntg * 4 + ks) * 32 + (lane ^ ntg)) * 2);
        b[nt][0] = t2.x; b[nt][1] = t2.y;
      }
#pragma unroll
      for (int mt = 0; mt < 4; mt++)
#pragma unroll
        for (int nt = 0; nt < 8; nt++) mma_tf32(acc[mt][nt], a[mt], b[nt]);
    }

    if (more) stor((kt & 1) ? As0 : As1, (kt & 1) ? Bs0 : Bs1);
    __syncthreads();
  }

  // ---- fused epilogue ----
  const int gid = lane >> 2, tig = lane & 3;
  const float* Tz = gf.T[z];
  const float* upz = gf.up[z];
  float* dst = gf.dst[z];
  const int seq = gf.seq[z], rowOff = gf.rowOff[z], doRMS = gf.rms[z];

  float bb0[8], bb1[8];
#pragma unroll
  for (int nt = 0; nt < 8; nt++) {
    int col = n0 + (warpN * 8 + nt) * 8 + tig * 2;
    bb0[nt] = bias ? bias[col] : 0.f;
    bb1[nt] = bias ? bias[col + 1] : 0.f;
  }
#pragma unroll
  for (int mt = 0; mt < 4; mt++) {
    int gr0 = m0 + (warpM * 4 + mt) * 16 + gid;
#pragma unroll
    for (int nt = 0; nt < 8; nt++) {
      acc[mt][nt][0] += bb0[nt]; acc[mt][nt][1] += bb1[nt];
      acc[mt][nt][2] += bb0[nt]; acc[mt][nt][3] += bb1[nt];
    }
    if (upz) {
      int l0 = gr0 - (M - COND_);
      int l1 = l0 + 8;
      if (l1 >= 0) {
        bool h0 = (l0 >= 0);
#pragma unroll
        for (int i0 = 0; i0 < 16; i0 += 4) {
          float4 t1q = *(const float4*)(Tz + (size_t)l1 * 16 + i0);
          float4 t0q = h0 ? *(const float4*)(Tz + (size_t)l0 * 16 + i0)
                          : make_float4(0.f, 0.f, 0.f, 0.f);
          float tv0[4] = {t0q.x, t0q.y, t0q.z, t0q.w};
          float tv1[4] = {t1q.x, t1q.y, t1q.z, t1q.w};
#pragma unroll
          for (int j = 0; j < 4; j++) {
#pragma unroll
            for (int nt = 0; nt < 8; nt++) {
              int col = n0 + (warpN * 8 + nt) * 8 + tig * 2;
              float2 u = *(const float2*)(upz + (size_t)(i0 + j) * N + col);
              acc[mt][nt][0] = fmaf(tv0[j], u.x, acc[mt][nt][0]);
              acc[mt][nt][1] = fmaf(tv0[j], u.y, acc[mt][nt][1]);
              acc[mt][nt][2] = fmaf(tv1[j], u.x, acc[mt][nt][2]);
              acc[mt][nt][3] = fmaf(tv1[j], u.y, acc[mt][nt][3]);
            }
          }
        }
      }
    }
  }

  if (doRMS) {
    float* ssm = (float*)smu;  // [256][2], 2KB (mainloop smem dead)
#pragma unroll
    for (int mt = 0; mt < 4; mt++) {
      int lr = (warpM * 4 + mt) * 16 + gid;
      float ss0 = 0.f, ss1 = 0.f;
#pragma unroll
      for (int nt = 0; nt < 8; nt++) {
        ss0 = fmaf(acc[mt][nt][0], acc[mt][nt][0], ss0);
        ss0 = fmaf(acc[mt][nt][1], acc[mt][nt][1], ss0);
        ss1 = fmaf(acc[mt][nt][2], acc[mt][nt][2], ss1);
        ss1 = fmaf(acc[mt][nt][3], acc[mt][nt][3], ss1);
      }
      ss0 += __shfl_xor_sync(0xffffffffu, ss0, 1);
      ss0 += __shfl_xor_sync(0xffffffffu, ss0, 2);
      ss1 += __shfl_xor_sync(0xffffffffu, ss1, 1);
      ss1 += __shfl_xor_sync(0xffffffffu, ss1, 2);
      if (tig == 0) {
        ssm[lr * 2 + warpN] = ss0;
        ssm[(lr + 8) * 2 + warpN] = ss1;
      }
    }
    __syncthreads();
#pragma unroll
    for (int mt = 0; mt < 4; mt++) {
      int lr = (warpM * 4 + mt) * 16 + gid;
      float s0 = ssm[lr * 2] + ssm[lr * 2 + 1];
      float s1 = ssm[(lr + 8) * 2] + ssm[(lr + 8) * 2 + 1];
      float sc0 = rsqrtf(s0 * (1.f / 128.f) + EPS_);
      float sc1 = rsqrtf(s1 * (1.f / 128.f) + EPS_);
#pragma unroll
      for (int nt = 0; nt < 8; nt++) {
        acc[mt][nt][0] *= sc0; acc[mt][nt][1] *= sc0;
        acc[mt][nt][2] *= sc1; acc[mt][nt][3] *= sc1;
      }
    }
  }

  const int head = n0 >> 7;
#pragma unroll
  for (int mt = 0; mt < 4; mt++) {
    int gr0 = m0 + (warpM * 4 + mt) * 16 + gid;
    int gr1 = gr0 + 8;
#pragma unroll
    for (int nt = 0; nt < 8; nt++) {
      int colh = (warpN * 8 + nt) * 8 + tig * 2;
      float2 v0 = make_float2(acc[mt][nt][0], acc[mt][nt][1]);
      float2 v1 = make_float2(acc[mt][nt][2], acc[mt][nt][3]);
      if (seq) {
        float* bp = dst + ((size_t)head * seq + rowOff) * 128 + colh;
        if (gr0 < M) *(float2*)(bp + (size_t)gr0 * 128) = v0;
        if (gr1 < M) *(float2*)(bp + (size_t)gr1 * 128) = v1;
      } else {
        if (gr0 < M) *(float2*)(dst + (size_t)gr0 * N + n0 + colh) = v0;
        if (gr1 < M) *(float2*)(dst + (size_t)gr1 * N + n0 + colh) = v1;
      }
    }
  }
}

// ---------------- single LoRA for the output projection (post-Wo, in-place) ----------------
__global__ void __launch_bounds__(256) lora_kernel(
    const float* __restrict__ A, const float* __restrict__ dn,
    const float* __restrict__ up, float* __restrict__ C) {
  __shared__ float red[8 * 16];
  __shared__ float st[16];
  const int r = blockIdx.x, tid = threadIdx.x, lane = tid & 31, wid = tid >> 5;
  const float* a = A + (size_t)r * D_;
  float p[16];
#pragma unroll
  for (int i = 0; i < 16; i++) p[i] = 0.f;
  for (int k = tid; k < D_; k += 256) {
    float av = a[k];
    float4 d0 = *(const float4*)(dn + k * 16);
    float4 d1 = *(const float4*)(dn + k * 16 + 4);
    float4 d2 = *(const float4*)(dn + k * 16 + 8);
    float4 d3 = *(const float4*)(dn + k * 16 + 12);
    p[0]  = fmaf(av, d0.x, p[0]);  p[1]  = fmaf(av, d0.y, p[1]);
    p[2]  = fmaf(av, d0.z, p[2]);  p[3]  = fmaf(av, d0.w, p[3]);
    p[4]  = fmaf(av, d1.x, p[4]);  p[5]  = fmaf(av, d1.y, p[5]);
    p[6]  = fmaf(av, d1.z, p[6]);  p[7]  = fmaf(av, d1.w, p[7]);
    p[8]  = fmaf(av, d2.x, p[8]);  p[9]  = fmaf(av, d2.y, p[9]);
    p[10] = fmaf(av, d2.z, p[10]); p[11] = fmaf(av, d2.w, p[11]);
    p[12] = fmaf(av, d3.x, p[12]); p[13] = fmaf(av, d3.y, p[13]);
    p[14] = fmaf(av, d3.z, p[14]); p[15] = fmaf(av, d3.w, p[15]);
  }
#pragma unroll
  for (int o = 16; o; o >>= 1)
#pragma unroll
    for (int i = 0; i < 16; i++) p[i] += __shfl_xor_sync(0xffffffffu, p[i], o);
  if (lane == 0)
#pragma unroll
    for (int i = 0; i < 16; i++) red[wid * 16 + i] = p[i];
  __syncthreads();
  if (tid < 16) {
    float s = 0.f;
#pragma unroll
    for (int w = 0; w < 8; w++) s += red[w * 16 + tid];
    st[tid] = s;
  }
  __syncthreads();
  float t0[16];
#pragma unroll
  for (int i = 0; i < 16; i++) t0[i] = st[i];
  float* crow = C + (size_t)r * D_;
  for (int c = tid; c < D_; c += 256) {
    float s = 0.f;
#pragma unroll
    for (int i = 0; i < 16; i++) s = fmaf(t0[i], up[(size_t)i * D_ + c], s);
    crow[c] += s;
  }
}

// ---------------- tensor-core flash attention + fused IP attention (unchanged R7) ----------------
__global__ void __launch_bounds__(256) attn_mma_kernel(
    const float* __restrict__ Q, const float* __restrict__ K,
    const float* __restrict__ V, const float* __restrict__ KIP,
    const float* __restrict__ VIP, float* __restrict__ outE,
    float* __restrict__ outM) {
  extern __shared__ uint32_t smA[];
  uint32_t* Ks = smA;            // 8192 words
  uint32_t* Vs = smA + 8192;     // 8192 words
  const int tid = threadIdx.x, lane = tid & 31, w = tid >> 5;
  const int gid = lane >> 2, tig = lane & 3;
  const int h = blockIdx.y, q0 = blockIdx.x * 128;

  uint32_t qf[16][4];
  {
    const float* Qg = Q + ((size_t)h * SL_ + q0) * DH_;
    const float* qr0 = Qg + (w * 16 + gid) * DH_;
    const float* qr1 = qr0 + 8 * DH_;
#pragma unroll
    for (int ks = 0; ks < 16; ks++) {
      qf[ks][0] = f2tf32(qr0[ks * 8 + tig] * SCALE_);
      qf[ks][1] = f2tf32(qr1[ks * 8 + tig] * SCALE_);
      qf[ks][2] = f2tf32(qr0[ks * 8 + tig + 4] * SCALE_);
      qf[ks][3] = f2tf32(qr1[ks * 8 + tig + 4] * SCALE_);
    }
  }

  float o[16][4];
#pragma unroll
  for (int i = 0; i < 16; i++) { o[i][0] = o[i][1] = o[i][2] = o[i][3] = 0.f; }
  float m0 = -1e30f, m1 = -1e30f, l0 = 0.f, l1 = 0.f;

  const int lr = tid >> 5;
  const int lc4 = (tid & 31) << 2;

  const int kt0 = (q0 >= SB_) ? (SB_ / 64) : 0;
  for (int kt = kt0; kt < SL_ / 64; kt++) {
    __syncthreads();
    const float* Kt = K + ((size_t)h * SL_ + kt * 64) * DH_;
    const float* Vt = V + ((size_t)h * SL_ + kt * 64) * DH_;
    float4 ka[8], va[8];
#pragma unroll
    for (int it = 0; it < 8; it++) ka[it] = *(const float4*)(Kt + (lr + it * 8) * DH_ + lc4);
#pragma unroll
    for (int it = 0; it < 8; it++) va[it] = *(const float4*)(Vt + (lr + it * 8) * DH_ + lc4);
#pragma unroll
    for (int it = 0; it < 8; it++) {
      int r = lr + it * 8;
      int nt = r >> 3, j = r & 7;
      int nn = ((j & 3) << 1) | (j >> 2);  // pi(j)
      float vv[4] = {ka[it].x, ka[it].y, ka[it].z, ka[it].w};
#pragma unroll
      for (int e = 0; e < 4; e++) {
        int c = lc4 + e;
        int ks = c >> 3, reg = (c >> 2) & 1, tg = c & 3;
        Ks[((nt * 16 + ks) * 32 + ((nn * 4 + tg) ^ ks)) * 2 + reg] = f2tf32(vv[e]);
      }
    }
    __syncthreads();

    float sa[8][4];
#pragma unroll
    for (int nt = 0; nt < 8; nt++) { sa[nt][0] = sa[nt][1] = sa[nt][2] = sa[nt][3] = 0.f; }
#pragma unroll
    for (int ks = 0; ks < 16; ks++) {
#pragma unroll
      for (int nt = 0; nt < 8; nt++) {
        uint2 b2 = *(const uint2*)(Ks + ((nt * 16 + ks) * 32 + (lane ^ ks)) * 2);
        uint32_t bb[2] = {b2.x, b2.y};
        mma_tf32(sa[nt], qf[ks], bb);
      }
    }

    float rm0 = -1e30f, rm1 = -1e30f;
#pragma unroll
    for (int nt = 0; nt < 8; nt++) {
      rm0 = fmaxf(rm0, fmaxf(sa[nt][0], sa[nt][1]));
      rm1 = fmaxf(rm1, fmaxf(sa[nt][2], sa[nt][3]));
    }
#pragma unroll
    for (int off = 1; off < 4; off <<= 1) {
      rm0 = fmaxf(rm0, __shfl_xor_sync(0xffffffffu, rm0, off));
      rm1 = fmaxf(rm1, __shfl_xor_sync(0xffffffffu, rm1, off));
    }
    float mn0 = fmaxf(m0, rm0), mn1 = fmaxf(m1, rm1);
    float corr0 = __expf(m0 - mn0), corr1 = __expf(m1 - mn1);
    m0 = mn0; m1 = mn1;
    float rs0 = 0.f, rs1 = 0.f;
#pragma unroll
    for (int nt = 0; nt < 8; nt++) {
      sa[nt][0] = __expf(sa[nt][0] - mn0); rs0 += sa[nt][0];
      sa[nt][1] = __expf(sa[nt][1] - mn0); rs0 += sa[nt][1];
      sa[nt][2] = __expf(sa[nt][2] - mn1); rs1 += sa[nt][2];
      sa[nt][3] = __expf(sa[nt][3] - mn1); rs1 += sa[nt][3];
    }
#pragma unroll
    for (int off = 1; off < 4; off <<= 1) {
      rs0 += __shfl_xor_sync(0xffffffffu, rs0, off);
      rs1 += __shfl_xor_sync(0xffffffffu, rs1, off);
    }
    l0 = l0 * corr0 + rs0;
    l1 = l1 * corr1 + rs1;
#pragma unroll
    for (int i = 0; i < 16; i++) {
      o[i][0] *= corr0; o[i][1] *= corr0; o[i][2] *= corr1; o[i][3] *= corr1;
    }

#pragma unroll
    for (int it = 0; it < 8; it++) {
      int k2 = lr + it * 8;
      int ks = k2 >> 3, reg = (k2 >> 2) & 1, tg = k2 & 3;
      float vv[4] = {va[it].x, va[it].y, va[it].z, va[it].w};
#pragma unroll
      for (int e = 0; e < 4; e++) {
        int c = lc4 + e;
        int ntd = c >> 3, n = c & 7;
        Vs[((ntd * 8 + ks) * 32 + ((n * 4 + tg) ^ ntd)) * 2 + reg] = f2tf32(vv[e]);
      }
    }
    __syncthreads();

#pragma unroll
    for (int nt = 0; nt < 8; nt++) {
      uint32_t pf[4];
      pf[0] = f2tf32(sa[nt][0]);
      pf[1] = f2tf32(sa[nt][2]);
      pf[2] = f2tf32(sa[nt][1]);
      pf[3] = f2tf32(sa[nt][3]);
#pragma unroll
      for (int ntd = 0; ntd < 16; ntd++) {
        uint2 b2 = *(const uint2*)(Vs + ((ntd * 8 + nt) * 32 + (lane ^ ntd)) * 2);
        uint32_t bb[2] = {b2.x, b2.y};
        mma_tf32(o[ntd], pf, bb);
      }
    }
  }

  float inv0 = 1.f / l0, inv1 = 1.f / l1;
#pragma unroll
  for (int i = 0; i < 16; i++) {
    o[i][0] *= inv0; o[i][1] *= inv0; o[i][2] *= inv1; o[i][3] *= inv1;
  }

  if (q0 >= ENC_) {
    __syncthreads();
    const float* Kt = KIP + (size_t)h * NIP_ * DH_;
    const float* Vt = VIP + (size_t)h * NIP_ * DH_;
    float4 ka[8], va[8];
#pragma unroll
    for (int it = 0; it < 8; it++) ka[it] = *(const float4*)(Kt + (lr + it * 8) * DH_ + lc4);
#pragma unroll
    for (int it = 0; it < 8; it++) va[it] = *(const float4*)(Vt + (lr + it * 8) * DH_ + lc4);
#pragma unroll
    for (int it = 0; it < 8; it++) {
      int r = lr + it * 8;
      int nt = r >> 3, j = r & 7;
      int nn = ((j & 3) << 1) | (j >> 2);
      float vv[4] = {ka[it].x, ka[it].y, ka[it].z, ka[it].w};
#pragma unroll
      for (int e = 0; e < 4; e++) {
        int c = lc4 + e;
        int ks = c >> 3, reg = (c >> 2) & 1, tg = c & 3;
        Ks[((nt * 16 + ks) * 32 + ((nn * 4 + tg) ^ ks)) * 2 + reg] = f2tf32(vv[e]);
      }
    }
    __syncthreads();

    float sa[8][4];
#pragma unroll
    for (int nt = 0; nt < 8; nt++) { sa[nt][0] = sa[nt][1] = sa[nt][2] = sa[nt][3] = 0.f; }
#pragma unroll
    for (int ks = 0; ks < 16; ks++) {
#pragma unroll
      for (int nt = 0; nt < 8; nt++) {
        uint2 b2 = *(const uint2*)(Ks + ((nt * 16 + ks) * 32 + (lane ^ ks)) * 2);
        uint32_t bb[2] = {b2.x, b2.y};
        mma_tf32(sa[nt], qf[ks], bb);
      }
    }
    float rm0 = -1e30f, rm1 = -1e30f;
#pragma unroll
    for (int nt = 0; nt < 8; nt++) {
      rm0 = fmaxf(rm0, fmaxf(sa[nt][0], sa[nt][1]));
      rm1 = fmaxf(rm1, fmaxf(sa[nt][2], sa[nt][3]));
    }
#pragma unroll
    for (int off = 1; off < 4; off <<= 1) {
      rm0 = fmaxf(rm0, __shfl_xor_sync(0xffffffffu, rm0, off));
      rm1 = fmaxf(rm1, __shfl_xor_sync(0xffffffffu, rm1, off));
    }
    float rs0 = 0.f, rs1 = 0.f;
#pragma unroll
    for (int nt = 0; nt < 8; nt++) {
      sa[nt][0] = __expf(sa[nt][0] - rm0); rs0 += sa[nt][0];
      sa[nt][1] = __expf(sa[nt][1] - rm0); rs0 += sa[nt][1];
      sa[nt][2] = __expf(sa[nt][2] - rm1); rs1 += sa[nt][2];
      sa[nt][3] = __expf(sa[nt][3] - rm1); rs1 += sa[nt][3];
    }
#pragma unroll
    for (int off = 1; off < 4; off <<= 1) {
      rs0 += __shfl_xor_sync(0xffffffffu, rs0, off);
      rs1 += __shfl_xor_sync(0xffffffffu, rs1, off);
    }
    float iv0 = 1.f / rs0, iv1 = 1.f / rs1;
#pragma unroll
    for (int it = 0; it < 8; it++) {
      int k2 = lr + it * 8;
      int ks = k2 >> 3, reg = (k2 >> 2) & 1, tg = k2 & 3;
      float vv[4] = {va[it].x, va[it].y, va[it].z, va[it].w};
#pragma unroll
      for (int e = 0; e < 4; e++) {
        int c = lc4 + e;
        int ntd = c >> 3, n = c & 7;
        Vs[((ntd * 8 + ks) * 32 + ((n * 4 + tg) ^ ntd)) * 2 + reg] = f2tf32(vv[e]);
      }
    }
    __syncthreads();
#pragma unroll
    for (int nt = 0; nt < 8; nt++) {
      uint32_t pf[4];
      pf[0] = f2tf32(sa[nt][0] * iv0);
      pf[1] = f2tf32(sa[nt][2] * iv1);
      pf[2] = f2tf32(sa[nt][1] * iv0);
      pf[3] = f2tf32(sa[nt][3] * iv1);
#pragma unroll
      for (int ntd = 0; ntd < 16; ntd++) {
        uint2 b2 = *(const uint2*)(Vs + ((ntd * 8 + nt) * 32 + (lane ^ ntd)) * 2);
        uint32_t bb[2] = {b2.x, b2.y};
        mma_tf32(o[ntd], pf, bb);
      }
    }
  }

  int row0 = q0 + w * 16 + gid, row1 = row0 + 8;
#pragma unroll
  for (int ntd = 0; ntd < 16; ntd++) {
    int col = h * DH_ + ntd * 8 + tig * 2;
    float2 v0 = make_float2(o[ntd][0], o[ntd][1]);
    float2 v1 = make_float2(o[ntd][2], o[ntd][3]);
    if (row0 < ENC_) {
      *(float2*)(outE + (size_t)row0 * D_ + col) = v0;
      *(float2*)(outE + (size_t)row1 * D_ + col) = v1;
    } else {
      *(float2*)(outM + (size_t)(row0 - ENC_) * D_ + col) = v0;
      *(float2*)(outM + (size_t)(row1 - ENC_) * D_ + col) = v1;
    }
  }
}

// ---------------- launch ----------------
extern "C" void kernel_launch(void* const* d_in, const int* in_sizes, int n_in,
                              void* d_out, int out_size) {
  const float* hs   = (const float*)d_in[0];
  const float* ehs  = (const float*)d_in[1];
  const float* img  = (const float*)d_in[2];
  const float* Wq   = (const float*)d_in[3];  const float* bq  = (const float*)d_in[4];
  const float* Wk   = (const float*)d_in[5];  const float* bk  = (const float*)d_in[6];
  const float* Wv   = (const float*)d_in[7];  const float* bv  = (const float*)d_in[8];
  const float* Waq  = (const float*)d_in[9];  const float* baq = (const float*)d_in[10];
  const float* Wak  = (const float*)d_in[11]; const float* bak = (const float*)d_in[12];
  const float* Wav  = (const float*)d_in[13]; const float* bav = (const float*)d_in[14];
  const float* Wo   = (const float*)d_in[15]; const float* bo  = (const float*)d_in[16];
  const float* Wao  = (const float*)d_in[17]; const float* bao = (const float*)d_in[18];
  const float* Wkip = (const float*)d_in[19]; const float* Wvip = (const float*)d_in[20];
  const float* lq_dn = (const float*)d_in[21]; const float* lq_up = (const float*)d_in[22];
  const float* lk_dn = (const float*)d_in[23]; const float* lk_up = (const float*)d_in[24];
  const float* lv_dn = (const float*)d_in[25]; const float* lv_up = (const float*)d_in[26];
  const float* lp_dn = (const float*)d_in[27]; const float* lp_up = (const float*)d_in[28];
  float* out = (float*)d_out;

  float *Q, *K, *V, *KIP, *VIP, *am, *ae, *T3;
  cudaGetSymbolAddress((void**)&Q, g_Q);
  cudaGetSymbolAddress((void**)&K, g_K);
  cudaGetSymbolAddress((void**)&V, g_V);
  cudaGetSymbolAddress((void**)&KIP, g_KIP);
  cudaGetSymbolAddress((void**)&VIP, g_VIP);
  cudaGetSymbolAddress((void**)&am, g_am);
  cudaGetSymbolAddress((void**)&ae, g_ae);
  cudaGetSymbolAddress((void**)&T3, g_T3);

  const int G_SMEM = 2 * (32768 + 16384);   // 98304
  const int ATTN_SMEM = (8192 + 8192) * 4;  // 65536
  cudaFuncSetAttribute(gemm_f, cudaFuncAttributeMaxDynamicSharedMemorySize, G_SMEM);
  cudaFuncSetAttribute(attn_mma_kernel, cudaFuncAttributeMaxDynamicSharedMemorySize, ATTN_SMEM);

  float* outMain = out + (size_t)ENC_ * D_;
  const float* hsC = hs + (size_t)(S_ - COND_) * D_;

  // 1. lora-down temps for q,k,v
  D3 d3 = {{lq_dn, lk_dn, lv_dn}};
  lora_dn3<<<COND_ / 8, 256>>>(hsC, d3, T3);

  // 2. main QKV projections, fully fused (bias + lora-up + RMS + head-major)
  GF gqkv = {
    {hs, hs, hs, 0, 0}, {Wq, Wk, Wv, 0, 0}, {bq, bk, bv, 0, 0},
    {T3, T3 + COND_ * 16, T3 + 2 * COND_ * 16, 0, 0}, {lq_up, lk_up, lv_up, 0, 0},
    {Q, K, V, 0, 0},
    {S_, S_, S_, 1, 1}, {SL_, SL_, SL_, 1, 1}, {ENC_, ENC_, ENC_, 0, 0}, {1, 1, 0, 0, 0}};
  gemm_f<<<dim3(24, 8, 3), 256, G_SMEM>>>(gqkv, D_, D_);

  // 3. encoder + IP projections in one launch (bias/RMS as needed, head-major)
  GF gei = {
    {ehs, ehs, ehs, img, img}, {Waq, Wak, Wav, Wkip, Wvip}, {baq, bak, bav, 0, 0},
    {0, 0, 0, 0, 0}, {0, 0, 0, 0, 0},
    {Q, K, V, KIP, VIP},
    {ENC_, ENC_, ENC_, NIP_, NIP_}, {SL_, SL_, SL_, NIP_, NIP_},
    {0, 0, 0, 0, 0}, {1, 1, 0, 1, 0}};
  gemm_f<<<dim3(24, 2, 5), 256, G_SMEM>>>(gei, D_, D_);

  // 4. joint attention with fused IP attention
  attn_mma_kernel<<<dim3(SL_ / 128, H_), 256, ATTN_SMEM>>>(Q, K, V, KIP, VIP, ae, am);

  // 5. output projections (Wo + Wao batched), plain row-major epilogue
  GF gout = {
    {am, ae, 0, 0, 0}, {Wo, Wao, 0, 0, 0}, {bo, bao, 0, 0, 0},
    {0, 0, 0, 0, 0}, {0, 0, 0, 0, 0},
    {outMain, out, 0, 0, 0},
    {S_, ENC_, 1, 1, 1}, {0, 0, 0, 0, 0}, {0, 0, 0, 0, 0}, {0, 0, 0, 0, 0}};
  gemm_f<<<dim3(24, 8, 2), 256, G_SMEM>>>(gout, D_, D_);

  // 6. output LoRA (post-Wo, in-place on last COND rows)
  float* outCond = outMain + (size_t)(S_ - COND_) * D_;
  lora_kernel<<<COND_, 256>>>(outCond, lp_dn, lp_up, outCond);
}

// round 10
// speedup vs baseline: 5.6897x; 1.0524x over previous
#include <cuda_runtime.h>
#include <math.h>
#include <stdint.h>

// ---------------- problem constants ----------------
#define D_    3072
#define S_    2048
#define H_    24
#define DH_   128
#define ENC_  512
#define NIP_  64
#define COND_ 1024
#define SL_   2560   // ENC + S
#define SB_   1536   // SL - COND
#define RANK_ 16
#define EPS_  1e-5f
#define SCALE_ 0.08838834764831845f  // 1/sqrt(128)

// ---------------- scratch (device globals; no allocations allowed) ----------------
__device__ float g_Q[H_ * SL_ * DH_];
__device__ float g_K[H_ * SL_ * DH_];
__device__ float g_V[H_ * SL_ * DH_];
__device__ float g_KIP[H_ * NIP_ * DH_];
__device__ float g_VIP[H_ * NIP_ * DH_];
__device__ float g_am[S_ * D_];      // main attention out (incl. IP), token-major
__device__ float g_ae[ENC_ * D_];    // encoder attention out
__device__ float g_T3[3 * COND_ * RANK_];  // lora-down temps for q,k,v

// ---------------- tf32 / cp.async helpers ----------------
__device__ __forceinline__ uint32_t f2tf32(float x) {
  uint32_t r;
  asm("cvt.rna.tf32.f32 %0, %1;" : "=r"(r) : "f"(x));
  return r;
}

__device__ __forceinline__ void mma_tf32(float c[4], const uint32_t a[4], const uint32_t b[2]) {
  asm("mma.sync.aligned.m16n8k8.row.col.f32.tf32.tf32.f32 "
      "{%0,%1,%2,%3}, {%4,%5,%6,%7}, {%8,%9}, {%0,%1,%2,%3};"
      : "+f"(c[0]), "+f"(c[1]), "+f"(c[2]), "+f"(c[3])
      : "r"(a[0]), "r"(a[1]), "r"(a[2]), "r"(a[3]), "r"(b[0]), "r"(b[1]));
}

__device__ __forceinline__ void cp_async16(uint32_t smem_addr, const void* gptr, int src_bytes) {
  asm volatile("cp.async.cg.shared.global [%0], [%1], 16, %2;"
               :: "r"(smem_addr), "l"(gptr), "r"(src_bytes) : "memory");
}
#define CP_COMMIT() asm volatile("cp.async.commit_group;" ::: "memory")
#define CP_WAIT1()  asm volatile("cp.async.wait_group 1;" ::: "memory")
#define CP_WAIT0()  asm volatile("cp.async.wait_group 0;" ::: "memory")

// ---------------- lora-down: T[t][r][16] = hsC[r,:] @ dn_t (warp per row) ----------------
struct D3 { const float* dn[3]; };

__global__ void __launch_bounds__(256) lora_dn3(const float* __restrict__ A, D3 g,
                                                float* __restrict__ T) {
  const int tid = threadIdx.x, lane = tid & 31, w = tid >> 5;
  const int row = blockIdx.x * 8 + w;
  const float* a = A + (size_t)row * D_;
  float p[48];
#pragma unroll
  for (int i = 0; i < 48; i++) p[i] = 0.f;
  for (int k = lane; k < D_; k += 32) {
    float av = a[k];
#pragma unroll
    for (int t = 0; t < 3; t++) {
      const float* dk = g.dn[t] + k * 16;
      float4 d0 = *(const float4*)(dk);
      float4 d1 = *(const float4*)(dk + 4);
      float4 d2 = *(const float4*)(dk + 8);
      float4 d3 = *(const float4*)(dk + 12);
      float* pt = p + t * 16;
      pt[0]  = fmaf(av, d0.x, pt[0]);  pt[1]  = fmaf(av, d0.y, pt[1]);
      pt[2]  = fmaf(av, d0.z, pt[2]);  pt[3]  = fmaf(av, d0.w, pt[3]);
      pt[4]  = fmaf(av, d1.x, pt[4]);  pt[5]  = fmaf(av, d1.y, pt[5]);
      pt[6]  = fmaf(av, d1.z, pt[6]);  pt[7]  = fmaf(av, d1.w, pt[7]);
      pt[8]  = fmaf(av, d2.x, pt[8]);  pt[9]  = fmaf(av, d2.y, pt[9]);
      pt[10] = fmaf(av, d2.z, pt[10]); pt[11] = fmaf(av, d2.w, pt[11]);
      pt[12] = fmaf(av, d3.x, pt[12]); pt[13] = fmaf(av, d3.y, pt[13]);
      pt[14] = fmaf(av, d3.z, pt[14]); pt[15] = fmaf(av, d3.w, pt[15]);
    }
  }
#pragma unroll
  for (int off = 16; off; off >>= 1)
#pragma unroll
    for (int i = 0; i < 48; i++) p[i] += __shfl_xor_sync(0xffffffffu, p[i], off);
  if (lane == 0) {
#pragma unroll
    for (int t = 0; t < 3; t++) {
      float* dt = T + ((size_t)t * COND_ + row) * 16;
#pragma unroll
      for (int i = 0; i < 16; i += 4)
        *(float4*)(dt + i) = make_float4(p[t*16+i], p[t*16+i+1], p[t*16+i+2], p[t*16+i+3]);
    }
  }
}

// ---------------- fused tf32 GEMM: C = A@W (+bias) (+loraUp) (+perhead RMS) ----------------
// BM=256 x BN=128, BK=32, 512 threads (16 warps as 4M x 4N, warp tile 64x32).
// 3-stage cp.async pipeline: raw f32 tiles in smem (zero STS / zero staging cvt /
// zero prefetch registers); tf32 cvt at fragment load via conflict-free scalar LDS
// (A row stride 36 words, B k-row stride 136 words). Fragment element mapping is
// identical to the previous staged layout -> bit-identical accumulation order.
struct GF {
  const float* A[5]; const float* W[5]; const float* bias[5];
  const float* T[5]; const float* up[5];
  float* dst[5];
  int M[5]; int seq[5]; int rowOff[5]; int rms[5];
};

#define AW_ 36                      // A row stride (words)
#define BW_ 136                     // B k-row stride (words)
#define AWORDS_ (256 * AW_)         // 9216
#define STAGE_ (AWORDS_ + 32 * BW_) // 13568 words = 54272 B per stage

__global__ void __launch_bounds__(512) gemm_f(GF gf, int N, int K) {
  extern __shared__ float smf[];
  const uint32_t sbase = (uint32_t)__cvta_generic_to_shared(smf);

  const int z = blockIdx.z;
  const float* __restrict__ A = gf.A[z];
  const float* __restrict__ W = gf.W[z];
  const float* __restrict__ bias = gf.bias[z];
  const int M = gf.M[z];

  const int tid = threadIdx.x;
  const int lane = tid & 31;
  const int wid = tid >> 5;
  const int warpM = wid >> 2;   // 0..3 (64 rows each)
  const int warpN = wid & 3;    // 0..3 (32 cols each)
  const int m0 = blockIdx.y * 256;
  const int n0 = blockIdx.x * 128;
  if (m0 >= M) return;

  const int NKT = K / 32;

  auto issue = [&](int kt) {
    if (kt < NKT) {
      int k0 = kt * 32;
      uint32_t st = sbase + (uint32_t)((kt % 3) * STAGE_) * 4u;
#pragma unroll
      for (int p = 0; p < 4; p++) {
        int idx = tid + p * 512;
        int r = idx >> 3, c4 = (idx & 7) << 2;
        int gr = m0 + r;
        int sz = (gr < M) ? 16 : 0;
        if (gr >= M) gr = M - 1;
        cp_async16(st + (uint32_t)(r * AW_ + c4) * 4u,
                   A + (size_t)gr * K + k0 + c4, sz);
      }
      uint32_t stb = st + (uint32_t)AWORDS_ * 4u;
#pragma unroll
      for (int p = 0; p < 2; p++) {
        int idx = tid + p * 512;
        int kr = idx >> 5, nc4 = (idx & 31) << 2;
        cp_async16(stb + (uint32_t)(kr * BW_ + nc4) * 4u,
                   W + (size_t)(k0 + kr) * N + n0 + nc4, 16);
      }
    }
    CP_COMMIT();
  };

  float acc[4][4][4];
#pragma unroll
  for (int mt = 0; mt < 4; mt++)
#pragma unroll
    for (int nt = 0; nt < 4; nt++)
#pragma unroll
      for (int i = 0; i < 4; i++) acc[mt][nt][i] = 0.f;

  issue(0);
  issue(1);

  const int gid = lane >> 2, tig = lane & 3;

  for (int kt = 0; kt < NKT; kt++) {
    CP_WAIT1();
    __syncthreads();
    const float* sa = smf + (kt % 3) * STAGE_;
    const float* sb = sa + AWORDS_;
    const float* arow = sa + (warpM * 64 + gid) * AW_;
    const float* bcol = sb + warpN * 32 + gid;
#pragma unroll
    for (int ks = 0; ks < 4; ks++) {
      const int kk = ks * 8 + tig;
      uint32_t a[4][4];
      uint32_t b[4][2];
#pragma unroll
      for (int mt = 0; mt < 4; mt++) {
        const float* r0 = arow + mt * 16 * AW_;
        a[mt][0] = f2tf32(r0[kk]);
        a[mt][1] = f2tf32(r0[8 * AW_ + kk]);
        a[mt][2] = f2tf32(r0[kk + 4]);
        a[mt][3] = f2tf32(r0[8 * AW_ + kk + 4]);
      }
#pragma unroll
      for (int nt = 0; nt < 4; nt++) {
        b[nt][0] = f2tf32(bcol[kk * BW_ + nt * 8]);
        b[nt][1] = f2tf32(bcol[(kk + 4) * BW_ + nt * 8]);
      }
#pragma unroll
      for (int mt = 0; mt < 4; mt++)
#pragma unroll
        for (int nt = 0; nt < 4; nt++) mma_tf32(acc[mt][nt], a[mt], b[nt]);
    }
    issue(kt + 2);
  }
  CP_WAIT0();
  __syncthreads();

  // ---- fused epilogue ----
  const float* Tz = gf.T[z];
  const float* upz = gf.up[z];
  float* dst = gf.dst[z];
  const int seq = gf.seq[z], rowOff = gf.rowOff[z], doRMS = gf.rms[z];

  float bb0[4], bb1[4];
#pragma unroll
  for (int nt = 0; nt < 4; nt++) {
    int col = n0 + warpN * 32 + nt * 8 + tig * 2;
    bb0[nt] = bias ? bias[col] : 0.f;
    bb1[nt] = bias ? bias[col + 1] : 0.f;
  }
#pragma unroll
  for (int mt = 0; mt < 4; mt++) {
    int gr0 = m0 + warpM * 64 + mt * 16 + gid;
#pragma unroll
    for (int nt = 0; nt < 4; nt++) {
      acc[mt][nt][0] += bb0[nt]; acc[mt][nt][1] += bb1[nt];
      acc[mt][nt][2] += bb0[nt]; acc[mt][nt][3] += bb1[nt];
    }
    if (upz) {
      int l0 = gr0 - (M - COND_);
      int l1 = l0 + 8;
      if (l1 >= 0) {
        bool h0 = (l0 >= 0);
#pragma unroll
        for (int i0 = 0; i0 < 16; i0 += 4) {
          float4 t1q = *(const float4*)(Tz + (size_t)l1 * 16 + i0);
          float4 t0q = h0 ? *(const float4*)(Tz + (size_t)l0 * 16 + i0)
                          : make_float4(0.f, 0.f, 0.f, 0.f);
          float tv0[4] = {t0q.x, t0q.y, t0q.z, t0q.w};
          float tv1[4] = {t1q.x, t1q.y, t1q.z, t1q.w};
#pragma unroll
          for (int j = 0; j < 4; j++) {
#pragma unroll
            for (int nt = 0; nt < 4; nt++) {
              int col = n0 + warpN * 32 + nt * 8 + tig * 2;
              float2 u = *(const float2*)(upz + (size_t)(i0 + j) * N + col);
              acc[mt][nt][0] = fmaf(tv0[j], u.x, acc[mt][nt][0]);
              acc[mt][nt][1] = fmaf(tv0[j], u.y, acc[mt][nt][1]);
              acc[mt][nt][2] = fmaf(tv1[j], u.x, acc[mt][nt][2]);
              acc[mt][nt][3] = fmaf(tv1[j], u.y, acc[mt][nt][3]);
            }
          }
        }
      }
    }
  }

  if (doRMS) {
    float* ssm = smf;  // [256][4], 4KB (mainloop smem dead now)
#pragma unroll
    for (int mt = 0; mt < 4; mt++) {
      int lr = warpM * 64 + mt * 16 + gid;
      float ss0 = 0.f, ss1 = 0.f;
#pragma unroll
      for (int nt = 0; nt < 4; nt++) {
        ss0 = fmaf(acc[mt][nt][0], acc[mt][nt][0], ss0);
        ss0 = fmaf(acc[mt][nt][1], acc[mt][nt][1], ss0);
        ss1 = fmaf(acc[mt][nt][2], acc[mt][nt][2], ss1);
        ss1 = fmaf(acc[mt][nt][3], acc[mt][nt][3], ss1);
      }
      ss0 += __shfl_xor_sync(0xffffffffu, ss0, 1);
      ss0 += __shfl_xor_sync(0xffffffffu, ss0, 2);
      ss1 += __shfl_xor_sync(0xffffffffu, ss1, 1);
      ss1 += __shfl_xor_sync(0xffffffffu, ss1, 2);
      if (tig == 0) {
        ssm[lr * 4 + warpN] = ss0;
        ssm[(lr + 8) * 4 + warpN] = ss1;
      }
    }
    __syncthreads();
#pragma unroll
    for (int mt = 0; mt < 4; mt++) {
      int lr = warpM * 64 + mt * 16 + gid;
      float4 s0 = *(const float4*)&ssm[lr * 4];
      float4 s1 = *(const float4*)&ssm[(lr + 8) * 4];
      float sc0 = rsqrtf((s0.x + s0.y + s0.z + s0.w) * (1.f / 128.f) + EPS_);
      float sc1 = rsqrtf((s1.x + s1.y + s1.z + s1.w) * (1.f / 128.f) + EPS_);
#pragma unroll
      for (int nt = 0; nt < 4; nt++) {
        acc[mt][nt][0] *= sc0; acc[mt][nt][1] *= sc0;
        acc[mt][nt][2] *= sc1; acc[mt][nt][3] *= sc1;
      }
    }
  }

  const int head = n0 >> 7;
#pragma unroll
  for (int mt = 0; mt < 4; mt++) {
    int gr0 = m0 + warpM * 64 + mt * 16 + gid;
    int gr1 = gr0 + 8;
#pragma unroll
    for (int nt = 0; nt < 4; nt++) {
      int colh = warpN * 32 + nt * 8 + tig * 2;
      float2 v0 = make_float2(acc[mt][nt][0], acc[mt][nt][1]);
      float2 v1 = make_float2(acc[mt][nt][2], acc[mt][nt][3]);
      if (seq) {
        float* bp = dst + ((size_t)head * seq + rowOff) * 128 + colh;
        if (gr0 < M) *(float2*)(bp + (size_t)gr0 * 128) = v0;
        if (gr1 < M) *(float2*)(bp + (size_t)gr1 * 128) = v1;
      } else {
        if (gr0 < M) *(float2*)(dst + (size_t)gr0 * N + n0 + colh) = v0;
        if (gr1 < M) *(float2*)(dst + (size_t)gr1 * N + n0 + colh) = v1;
      }
    }
  }
}

// ---------------- single LoRA for the output projection (post-Wo, in-place) ----------------
__global__ void __launch_bounds__(256) lora_kernel(
    const float* __restrict__ A, const float* __restrict__ dn,
    const float* __restrict__ up, float* __restrict__ C) {
  __shared__ float red[8 * 16];
  __shared__ float st[16];
  const int r = blockIdx.x, tid = threadIdx.x, lane = tid & 31, wid = tid >> 5;
  const float* a = A + (size_t)r * D_;
  float p[16];
#pragma unroll
  for (int i = 0; i < 16; i++) p[i] = 0.f;
  for (int k = tid; k < D_; k += 256) {
    float av = a[k];
    float4 d0 = *(const float4*)(dn + k * 16);
    float4 d1 = *(const float4*)(dn + k * 16 + 4);
    float4 d2 = *(const float4*)(dn + k * 16 + 8);
    float4 d3 = *(const float4*)(dn + k * 16 + 12);
    p[0]  = fmaf(av, d0.x, p[0]);  p[1]  = fmaf(av, d0.y, p[1]);
    p[2]  = fmaf(av, d0.z, p[2]);  p[3]  = fmaf(av, d0.w, p[3]);
    p[4]  = fmaf(av, d1.x, p[4]);  p[5]  = fmaf(av, d1.y, p[5]);
    p[6]  = fmaf(av, d1.z, p[6]);  p[7]  = fmaf(av, d1.w, p[7]);
    p[8]  = fmaf(av, d2.x, p[8]);  p[9]  = fmaf(av, d2.y, p[9]);
    p[10] = fmaf(av, d2.z, p[10]); p[11] = fmaf(av, d2.w, p[11]);
    p[12] = fmaf(av, d3.x, p[12]); p[13] = fmaf(av, d3.y, p[13]);
    p[14] = fmaf(av, d3.z, p[14]); p[15] = fmaf(av, d3.w, p[15]);
  }
#pragma unroll
  for (int o = 16; o; o >>= 1)
#pragma unroll
    for (int i = 0; i < 16; i++) p[i] += __shfl_xor_sync(0xffffffffu, p[i], o);
  if (lane == 0)
#pragma unroll
    for (int i = 0; i < 16; i++) red[wid * 16 + i] = p[i];
  __syncthreads();
  if (tid < 16) {
    float s = 0.f;
#pragma unroll
    for (int w = 0; w < 8; w++) s += red[w * 16 + tid];
    st[tid] = s;
  }
  __syncthreads();
  float t0[16];
#pragma unroll
  for (int i = 0; i < 16; i++) t0[i] = st[i];
  float* crow = C + (size_t)r * D_;
  for (int c = tid; c < D_; c += 256) {
    float s = 0.f;
#pragma unroll
    for (int i = 0; i < 16; i++) s = fmaf(t0[i], up[(size_t)i * D_ + c], s);
    crow[c] += s;
  }
}

// ---------------- tensor-core flash attention + fused IP attention (unchanged R8) ----------------
__global__ void __launch_bounds__(256) attn_mma_kernel(
    const float* __restrict__ Q, const float* __restrict__ K,
    const float* __restrict__ V, const float* __restrict__ KIP,
    const float* __restrict__ VIP, float* __restrict__ outE,
    float* __restrict__ outM) {
  extern __shared__ uint32_t smA[];
  uint32_t* Ks = smA;            // 8192 words
  uint32_t* Vs = smA + 8192;     // 8192 words
  const int tid = threadIdx.x, lane = tid & 31, w = tid >> 5;
  const int gid = lane >> 2, tig = lane & 3;
  const int h = blockIdx.y, q0 = blockIdx.x * 128;

  uint32_t qf[16][4];
  {
    const float* Qg = Q + ((size_t)h * SL_ + q0) * DH_;
    const float* qr0 = Qg + (w * 16 + gid) * DH_;
    const float* qr1 = qr0 + 8 * DH_;
#pragma unroll
    for (int ks = 0; ks < 16; ks++) {
      qf[ks][0] = f2tf32(qr0[ks * 8 + tig] * SCALE_);
      qf[ks][1] = f2tf32(qr1[ks * 8 + tig] * SCALE_);
      qf[ks][2] = f2tf32(qr0[ks * 8 + tig + 4] * SCALE_);
      qf[ks][3] = f2tf32(qr1[ks * 8 + tig + 4] * SCALE_);
    }
  }

  float o[16][4];
#pragma unroll
  for (int i = 0; i < 16; i++) { o[i][0] = o[i][1] = o[i][2] = o[i][3] = 0.f; }
  float m0 = -1e30f, m1 = -1e30f, l0 = 0.f, l1 = 0.f;

  const int lr = tid >> 5;
  const int lc4 = (tid & 31) << 2;

  const int kt0 = (q0 >= SB_) ? (SB_ / 64) : 0;
  for (int kt = kt0; kt < SL_ / 64; kt++) {
    __syncthreads();
    const float* Kt = K + ((size_t)h * SL_ + kt * 64) * DH_;
    const float* Vt = V + ((size_t)h * SL_ + kt * 64) * DH_;
    float4 ka[8], va[8];
#pragma unroll
    for (int it = 0; it < 8; it++) ka[it] = *(const float4*)(Kt + (lr + it * 8) * DH_ + lc4);
#pragma unroll
    for (int it = 0; it < 8; it++) va[it] = *(const float4*)(Vt + (lr + it * 8) * DH_ + lc4);
#pragma unroll
    for (int it = 0; it < 8; it++) {
      int r = lr + it * 8;
      int nt = r >> 3, j = r & 7;
      int nn = ((j & 3) << 1) | (j >> 2);  // pi(j)
      float vv[4] = {ka[it].x, ka[it].y, ka[it].z, ka[it].w};
#pragma unroll
      for (int e = 0; e < 4; e++) {
        int c = lc4 + e;
        int ks = c >> 3, reg = (c >> 2) & 1, tg = c & 3;
        Ks[((nt * 16 + ks) * 32 + ((nn * 4 + tg) ^ ks)) * 2 + reg] = f2tf32(vv[e]);
      }
    }
    __syncthreads();

    float sa[8][4];
#pragma unroll
    for (int nt = 0; nt < 8; nt++) { sa[nt][0] = sa[nt][1] = sa[nt][2] = sa[nt][3] = 0.f; }
#pragma unroll
    for (int ks = 0; ks < 16; ks++) {
#pragma unroll
      for (int nt = 0; nt < 8; nt++) {
        uint2 b2 = *(const uint2*)(Ks + ((nt * 16 + ks) * 32 + (lane ^ ks)) * 2);
        uint32_t bb[2] = {b2.x, b2.y};
        mma_tf32(sa[nt], qf[ks], bb);
      }
    }

    float rm0 = -1e30f, rm1 = -1e30f;
#pragma unroll
    for (int nt = 0; nt < 8; nt++) {
      rm0 = fmaxf(rm0, fmaxf(sa[nt][0], sa[nt][1]));
      rm1 = fmaxf(rm1, fmaxf(sa[nt][2], sa[nt][3]));
    }
#pragma unroll
    for (int off = 1; off < 4; off <<= 1) {
      rm0 = fmaxf(rm0, __shfl_xor_sync(0xffffffffu, rm0, off));
      rm1 = fmaxf(rm1, __shfl_xor_sync(0xffffffffu, rm1, off));
    }
    float mn0 = fmaxf(m0, rm0), mn1 = fmaxf(m1, rm1);
    float corr0 = __expf(m0 - mn0), corr1 = __expf(m1 - mn1);
    m0 = mn0; m1 = mn1;
    float rs0 = 0.f, rs1 = 0.f;
#pragma unroll
    for (int nt = 0; nt < 8; nt++) {
      sa[nt][0] = __expf(sa[nt][0] - mn0); rs0 += sa[nt][0];
      sa[nt][1] = __expf(sa[nt][1] - mn0); rs0 += sa[nt][1];
      sa[nt][2] = __expf(sa[nt][2] - mn1); rs1 += sa[nt][2];
      sa[nt][3] = __expf(sa[nt][3] - mn1); rs1 += sa[nt][3];
    }
#pragma unroll
    for (int off = 1; off < 4; off <<= 1) {
      rs0 += __shfl_xor_sync(0xffffffffu, rs0, off);
      rs1 += __shfl_xor_sync(0xffffffffu, rs1, off);
    }
    l0 = l0 * corr0 + rs0;
    l1 = l1 * corr1 + rs1;
#pragma unroll
    for (int i = 0; i < 16; i++) {
      o[i][0] *= corr0; o[i][1] *= corr0; o[i][2] *= corr1; o[i][3] *= corr1;
    }

#pragma unroll
    for (int it = 0; it < 8; it++) {
      int k2 = lr + it * 8;
      int ks = k2 >> 3, reg = (k2 >> 2) & 1, tg = k2 & 3;
      float vv[4] = {va[it].x, va[it].y, va[it].z, va[it].w};
#pragma unroll
      for (int e = 0; e < 4; e++) {
        int c = lc4 + e;
        int ntd = c >> 3, n = c & 7;
        Vs[((ntd * 8 + ks) * 32 + ((n * 4 + tg) ^ ntd)) * 2 + reg] = f2tf32(vv[e]);
      }
    }
    __syncthreads();

#pragma unroll
    for (int nt = 0; nt < 8; nt++) {
      uint32_t pf[4];
      pf[0] = f2tf32(sa[nt][0]);
      pf[1] = f2tf32(sa[nt][2]);
      pf[2] = f2tf32(sa[nt][1]);
      pf[3] = f2tf32(sa[nt][3]);
#pragma unroll
      for (int ntd = 0; ntd < 16; ntd++) {
        uint2 b2 = *(const uint2*)(Vs + ((ntd * 8 + nt) * 32 + (lane ^ ntd)) * 2);
        uint32_t bb[2] = {b2.x, b2.y};
        mma_tf32(o[ntd], pf, bb);
      }
    }
  }

  float inv0 = 1.f / l0, inv1 = 1.f / l1;
#pragma unroll
  for (int i = 0; i < 16; i++) {
    o[i][0] *= inv0; o[i][1] *= inv0; o[i][2] *= inv1; o[i][3] *= inv1;
  }

  if (q0 >= ENC_) {
    __syncthreads();
    const float* Kt = KIP + (size_t)h * NIP_ * DH_;
    const float* Vt = VIP + (size_t)h * NIP_ * DH_;
    float4 ka[8], va[8];
#pragma unroll
    for (int it = 0; it < 8; it++) ka[it] = *(const float4*)(Kt + (lr + it * 8) * DH_ + lc4);
#pragma unroll
    for (int it = 0; it < 8; it++) va[it] = *(const float4*)(Vt + (lr + it * 8) * DH_ + lc4);
#pragma unroll
    for (int it = 0; it < 8; it++) {
      int r = lr + it * 8;
      int nt = r >> 3, j = r & 7;
      int nn = ((j & 3) << 1) | (j >> 2);
      float vv[4] = {ka[it].x, ka[it].y, ka[it].z, ka[it].w};
#pragma unroll
      for (int e = 0; e < 4; e++) {
        int c = lc4 + e;
        int ks = c >> 3, reg = (c >> 2) & 1, tg = c & 3;
        Ks[((nt * 16 + ks) * 32 + ((nn * 4 + tg) ^ ks)) * 2 + reg] = f2tf32(vv[e]);
      }
    }
    __syncthreads();

    float sa[8][4];
#pragma unroll
    for (int nt = 0; nt < 8; nt++) { sa[nt][0] = sa[nt][1] = sa[nt][2] = sa[nt][3] = 0.f; }
#pragma unroll
    for (int ks = 0; ks < 16; ks++) {
#pragma unroll
      for (int nt = 0; nt < 8; nt++) {
        uint2 b2 = *(const uint2*)(Ks + ((nt * 16 + ks) * 32 + (lane ^ ks)) * 2);
        uint32_t bb[2] = {b2.x, b2.y};
        mma_tf32(sa[nt], qf[ks], bb);
      }
    }
    float rm0 = -1e30f, rm1 = -1e30f;
#pragma unroll
    for (int nt = 0; nt < 8; nt++) {
      rm0 = fmaxf(rm0, fmaxf(sa[nt][0], sa[nt][1]));
      rm1 = fmaxf(rm1, fmaxf(sa[nt][2], sa[nt][3]));
    }
#pragma unroll
    for (int off = 1; off < 4; off <<= 1) {
      rm0 = fmaxf(rm0, __shfl_xor_sync(0xffffffffu, rm0, off));
      rm1 = fmaxf(rm1, __shfl_xor_sync(0xffffffffu, rm1, off));
    }
    float rs0 = 0.f, rs1 = 0.f;
#pragma unroll
    for (int nt = 0; nt < 8; nt++) {
      sa[nt][0] = __expf(sa[nt][0] - rm0); rs0 += sa[nt][0];
      sa[nt][1] = __expf(sa[nt][1] - rm0); rs0 += sa[nt][1];
      sa[nt][2] = __expf(sa[nt][2] - rm1); rs1 += sa[nt][2];
      sa[nt][3] = __expf(sa[nt][3] - rm1); rs1 += sa[nt][3];
    }
#pragma unroll
    for (int off = 1; off < 4; off <<= 1) {
      rs0 += __shfl_xor_sync(0xffffffffu, rs0, off);
      rs1 += __shfl_xor_sync(0xffffffffu, rs1, off);
    }
    float iv0 = 1.f / rs0, iv1 = 1.f / rs1;
#pragma unroll
    for (int it = 0; it < 8; it++) {
      int k2 = lr + it * 8;
      int ks = k2 >> 3, reg = (k2 >> 2) & 1, tg = k2 & 3;
      float vv[4] = {va[it].x, va[it].y, va[it].z, va[it].w};
#pragma unroll
      for (int e = 0; e < 4; e++) {
        int c = lc4 + e;
        int ntd = c >> 3, n = c & 7;
        Vs[((ntd * 8 + ks) * 32 + ((n * 4 + tg) ^ ntd)) * 2 + reg] = f2tf32(vv[e]);
      }
    }
    __syncthreads();
#pragma unroll
    for (int nt = 0; nt < 8; nt++) {
      uint32_t pf[4];
      pf[0] = f2tf32(sa[nt][0] * iv0);
      pf[1] = f2tf32(sa[nt][2] * iv1);
      pf[2] = f2tf32(sa[nt][1] * iv0);
      pf[3] = f2tf32(sa[nt][3] * iv1);
#pragma unroll
      for (int ntd = 0; ntd < 16; ntd++) {
        uint2 b2 = *(const uint2*)(Vs + ((ntd * 8 + nt) * 32 + (lane ^ ntd)) * 2);
        uint32_t bb[2] = {b2.x, b2.y};
        mma_tf32(o[ntd], pf, bb);
      }
    }
  }

  int row0 = q0 + w * 16 + gid, row1 = row0 + 8;
#pragma unroll
  for (int ntd = 0; ntd < 16; ntd++) {
    int col = h * DH_ + ntd * 8 + tig * 2;
    float2 v0 = make_float2(o[ntd][0], o[ntd][1]);
    float2 v1 = make_float2(o[ntd][2], o[ntd][3]);
    if (row0 < ENC_) {
      *(float2*)(outE + (size_t)row0 * D_ + col) = v0;
      *(float2*)(outE + (size_t)row1 * D_ + col) = v1;
    } else {
      *(float2*)(outM + (size_t)(row0 - ENC_) * D_ + col) = v0;
      *(float2*)(outM + (size_t)(row1 - ENC_) * D_ + col) = v1;
    }
  }
}

// ---------------- launch ----------------
extern "C" void kernel_launch(void* const* d_in, const int* in_sizes, int n_in,
                              void* d_out, int out_size) {
  const float* hs   = (const float*)d_in[0];
  const float* ehs  = (const float*)d_in[1];
  const float* img  = (const float*)d_in[2];
  const float* Wq   = (const float*)d_in[3];  const float* bq  = (const float*)d_in[4];
  const float* Wk   = (const float*)d_in[5];  const float* bk  = (const float*)d_in[6];
  const float* Wv   = (const float*)d_in[7];  const float* bv  = (const float*)d_in[8];
  const float* Waq  = (const float*)d_in[9];  const float* baq = (const float*)d_in[10];
  const float* Wak  = (const float*)d_in[11]; const float* bak = (const float*)d_in[12];
  const float* Wav  = (const float*)d_in[13]; const float* bav = (const float*)d_in[14];
  const float* Wo   = (const float*)d_in[15]; const float* bo  = (const float*)d_in[16];
  const float* Wao  = (const float*)d_in[17]; const float* bao = (const float*)d_in[18];
  const float* Wkip = (const float*)d_in[19]; const float* Wvip = (const float*)d_in[20];
  const float* lq_dn = (const float*)d_in[21]; const float* lq_up = (const float*)d_in[22];
  const float* lk_dn = (const float*)d_in[23]; const float* lk_up = (const float*)d_in[24];
  const float* lv_dn = (const float*)d_in[25]; const float* lv_up = (const float*)d_in[26];
  const float* lp_dn = (const float*)d_in[27]; const float* lp_up = (const float*)d_in[28];
  float* out = (float*)d_out;

  float *Q, *K, *V, *KIP, *VIP, *am, *ae, *T3;
  cudaGetSymbolAddress((void**)&Q, g_Q);
  cudaGetSymbolAddress((void**)&K, g_K);
  cudaGetSymbolAddress((void**)&V, g_V);
  cudaGetSymbolAddress((void**)&KIP, g_KIP);
  cudaGetSymbolAddress((void**)&VIP, g_VIP);
  cudaGetSymbolAddress((void**)&am, g_am);
  cudaGetSymbolAddress((void**)&ae, g_ae);
  cudaGetSymbolAddress((void**)&T3, g_T3);

  const int G_SMEM = 3 * STAGE_ * 4;        // 162816 B
  const int ATTN_SMEM = (8192 + 8192) * 4;  // 65536
  cudaFuncSetAttribute(gemm_f, cudaFuncAttributeMaxDynamicSharedMemorySize, G_SMEM);
  cudaFuncSetAttribute(attn_mma_kernel, cudaFuncAttributeMaxDynamicSharedMemorySize, ATTN_SMEM);

  float* outMain = out + (size_t)ENC_ * D_;
  const float* hsC = hs + (size_t)(S_ - COND_) * D_;

  // 1. lora-down temps for q,k,v
  D3 d3 = {{lq_dn, lk_dn, lv_dn}};
  lora_dn3<<<COND_ / 8, 256>>>(hsC, d3, T3);

  // 2. main QKV projections, fully fused (bias + lora-up + RMS + head-major)
  GF gqkv = {
    {hs, hs, hs, 0, 0}, {Wq, Wk, Wv, 0, 0}, {bq, bk, bv, 0, 0},
    {T3, T3 + COND_ * 16, T3 + 2 * COND_ * 16, 0, 0}, {lq_up, lk_up, lv_up, 0, 0},
    {Q, K, V, 0, 0},
    {S_, S_, S_, 1, 1}, {SL_, SL_, SL_, 1, 1}, {ENC_, ENC_, ENC_, 0, 0}, {1, 1, 0, 0, 0}};
  gemm_f<<<dim3(24, 8, 3), 512, G_SMEM>>>(gqkv, D_, D_);

  // 3. encoder + IP projections in one launch (bias/RMS as needed, head-major)
  GF gei = {
    {ehs, ehs, ehs, img, img}, {Waq, Wak, Wav, Wkip, Wvip}, {baq, bak, bav, 0, 0},
    {0, 0, 0, 0, 0}, {0, 0, 0, 0, 0},
    {Q, K, V, KIP, VIP},
    {ENC_, ENC_, ENC_, NIP_, NIP_}, {SL_, SL_, SL_, NIP_, NIP_},
    {0, 0, 0, 0, 0}, {1, 1, 0, 1, 0}};
  gemm_f<<<dim3(24, 2, 5), 512, G_SMEM>>>(gei, D_, D_);

  // 4. joint attention with fused IP attention
  attn_mma_kernel<<<dim3(SL_ / 128, H_), 256, ATTN_SMEM>>>(Q, K, V, KIP, VIP, ae, am);

  // 5. output projections (Wo + Wao batched), plain row-major epilogue
  GF gout = {
    {am, ae, 0, 0, 0}, {Wo, Wao, 0, 0, 0}, {bo, bao, 0, 0, 0},
    {0, 0, 0, 0, 0}, {0, 0, 0, 0, 0},
    {outMain, out, 0, 0, 0},
    {S_, ENC_, 1, 1, 1}, {0, 0, 0, 0, 0}, {0, 0, 0, 0, 0}, {0, 0, 0, 0, 0}};
  gemm_f<<<dim3(24, 8, 2), 512, G_SMEM>>>(gout, D_, D_);

  // 6. output LoRA (post-Wo, in-place on last COND rows)
  float* outCond = outMain + (size_t)(S_ - COND_) * D_;
  lora_kernel<<<COND_, 256>>>(outCond, lp_dn, lp_up, outCond);
}

// round 11
// speedup vs baseline: 5.7024x; 1.0022x over previous
#include <cuda_runtime.h>
#include <math.h>
#include <stdint.h>

// ---------------- problem constants ----------------
#define D_    3072
#define S_    2048
#define H_    24
#define DH_   128
#define ENC_  512
#define NIP_  64
#define COND_ 1024
#define SL_   2560   // ENC + S
#define SB_   1536   // SL - COND
#define RANK_ 16
#define EPS_  1e-5f
#define SCALE_ 0.08838834764831845f  // 1/sqrt(128)

// ---------------- scratch (device globals; no allocations allowed) ----------------
__device__ float g_Q[H_ * SL_ * DH_];
__device__ float g_K[H_ * SL_ * DH_];
__device__ float g_V[H_ * SL_ * DH_];
__device__ float g_KIP[H_ * NIP_ * DH_];
__device__ float g_VIP[H_ * NIP_ * DH_];
__device__ float g_am[S_ * D_];      // main attention out (incl. IP), token-major
__device__ float g_ae[ENC_ * D_];    // encoder attention out
__device__ float g_T3[3 * COND_ * RANK_];  // lora-down temps for q,k,v

// ---------------- tf32 / fp16 / cp.async helpers ----------------
__device__ __forceinline__ uint32_t f2tf32(float x) {
  uint32_t r;
  asm("cvt.rna.tf32.f32 %0, %1;" : "=r"(r) : "f"(x));
  return r;
}

__device__ __forceinline__ uint32_t pack_h2(float lo, float hi) {
  uint32_t r;
  asm("cvt.rn.f16x2.f32 %0, %1, %2;" : "=r"(r) : "f"(hi), "f"(lo));
  return r;
}

__device__ __forceinline__ void mma_tf32(float c[4], const uint32_t a[4], const uint32_t b[2]) {
  asm("mma.sync.aligned.m16n8k8.row.col.f32.tf32.tf32.f32 "
      "{%0,%1,%2,%3}, {%4,%5,%6,%7}, {%8,%9}, {%0,%1,%2,%3};"
      : "+f"(c[0]), "+f"(c[1]), "+f"(c[2]), "+f"(c[3])
      : "r"(a[0]), "r"(a[1]), "r"(a[2]), "r"(a[3]), "r"(b[0]), "r"(b[1]));
}

__device__ __forceinline__ void mma_f16(float c[4], const uint32_t a[4], const uint32_t b[2]) {
  asm("mma.sync.aligned.m16n8k16.row.col.f32.f16.f16.f32 "
      "{%0,%1,%2,%3}, {%4,%5,%6,%7}, {%8,%9}, {%0,%1,%2,%3};"
      : "+f"(c[0]), "+f"(c[1]), "+f"(c[2]), "+f"(c[3])
      : "r"(a[0]), "r"(a[1]), "r"(a[2]), "r"(a[3]), "r"(b[0]), "r"(b[1]));
}

__device__ __forceinline__ void cp_async16(uint32_t smem_addr, const void* gptr, int src_bytes) {
  asm volatile("cp.async.cg.shared.global [%0], [%1], 16, %2;"
               :: "r"(smem_addr), "l"(gptr), "r"(src_bytes) : "memory");
}
#define CP_COMMIT() asm volatile("cp.async.commit_group;" ::: "memory")
#define CP_WAIT1()  asm volatile("cp.async.wait_group 1;" ::: "memory")
#define CP_WAIT0()  asm volatile("cp.async.wait_group 0;" ::: "memory")

// ---------------- lora-down: T[t][r][16] = hsC[r,:] @ dn_t (warp per row) ----------------
struct D3 { const float* dn[3]; };

__global__ void __launch_bounds__(256) lora_dn3(const float* __restrict__ A, D3 g,
                                                float* __restrict__ T) {
  const int tid = threadIdx.x, lane = tid & 31, w = tid >> 5;
  const int row = blockIdx.x * 8 + w;
  const float* a = A + (size_t)row * D_;
  float p[48];
#pragma unroll
  for (int i = 0; i < 48; i++) p[i] = 0.f;
  for (int k = lane; k < D_; k += 32) {
    float av = a[k];
#pragma unroll
    for (int t = 0; t < 3; t++) {
      const float* dk = g.dn[t] + k * 16;
      float4 d0 = *(const float4*)(dk);
      float4 d1 = *(const float4*)(dk + 4);
      float4 d2 = *(const float4*)(dk + 8);
      float4 d3 = *(const float4*)(dk + 12);
      float* pt = p + t * 16;
      pt[0]  = fmaf(av, d0.x, pt[0]);  pt[1]  = fmaf(av, d0.y, pt[1]);
      pt[2]  = fmaf(av, d0.z, pt[2]);  pt[3]  = fmaf(av, d0.w, pt[3]);
      pt[4]  = fmaf(av, d1.x, pt[4]);  pt[5]  = fmaf(av, d1.y, pt[5]);
      pt[6]  = fmaf(av, d1.z, pt[6]);  pt[7]  = fmaf(av, d1.w, pt[7]);
      pt[8]  = fmaf(av, d2.x, pt[8]);  pt[9]  = fmaf(av, d2.y, pt[9]);
      pt[10] = fmaf(av, d2.z, pt[10]); pt[11] = fmaf(av, d2.w, pt[11]);
      pt[12] = fmaf(av, d3.x, pt[12]); pt[13] = fmaf(av, d3.y, pt[13]);
      pt[14] = fmaf(av, d3.z, pt[14]); pt[15] = fmaf(av, d3.w, pt[15]);
    }
  }
#pragma unroll
  for (int off = 16; off; off >>= 1)
#pragma unroll
    for (int i = 0; i < 48; i++) p[i] += __shfl_xor_sync(0xffffffffu, p[i], off);
  if (lane == 0) {
#pragma unroll
    for (int t = 0; t < 3; t++) {
      float* dt = T + ((size_t)t * COND_ + row) * 16;
#pragma unroll
      for (int i = 0; i < 16; i += 4)
        *(float4*)(dt + i) = make_float4(p[t*16+i], p[t*16+i+1], p[t*16+i+2], p[t*16+i+3]);
    }
  }
}

// ---------------- fused fp16-MMA GEMM: C = A@W (+bias) (+loraUp) (+perhead RMS) ----------------
// BM=256 x BN=128, BK=32, 512 threads (16 warps as 4M x 4N, warp tile 64x32).
// 3-stage cp.async pipeline; raw f32 tiles in smem; f32->f16x2 pack at fragment load.
// m16n8k16 fp16 mma (same 11-bit mantissa as tf32, fp32 accum): halves HMMA and CVT
// counts per FLOP vs tf32 m16n8k8. C-fragment layout identical -> epilogue unchanged.
struct GF {
  const float* A[5]; const float* W[5]; const float* bias[5];
  const float* T[5]; const float* up[5];
  float* dst[5];
  int M[5]; int seq[5]; int rowOff[5]; int rms[5];
};

#define AW_ 36                      // A row stride (words)
#define BW_ 132                     // B k-row stride (words): bank = 8*tig+gid, conflict-free
#define AWORDS_ (256 * AW_)         // 9216
#define STAGE_ (AWORDS_ + 32 * BW_) // 13440 words = 53760 B per stage

__global__ void __launch_bounds__(512) gemm_f(GF gf, int N, int K) {
  extern __shared__ float smf[];
  const uint32_t sbase = (uint32_t)__cvta_generic_to_shared(smf);

  const int z = blockIdx.z;
  const float* __restrict__ A = gf.A[z];
  const float* __restrict__ W = gf.W[z];
  const float* __restrict__ bias = gf.bias[z];
  const int M = gf.M[z];

  const int tid = threadIdx.x;
  const int lane = tid & 31;
  const int wid = tid >> 5;
  const int warpM = wid >> 2;   // 0..3 (64 rows each)
  const int warpN = wid & 3;    // 0..3 (32 cols each)
  const int m0 = blockIdx.y * 256;
  const int n0 = blockIdx.x * 128;
  if (m0 >= M) return;

  const int NKT = K / 32;

  auto issue = [&](int kt) {
    if (kt < NKT) {
      int k0 = kt * 32;
      uint32_t st = sbase + (uint32_t)((kt % 3) * STAGE_) * 4u;
#pragma unroll
      for (int p = 0; p < 4; p++) {
        int idx = tid + p * 512;
        int r = idx >> 3, c4 = (idx & 7) << 2;
        int gr = m0 + r;
        int sz = (gr < M) ? 16 : 0;
        if (gr >= M) gr = M - 1;
        cp_async16(st + (uint32_t)(r * AW_ + c4) * 4u,
                   A + (size_t)gr * K + k0 + c4, sz);
      }
      uint32_t stb = st + (uint32_t)AWORDS_ * 4u;
#pragma unroll
      for (int p = 0; p < 2; p++) {
        int idx = tid + p * 512;
        int kr = idx >> 5, nc4 = (idx & 31) << 2;
        cp_async16(stb + (uint32_t)(kr * BW_ + nc4) * 4u,
                   W + (size_t)(k0 + kr) * N + n0 + nc4, 16);
      }
    }
    CP_COMMIT();
  };

  float acc[4][4][4];
#pragma unroll
  for (int mt = 0; mt < 4; mt++)
#pragma unroll
    for (int nt = 0; nt < 4; nt++)
#pragma unroll
      for (int i = 0; i < 4; i++) acc[mt][nt][i] = 0.f;

  issue(0);
  issue(1);

  const int gid = lane >> 2, tig = lane & 3;

  for (int kt = 0; kt < NKT; kt++) {
    CP_WAIT1();
    __syncthreads();
    const float* sa = smf + (kt % 3) * STAGE_;
    const float* sb = sa + AWORDS_;
    const float* arow = sa + (warpM * 64 + gid) * AW_;
    const float* bcol = sb + warpN * 32 + gid;
#pragma unroll
    for (int ks2 = 0; ks2 < 2; ks2++) {      // two k16 steps per BK=32 tile
      const int kk = ks2 * 16 + tig * 2;     // lo k index for this thread's pairs
      uint32_t a[4][4];
      uint32_t b[4][2];
#pragma unroll
      for (int mt = 0; mt < 4; mt++) {
        const float* r0 = arow + mt * 16 * AW_;
        float2 p0 = *(const float2*)(r0 + kk);
        float2 p1 = *(const float2*)(r0 + 8 * AW_ + kk);
        float2 p2 = *(const float2*)(r0 + kk + 8);
        float2 p3 = *(const float2*)(r0 + 8 * AW_ + kk + 8);
        a[mt][0] = pack_h2(p0.x, p0.y);
        a[mt][1] = pack_h2(p1.x, p1.y);
        a[mt][2] = pack_h2(p2.x, p2.y);
        a[mt][3] = pack_h2(p3.x, p3.y);
      }
#pragma unroll
      for (int nt = 0; nt < 4; nt++) {
        const float* bp = bcol + nt * 8;
        b[nt][0] = pack_h2(bp[kk * BW_], bp[(kk + 1) * BW_]);
        b[nt][1] = pack_h2(bp[(kk + 8) * BW_], bp[(kk + 9) * BW_]);
      }
#pragma unroll
      for (int mt = 0; mt < 4; mt++)
#pragma unroll
        for (int nt = 0; nt < 4; nt++) mma_f16(acc[mt][nt], a[mt], b[nt]);
    }
    issue(kt + 2);
  }
  CP_WAIT0();
  __syncthreads();

  // ---- fused epilogue ----
  const float* Tz = gf.T[z];
  const float* upz = gf.up[z];
  float* dst = gf.dst[z];
  const int seq = gf.seq[z], rowOff = gf.rowOff[z], doRMS = gf.rms[z];

  float bb0[4], bb1[4];
#pragma unroll
  for (int nt = 0; nt < 4; nt++) {
    int col = n0 + warpN * 32 + nt * 8 + tig * 2;
    bb0[nt] = bias ? bias[col] : 0.f;
    bb1[nt] = bias ? bias[col + 1] : 0.f;
  }
#pragma unroll
  for (int mt = 0; mt < 4; mt++) {
    int gr0 = m0 + warpM * 64 + mt * 16 + gid;
#pragma unroll
    for (int nt = 0; nt < 4; nt++) {
      acc[mt][nt][0] += bb0[nt]; acc[mt][nt][1] += bb1[nt];
      acc[mt][nt][2] += bb0[nt]; acc[mt][nt][3] += bb1[nt];
    }
    if (upz) {
      int l0 = gr0 - (M - COND_);
      int l1 = l0 + 8;
      if (l1 >= 0) {
        bool h0 = (l0 >= 0);
#pragma unroll
        for (int i0 = 0; i0 < 16; i0 += 4) {
          float4 t1q = *(const float4*)(Tz + (size_t)l1 * 16 + i0);
          float4 t0q = h0 ? *(const float4*)(Tz + (size_t)l0 * 16 + i0)
                          : make_float4(0.f, 0.f, 0.f, 0.f);
          float tv0[4] = {t0q.x, t0q.y, t0q.z, t0q.w};
          float tv1[4] = {t1q.x, t1q.y, t1q.z, t1q.w};
#pragma unroll
          for (int j = 0; j < 4; j++) {
#pragma unroll
            for (int nt = 0; nt < 4; nt++) {
              int col = n0 + warpN * 32 + nt * 8 + tig * 2;
              float2 u = *(const float2*)(upz + (size_t)(i0 + j) * N + col);
              acc[mt][nt][0] = fmaf(tv0[j], u.x, acc[mt][nt][0]);
              acc[mt][nt][1] = fmaf(tv0[j], u.y, acc[mt][nt][1]);
              acc[mt][nt][2] = fmaf(tv1[j], u.x, acc[mt][nt][2]);
              acc[mt][nt][3] = fmaf(tv1[j], u.y, acc[mt][nt][3]);
            }
          }
        }
      }
    }
  }

  if (doRMS) {
    float* ssm = smf;  // [256][4], 4KB (mainloop smem dead now)
#pragma unroll
    for (int mt = 0; mt < 4; mt++) {
      int lr = warpM * 64 + mt * 16 + gid;
      float ss0 = 0.f, ss1 = 0.f;
#pragma unroll
      for (int nt = 0; nt < 4; nt++) {
        ss0 = fmaf(acc[mt][nt][0], acc[mt][nt][0], ss0);
        ss0 = fmaf(acc[mt][nt][1], acc[mt][nt][1], ss0);
        ss1 = fmaf(acc[mt][nt][2], acc[mt][nt][2], ss1);
        ss1 = fmaf(acc[mt][nt][3], acc[mt][nt][3], ss1);
      }
      ss0 += __shfl_xor_sync(0xffffffffu, ss0, 1);
      ss0 += __shfl_xor_sync(0xffffffffu, ss0, 2);
      ss1 += __shfl_xor_sync(0xffffffffu, ss1, 1);
      ss1 += __shfl_xor_sync(0xffffffffu, ss1, 2);
      if (tig == 0) {
        ssm[lr * 4 + warpN] = ss0;
        ssm[(lr + 8) * 4 + warpN] = ss1;
      }
    }
    __syncthreads();
#pragma unroll
    for (int mt = 0; mt < 4; mt++) {
      int lr = warpM * 64 + mt * 16 + gid;
      float4 s0 = *(const float4*)&ssm[lr * 4];
      float4 s1 = *(const float4*)&ssm[(lr + 8) * 4];
      float sc0 = rsqrtf((s0.x + s0.y + s0.z + s0.w) * (1.f / 128.f) + EPS_);
      float sc1 = rsqrtf((s1.x + s1.y + s1.z + s1.w) * (1.f / 128.f) + EPS_);
#pragma unroll
      for (int nt = 0; nt < 4; nt++) {
        acc[mt][nt][0] *= sc0; acc[mt][nt][1] *= sc0;
        acc[mt][nt][2] *= sc1; acc[mt][nt][3] *= sc1;
      }
    }
  }

  const int head = n0 >> 7;
#pragma unroll
  for (int mt = 0; mt < 4; mt++) {
    int gr0 = m0 + warpM * 64 + mt * 16 + gid;
    int gr1 = gr0 + 8;
#pragma unroll
    for (int nt = 0; nt < 4; nt++) {
      int colh = warpN * 32 + nt * 8 + tig * 2;
      float2 v0 = make_float2(acc[mt][nt][0], acc[mt][nt][1]);
      float2 v1 = make_float2(acc[mt][nt][2], acc[mt][nt][3]);
      if (seq) {
        float* bp = dst + ((size_t)head * seq + rowOff) * 128 + colh;
        if (gr0 < M) *(float2*)(bp + (size_t)gr0 * 128) = v0;
        if (gr1 < M) *(float2*)(bp + (size_t)gr1 * 128) = v1;
      } else {
        if (gr0 < M) *(float2*)(dst + (size_t)gr0 * N + n0 + colh) = v0;
        if (gr1 < M) *(float2*)(dst + (size_t)gr1 * N + n0 + colh) = v1;
      }
    }
  }
}

// ---------------- single LoRA for the output projection (post-Wo, in-place) ----------------
__global__ void __launch_bounds__(256) lora_kernel(
    const float* __restrict__ A, const float* __restrict__ dn,
    const float* __restrict__ up, float* __restrict__ C) {
  __shared__ float red[8 * 16];
  __shared__ float st[16];
  const int r = blockIdx.x, tid = threadIdx.x, lane = tid & 31, wid = tid >> 5;
  const float* a = A + (size_t)r * D_;
  float p[16];
#pragma unroll
  for (int i = 0; i < 16; i++) p[i] = 0.f;
  for (int k = tid; k < D_; k += 256) {
    float av = a[k];
    float4 d0 = *(const float4*)(dn + k * 16);
    float4 d1 = *(const float4*)(dn + k * 16 + 4);
    float4 d2 = *(const float4*)(dn + k * 16 + 8);
    float4 d3 = *(const float4*)(dn + k * 16 + 12);
    p[0]  = fmaf(av, d0.x, p[0]);  p[1]  = fmaf(av, d0.y, p[1]);
    p[2]  = fmaf(av, d0.z, p[2]);  p[3]  = fmaf(av, d0.w, p[3]);
    p[4]  = fmaf(av, d1.x, p[4]);  p[5]  = fmaf(av, d1.y, p[5]);
    p[6]  = fmaf(av, d1.z, p[6]);  p[7]  = fmaf(av, d1.w, p[7]);
    p[8]  = fmaf(av, d2.x, p[8]);  p[9]  = fmaf(av, d2.y, p[9]);
    p[10] = fmaf(av, d2.z, p[10]); p[11] = fmaf(av, d2.w, p[11]);
    p[12] = fmaf(av, d3.x, p[12]); p[13] = fmaf(av, d3.y, p[13]);
    p[14] = fmaf(av, d3.z, p[14]); p[15] = fmaf(av, d3.w, p[15]);
  }
#pragma unroll
  for (int o = 16; o; o >>= 1)
#pragma unroll
    for (int i = 0; i < 16; i++) p[i] += __shfl_xor_sync(0xffffffffu, p[i], o);
  if (lane == 0)
#pragma unroll
    for (int i = 0; i < 16; i++) red[wid * 16 + i] = p[i];
  __syncthreads();
  if (tid < 16) {
    float s = 0.f;
#pragma unroll
    for (int w = 0; w < 8; w++) s += red[w * 16 + tid];
    st[tid] = s;
  }
  __syncthreads();
  float t0[16];
#pragma unroll
  for (int i = 0; i < 16; i++) t0[i] = st[i];
  float* crow = C + (size_t)r * D_;
  for (int c = tid; c < D_; c += 256) {
    float s = 0.f;
#pragma unroll
    for (int i = 0; i < 16; i++) s = fmaf(t0[i], up[(size_t)i * D_ + c], s);
    crow[c] += s;
  }
}

// ---------------- tensor-core flash attention + fused IP attention (unchanged) ----------------
__global__ void __launch_bounds__(256) attn_mma_kernel(
    const float* __restrict__ Q, const float* __restrict__ K,
    const float* __restrict__ V, const float* __restrict__ KIP,
    const float* __restrict__ VIP, float* __restrict__ outE,
    float* __restrict__ outM) {
  extern __shared__ uint32_t smA[];
  uint32_t* Ks = smA;            // 8192 words
  uint32_t* Vs = smA + 8192;     // 8192 words
  const int tid = threadIdx.x, lane = tid & 31, w = tid >> 5;
  const int gid = lane >> 2, tig = lane & 3;
  const int h = blockIdx.y, q0 = blockIdx.x * 128;

  uint32_t qf[16][4];
  {
    const float* Qg = Q + ((size_t)h * SL_ + q0) * DH_;
    const float* qr0 = Qg + (w * 16 + gid) * DH_;
    const float* qr1 = qr0 + 8 * DH_;
#pragma unroll
    for (int ks = 0; ks < 16; ks++) {
      qf[ks][0] = f2tf32(qr0[ks * 8 + tig] * SCALE_);
      qf[ks][1] = f2tf32(qr1[ks * 8 + tig] * SCALE_);
      qf[ks][2] = f2tf32(qr0[ks * 8 + tig + 4] * SCALE_);
      qf[ks][3] = f2tf32(qr1[ks * 8 + tig + 4] * SCALE_);
    }
  }

  float o[16][4];
#pragma unroll
  for (int i = 0; i < 16; i++) { o[i][0] = o[i][1] = o[i][2] = o[i][3] = 0.f; }
  float m0 = -1e30f, m1 = -1e30f, l0 = 0.f, l1 = 0.f;

  const int lr = tid >> 5;
  const int lc4 = (tid & 31) << 2;

  const int kt0 = (q0 >= SB_) ? (SB_ / 64) : 0;
  for (int kt = kt0; kt < SL_ / 64; kt++) {
    __syncthreads();
    const float* Kt = K + ((size_t)h * SL_ + kt * 64) * DH_;
    const float* Vt = V + ((size_t)h * SL_ + kt * 64) * DH_;
    float4 ka[8], va[8];
#pragma unroll
    for (int it = 0; it < 8; it++) ka[it] = *(const float4*)(Kt + (lr + it * 8) * DH_ + lc4);
#pragma unroll
    for (int it = 0; it < 8; it++) va[it] = *(const float4*)(Vt + (lr + it * 8) * DH_ + lc4);
#pragma unroll
    for (int it = 0; it < 8; it++) {
      int r = lr + it * 8;
      int nt = r >> 3, j = r & 7;
      int nn = ((j & 3) << 1) | (j >> 2);  // pi(j)
      float vv[4] = {ka[it].x, ka[it].y, ka[it].z, ka[it].w};
#pragma unroll
      for (int e = 0; e < 4; e++) {
        int c = lc4 + e;
        int ks = c >> 3, reg = (c >> 2) & 1, tg = c & 3;
        Ks[((nt * 16 + ks) * 32 + ((nn * 4 + tg) ^ ks)) * 2 + reg] = f2tf32(vv[e]);
      }
    }
    __syncthreads();

    float sa[8][4];
#pragma unroll
    for (int nt = 0; nt < 8; nt++) { sa[nt][0] = sa[nt][1] = sa[nt][2] = sa[nt][3] = 0.f; }
#pragma unroll
    for (int ks = 0; ks < 16; ks++) {
#pragma unroll
      for (int nt = 0; nt < 8; nt++) {
        uint2 b2 = *(const uint2*)(Ks + ((nt * 16 + ks) * 32 + (lane ^ ks)) * 2);
        uint32_t bb[2] = {b2.x, b2.y};
        mma_tf32(sa[nt], qf[ks], bb);
      }
    }

    float rm0 = -1e30f, rm1 = -1e30f;
#pragma unroll
    for (int nt = 0; nt < 8; nt++) {
      rm0 = fmaxf(rm0, fmaxf(sa[nt][0], sa[nt][1]));
      rm1 = fmaxf(rm1, fmaxf(sa[nt][2], sa[nt][3]));
    }
#pragma unroll
    for (int off = 1; off < 4; off <<= 1) {
      rm0 = fmaxf(rm0, __shfl_xor_sync(0xffffffffu, rm0, off));
      rm1 = fmaxf(rm1, __shfl_xor_sync(0xffffffffu, rm1, off));
    }
    float mn0 = fmaxf(m0, rm0), mn1 = fmaxf(m1, rm1);
    float corr0 = __expf(m0 - mn0), corr1 = __expf(m1 - mn1);
    m0 = mn0; m1 = mn1;
    float rs0 = 0.f, rs1 = 0.f;
#pragma unroll
    for (int nt = 0; nt < 8; nt++) {
      sa[nt][0] = __expf(sa[nt][0] - mn0); rs0 += sa[nt][0];
      sa[nt][1] = __expf(sa[nt][1] - mn0); rs0 += sa[nt][1];
      sa[nt][2] = __expf(sa[nt][2] - mn1); rs1 += sa[nt][2];
      sa[nt][3] = __expf(sa[nt][3] - mn1); rs1 += sa[nt][3];
    }
#pragma unroll
    for (int off = 1; off < 4; off <<= 1) {
      rs0 += __shfl_xor_sync(0xffffffffu, rs0, off);
      rs1 += __shfl_xor_sync(0xffffffffu, rs1, off);
    }
    l0 = l0 * corr0 + rs0;
    l1 = l1 * corr1 + rs1;
#pragma unroll
    for (int i = 0; i < 16; i++) {
      o[i][0] *= corr0; o[i][1] *= corr0; o[i][2] *= corr1; o[i][3] *= corr1;
    }

#pragma unroll
    for (int it = 0; it < 8; it++) {
      int k2 = lr + it * 8;
      int ks = k2 >> 3, reg = (k2 >> 2) & 1, tg = k2 & 3;
      float vv[4] = {va[it].x, va[it].y, va[it].z, va[it].w};
#pragma unroll
      for (int e = 0; e < 4; e++) {
        int c = lc4 + e;
        int ntd = c >> 3, n = c & 7;
        Vs[((ntd * 8 + ks) * 32 + ((n * 4 + tg) ^ ntd)) * 2 + reg] = f2tf32(vv[e]);
      }
    }
    __syncthreads();

#pragma unroll
    for (int nt = 0; nt < 8; nt++) {
      uint32_t pf[4];
      pf[0] = f2tf32(sa[nt][0]);
      pf[1] = f2tf32(sa[nt][2]);
      pf[2] = f2tf32(sa[nt][1]);
      pf[3] = f2tf32(sa[nt][3]);
#pragma unroll
      for (int ntd = 0; ntd < 16; ntd++) {
        uint2 b2 = *(const uint2*)(Vs + ((ntd * 8 + nt) * 32 + (lane ^ ntd)) * 2);
        uint32_t bb[2] = {b2.x, b2.y};
        mma_tf32(o[ntd], pf, bb);
      }
    }
  }

  float inv0 = 1.f / l0, inv1 = 1.f / l1;
#pragma unroll
  for (int i = 0; i < 16; i++) {
    o[i][0] *= inv0; o[i][1] *= inv0; o[i][2] *= inv1; o[i][3] *= inv1;
  }

  if (q0 >= ENC_) {
    __syncthreads();
    const float* Kt = KIP + (size_t)h * NIP_ * DH_;
    const float* Vt = VIP + (size_t)h * NIP_ * DH_;
    float4 ka[8], va[8];
#pragma unroll
    for (int it = 0; it < 8; it++) ka[it] = *(const float4*)(Kt + (lr + it * 8) * DH_ + lc4);
#pragma unroll
    for (int it = 0; it < 8; it++) va[it] = *(const float4*)(Vt + (lr + it * 8) * DH_ + lc4);
#pragma unroll
    for (int it = 0; it < 8; it++) {
      int r = lr + it * 8;
      int nt = r >> 3, j = r & 7;
      int nn = ((j & 3) << 1) | (j >> 2);
      float vv[4] = {ka[it].x, ka[it].y, ka[it].z, ka[it].w};
#pragma unroll
      for (int e = 0; e < 4; e++) {
        int c = lc4 + e;
        int ks = c >> 3, reg = (c >> 2) & 1, tg = c & 3;
        Ks[((nt * 16 + ks) * 32 + ((nn * 4 + tg) ^ ks)) * 2 + reg] = f2tf32(vv[e]);
      }
    }
    __syncthreads();

    float sa[8][4];
#pragma unroll
    for (int nt = 0; nt < 8; nt++) { sa[nt][0] = sa[nt][1] = sa[nt][2] = sa[nt][3] = 0.f; }
#pragma unroll
    for (int ks = 0; ks < 16; ks++) {
#pragma unroll
      for (int nt = 0; nt < 8; nt++) {
        uint2 b2 = *(const uint2*)(Ks + ((nt * 16 + ks) * 32 + (lane ^ ks)) * 2);
        uint32_t bb[2] = {b2.x, b2.y};
        mma_tf32(sa[nt], qf[ks], bb);
      }
    }
    float rm0 = -1e30f, rm1 = -1e30f;
#pragma unroll
    for (int nt = 0; nt < 8; nt++) {
      rm0 = fmaxf(rm0, fmaxf(sa[nt][0], sa[nt][1]));
      rm1 = fmaxf(rm1, fmaxf(sa[nt][2], sa[nt][3]));
    }
#pragma unroll
    for (int off = 1; off < 4; off <<= 1) {
      rm0 = fmaxf(rm0, __shfl_xor_sync(0xffffffffu, rm0, off));
      rm1 = fmaxf(rm1, __shfl_xor_sync(0xffffffffu, rm1, off));
    }
    float rs0 = 0.f, rs1 = 0.f;
#pragma unroll
    for (int nt = 0; nt < 8; nt++) {
      sa[nt][0] = __expf(sa[nt][0] - rm0); rs0 += sa[nt][0];
      sa[nt][1] = __expf(sa[nt][1] - rm0); rs0 += sa[nt][1];
      sa[nt][2] = __expf(sa[nt][2] - rm1); rs1 += sa[nt][2];
      sa[nt][3] = __expf(sa[nt][3] - rm1); rs1 += sa[nt][3];
    }
#pragma unroll
    for (int off = 1; off < 4; off <<= 1) {
      rs0 += __shfl_xor_sync(0xffffffffu, rs0, off);
      rs1 += __shfl_xor_sync(0xffffffffu, rs1, off);
    }
    float iv0 = 1.f / rs0, iv1 = 1.f / rs1;
#pragma unroll
    for (int it = 0; it < 8; it++) {
      int k2 = lr + it * 8;
      int ks = k2 >> 3, reg = (k2 >> 2) & 1, tg = k2 & 3;
      float vv[4] = {va[it].x, va[it].y, va[it].z, va[it].w};
#pragma unroll
      for (int e = 0; e < 4; e++) {
        int c = lc4 + e;
        int ntd = c >> 3, n = c & 7;
        Vs[((ntd * 8 + ks) * 32 + ((n * 4 + tg) ^ ntd)) * 2 + reg] = f2tf32(vv[e]);
      }
    }
    __syncthreads();
#pragma unroll
    for (int nt = 0; nt < 8; nt++) {
      uint32_t pf[4];
      pf[0] = f2tf32(sa[nt][0] * iv0);
      pf[1] = f2tf32(sa[nt][2] * iv1);
      pf[2] = f2tf32(sa[nt][1] * iv0);
      pf[3] = f2tf32(sa[nt][3] * iv1);
#pragma unroll
      for (int ntd = 0; ntd < 16; ntd++) {
        uint2 b2 = *(const uint2*)(Vs + ((ntd * 8 + nt) * 32 + (lane ^ ntd)) * 2);
        uint32_t bb[2] = {b2.x, b2.y};
        mma_tf32(o[ntd], pf, bb);
      }
    }
  }

  int row0 = q0 + w * 16 + gid, row1 = row0 + 8;
#pragma unroll
  for (int ntd = 0; ntd < 16; ntd++) {
    int col = h * DH_ + ntd * 8 + tig * 2;
    float2 v0 = make_float2(o[ntd][0], o[ntd][1]);
    float2 v1 = make_float2(o[ntd][2], o[ntd][3]);
    if (row0 < ENC_) {
      *(float2*)(outE + (size_t)row0 * D_ + col) = v0;
      *(float2*)(outE + (size_t)row1 * D_ + col) = v1;
    } else {
      *(float2*)(outM + (size_t)(row0 - ENC_) * D_ + col) = v0;
      *(float2*)(outM + (size_t)(row1 - ENC_) * D_ + col) = v1;
    }
  }
}

// ---------------- launch ----------------
extern "C" void kernel_launch(void* const* d_in, const int* in_sizes, int n_in,
                              void* d_out, int out_size) {
  const float* hs   = (const float*)d_in[0];
  const float* ehs  = (const float*)d_in[1];
  const float* img  = (const float*)d_in[2];
  const float* Wq   = (const float*)d_in[3];  const float* bq  = (const float*)d_in[4];
  const float* Wk   = (const float*)d_in[5];  const float* bk  = (const float*)d_in[6];
  const float* Wv   = (const float*)d_in[7];  const float* bv  = (const float*)d_in[8];
  const float* Waq  = (const float*)d_in[9];  const float* baq = (const float*)d_in[10];
  const float* Wak  = (const float*)d_in[11]; const float* bak = (const float*)d_in[12];
  const float* Wav  = (const float*)d_in[13]; const float* bav = (const float*)d_in[14];
  const float* Wo   = (const float*)d_in[15]; const float* bo  = (const float*)d_in[16];
  const float* Wao  = (const float*)d_in[17]; const float* bao = (const float*)d_in[18];
  const float* Wkip = (const float*)d_in[19]; const float* Wvip = (const float*)d_in[20];
  const float* lq_dn = (const float*)d_in[21]; const float* lq_up = (const float*)d_in[22];
  const float* lk_dn = (const float*)d_in[23]; const float* lk_up = (const float*)d_in[24];
  const float* lv_dn = (const float*)d_in[25]; const float* lv_up = (const float*)d_in[26];
  const float* lp_dn = (const float*)d_in[27]; const float* lp_up = (const float*)d_in[28];
  float* out = (float*)d_out;

  float *Q, *K, *V, *KIP, *VIP, *am, *ae, *T3;
  cudaGetSymbolAddress((void**)&Q, g_Q);
  cudaGetSymbolAddress((void**)&K, g_K);
  cudaGetSymbolAddress((void**)&V, g_V);
  cudaGetSymbolAddress((void**)&KIP, g_KIP);
  cudaGetSymbolAddress((void**)&VIP, g_VIP);
  cudaGetSymbolAddress((void**)&am, g_am);
  cudaGetSymbolAddress((void**)&ae, g_ae);
  cudaGetSymbolAddress((void**)&T3, g_T3);

  const int G_SMEM = 3 * STAGE_ * 4;        // 161280 B
  const int ATTN_SMEM = (8192 + 8192) * 4;  // 65536
  cudaFuncSetAttribute(gemm_f, cudaFuncAttributeMaxDynamicSharedMemorySize, G_SMEM);
  cudaFuncSetAttribute(attn_mma_kernel, cudaFuncAttributeMaxDynamicSharedMemorySize, ATTN_SMEM);

  float* outMain = out + (size_t)ENC_ * D_;
  const float* hsC = hs + (size_t)(S_ - COND_) * D_;

  // 1. lora-down temps for q,k,v
  D3 d3 = {{lq_dn, lk_dn, lv_dn}};
  lora_dn3<<<COND_ / 8, 256>>>(hsC, d3, T3);

  // 2. main QKV projections, fully fused (bias + lora-up + RMS + head-major)
  GF gqkv = {
    {hs, hs, hs, 0, 0}, {Wq, Wk, Wv, 0, 0}, {bq, bk, bv, 0, 0},
    {T3, T3 + COND_ * 16, T3 + 2 * COND_ * 16, 0, 0}, {lq_up, lk_up, lv_up, 0, 0},
    {Q, K, V, 0, 0},
    {S_, S_, S_, 1, 1}, {SL_, SL_, SL_, 1, 1}, {ENC_, ENC_, ENC_, 0, 0}, {1, 1, 0, 0, 0}};
  gemm_f<<<dim3(24, 8, 3), 512, G_SMEM>>>(gqkv, D_, D_);

  // 3. encoder + IP projections in one launch (bias/RMS as needed, head-major)
  GF gei = {
    {ehs, ehs, ehs, img, img}, {Waq, Wak, Wav, Wkip, Wvip}, {baq, bak, bav, 0, 0},
    {0, 0, 0, 0, 0}, {0, 0, 0, 0, 0},
    {Q, K, V, KIP, VIP},
    {ENC_, ENC_, ENC_, NIP_, NIP_}, {SL_, SL_, SL_, NIP_, NIP_},
    {0, 0, 0, 0, 0}, {1, 1, 0, 1, 0}};
  gemm_f<<<dim3(24, 2, 5), 512, G_SMEM>>>(gei, D_, D_);

  // 4. joint attention with fused IP attention
  attn_mma_kernel<<<dim3(SL_ / 128, H_), 256, ATTN_SMEM>>>(Q, K, V, KIP, VIP, ae, am);

  // 5. output projections (Wo + Wao batched), plain row-major epilogue
  GF gout = {
    {am, ae, 0, 0, 0}, {Wo, Wao, 0, 0, 0}, {bo, bao, 0, 0, 0},
    {0, 0, 0, 0, 0}, {0, 0, 0, 0, 0},
    {outMain, out, 0, 0, 0},
    {S_, ENC_, 1, 1, 1}, {0, 0, 0, 0, 0}, {0, 0, 0, 0, 0}, {0, 0, 0, 0, 0}};
  gemm_f<<<dim3(24, 8, 2), 512, G_SMEM>>>(gout, D_, D_);

  // 6. output LoRA (post-Wo, in-place on last COND rows)
  float* outCond = outMain + (size_t)(S_ - COND_) * D_;
  lora_kernel<<<COND_, 256>>>(outCond, lp_dn, lp_up, outCond);
}

// round 12
// speedup vs baseline: 6.7570x; 1.1849x over previous
#include <cuda_runtime.h>
#include <math.h>
#include <stdint.h>

// ---------------- problem constants ----------------
#define D_    3072
#define K2_   1536   // D/2 (packed f16x2 along k)
#define S_    2048
#define H_    24
#define DH_   128
#define ENC_  512
#define NIP_  64
#define COND_ 1024
#define SL_   2560   // ENC + S
#define SB_   1536   // SL - COND
#define RANK_ 16
#define EPS_  1e-5f
#define SCALE_ 0.08838834764831845f  // 1/sqrt(128)

// ---------------- scratch (device globals; no allocations allowed) ----------------
__device__ float g_Q[H_ * SL_ * DH_];
__device__ float g_K[H_ * SL_ * DH_];
__device__ float g_V[H_ * SL_ * DH_];
__device__ float g_KIP[H_ * NIP_ * DH_];
__device__ float g_VIP[H_ * NIP_ * DH_];
__device__ float g_T3[3 * COND_ * RANK_];   // lora-down temps for q,k,v
// packed f16x2 operand buffers
__device__ uint32_t g_WH[10 * K2_ * D_];    // 10 weight matrices, [k2][n]
__device__ uint32_t g_hsH[S_ * K2_];        // activations, [row][k2]
__device__ uint32_t g_ehsH[ENC_ * K2_];
__device__ uint32_t g_imgH[NIP_ * K2_];
__device__ uint32_t g_amH[S_ * K2_];        // attention main out (incl. IP), packed
__device__ uint32_t g_aeH[ENC_ * K2_];      // attention encoder out, packed

// ---------------- helpers ----------------
__device__ __forceinline__ uint32_t f2tf32(float x) {
  uint32_t r;
  asm("cvt.rna.tf32.f32 %0, %1;" : "=r"(r) : "f"(x));
  return r;
}

__device__ __forceinline__ uint32_t pack_h2(float lo, float hi) {
  uint32_t r;
  asm("cvt.rn.f16x2.f32 %0, %1, %2;" : "=r"(r) : "f"(hi), "f"(lo));
  return r;
}

__device__ __forceinline__ void mma_tf32(float c[4], const uint32_t a[4], const uint32_t b[2]) {
  asm("mma.sync.aligned.m16n8k8.row.col.f32.tf32.tf32.f32 "
      "{%0,%1,%2,%3}, {%4,%5,%6,%7}, {%8,%9}, {%0,%1,%2,%3};"
      : "+f"(c[0]), "+f"(c[1]), "+f"(c[2]), "+f"(c[3])
      : "r"(a[0]), "r"(a[1]), "r"(a[2]), "r"(a[3]), "r"(b[0]), "r"(b[1]));
}

__device__ __forceinline__ void mma_f16(float c[4], const uint32_t a[4], const uint32_t b[2]) {
  asm("mma.sync.aligned.m16n8k16.row.col.f32.f16.f16.f32 "
      "{%0,%1,%2,%3}, {%4,%5,%6,%7}, {%8,%9}, {%0,%1,%2,%3};"
      : "+f"(c[0]), "+f"(c[1]), "+f"(c[2]), "+f"(c[3])
      : "r"(a[0]), "r"(a[1]), "r"(a[2]), "r"(a[3]), "r"(b[0]), "r"(b[1]));
}

__device__ __forceinline__ void cp_async16(uint32_t smem_addr, const void* gptr, int src_bytes) {
  asm volatile("cp.async.cg.shared.global [%0], [%1], 16, %2;"
               :: "r"(smem_addr), "l"(gptr), "r"(src_bytes) : "memory");
}
#define CP_COMMIT() asm volatile("cp.async.commit_group;" ::: "memory")
#define CP_WAIT1()  asm volatile("cp.async.wait_group 1;" ::: "memory")
#define CP_WAIT0()  asm volatile("cp.async.wait_group 0;" ::: "memory")

// ---------------- conversion kernels ----------------
// A-layout: AH[row*K2 + k2] = pack(A[row*K + 2k2], A[row*K + 2k2+1]) == pack(A[2i], A[2i+1])
__global__ void cvtA_kernel(const float* __restrict__ A, uint32_t* __restrict__ AH, int n) {
  int i = blockIdx.x * 256 + threadIdx.x;
  if (i < n) {
    float2 v = *(const float2*)(A + 2 * (size_t)i);
    AH[i] = pack_h2(v.x, v.y);
  }
}

// B-layout: WH[k2*N + n] = pack(W[2k2*N + n], W[(2k2+1)*N + n])
struct W10 { const float* W[10]; };
__global__ void cvtB_kernel(W10 g, uint32_t* __restrict__ WH) {
  int z = blockIdx.y;
  const float* W = g.W[z];
  uint32_t* dst = WH + (size_t)z * K2_ * D_;
  int i = blockIdx.x * 256 + threadIdx.x;   // over K2*N
  int k2 = i / D_, n = i - k2 * D_;
  dst[i] = pack_h2(W[(size_t)(2 * k2) * D_ + n], W[(size_t)(2 * k2 + 1) * D_ + n]);
}

// ---------------- lora-down: T[t][r][16] = hsC[r,:] @ dn_t (warp per row) ----------------
struct D3 { const float* dn[3]; };

__global__ void __launch_bounds__(256) lora_dn3(const float* __restrict__ A, D3 g,
                                                float* __restrict__ T) {
  const int tid = threadIdx.x, lane = tid & 31, w = tid >> 5;
  const int row = blockIdx.x * 8 + w;
  const float* a = A + (size_t)row * D_;
  float p[48];
#pragma unroll
  for (int i = 0; i < 48; i++) p[i] = 0.f;
  for (int k = lane; k < D_; k += 32) {
    float av = a[k];
#pragma unroll
    for (int t = 0; t < 3; t++) {
      const float* dk = g.dn[t] + k * 16;
      float4 d0 = *(const float4*)(dk);
      float4 d1 = *(const float4*)(dk + 4);
      float4 d2 = *(const float4*)(dk + 8);
      float4 d3 = *(const float4*)(dk + 12);
      float* pt = p + t * 16;
      pt[0]  = fmaf(av, d0.x, pt[0]);  pt[1]  = fmaf(av, d0.y, pt[1]);
      pt[2]  = fmaf(av, d0.z, pt[2]);  pt[3]  = fmaf(av, d0.w, pt[3]);
      pt[4]  = fmaf(av, d1.x, pt[4]);  pt[5]  = fmaf(av, d1.y, pt[5]);
      pt[6]  = fmaf(av, d1.z, pt[6]);  pt[7]  = fmaf(av, d1.w, pt[7]);
      pt[8]  = fmaf(av, d2.x, pt[8]);  pt[9]  = fmaf(av, d2.y, pt[9]);
      pt[10] = fmaf(av, d2.z, pt[10]); pt[11] = fmaf(av, d2.w, pt[11]);
      pt[12] = fmaf(av, d3.x, pt[12]); pt[13] = fmaf(av, d3.y, pt[13]);
      pt[14] = fmaf(av, d3.z, pt[14]); pt[15] = fmaf(av, d3.w, pt[15]);
    }
  }
#pragma unroll
  for (int off = 16; off; off >>= 1)
#pragma unroll
    for (int i = 0; i < 48; i++) p[i] += __shfl_xor_sync(0xffffffffu, p[i], off);
  if (lane == 0) {
#pragma unroll
    for (int t = 0; t < 3; t++) {
      float* dt = T + ((size_t)t * COND_ + row) * 16;
#pragma unroll
      for (int i = 0; i < 16; i += 4)
        *(float4*)(dt + i) = make_float4(p[t*16+i], p[t*16+i+1], p[t*16+i+2], p[t*16+i+3]);
    }
  }
}

// ---------------- fused fp16 GEMM on pre-packed operands ----------------
// BM=128 x BN=128, BK=32 (16 u32), 256 threads (8 warps 2M x 4N, warp tile 64x32),
// __launch_bounds__(256,2) -> 2 blocks/SM. 3-stage cp.async of packed u32 tiles
// (half the bytes, zero mainloop CVTs). A smem stride 20 u32, B stride 136 u32:
// both fragment-LDS patterns are exact 32-bank permutations. Fragment values and
// accumulation order identical to R10 -> bit-identical numerics.
struct GF {
  const uint32_t* A[5]; const uint32_t* W[5]; const float* bias[5];
  const float* T[5]; const float* up[5];
  float* dst[5];
  int M[5]; int seq[5]; int rowOff[5]; int rms[5];
};

#define AW2_ 20
#define BW2_ 136
#define AWORDS2_ (128 * AW2_)            // 2560
#define STAGE2_ (AWORDS2_ + 16 * BW2_)   // 4736 u32 = 18944 B

__global__ void __launch_bounds__(256, 2) gemm_h(GF gf, int N, int K) {
  extern __shared__ uint32_t smu[];
  const uint32_t sbase = (uint32_t)__cvta_generic_to_shared(smu);

  const int z = blockIdx.z;
  const uint32_t* __restrict__ A = gf.A[z];
  const uint32_t* __restrict__ W = gf.W[z];
  const float* __restrict__ bias = gf.bias[z];
  const int M = gf.M[z];
  const int K2 = K / 2;

  const int tid = threadIdx.x;
  const int lane = tid & 31;
  const int wid = tid >> 5;
  const int warpM = wid >> 2;   // 0..1 (64 rows each)
  const int warpN = wid & 3;    // 0..3 (32 cols each)
  const int m0 = blockIdx.y * 128;
  const int n0 = blockIdx.x * 128;
  if (m0 >= M) return;

  const int NKT = K / 32;

  auto issue = [&](int kt) {
    if (kt < NKT) {
      int k20 = kt * 16;
      uint32_t st = sbase + (uint32_t)((kt % 3) * STAGE2_) * 4u;
#pragma unroll
      for (int p = 0; p < 2; p++) {
        int ch = tid + p * 256;
        int r = ch >> 2, c4 = (ch & 3) << 2;
        int gr = m0 + r;
        int sz = (gr < M) ? 16 : 0;
        if (gr >= M) gr = M - 1;
        cp_async16(st + (uint32_t)(r * AW2_ + c4) * 4u,
                   A + (size_t)gr * K2 + k20 + c4, sz);
      }
      uint32_t stb = st + (uint32_t)AWORDS2_ * 4u;
#pragma unroll
      for (int p = 0; p < 2; p++) {
        int ch = tid + p * 256;
        int kr = ch >> 5, n4 = (ch & 31) << 2;
        cp_async16(stb + (uint32_t)(kr * BW2_ + n4) * 4u,
                   W + (size_t)(k20 + kr) * N + n0 + n4, 16);
      }
    }
    CP_COMMIT();
  };

  float acc[4][4][4];
#pragma unroll
  for (int mt = 0; mt < 4; mt++)
#pragma unroll
    for (int nt = 0; nt < 4; nt++)
#pragma unroll
      for (int i = 0; i < 4; i++) acc[mt][nt][i] = 0.f;

  issue(0);
  issue(1);

  const int gid = lane >> 2, tig = lane & 3;

  for (int kt = 0; kt < NKT; kt++) {
    CP_WAIT1();
    __syncthreads();
    const uint32_t* sa = smu + (kt % 3) * STAGE2_;
    const uint32_t* sb = sa + AWORDS2_;
    const uint32_t* arow = sa + (warpM * 64 + gid) * AW2_;
    const uint32_t* bcol = sb + warpN * 32 + gid;
#pragma unroll
    for (int ks2 = 0; ks2 < 2; ks2++) {
      const int kb = ks2 * 8;
      uint32_t a[4][4];
      uint32_t b[4][2];
#pragma unroll
      for (int mt = 0; mt < 4; mt++) {
        const uint32_t* r0 = arow + mt * 16 * AW2_;
        a[mt][0] = r0[kb + tig];
        a[mt][1] = r0[8 * AW2_ + kb + tig];
        a[mt][2] = r0[kb + tig + 4];
        a[mt][3] = r0[8 * AW2_ + kb + tig + 4];
      }
#pragma unroll
      for (int nt = 0; nt < 4; nt++) {
        const uint32_t* bp = bcol + nt * 8;
        b[nt][0] = bp[(kb + tig) * BW2_];
        b[nt][1] = bp[(kb + tig + 4) * BW2_];
      }
#pragma unroll
      for (int mt = 0; mt < 4; mt++)
#pragma unroll
        for (int nt = 0; nt < 4; nt++) mma_f16(acc[mt][nt], a[mt], b[nt]);
    }
    issue(kt + 2);
  }
  CP_WAIT0();
  __syncthreads();

  // ---- fused epilogue (f32, unchanged math order) ----
  const float* Tz = gf.T[z];
  const float* upz = gf.up[z];
  float* dst = gf.dst[z];
  const int seq = gf.seq[z], rowOff = gf.rowOff[z], doRMS = gf.rms[z];

  float bb0[4], bb1[4];
#pragma unroll
  for (int nt = 0; nt < 4; nt++) {
    int col = n0 + warpN * 32 + nt * 8 + tig * 2;
    bb0[nt] = bias ? bias[col] : 0.f;
    bb1[nt] = bias ? bias[col + 1] : 0.f;
  }
#pragma unroll
  for (int mt = 0; mt < 4; mt++) {
    int gr0 = m0 + warpM * 64 + mt * 16 + gid;
#pragma unroll
    for (int nt = 0; nt < 4; nt++) {
      acc[mt][nt][0] += bb0[nt]; acc[mt][nt][1] += bb1[nt];
      acc[mt][nt][2] += bb0[nt]; acc[mt][nt][3] += bb1[nt];
    }
    if (upz) {
      int l0 = gr0 - (M - COND_);
      int l1 = l0 + 8;
      if (l1 >= 0) {
        bool h0 = (l0 >= 0);
#pragma unroll
        for (int i0 = 0; i0 < 16; i0 += 4) {
          float4 t1q = *(const float4*)(Tz + (size_t)l1 * 16 + i0);
          float4 t0q = h0 ? *(const float4*)(Tz + (size_t)l0 * 16 + i0)
                          : make_float4(0.f, 0.f, 0.f, 0.f);
          float tv0[4] = {t0q.x, t0q.y, t0q.z, t0q.w};
          float tv1[4] = {t1q.x, t1q.y, t1q.z, t1q.w};
#pragma unroll
          for (int j = 0; j < 4; j++) {
#pragma unroll
            for (int nt = 0; nt < 4; nt++) {
              int col = n0 + warpN * 32 + nt * 8 + tig * 2;
              float2 u = *(const float2*)(upz + (size_t)(i0 + j) * N + col);
              acc[mt][nt][0] = fmaf(tv0[j], u.x, acc[mt][nt][0]);
              acc[mt][nt][1] = fmaf(tv0[j], u.y, acc[mt][nt][1]);
              acc[mt][nt][2] = fmaf(tv1[j], u.x, acc[mt][nt][2]);
              acc[mt][nt][3] = fmaf(tv1[j], u.y, acc[mt][nt][3]);
            }
          }
        }
      }
    }
  }

  if (doRMS) {
    float* ssm = (float*)smu;  // [128][4], 2KB (mainloop smem dead)
#pragma unroll
    for (int mt = 0; mt < 4; mt++) {
      int lr = warpM * 64 + mt * 16 + gid;
      float ss0 = 0.f, ss1 = 0.f;
#pragma unroll
      for (int nt = 0; nt < 4; nt++) {
        ss0 = fmaf(acc[mt][nt][0], acc[mt][nt][0], ss0);
        ss0 = fmaf(acc[mt][nt][1], acc[mt][nt][1], ss0);
        ss1 = fmaf(acc[mt][nt][2], acc[mt][nt][2], ss1);
        ss1 = fmaf(acc[mt][nt][3], acc[mt][nt][3], ss1);
      }
      ss0 += __shfl_xor_sync(0xffffffffu, ss0, 1);
      ss0 += __shfl_xor_sync(0xffffffffu, ss0, 2);
      ss1 += __shfl_xor_sync(0xffffffffu, ss1, 1);
      ss1 += __shfl_xor_sync(0xffffffffu, ss1, 2);
      if (tig == 0) {
        ssm[lr * 4 + warpN] = ss0;
        ssm[(lr + 8) * 4 + warpN] = ss1;
      }
    }
    __syncthreads();
#pragma unroll
    for (int mt = 0; mt < 4; mt++) {
      int lr = warpM * 64 + mt * 16 + gid;
      float4 s0 = *(const float4*)&ssm[lr * 4];
      float4 s1 = *(const float4*)&ssm[(lr + 8) * 4];
      float sc0 = rsqrtf((s0.x + s0.y + s0.z + s0.w) * (1.f / 128.f) + EPS_);
      float sc1 = rsqrtf((s1.x + s1.y + s1.z + s1.w) * (1.f / 128.f) + EPS_);
#pragma unroll
      for (int nt = 0; nt < 4; nt++) {
        acc[mt][nt][0] *= sc0; acc[mt][nt][1] *= sc0;
        acc[mt][nt][2] *= sc1; acc[mt][nt][3] *= sc1;
      }
    }
  }

  const int head = n0 >> 7;
#pragma unroll
  for (int mt = 0; mt < 4; mt++) {
    int gr0 = m0 + warpM * 64 + mt * 16 + gid;
    int gr1 = gr0 + 8;
#pragma unroll
    for (int nt = 0; nt < 4; nt++) {
      int colh = warpN * 32 + nt * 8 + tig * 2;
      float2 v0 = make_float2(acc[mt][nt][0], acc[mt][nt][1]);
      float2 v1 = make_float2(acc[mt][nt][2], acc[mt][nt][3]);
      if (seq) {
        float* bp = dst + ((size_t)head * seq + rowOff) * 128 + colh;
        if (gr0 < M) *(float2*)(bp + (size_t)gr0 * 128) = v0;
        if (gr1 < M) *(float2*)(bp + (size_t)gr1 * 128) = v1;
      } else {
        if (gr0 < M) *(float2*)(dst + (size_t)gr0 * N + n0 + colh) = v0;
        if (gr1 < M) *(float2*)(dst + (size_t)gr1 * N + n0 + colh) = v1;
      }
    }
  }
}

// ---------------- single LoRA for the output projection (post-Wo, in-place) ----------------
__global__ void __launch_bounds__(256) lora_kernel(
    const float* __restrict__ A, const float* __restrict__ dn,
    const float* __restrict__ up, float* __restrict__ C) {
  __shared__ float red[8 * 16];
  __shared__ float st[16];
  const int r = blockIdx.x, tid = threadIdx.x, lane = tid & 31, wid = tid >> 5;
  const float* a = A + (size_t)r * D_;
  float p[16];
#pragma unroll
  for (int i = 0; i < 16; i++) p[i] = 0.f;
  for (int k = tid; k < D_; k += 256) {
    float av = a[k];
    float4 d0 = *(const float4*)(dn + k * 16);
    float4 d1 = *(const float4*)(dn + k * 16 + 4);
    float4 d2 = *(const float4*)(dn + k * 16 + 8);
    float4 d3 = *(const float4*)(dn + k * 16 + 12);
    p[0]  = fmaf(av, d0.x, p[0]);  p[1]  = fmaf(av, d0.y, p[1]);
    p[2]  = fmaf(av, d0.z, p[2]);  p[3]  = fmaf(av, d0.w, p[3]);
    p[4]  = fmaf(av, d1.x, p[4]);  p[5]  = fmaf(av, d1.y, p[5]);
    p[6]  = fmaf(av, d1.z, p[6]);  p[7]  = fmaf(av, d1.w, p[7]);
    p[8]  = fmaf(av, d2.x, p[8]);  p[9]  = fmaf(av, d2.y, p[9]);
    p[10] = fmaf(av, d2.z, p[10]); p[11] = fmaf(av, d2.w, p[11]);
    p[12] = fmaf(av, d3.x, p[12]); p[13] = fmaf(av, d3.y, p[13]);
    p[14] = fmaf(av, d3.z, p[14]); p[15] = fmaf(av, d3.w, p[15]);
  }
#pragma unroll
  for (int o = 16; o; o >>= 1)
#pragma unroll
    for (int i = 0; i < 16; i++) p[i] += __shfl_xor_sync(0xffffffffu, p[i], o);
  if (lane == 0)
#pragma unroll
    for (int i = 0; i < 16; i++) red[wid * 16 + i] = p[i];
  __syncthreads();
  if (tid < 16) {
    float s = 0.f;
#pragma unroll
    for (int w = 0; w < 8; w++) s += red[w * 16 + tid];
    st[tid] = s;
  }
  __syncthreads();
  float t0[16];
#pragma unroll
  for (int i = 0; i < 16; i++) t0[i] = st[i];
  float* crow = C + (size_t)r * D_;
  for (int c = tid; c < D_; c += 256) {
    float s = 0.f;
#pragma unroll
    for (int i = 0; i < 16; i++) s = fmaf(t0[i], up[(size_t)i * D_ + c], s);
    crow[c] += s;
  }
}

// ---------------- tensor-core flash attention + fused IP attention ----------------
// Unchanged mainloop; epilogue writes packed f16x2 (same cvt.rn the GEMM applied before).
__global__ void __launch_bounds__(256) attn_mma_kernel(
    const float* __restrict__ Q, const float* __restrict__ K,
    const float* __restrict__ V, const float* __restrict__ KIP,
    const float* __restrict__ VIP, uint32_t* __restrict__ outE,
    uint32_t* __restrict__ outM) {
  extern __shared__ uint32_t smA[];
  uint32_t* Ks = smA;            // 8192 words
  uint32_t* Vs = smA + 8192;     // 8192 words
  const int tid = threadIdx.x, lane = tid & 31, w = tid >> 5;
  const int gid = lane >> 2, tig = lane & 3;
  const int h = blockIdx.y, q0 = blockIdx.x * 128;

  uint32_t qf[16][4];
  {
    const float* Qg = Q + ((size_t)h * SL_ + q0) * DH_;
    const float* qr0 = Qg + (w * 16 + gid) * DH_;
    const float* qr1 = qr0 + 8 * DH_;
#pragma unroll
    for (int ks = 0; ks < 16; ks++) {
      qf[ks][0] = f2tf32(qr0[ks * 8 + tig] * SCALE_);
      qf[ks][1] = f2tf32(qr1[ks * 8 + tig] * SCALE_);
      qf[ks][2] = f2tf32(qr0[ks * 8 + tig + 4] * SCALE_);
      qf[ks][3] = f2tf32(qr1[ks * 8 + tig + 4] * SCALE_);
    }
  }

  float o[16][4];
#pragma unroll
  for (int i = 0; i < 16; i++) { o[i][0] = o[i][1] = o[i][2] = o[i][3] = 0.f; }
  float m0 = -1e30f, m1 = -1e30f, l0 = 0.f, l1 = 0.f;

  const int lr = tid >> 5;
  const int lc4 = (tid & 31) << 2;

  const int kt0 = (q0 >= SB_) ? (SB_ / 64) : 0;
  for (int kt = kt0; kt < SL_ / 64; kt++) {
    __syncthreads();
    const float* Kt = K + ((size_t)h * SL_ + kt * 64) * DH_;
    const float* Vt = V + ((size_t)h * SL_ + kt * 64) * DH_;
    float4 ka[8], va[8];
#pragma unroll
    for (int it = 0; it < 8; it++) ka[it] = *(const float4*)(Kt + (lr + it * 8) * DH_ + lc4);
#pragma unroll
    for (int it = 0; it < 8; it++) va[it] = *(const float4*)(Vt + (lr + it * 8) * DH_ + lc4);
#pragma unroll
    for (int it = 0; it < 8; it++) {
      int r = lr + it * 8;
      int nt = r >> 3, j = r & 7;
      int nn = ((j & 3) << 1) | (j >> 2);  // pi(j)
      float vv[4] = {ka[it].x, ka[it].y, ka[it].z, ka[it].w};
#pragma unroll
      for (int e = 0; e < 4; e++) {
        int c = lc4 + e;
        int ks = c >> 3, reg = (c >> 2) & 1, tg = c & 3;
        Ks[((nt * 16 + ks) * 32 + ((nn * 4 + tg) ^ ks)) * 2 + reg] = f2tf32(vv[e]);
      }
    }
    __syncthreads();

    float sa[8][4];
#pragma unroll
    for (int nt = 0; nt < 8; nt++) { sa[nt][0] = sa[nt][1] = sa[nt][2] = sa[nt][3] = 0.f; }
#pragma unroll
    for (int ks = 0; ks < 16; ks++) {
#pragma unroll
      for (int nt = 0; nt < 8; nt++) {
        uint2 b2 = *(const uint2*)(Ks + ((nt * 16 + ks) * 32 + (lane ^ ks)) * 2);
        uint32_t bb[2] = {b2.x, b2.y};
        mma_tf32(sa[nt], qf[ks], bb);
      }
    }

    float rm0 = -1e30f, rm1 = -1e30f;
#pragma unroll
    for (int nt = 0; nt < 8; nt++) {
      rm0 = fmaxf(rm0, fmaxf(sa[nt][0], sa[nt][1]));
      rm1 = fmaxf(rm1, fmaxf(sa[nt][2], sa[nt][3]));
    }
#pragma unroll
    for (int off = 1; off < 4; off <<= 1) {
      rm0 = fmaxf(rm0, __shfl_xor_sync(0xffffffffu, rm0, off));
      rm1 = fmaxf(rm1, __shfl_xor_sync(0xffffffffu, rm1, off));
    }
    float mn0 = fmaxf(m0, rm0), mn1 = fmaxf(m1, rm1);
    float corr0 = __expf(m0 - mn0), corr1 = __expf(m1 - mn1);
    m0 = mn0; m1 = mn1;
    float rs0 = 0.f, rs1 = 0.f;
#pragma unroll
    for (int nt = 0; nt < 8; nt++) {
      sa[nt][0] = __expf(sa[nt][0] - mn0); rs0 += sa[nt][0];
      sa[nt][1] = __expf(sa[nt][1] - mn0); rs0 += sa[nt][1];
      sa[nt][2] = __expf(sa[nt][2] - mn1); rs1 += sa[nt][2];
      sa[nt][3] = __expf(sa[nt][3] - mn1); rs1 += sa[nt][3];
    }
#pragma unroll
    for (int off = 1; off < 4; off <<= 1) {
      rs0 += __shfl_xor_sync(0xffffffffu, rs0, off);
      rs1 += __shfl_xor_sync(0xffffffffu, rs1, off);
    }
    l0 = l0 * corr0 + rs0;
    l1 = l1 * corr1 + rs1;
#pragma unroll
    for (int i = 0; i < 16; i++) {
      o[i][0] *= corr0; o[i][1] *= corr0; o[i][2] *= corr1; o[i][3] *= corr1;
    }

#pragma unroll
    for (int it = 0; it < 8; it++) {
      int k2 = lr + it * 8;
      int ks = k2 >> 3, reg = (k2 >> 2) & 1, tg = k2 & 3;
      float vv[4] = {va[it].x, va[it].y, va[it].z, va[it].w};
#pragma unroll
      for (int e = 0; e < 4; e++) {
        int c = lc4 + e;
        int ntd = c >> 3, n = c & 7;
        Vs[((ntd * 8 + ks) * 32 + ((n * 4 + tg) ^ ntd)) * 2 + reg] = f2tf32(vv[e]);
      }
    }
    __syncthreads();

#pragma unroll
    for (int nt = 0; nt < 8; nt++) {
      uint32_t pf[4];
      pf[0] = f2tf32(sa[nt][0]);
      pf[1] = f2tf32(sa[nt][2]);
      pf[2] = f2tf32(sa[nt][1]);
      pf[3] = f2tf32(sa[nt][3]);
#pragma unroll
      for (int ntd = 0; ntd < 16; ntd++) {
        uint2 b2 = *(const uint2*)(Vs + ((ntd * 8 + nt) * 32 + (lane ^ ntd)) * 2);
        uint32_t bb[2] = {b2.x, b2.y};
        mma_tf32(o[ntd], pf, bb);
      }
    }
  }

  float inv0 = 1.f / l0, inv1 = 1.f / l1;
#pragma unroll
  for (int i = 0; i < 16; i++) {
    o[i][0] *= inv0; o[i][1] *= inv0; o[i][2] *= inv1; o[i][3] *= inv1;
  }

  if (q0 >= ENC_) {
    __syncthreads();
    const float* Kt = KIP + (size_t)h * NIP_ * DH_;
    const float* Vt = VIP + (size_t)h * NIP_ * DH_;
    float4 ka[8], va[8];
#pragma unroll
    for (int it = 0; it < 8; it++) ka[it] = *(const float4*)(Kt + (lr + it * 8) * DH_ + lc4);
#pragma unroll
    for (int it = 0; it < 8; it++) va[it] = *(const float4*)(Vt + (lr + it * 8) * DH_ + lc4);
#pragma unroll
    for (int it = 0; it < 8; it++) {
      int r = lr + it * 8;
      int nt = r >> 3, j = r & 7;
      int nn = ((j & 3) << 1) | (j >> 2);
      float vv[4] = {ka[it].x, ka[it].y, ka[it].z, ka[it].w};
#pragma unroll
      for (int e = 0; e < 4; e++) {
        int c = lc4 + e;
        int ks = c >> 3, reg = (c >> 2) & 1, tg = c & 3;
        Ks[((nt * 16 + ks) * 32 + ((nn * 4 + tg) ^ ks)) * 2 + reg] = f2tf32(vv[e]);
      }
    }
    __syncthreads();

    float sa[8][4];
#pragma unroll
    for (int nt = 0; nt < 8; nt++) { sa[nt][0] = sa[nt][1] = sa[nt][2] = sa[nt][3] = 0.f; }
#pragma unroll
    for (int ks = 0; ks < 16; ks++) {
#pragma unroll
      for (int nt = 0; nt < 8; nt++) {
        uint2 b2 = *(const uint2*)(Ks + ((nt * 16 + ks) * 32 + (lane ^ ks)) * 2);
        uint32_t bb[2] = {b2.x, b2.y};
        mma_tf32(sa[nt], qf[ks], bb);
      }
    }
    float rm0 = -1e30f, rm1 = -1e30f;
#pragma unroll
    for (int nt = 0; nt < 8; nt++) {
      rm0 = fmaxf(rm0, fmaxf(sa[nt][0], sa[nt][1]));
      rm1 = fmaxf(rm1, fmaxf(sa[nt][2], sa[nt][3]));
    }
#pragma unroll
    for (int off = 1; off < 4; off <<= 1) {
      rm0 = fmaxf(rm0, __shfl_xor_sync(0xffffffffu, rm0, off));
      rm1 = fmaxf(rm1, __shfl_xor_sync(0xffffffffu, rm1, off));
    }
    float rs0 = 0.f, rs1 = 0.f;
#pragma unroll
    for (int nt = 0; nt < 8; nt++) {
      sa[nt][0] = __expf(sa[nt][0] - rm0); rs0 += sa[nt][0];
      sa[nt][1] = __expf(sa[nt][1] - rm0); rs0 += sa[nt][1];
      sa[nt][2] = __expf(sa[nt][2] - rm1); rs1 += sa[nt][2];
      sa[nt][3] = __expf(sa[nt][3] - rm1); rs1 += sa[nt][3];
    }
#pragma unroll
    for (int off = 1; off < 4; off <<= 1) {
      rs0 += __shfl_xor_sync(0xffffffffu, rs0, off);
      rs1 += __shfl_xor_sync(0xffffffffu, rs1, off);
    }
    float iv0 = 1.f / rs0, iv1 = 1.f / rs1;
#pragma unroll
    for (int it = 0; it < 8; it++) {
      int k2 = lr + it * 8;
      int ks = k2 >> 3, reg = (k2 >> 2) & 1, tg = k2 & 3;
      float vv[4] = {va[it].x, va[it].y, va[it].z, va[it].w};
#pragma unroll
      for (int e = 0; e < 4; e++) {
        int c = lc4 + e;
        int ntd = c >> 3, n = c & 7;
        Vs[((ntd * 8 + ks) * 32 + ((n * 4 + tg) ^ ntd)) * 2 + reg] = f2tf32(vv[e]);
      }
    }
    __syncthreads();
#pragma unroll
    for (int nt = 0; nt < 8; nt++) {
      uint32_t pf[4];
      pf[0] = f2tf32(sa[nt][0] * iv0);
      pf[1] = f2tf32(sa[nt][2] * iv1);
      pf[2] = f2tf32(sa[nt][1] * iv0);
      pf[3] = f2tf32(sa[nt][3] * iv1);
#pragma unroll
      for (int ntd = 0; ntd < 16; ntd++) {
        uint2 b2 = *(const uint2*)(Vs + ((ntd * 8 + nt) * 32 + (lane ^ ntd)) * 2);
        uint32_t bb[2] = {b2.x, b2.y};
        mma_tf32(o[ntd], pf, bb);
      }
    }
  }

  // ---- epilogue: pack f16x2 and scatter token-major (packed k2 layout) ----
  int row0 = q0 + w * 16 + gid, row1 = row0 + 8;
#pragma unroll
  for (int ntd = 0; ntd < 16; ntd++) {
    int c2 = h * 64 + ntd * 4 + tig;  // (h*128 + ntd*8 + tig*2) / 2
    uint32_t p0 = pack_h2(o[ntd][0], o[ntd][1]);
    uint32_t p1 = pack_h2(o[ntd][2], o[ntd][3]);
    if (row0 < ENC_) {
      outE[(size_t)row0 * K2_ + c2] = p0;
      outE[(size_t)row1 * K2_ + c2] = p1;
    } else {
      outM[(size_t)(row0 - ENC_) * K2_ + c2] = p0;
      outM[(size_t)(row1 - ENC_) * K2_ + c2] = p1;
    }
  }
}

// ---------------- launch ----------------
extern "C" void kernel_launch(void* const* d_in, const int* in_sizes, int n_in,
                              void* d_out, int out_size) {
  const float* hs   = (const float*)d_in[0];
  const float* ehs  = (const float*)d_in[1];
  const float* img  = (const float*)d_in[2];
  const float* Wq   = (const float*)d_in[3];  const float* bq  = (const float*)d_in[4];
  const float* Wk   = (const float*)d_in[5];  const float* bk  = (const float*)d_in[6];
  const float* Wv   = (const float*)d_in[7];  const float* bv  = (const float*)d_in[8];
  const float* Waq  = (const float*)d_in[9];  const float* baq = (const float*)d_in[10];
  const float* Wak  = (const float*)d_in[11]; const float* bak = (const float*)d_in[12];
  const float* Wav  = (const float*)d_in[13]; const float* bav = (const float*)d_in[14];
  const float* Wo   = (const float*)d_in[15]; const float* bo  = (const float*)d_in[16];
  const float* Wao  = (const float*)d_in[17]; const float* bao = (const float*)d_in[18];
  const float* Wkip = (const float*)d_in[19]; const float* Wvip = (const float*)d_in[20];
  const float* lq_dn = (const float*)d_in[21]; const float* lq_up = (const float*)d_in[22];
  const float* lk_dn = (const float*)d_in[23]; const float* lk_up = (const float*)d_in[24];
  const float* lv_dn = (const float*)d_in[25]; const float* lv_up = (const float*)d_in[26];
  const float* lp_dn = (const float*)d_in[27]; const float* lp_up = (const float*)d_in[28];
  float* out = (float*)d_out;

  float *Q, *K, *V, *KIP, *VIP, *T3;
  uint32_t *WH, *hsH, *ehsH, *imgH, *amH, *aeH;
  cudaGetSymbolAddress((void**)&Q, g_Q);
  cudaGetSymbolAddress((void**)&K, g_K);
  cudaGetSymbolAddress((void**)&V, g_V);
  cudaGetSymbolAddress((void**)&KIP, g_KIP);
  cudaGetSymbolAddress((void**)&VIP, g_VIP);
  cudaGetSymbolAddress((void**)&T3, g_T3);
  cudaGetSymbolAddress((void**)&WH, g_WH);
  cudaGetSymbolAddress((void**)&hsH, g_hsH);
  cudaGetSymbolAddress((void**)&ehsH, g_ehsH);
  cudaGetSymbolAddress((void**)&imgH, g_imgH);
  cudaGetSymbolAddress((void**)&amH, g_amH);
  cudaGetSymbolAddress((void**)&aeH, g_aeH);

  const int G_SMEM = 3 * STAGE2_ * 4;       // 56832 B
  const int ATTN_SMEM = (8192 + 8192) * 4;  // 65536
  cudaFuncSetAttribute(gemm_h, cudaFuncAttributeMaxDynamicSharedMemorySize, G_SMEM);
  cudaFuncSetAttribute(attn_mma_kernel, cudaFuncAttributeMaxDynamicSharedMemorySize, ATTN_SMEM);

  float* outMain = out + (size_t)ENC_ * D_;
  const float* hsC = hs + (size_t)(S_ - COND_) * D_;

  // 0. pack operands to f16x2
  W10 w10 = {{Wq, Wk, Wv, Waq, Wak, Wav, Wkip, Wvip, Wo, Wao}};
  cvtB_kernel<<<dim3(K2_ * D_ / 256, 10), 256>>>(w10, WH);
  cvtA_kernel<<<S_ * K2_ / 256, 256>>>(hs, hsH, S_ * K2_);
  cvtA_kernel<<<ENC_ * K2_ / 256, 256>>>(ehs, ehsH, ENC_ * K2_);
  cvtA_kernel<<<NIP_ * K2_ / 256, 256>>>(img, imgH, NIP_ * K2_);

  // 1. lora-down temps for q,k,v
  D3 d3 = {{lq_dn, lk_dn, lv_dn}};
  lora_dn3<<<COND_ / 8, 256>>>(hsC, d3, T3);

  // 2. main QKV projections, fully fused (bias + lora-up + RMS + head-major)
  const uint32_t* WHq = WH;
  GF gqkv = {
    {hsH, hsH, hsH, 0, 0},
    {WHq, WHq + (size_t)K2_ * D_, WHq + 2 * (size_t)K2_ * D_, 0, 0},
    {bq, bk, bv, 0, 0},
    {T3, T3 + COND_ * 16, T3 + 2 * COND_ * 16, 0, 0}, {lq_up, lk_up, lv_up, 0, 0},
    {Q, K, V, 0, 0},
    {S_, S_, S_, 1, 1}, {SL_, SL_, SL_, 1, 1}, {ENC_, ENC_, ENC_, 0, 0}, {1, 1, 0, 0, 0}};
  gemm_h<<<dim3(24, 16, 3), 256, G_SMEM>>>(gqkv, D_, D_);

  // 3. encoder + IP projections in one launch (bias/RMS as needed, head-major)
  GF gei = {
    {ehsH, ehsH, ehsH, imgH, imgH},
    {WHq + 3 * (size_t)K2_ * D_, WHq + 4 * (size_t)K2_ * D_, WHq + 5 * (size_t)K2_ * D_,
     WHq + 6 * (size_t)K2_ * D_, WHq + 7 * (size_t)K2_ * D_},
    {baq, bak, bav, 0, 0},
    {0, 0, 0, 0, 0}, {0, 0, 0, 0, 0},
    {Q, K, V, KIP, VIP},
    {ENC_, ENC_, ENC_, NIP_, NIP_}, {SL_, SL_, SL_, NIP_, NIP_},
    {0, 0, 0, 0, 0}, {1, 1, 0, 1, 0}};
  gemm_h<<<dim3(24, 4, 5), 256, G_SMEM>>>(gei, D_, D_);

  // 4. joint attention with fused IP attention (writes packed f16x2 amH/aeH)
  attn_mma_kernel<<<dim3(SL_ / 128, H_), 256, ATTN_SMEM>>>(Q, K, V, KIP, VIP, aeH, amH);

  // 5. output projections (Wo + Wao batched), plain row-major f32 epilogue
  GF gout = {
    {amH, aeH, 0, 0, 0},
    {WHq + 8 * (size_t)K2_ * D_, WHq + 9 * (size_t)K2_ * D_, 0, 0, 0},
    {bo, bao, 0, 0, 0},
    {0, 0, 0, 0, 0}, {0, 0, 0, 0, 0},
    {outMain, out, 0, 0, 0},
    {S_, ENC_, 1, 1, 1}, {0, 0, 0, 0, 0}, {0, 0, 0, 0, 0}, {0, 0, 0, 0, 0}};
  gemm_h<<<dim3(24, 16, 2), 256, G_SMEM>>>(gout, D_, D_);

  // 6. output LoRA (post-Wo, in-place on last COND rows)
  float* outCond = outMain + (size_t)(S_ - COND_) * D_;
  lora_kernel<<<COND_, 256>>>(outCond, lp_dn, lp_up, outCond);
}

// round 13
// speedup vs baseline: 7.3621x; 1.0896x over previous
#include <cuda_runtime.h>
#include <math.h>
#include <stdint.h>

// ---------------- problem constants ----------------
#define D_    3072
#define K2_   1536   // D/2 (packed f16x2 along k)
#define S_    2048
#define H_    24
#define DH_   128
#define ENC_  512
#define NIP_  64
#define COND_ 1024
#define SL_   2560   // ENC + S
#define SB_   1536   // SL - COND
#define RANK_ 16
#define EPS_  1e-5f
#define SCALE_ 0.08838834764831845f  // 1/sqrt(128)

// ---------------- scratch (device globals; no allocations allowed) ----------------
__device__ float g_Q[H_ * SL_ * DH_];
__device__ float g_K[H_ * SL_ * DH_];
__device__ float g_V[H_ * SL_ * DH_];
__device__ float g_KIP[H_ * NIP_ * DH_];
__device__ float g_VIP[H_ * NIP_ * DH_];
__device__ float g_T3[3 * COND_ * RANK_];   // lora-down temps for q,k,v
// packed f16x2 operand buffers
__device__ uint32_t g_WH[10 * K2_ * D_];    // 10 weight matrices, [k2][n]
__device__ uint32_t g_hsH[S_ * K2_];        // activations, [row][k2]
__device__ uint32_t g_ehsH[ENC_ * K2_];
__device__ uint32_t g_imgH[NIP_ * K2_];
__device__ uint32_t g_amH[S_ * K2_];        // attention main out (incl. IP), packed
__device__ uint32_t g_aeH[ENC_ * K2_];      // attention encoder out, packed

// ---------------- helpers ----------------
__device__ __forceinline__ uint32_t pack_h2(float lo, float hi) {
  uint32_t r;
  asm("cvt.rn.f16x2.f32 %0, %1, %2;" : "=r"(r) : "f"(hi), "f"(lo));
  return r;
}

__device__ __forceinline__ void mma_f16(float c[4], const uint32_t a[4], const uint32_t b[2]) {
  asm("mma.sync.aligned.m16n8k16.row.col.f32.f16.f16.f32 "
      "{%0,%1,%2,%3}, {%4,%5,%6,%7}, {%8,%9}, {%0,%1,%2,%3};"
      : "+f"(c[0]), "+f"(c[1]), "+f"(c[2]), "+f"(c[3])
      : "r"(a[0]), "r"(a[1]), "r"(a[2]), "r"(a[3]), "r"(b[0]), "r"(b[1]));
}

__device__ __forceinline__ void cp_async16(uint32_t smem_addr, const void* gptr, int src_bytes) {
  asm volatile("cp.async.cg.shared.global [%0], [%1], 16, %2;"
               :: "r"(smem_addr), "l"(gptr), "r"(src_bytes) : "memory");
}
#define CP_COMMIT() asm volatile("cp.async.commit_group;" ::: "memory")
#define CP_WAIT1()  asm volatile("cp.async.wait_group 1;" ::: "memory")
#define CP_WAIT0()  asm volatile("cp.async.wait_group 0;" ::: "memory")

// ---------------- conversion kernels ----------------
__global__ void cvtA_kernel(const float* __restrict__ A, uint32_t* __restrict__ AH, int n) {
  int i = blockIdx.x * 256 + threadIdx.x;
  if (i < n) {
    float2 v = *(const float2*)(A + 2 * (size_t)i);
    AH[i] = pack_h2(v.x, v.y);
  }
}

struct W10 { const float* W[10]; };
__global__ void cvtB_kernel(W10 g, uint32_t* __restrict__ WH) {
  int z = blockIdx.y;
  const float* W = g.W[z];
  uint32_t* dst = WH + (size_t)z * K2_ * D_;
  int i = blockIdx.x * 256 + threadIdx.x;
  int k2 = i / D_, n = i - k2 * D_;
  dst[i] = pack_h2(W[(size_t)(2 * k2) * D_ + n], W[(size_t)(2 * k2 + 1) * D_ + n]);
}

// ---------------- lora-down: T[t][r][16] = hsC[r,:] @ dn_t (warp per row) ----------------
struct D3 { const float* dn[3]; };

__global__ void __launch_bounds__(256) lora_dn3(const float* __restrict__ A, D3 g,
                                                float* __restrict__ T) {
  const int tid = threadIdx.x, lane = tid & 31, w = tid >> 5;
  const int row = blockIdx.x * 8 + w;
  const float* a = A + (size_t)row * D_;
  float p[48];
#pragma unroll
  for (int i = 0; i < 48; i++) p[i] = 0.f;
  for (int k = lane; k < D_; k += 32) {
    float av = a[k];
#pragma unroll
    for (int t = 0; t < 3; t++) {
      const float* dk = g.dn[t] + k * 16;
      float4 d0 = *(const float4*)(dk);
      float4 d1 = *(const float4*)(dk + 4);
      float4 d2 = *(const float4*)(dk + 8);
      float4 d3 = *(const float4*)(dk + 12);
      float* pt = p + t * 16;
      pt[0]  = fmaf(av, d0.x, pt[0]);  pt[1]  = fmaf(av, d0.y, pt[1]);
      pt[2]  = fmaf(av, d0.z, pt[2]);  pt[3]  = fmaf(av, d0.w, pt[3]);
      pt[4]  = fmaf(av, d1.x, pt[4]);  pt[5]  = fmaf(av, d1.y, pt[5]);
      pt[6]  = fmaf(av, d1.z, pt[6]);  pt[7]  = fmaf(av, d1.w, pt[7]);
      pt[8]  = fmaf(av, d2.x, pt[8]);  pt[9]  = fmaf(av, d2.y, pt[9]);
      pt[10] = fmaf(av, d2.z, pt[10]); pt[11] = fmaf(av, d2.w, pt[11]);
      pt[12] = fmaf(av, d3.x, pt[12]); pt[13] = fmaf(av, d3.y, pt[13]);
      pt[14] = fmaf(av, d3.z, pt[14]); pt[15] = fmaf(av, d3.w, pt[15]);
    }
  }
#pragma unroll
  for (int off = 16; off; off >>= 1)
#pragma unroll
    for (int i = 0; i < 48; i++) p[i] += __shfl_xor_sync(0xffffffffu, p[i], off);
  if (lane == 0) {
#pragma unroll
    for (int t = 0; t < 3; t++) {
      float* dt = T + ((size_t)t * COND_ + row) * 16;
#pragma unroll
      for (int i = 0; i < 16; i += 4)
        *(float4*)(dt + i) = make_float4(p[t*16+i], p[t*16+i+1], p[t*16+i+2], p[t*16+i+3]);
    }
  }
}

// ---------------- fused fp16 GEMM on pre-packed operands (unchanged R11) ----------------
struct GF {
  const uint32_t* A[5]; const uint32_t* W[5]; const float* bias[5];
  const float* T[5]; const float* up[5];
  float* dst[5];
  int M[5]; int seq[5]; int rowOff[5]; int rms[5];
};

#define AW2_ 20
#define BW2_ 136
#define AWORDS2_ (128 * AW2_)            // 2560
#define STAGE2_ (AWORDS2_ + 16 * BW2_)   // 4736 u32 = 18944 B

__global__ void __launch_bounds__(256, 2) gemm_h(GF gf, int N, int K) {
  extern __shared__ uint32_t smu[];
  const uint32_t sbase = (uint32_t)__cvta_generic_to_shared(smu);

  const int z = blockIdx.z;
  const uint32_t* __restrict__ A = gf.A[z];
  const uint32_t* __restrict__ W = gf.W[z];
  const float* __restrict__ bias = gf.bias[z];
  const int M = gf.M[z];
  const int K2 = K / 2;

  const int tid = threadIdx.x;
  const int lane = tid & 31;
  const int wid = tid >> 5;
  const int warpM = wid >> 2;
  const int warpN = wid & 3;
  const int m0 = blockIdx.y * 128;
  const int n0 = blockIdx.x * 128;
  if (m0 >= M) return;

  const int NKT = K / 32;

  auto issue = [&](int kt) {
    if (kt < NKT) {
      int k20 = kt * 16;
      uint32_t st = sbase + (uint32_t)((kt % 3) * STAGE2_) * 4u;
#pragma unroll
      for (int p = 0; p < 2; p++) {
        int ch = tid + p * 256;
        int r = ch >> 2, c4 = (ch & 3) << 2;
        int gr = m0 + r;
        int sz = (gr < M) ? 16 : 0;
        if (gr >= M) gr = M - 1;
        cp_async16(st + (uint32_t)(r * AW2_ + c4) * 4u,
                   A + (size_t)gr * K2 + k20 + c4, sz);
      }
      uint32_t stb = st + (uint32_t)AWORDS2_ * 4u;
#pragma unroll
      for (int p = 0; p < 2; p++) {
        int ch = tid + p * 256;
        int kr = ch >> 5, n4 = (ch & 31) << 2;
        cp_async16(stb + (uint32_t)(kr * BW2_ + n4) * 4u,
                   W + (size_t)(k20 + kr) * N + n0 + n4, 16);
      }
    }
    CP_COMMIT();
  };

  float acc[4][4][4];
#pragma unroll
  for (int mt = 0; mt < 4; mt++)
#pragma unroll
    for (int nt = 0; nt < 4; nt++)
#pragma unroll
      for (int i = 0; i < 4; i++) acc[mt][nt][i] = 0.f;

  issue(0);
  issue(1);

  const int gid = lane >> 2, tig = lane & 3;

  for (int kt = 0; kt < NKT; kt++) {
    CP_WAIT1();
    __syncthreads();
    const uint32_t* sa = smu + (kt % 3) * STAGE2_;
    const uint32_t* sb = sa + AWORDS2_;
    const uint32_t* arow = sa + (warpM * 64 + gid) * AW2_;
    const uint32_t* bcol = sb + warpN * 32 + gid;
#pragma unroll
    for (int ks2 = 0; ks2 < 2; ks2++) {
      const int kb = ks2 * 8;
      uint32_t a[4][4];
      uint32_t b[4][2];
#pragma unroll
      for (int mt = 0; mt < 4; mt++) {
        const uint32_t* r0 = arow + mt * 16 * AW2_;
        a[mt][0] = r0[kb + tig];
        a[mt][1] = r0[8 * AW2_ + kb + tig];
        a[mt][2] = r0[kb + tig + 4];
        a[mt][3] = r0[8 * AW2_ + kb + tig + 4];
      }
#pragma unroll
      for (int nt = 0; nt < 4; nt++) {
        const uint32_t* bp = bcol + nt * 8;
        b[nt][0] = bp[(kb + tig) * BW2_];
        b[nt][1] = bp[(kb + tig + 4) * BW2_];
      }
#pragma unroll
      for (int mt = 0; mt < 4; mt++)
#pragma unroll
        for (int nt = 0; nt < 4; nt++) mma_f16(acc[mt][nt], a[mt], b[nt]);
    }
    issue(kt + 2);
  }
  CP_WAIT0();
  __syncthreads();

  // ---- fused epilogue ----
  const float* Tz = gf.T[z];
  const float* upz = gf.up[z];
  float* dst = gf.dst[z];
  const int seq = gf.seq[z], rowOff = gf.rowOff[z], doRMS = gf.rms[z];

  float bb0[4], bb1[4];
#pragma unroll
  for (int nt = 0; nt < 4; nt++) {
    int col = n0 + warpN * 32 + nt * 8 + tig * 2;
    bb0[nt] = bias ? bias[col] : 0.f;
    bb1[nt] = bias ? bias[col + 1] : 0.f;
  }
#pragma unroll
  for (int mt = 0; mt < 4; mt++) {
    int gr0 = m0 + warpM * 64 + mt * 16 + gid;
#pragma unroll
    for (int nt = 0; nt < 4; nt++) {
      acc[mt][nt][0] += bb0[nt]; acc[mt][nt][1] += bb1[nt];
      acc[mt][nt][2] += bb0[nt]; acc[mt][nt][3] += bb1[nt];
    }
    if (upz) {
      int l0 = gr0 - (M - COND_);
      int l1 = l0 + 8;
      if (l1 >= 0) {
        bool h0 = (l0 >= 0);
#pragma unroll
        for (int i0 = 0; i0 < 16; i0 += 4) {
          float4 t1q = *(const float4*)(Tz + (size_t)l1 * 16 + i0);
          float4 t0q = h0 ? *(const float4*)(Tz + (size_t)l0 * 16 + i0)
                          : make_float4(0.f, 0.f, 0.f, 0.f);
          float tv0[4] = {t0q.x, t0q.y, t0q.z, t0q.w};
          float tv1[4] = {t1q.x, t1q.y, t1q.z, t1q.w};
#pragma unroll
          for (int j = 0; j < 4; j++) {
#pragma unroll
            for (int nt = 0; nt < 4; nt++) {
              int col = n0 + warpN * 32 + nt * 8 + tig * 2;
              float2 u = *(const float2*)(upz + (size_t)(i0 + j) * N + col);
              acc[mt][nt][0] = fmaf(tv0[j], u.x, acc[mt][nt][0]);
              acc[mt][nt][1] = fmaf(tv0[j], u.y, acc[mt][nt][1]);
              acc[mt][nt][2] = fmaf(tv1[j], u.x, acc[mt][nt][2]);
              acc[mt][nt][3] = fmaf(tv1[j], u.y, acc[mt][nt][3]);
            }
          }
        }
      }
    }
  }

  if (doRMS) {
    float* ssm = (float*)smu;
#pragma unroll
    for (int mt = 0; mt < 4; mt++) {
      int lr = warpM * 64 + mt * 16 + gid;
      float ss0 = 0.f, ss1 = 0.f;
#pragma unroll
      for (int nt = 0; nt < 4; nt++) {
        ss0 = fmaf(acc[mt][nt][0], acc[mt][nt][0], ss0);
        ss0 = fmaf(acc[mt][nt][1], acc[mt][nt][1], ss0);
        ss1 = fmaf(acc[mt][nt][2], acc[mt][nt][2], ss1);
        ss1 = fmaf(acc[mt][nt][3], acc[mt][nt][3], ss1);
      }
      ss0 += __shfl_xor_sync(0xffffffffu, ss0, 1);
      ss0 += __shfl_xor_sync(0xffffffffu, ss0, 2);
      ss1 += __shfl_xor_sync(0xffffffffu, ss1, 1);
      ss1 += __shfl_xor_sync(0xffffffffu, ss1, 2);
      if (tig == 0) {
        ssm[lr * 4 + warpN] = ss0;
        ssm[(lr + 8) * 4 + warpN] = ss1;
      }
    }
    __syncthreads();
#pragma unroll
    for (int mt = 0; mt < 4; mt++) {
      int lr = warpM * 64 + mt * 16 + gid;
      float4 s0 = *(const float4*)&ssm[lr * 4];
      float4 s1 = *(const float4*)&ssm[(lr + 8) * 4];
      float sc0 = rsqrtf((s0.x + s0.y + s0.z + s0.w) * (1.f / 128.f) + EPS_);
      float sc1 = rsqrtf((s1.x + s1.y + s1.z + s1.w) * (1.f / 128.f) + EPS_);
#pragma unroll
      for (int nt = 0; nt < 4; nt++) {
        acc[mt][nt][0] *= sc0; acc[mt][nt][1] *= sc0;
        acc[mt][nt][2] *= sc1; acc[mt][nt][3] *= sc1;
      }
    }
  }

  const int head = n0 >> 7;
#pragma unroll
  for (int mt = 0; mt < 4; mt++) {
    int gr0 = m0 + warpM * 64 + mt * 16 + gid;
    int gr1 = gr0 + 8;
#pragma unroll
    for (int nt = 0; nt < 4; nt++) {
      int colh = warpN * 32 + nt * 8 + tig * 2;
      float2 v0 = make_float2(acc[mt][nt][0], acc[mt][nt][1]);
      float2 v1 = make_float2(acc[mt][nt][2], acc[mt][nt][3]);
      if (seq) {
        float* bp = dst + ((size_t)head * seq + rowOff) * 128 + colh;
        if (gr0 < M) *(float2*)(bp + (size_t)gr0 * 128) = v0;
        if (gr1 < M) *(float2*)(bp + (size_t)gr1 * 128) = v1;
      } else {
        if (gr0 < M) *(float2*)(dst + (size_t)gr0 * N + n0 + colh) = v0;
        if (gr1 < M) *(float2*)(dst + (size_t)gr1 * N + n0 + colh) = v1;
      }
    }
  }
}

// ---------------- single LoRA for the output projection (post-Wo, in-place) ----------------
__global__ void __launch_bounds__(256) lora_kernel(
    const float* __restrict__ A, const float* __restrict__ dn,
    const float* __restrict__ up, float* __restrict__ C) {
  __shared__ float red[8 * 16];
  __shared__ float st[16];
  const int r = blockIdx.x, tid = threadIdx.x, lane = tid & 31, wid = tid >> 5;
  const float* a = A + (size_t)r * D_;
  float p[16];
#pragma unroll
  for (int i = 0; i < 16; i++) p[i] = 0.f;
  for (int k = tid; k < D_; k += 256) {
    float av = a[k];
    float4 d0 = *(const float4*)(dn + k * 16);
    float4 d1 = *(const float4*)(dn + k * 16 + 4);
    float4 d2 = *(const float4*)(dn + k * 16 + 8);
    float4 d3 = *(const float4*)(dn + k * 16 + 12);
    p[0]  = fmaf(av, d0.x, p[0]);  p[1]  = fmaf(av, d0.y, p[1]);
    p[2]  = fmaf(av, d0.z, p[2]);  p[3]  = fmaf(av, d0.w, p[3]);
    p[4]  = fmaf(av, d1.x, p[4]);  p[5]  = fmaf(av, d1.y, p[5]);
    p[6]  = fmaf(av, d1.z, p[6]);  p[7]  = fmaf(av, d1.w, p[7]);
    p[8]  = fmaf(av, d2.x, p[8]);  p[9]  = fmaf(av, d2.y, p[9]);
    p[10] = fmaf(av, d2.z, p[10]); p[11] = fmaf(av, d2.w, p[11]);
    p[12] = fmaf(av, d3.x, p[12]); p[13] = fmaf(av, d3.y, p[13]);
    p[14] = fmaf(av, d3.z, p[14]); p[15] = fmaf(av, d3.w, p[15]);
  }
#pragma unroll
  for (int o = 16; o; o >>= 1)
#pragma unroll
    for (int i = 0; i < 16; i++) p[i] += __shfl_xor_sync(0xffffffffu, p[i], o);
  if (lane == 0)
#pragma unroll
    for (int i = 0; i < 16; i++) red[wid * 16 + i] = p[i];
  __syncthreads();
  if (tid < 16) {
    float s = 0.f;
#pragma unroll
    for (int w = 0; w < 8; w++) s += red[w * 16 + tid];
    st[tid] = s;
  }
  __syncthreads();
  float t0[16];
#pragma unroll
  for (int i = 0; i < 16; i++) t0[i] = st[i];
  float* crow = C + (size_t)r * D_;
  for (int c = tid; c < D_; c += 256) {
    float s = 0.f;
#pragma unroll
    for (int i = 0; i < 16; i++) s = fmaf(t0[i], up[(size_t)i * D_ + c], s);
    crow[c] += s;
  }
}

// ---------------- fp16 tensor-core flash attention + fused IP attention ----------------
// 128q x 64k tiles, 8 warps x 16 q-rows, m16n8k16 fp16 (same 11-bit mantissa as tf32).
// Half the MMAs/LDS/smem of the tf32 version. No key permutation needed: the S C-frag
// column pairing (2tig,2tig+1) IS the PV A-frag k-pairing.
// Ks frag word: ((nt*8+ks)*32 + (lane ^ (ks<<2)))*2 + reg   (8x8 frags, conflict-free)
// Vs frag word: ((ntd*4+g)*32 + (lane ^ ntd))*2 + reg       (16x4 frags, conflict-free)
__global__ void __launch_bounds__(256) attn_mma_kernel(
    const float* __restrict__ Q, const float* __restrict__ K,
    const float* __restrict__ V, const float* __restrict__ KIP,
    const float* __restrict__ VIP, uint32_t* __restrict__ outE,
    uint32_t* __restrict__ outM) {
  extern __shared__ uint32_t smA[];
  uint32_t* Ks = smA;            // 4096 words
  uint32_t* Vs = smA + 4096;     // 4096 words
  const int tid = threadIdx.x, lane = tid & 31, w = tid >> 5;
  const int gid = lane >> 2, tig = lane & 3;
  const int h = blockIdx.y, q0 = blockIdx.x * 128;

  // Q fragments fp16 (scale folded): 8 k16-steps x 4 regs
  uint32_t qf[8][4];
  {
    const float* qr0 = Q + ((size_t)h * SL_ + q0 + w * 16 + gid) * DH_;
    const float* qr1 = qr0 + 8 * DH_;
#pragma unroll
    for (int s = 0; s < 8; s++) {
      float2 p0 = *(const float2*)(qr0 + s * 16 + 2 * tig);
      float2 p1 = *(const float2*)(qr1 + s * 16 + 2 * tig);
      float2 p2 = *(const float2*)(qr0 + s * 16 + 2 * tig + 8);
      float2 p3 = *(const float2*)(qr1 + s * 16 + 2 * tig + 8);
      qf[s][0] = pack_h2(p0.x * SCALE_, p0.y * SCALE_);
      qf[s][1] = pack_h2(p1.x * SCALE_, p1.y * SCALE_);
      qf[s][2] = pack_h2(p2.x * SCALE_, p2.y * SCALE_);
      qf[s][3] = pack_h2(p3.x * SCALE_, p3.y * SCALE_);
    }
  }

  float o[16][4];
#pragma unroll
  for (int i = 0; i < 16; i++) { o[i][0] = o[i][1] = o[i][2] = o[i][3] = 0.f; }
  float m0 = -1e30f, m1 = -1e30f, l0 = 0.f, l1 = 0.f;

  // loader coords
  const int kc0 = 16 * (lane >> 2) + 2 * (lane & 3);       // K: k-column base
  const int cgv = 2 * (lane & 15) + (lane >> 4);           // V: rotated col group
  const int ksl = lane >> 2, tgl = lane & 3;               // K staging frag coords

  const int kt0 = (q0 >= SB_) ? (SB_ / 64) : 0;
  for (int kt = kt0; kt < SL_ / 64; kt++) {
    __syncthreads();
    const float* Kt = K + ((size_t)h * SL_ + kt * 64) * DH_;
    const float* Vt = V + ((size_t)h * SL_ + kt * 64) * DH_;
    float2 kf0[8], kf1[8];
    float4 vf0[4], vf1[4];
#pragma unroll
    for (int it = 0; it < 8; it++) {
      int r = w + it * 8;
      kf0[it] = *(const float2*)(Kt + r * DH_ + kc0);
      kf1[it] = *(const float2*)(Kt + r * DH_ + kc0 + 8);
    }
#pragma unroll
    for (int it = 0; it < 4; it++) {
      int m = w + it * 8;
      vf0[it] = *(const float4*)(Vt + (2 * m) * DH_ + cgv * 4);
      vf1[it] = *(const float4*)(Vt + (2 * m + 1) * DH_ + cgv * 4);
    }
    // stage K
#pragma unroll
    for (int it = 0; it < 8; it++) {
      int r = w + it * 8;
      int nt = r >> 3, gk = r & 7;
      uint32_t* dst = Ks + ((nt * 8 + ksl) * 32 + ((gk * 4 + tgl) ^ (ksl << 2))) * 2;
      dst[0] = pack_h2(kf0[it].x, kf0[it].y);
      dst[1] = pack_h2(kf1[it].x, kf1[it].y);
    }
    __syncthreads();

    // ---- S = Q @ K^T (fp16 k16) ----
    float sa[8][4];
#pragma unroll
    for (int nt = 0; nt < 8; nt++) { sa[nt][0] = sa[nt][1] = sa[nt][2] = sa[nt][3] = 0.f; }
#pragma unroll
    for (int ks = 0; ks < 8; ks++) {
#pragma unroll
      for (int nt = 0; nt < 8; nt++) {
        uint2 b2 = *(const uint2*)(Ks + ((nt * 8 + ks) * 32 + (lane ^ (ks << 2))) * 2);
        uint32_t bb[2] = {b2.x, b2.y};
        mma_f16(sa[nt], qf[ks], bb);
      }
    }

    // ---- online softmax (row stats over tig: shfl 1,2) ----
    float rm0 = -1e30f, rm1 = -1e30f;
#pragma unroll
    for (int nt = 0; nt < 8; nt++) {
      rm0 = fmaxf(rm0, fmaxf(sa[nt][0], sa[nt][1]));
      rm1 = fmaxf(rm1, fmaxf(sa[nt][2], sa[nt][3]));
    }
#pragma unroll
    for (int off = 1; off < 4; off <<= 1) {
      rm0 = fmaxf(rm0, __shfl_xor_sync(0xffffffffu, rm0, off));
      rm1 = fmaxf(rm1, __shfl_xor_sync(0xffffffffu, rm1, off));
    }
    float mn0 = fmaxf(m0, rm0), mn1 = fmaxf(m1, rm1);
    float corr0 = __expf(m0 - mn0), corr1 = __expf(m1 - mn1);
    m0 = mn0; m1 = mn1;
    float rs0 = 0.f, rs1 = 0.f;
#pragma unroll
    for (int nt = 0; nt < 8; nt++) {
      sa[nt][0] = __expf(sa[nt][0] - mn0); rs0 += sa[nt][0];
      sa[nt][1] = __expf(sa[nt][1] - mn0); rs0 += sa[nt][1];
      sa[nt][2] = __expf(sa[nt][2] - mn1); rs1 += sa[nt][2];
      sa[nt][3] = __expf(sa[nt][3] - mn1); rs1 += sa[nt][3];
    }
#pragma unroll
    for (int off = 1; off < 4; off <<= 1) {
      rs0 += __shfl_xor_sync(0xffffffffu, rs0, off);
      rs1 += __shfl_xor_sync(0xffffffffu, rs1, off);
    }
    l0 = l0 * corr0 + rs0;
    l1 = l1 * corr1 + rs1;
#pragma unroll
    for (int i = 0; i < 16; i++) {
      o[i][0] *= corr0; o[i][1] *= corr0; o[i][2] *= corr1; o[i][3] *= corr1;
    }

    // stage V (vertical k-pairs from prefetched rows)
#pragma unroll
    for (int it = 0; it < 4; it++) {
      int m = w + it * 8;
      int g = m >> 3, ov = m & 7, reg = ov >> 2, tv = ov & 3;
      float v0e[4] = {vf0[it].x, vf0[it].y, vf0[it].z, vf0[it].w};
      float v1e[4] = {vf1[it].x, vf1[it].y, vf1[it].z, vf1[it].w};
#pragma unroll
      for (int e = 0; e < 4; e++) {
        int d = cgv * 4 + e;
        int ntd = d >> 3, gn = d & 7;
        Vs[((ntd * 4 + g) * 32 + ((gn * 4 + tv) ^ ntd)) * 2 + reg] = pack_h2(v0e[e], v1e[e]);
      }
    }
    __syncthreads();

    // ---- O += P @ V (fp16; S C-frags pair directly into PV A-frags) ----
#pragma unroll
    for (int g = 0; g < 4; g++) {
      uint32_t pf[4];
      pf[0] = pack_h2(sa[2 * g][0], sa[2 * g][1]);
      pf[1] = pack_h2(sa[2 * g][2], sa[2 * g][3]);
      pf[2] = pack_h2(sa[2 * g + 1][0], sa[2 * g + 1][1]);
      pf[3] = pack_h2(sa[2 * g + 1][2], sa[2 * g + 1][3]);
#pragma unroll
      for (int ntd = 0; ntd < 16; ntd++) {
        uint2 b2 = *(const uint2*)(Vs + ((ntd * 4 + g) * 32 + (lane ^ ntd)) * 2);
        uint32_t bb[2] = {b2.x, b2.y};
        mma_f16(o[ntd], pf, bb);
      }
    }
  }

  // ---- normalize main result ----
  float inv0 = 1.f / l0, inv1 = 1.f / l1;
#pragma unroll
  for (int i = 0; i < 16; i++) {
    o[i][0] *= inv0; o[i][1] *= inv0; o[i][2] *= inv1; o[i][3] *= inv1;
  }

  // ---- fused IP attention tile (main rows only; one 64-key tile) ----
  if (q0 >= ENC_) {
    __syncthreads();
    const float* Kt = KIP + (size_t)h * NIP_ * DH_;
    const float* Vt = VIP + (size_t)h * NIP_ * DH_;
    float2 kf0[8], kf1[8];
    float4 vf0[4], vf1[4];
#pragma unroll
    for (int it = 0; it < 8; it++) {
      int r = w + it * 8;
      kf0[it] = *(const float2*)(Kt + r * DH_ + kc0);
      kf1[it] = *(const float2*)(Kt + r * DH_ + kc0 + 8);
    }
#pragma unroll
    for (int it = 0; it < 4; it++) {
      int m = w + it * 8;
      vf0[it] = *(const float4*)(Vt + (2 * m) * DH_ + cgv * 4);
      vf1[it] = *(const float4*)(Vt + (2 * m + 1) * DH_ + cgv * 4);
    }
#pragma unroll
    for (int it = 0; it < 8; it++) {
      int r = w + it * 8;
      int nt = r >> 3, gk = r & 7;
      uint32_t* dst = Ks + ((nt * 8 + ksl) * 32 + ((gk * 4 + tgl) ^ (ksl << 2))) * 2;
      dst[0] = pack_h2(kf0[it].x, kf0[it].y);
      dst[1] = pack_h2(kf1[it].x, kf1[it].y);
    }
    __syncthreads();

    float sa[8][4];
#pragma unroll
    for (int nt = 0; nt < 8; nt++) { sa[nt][0] = sa[nt][1] = sa[nt][2] = sa[nt][3] = 0.f; }
#pragma unroll
    for (int ks = 0; ks < 8; ks++) {
#pragma unroll
      for (int nt = 0; nt < 8; nt++) {
        uint2 b2 = *(const uint2*)(Ks + ((nt * 8 + ks) * 32 + (lane ^ (ks << 2))) * 2);
        uint32_t bb[2] = {b2.x, b2.y};
        mma_f16(sa[nt], qf[ks], bb);
      }
    }
    // complete softmax over the single tile
    float rm0 = -1e30f, rm1 = -1e30f;
#pragma unroll
    for (int nt = 0; nt < 8; nt++) {
      rm0 = fmaxf(rm0, fmaxf(sa[nt][0], sa[nt][1]));
      rm1 = fmaxf(rm1, fmaxf(sa[nt][2], sa[nt][3]));
    }
#pragma unroll
    for (int off = 1; off < 4; off <<= 1) {
      rm0 = fmaxf(rm0, __shfl_xor_sync(0xffffffffu, rm0, off));
      rm1 = fmaxf(rm1, __shfl_xor_sync(0xffffffffu, rm1, off));
    }
    float rs0 = 0.f, rs1 = 0.f;
#pragma unroll
    for (int nt = 0; nt < 8; nt++) {
      sa[nt][0] = __expf(sa[nt][0] - rm0); rs0 += sa[nt][0];
      sa[nt][1] = __expf(sa[nt][1] - rm0); rs0 += sa[nt][1];
      sa[nt][2] = __expf(sa[nt][2] - rm1); rs1 += sa[nt][2];
      sa[nt][3] = __expf(sa[nt][3] - rm1); rs1 += sa[nt][3];
    }
#pragma unroll
    for (int off = 1; off < 4; off <<= 1) {
      rs0 += __shfl_xor_sync(0xffffffffu, rs0, off);
      rs1 += __shfl_xor_sync(0xffffffffu, rs1, off);
    }
    float iv0 = 1.f / rs0, iv1 = 1.f / rs1;
#pragma unroll
    for (int it = 0; it < 4; it++) {
      int m = w + it * 8;
      int g = m >> 3, ov = m & 7, reg = ov >> 2, tv = ov & 3;
      float v0e[4] = {vf0[it].x, vf0[it].y, vf0[it].z, vf0[it].w};
      float v1e[4] = {vf1[it].x, vf1[it].y, vf1[it].z, vf1[it].w};
#pragma unroll
      for (int e = 0; e < 4; e++) {
        int d = cgv * 4 + e;
        int ntd = d >> 3, gn = d & 7;
        Vs[((ntd * 4 + g) * 32 + ((gn * 4 + tv) ^ ntd)) * 2 + reg] = pack_h2(v0e[e], v1e[e]);
      }
    }
    __syncthreads();
    // pre-normalized IP P@V accumulates into the normalized main O
#pragma unroll
    for (int g = 0; g < 4; g++) {
      uint32_t pf[4];
      pf[0] = pack_h2(sa[2 * g][0] * iv0, sa[2 * g][1] * iv0);
      pf[1] = pack_h2(sa[2 * g][2] * iv1, sa[2 * g][3] * iv1);
      pf[2] = pack_h2(sa[2 * g + 1][0] * iv0, sa[2 * g + 1][1] * iv0);
      pf[3] = pack_h2(sa[2 * g + 1][2] * iv1, sa[2 * g + 1][3] * iv1);
#pragma unroll
      for (int ntd = 0; ntd < 16; ntd++) {
        uint2 b2 = *(const uint2*)(Vs + ((ntd * 4 + g) * 32 + (lane ^ ntd)) * 2);
        uint32_t bb[2] = {b2.x, b2.y};
        mma_f16(o[ntd], pf, bb);
      }
    }
  }

  // ---- epilogue: pack f16x2 and scatter token-major (packed k2 layout) ----
  int row0 = q0 + w * 16 + gid, row1 = row0 + 8;
#pragma unroll
  for (int ntd = 0; ntd < 16; ntd++) {
    int c2 = h * 64 + ntd * 4 + tig;  // cols ntd*8+2tig,+1 packed
    uint32_t p0 = pack_h2(o[ntd][0], o[ntd][1]);
    uint32_t p1 = pack_h2(o[ntd][2], o[ntd][3]);
    if (row0 < ENC_) {
      outE[(size_t)row0 * K2_ + c2] = p0;
      outE[(size_t)row1 * K2_ + c2] = p1;
    } else {
      outM[(size_t)(row0 - ENC_) * K2_ + c2] = p0;
      outM[(size_t)(row1 - ENC_) * K2_ + c2] = p1;
    }
  }
}

// ---------------- launch ----------------
extern "C" void kernel_launch(void* const* d_in, const int* in_sizes, int n_in,
                              void* d_out, int out_size) {
  const float* hs   = (const float*)d_in[0];
  const float* ehs  = (const float*)d_in[1];
  const float* img  = (const float*)d_in[2];
  const float* Wq   = (const float*)d_in[3];  const float* bq  = (const float*)d_in[4];
  const float* Wk   = (const float*)d_in[5];  const float* bk  = (const float*)d_in[6];
  const float* Wv   = (const float*)d_in[7];  const float* bv  = (const float*)d_in[8];
  const float* Waq  = (const float*)d_in[9];  const float* baq = (const float*)d_in[10];
  const float* Wak  = (const float*)d_in[11]; const float* bak = (const float*)d_in[12];
  const float* Wav  = (const float*)d_in[13]; const float* bav = (const float*)d_in[14];
  const float* Wo   = (const float*)d_in[15]; const float* bo  = (const float*)d_in[16];
  const float* Wao  = (const float*)d_in[17]; const float* bao = (const float*)d_in[18];
  const float* Wkip = (const float*)d_in[19]; const float* Wvip = (const float*)d_in[20];
  const float* lq_dn = (const float*)d_in[21]; const float* lq_up = (const float*)d_in[22];
  const float* lk_dn = (const float*)d_in[23]; const float* lk_up = (const float*)d_in[24];
  const float* lv_dn = (const float*)d_in[25]; const float* lv_up = (const float*)d_in[26];
  const float* lp_dn = (const float*)d_in[27]; const float* lp_up = (const float*)d_in[28];
  float* out = (float*)d_out;

  float *Q, *K, *V, *KIP, *VIP, *T3;
  uint32_t *WH, *hsH, *ehsH, *imgH, *amH, *aeH;
  cudaGetSymbolAddress((void**)&Q, g_Q);
  cudaGetSymbolAddress((void**)&K, g_K);
  cudaGetSymbolAddress((void**)&V, g_V);
  cudaGetSymbolAddress((void**)&KIP, g_KIP);
  cudaGetSymbolAddress((void**)&VIP, g_VIP);
  cudaGetSymbolAddress((void**)&T3, g_T3);
  cudaGetSymbolAddress((void**)&WH, g_WH);
  cudaGetSymbolAddress((void**)&hsH, g_hsH);
  cudaGetSymbolAddress((void**)&ehsH, g_ehsH);
  cudaGetSymbolAddress((void**)&imgH, g_imgH);
  cudaGetSymbolAddress((void**)&amH, g_amH);
  cudaGetSymbolAddress((void**)&aeH, g_aeH);

  const int G_SMEM = 3 * STAGE2_ * 4;       // 56832 B
  const int ATTN_SMEM = (4096 + 4096) * 4;  // 32768 B
  cudaFuncSetAttribute(gemm_h, cudaFuncAttributeMaxDynamicSharedMemorySize, G_SMEM);
  cudaFuncSetAttribute(attn_mma_kernel, cudaFuncAttributeMaxDynamicSharedMemorySize, ATTN_SMEM);

  float* outMain = out + (size_t)ENC_ * D_;
  const float* hsC = hs + (size_t)(S_ - COND_) * D_;

  // 0. pack operands to f16x2
  W10 w10 = {{Wq, Wk, Wv, Waq, Wak, Wav, Wkip, Wvip, Wo, Wao}};
  cvtB_kernel<<<dim3(K2_ * D_ / 256, 10), 256>>>(w10, WH);
  cvtA_kernel<<<S_ * K2_ / 256, 256>>>(hs, hsH, S_ * K2_);
  cvtA_kernel<<<ENC_ * K2_ / 256, 256>>>(ehs, ehsH, ENC_ * K2_);
  cvtA_kernel<<<NIP_ * K2_ / 256, 256>>>(img, imgH, NIP_ * K2_);

  // 1. lora-down temps for q,k,v
  D3 d3 = {{lq_dn, lk_dn, lv_dn}};
  lora_dn3<<<COND_ / 8, 256>>>(hsC, d3, T3);

  // 2. main QKV projections, fully fused (bias + lora-up + RMS + head-major)
  const uint32_t* WHq = WH;
  GF gqkv = {
    {hsH, hsH, hsH, 0, 0},
    {WHq, WHq + (size_t)K2_ * D_, WHq + 2 * (size_t)K2_ * D_, 0, 0},
    {bq, bk, bv, 0, 0},
    {T3, T3 + COND_ * 16, T3 + 2 * COND_ * 16, 0, 0}, {lq_up, lk_up, lv_up, 0, 0},
    {Q, K, V, 0, 0},
    {S_, S_, S_, 1, 1}, {SL_, SL_, SL_, 1, 1}, {ENC_, ENC_, ENC_, 0, 0}, {1, 1, 0, 0, 0}};
  gemm_h<<<dim3(24, 16, 3), 256, G_SMEM>>>(gqkv, D_, D_);

  // 3. encoder + IP projections in one launch (bias/RMS as needed, head-major)
  GF gei = {
    {ehsH, ehsH, ehsH, imgH, imgH},
    {WHq + 3 * (size_t)K2_ * D_, WHq + 4 * (size_t)K2_ * D_, WHq + 5 * (size_t)K2_ * D_,
     WHq + 6 * (size_t)K2_ * D_, WHq + 7 * (size_t)K2_ * D_},
    {baq, bak, bav, 0, 0},
    {0, 0, 0, 0, 0}, {0, 0, 0, 0, 0},
    {Q, K, V, KIP, VIP},
    {ENC_, ENC_, ENC_, NIP_, NIP_}, {SL_, SL_, SL_, NIP_, NIP_},
    {0, 0, 0, 0, 0}, {1, 1, 0, 1, 0}};
  gemm_h<<<dim3(24, 4, 5), 256, G_SMEM>>>(gei, D_, D_);

  // 4. joint attention with fused IP attention (writes packed f16x2 amH/aeH)
  attn_mma_kernel<<<dim3(SL_ / 128, H_), 256, ATTN_SMEM>>>(Q, K, V, KIP, VIP, aeH, amH);

  // 5. output projections (Wo + Wao batched), plain row-major f32 epilogue
  GF gout = {
    {amH, aeH, 0, 0, 0},
    {WHq + 8 * (size_t)K2_ * D_, WHq + 9 * (size_t)K2_ * D_, 0, 0, 0},
    {bo, bao, 0, 0, 0},
    {0, 0, 0, 0, 0}, {0, 0, 0, 0, 0},
    {outMain, out, 0, 0, 0},
    {S_, ENC_, 1, 1, 1}, {0, 0, 0, 0, 0}, {0, 0, 0, 0, 0}, {0, 0, 0, 0, 0}};
  gemm_h<<<dim3(24, 16, 2), 256, G_SMEM>>>(gout, D_, D_);

  // 6. output LoRA (post-Wo, in-place on last COND rows)
  float* outCond = outMain + (size_t)(S_ - COND_) * D_;
  lora_kernel<<<COND_, 256>>>(outCond, lp_dn, lp_up, outCond);
}

// round 15
// speedup vs baseline: 8.5417x; 1.1602x over previous
#include <cuda_runtime.h>
#include <math.h>
#include <stdint.h>

// ---------------- problem constants ----------------
#define D_    3072
#define K2_   1536   // D/2 (packed f16x2 along k)
#define S_    2048
#define H_    24
#define DH_   128
#define ENC_  512
#define NIP_  64
#define COND_ 1024
#define SL_   2560
#define SB_   1536
#define RANK_ 16
#define EPS_  1e-5f
#define SCALE_ 0.08838834764831845f

// ---------------- scratch ----------------
__device__ float g_Q[H_ * SL_ * DH_];
__device__ float g_K[H_ * SL_ * DH_];
__device__ float g_V[H_ * SL_ * DH_];
__device__ float g_KIP[H_ * NIP_ * DH_];
__device__ float g_VIP[H_ * NIP_ * DH_];
__device__ float g_T3[3 * COND_ * RANK_];
// packed f16x2 buffers, fragment-pair group layout:
// within each 8-u32 k-group, position p(j) = 2*(j&3) + (j>>2)
__device__ uint32_t g_WB[10 * K2_ * D_];   // weights: [g][n][8] per matrix
__device__ uint32_t g_hsH[S_ * K2_];       // activations: [row][g*8 + p(j)]
__device__ uint32_t g_ehsH[ENC_ * K2_];
__device__ uint32_t g_imgH[NIP_ * K2_];
__device__ uint32_t g_amH[S_ * K2_];
__device__ uint32_t g_aeH[ENC_ * K2_];

// ---------------- helpers ----------------
__device__ __forceinline__ uint32_t pack_h2(float lo, float hi) {
  uint32_t r;
  asm("cvt.rn.f16x2.f32 %0, %1, %2;" : "=r"(r) : "f"(hi), "f"(lo));
  return r;
}

__device__ __forceinline__ void mma_f16(float c[4], const uint32_t a[4], const uint32_t b[2]) {
  asm("mma.sync.aligned.m16n8k16.row.col.f32.f16.f16.f32 "
      "{%0,%1,%2,%3}, {%4,%5,%6,%7}, {%8,%9}, {%0,%1,%2,%3};"
      : "+f"(c[0]), "+f"(c[1]), "+f"(c[2]), "+f"(c[3])
      : "r"(a[0]), "r"(a[1]), "r"(a[2]), "r"(a[3]), "r"(b[0]), "r"(b[1]));
}

__device__ __forceinline__ void cp_async16(uint32_t smem_addr, const void* gptr, int src_bytes) {
  asm volatile("cp.async.cg.shared.global [%0], [%1], 16, %2;"
               :: "r"(smem_addr), "l"(gptr), "r"(src_bytes) : "memory");
}
#define CP_COMMIT() asm volatile("cp.async.commit_group;" ::: "memory")
#define CP_WAIT1()  asm volatile("cp.async.wait_group 1;" ::: "memory")
#define CP_WAIT0()  asm volatile("cp.async.wait_group 0;" ::: "memory")

// ---------------- conversion kernels ----------------
// activations: AH[row][(k2 & ~7) | p(k2&7)] = pack(A[2k2], A[2k2+1])
__global__ void cvtA_kernel(const float* __restrict__ A, uint32_t* __restrict__ AH, int n) {
  int i = blockIdx.x * 256 + threadIdx.x;
  if (i < n) {
    float2 v = *(const float2*)(A + 2 * (size_t)i);
    int j = i & 7;
    int o = (i & ~7) | (2 * (j & 3) + (j >> 2));
    AH[o] = pack_h2(v.x, v.y);
  }
}

struct W10 { const float* W[10]; };
// weights: WB[g*D + n][8], slot jp holds k2 = g*8 + j where j = (jp>>1) + 4*(jp&1).
// tiled 32n x 32k2 transpose via smem (coalesced reads and writes).
__global__ void __launch_bounds__(256) cvtB_kernel(W10 g, uint32_t* __restrict__ WB) {
  __shared__ float sm[64 * 33];
  const int z = blockIdx.z;
  const float* W = g.W[z];
  uint32_t* dst = WB + (size_t)z * K2_ * D_;
  const int n0t = blockIdx.x * 32, k20 = blockIdx.y * 32;
  const int tid = threadIdx.x;
#pragma unroll
  for (int p = 0; p < 8; p++) {
    int i = tid + p * 256;
    int r = i >> 5, c = i & 31;
    sm[r * 33 + c] = W[(size_t)(k20 * 2 + r) * D_ + n0t + c];
  }
  __syncthreads();
#pragma unroll
  for (int p = 0; p < 4; p++) {
    int i = tid + p * 256;
    int gl = i >> 8, rem = i & 255, n = rem >> 3, jp = rem & 7;
    int j = (jp >> 1) + ((jp & 1) << 2);
    int k2l = gl * 8 + j;
    dst[((size_t)((k20 >> 3) + gl) * D_ + n0t + n) * 8 + jp] =
        pack_h2(sm[(2 * k2l) * 33 + n], sm[(2 * k2l + 1) * 33 + n]);
  }
}

// ---------------- lora-down (unchanged) ----------------
struct D3 { const float* dn[3]; };

__global__ void __launch_bounds__(256) lora_dn3(const float* __restrict__ A, D3 g,
                                                float* __restrict__ T) {
  const int tid = threadIdx.x, lane = tid & 31, w = tid >> 5;
  const int row = blockIdx.x * 8 + w;
  const float* a = A + (size_t)row * D_;
  float p[48];
#pragma unroll
  for (int i = 0; i < 48; i++) p[i] = 0.f;
  for (int k = lane; k < D_; k += 32) {
    float av = a[k];
#pragma unroll
    for (int t = 0; t < 3; t++) {
      const float* dk = g.dn[t] + k * 16;
      float4 d0 = *(const float4*)(dk);
      float4 d1 = *(const float4*)(dk + 4);
      float4 d2 = *(const float4*)(dk + 8);
      float4 d3 = *(const float4*)(dk + 12);
      float* pt = p + t * 16;
      pt[0]  = fmaf(av, d0.x, pt[0]);  pt[1]  = fmaf(av, d0.y, pt[1]);
      pt[2]  = fmaf(av, d0.z, pt[2]);  pt[3]  = fmaf(av, d0.w, pt[3]);
      pt[4]  = fmaf(av, d1.x, pt[4]);  pt[5]  = fmaf(av, d1.y, pt[5]);
      pt[6]  = fmaf(av, d1.z, pt[6]);  pt[7]  = fmaf(av, d1.w, pt[7]);
      pt[8]  = fmaf(av, d2.x, pt[8]);  pt[9]  = fmaf(av, d2.y, pt[9]);
      pt[10] = fmaf(av, d2.z, pt[10]); pt[11] = fmaf(av, d2.w, pt[11]);
      pt[12] = fmaf(av, d3.x, pt[12]); pt[13] = fmaf(av, d3.y, pt[13]);
      pt[14] = fmaf(av, d3.z, pt[14]); pt[15] = fmaf(av, d3.w, pt[15]);
    }
  }
#pragma unroll
  for (int off = 16; off; off >>= 1)
#pragma unroll
    for (int i = 0; i < 48; i++) p[i] += __shfl_xor_sync(0xffffffffu, p[i], off);
  if (lane == 0) {
#pragma unroll
    for (int t = 0; t < 3; t++) {
      float* dt = T + ((size_t)t * COND_ + row) * 16;
#pragma unroll
      for (int i = 0; i < 16; i += 4)
        *(float4*)(dt + i) = make_float4(p[t*16+i], p[t*16+i+1], p[t*16+i+2], p[t*16+i+3]);
    }
  }
}

// ---------------- fused fp16 GEMM, fragment-pair layout, LDS.64 loads ----------------
// BM=128 x BN=128, BK=32 (2 k-groups), 256 threads (8 warps 2M x 4N), 2 blocks/SM.
// 3-stage cp.async. A smem stride 24 u32 (conflict-free LDS.64: banks 24g+2t),
// B smem [g][n][8] stride 8 (banks 8g+2t). Fragments = uint2 loads; values and
// mma order bit-identical to R12.
struct GF {
  const uint32_t* A[5]; const uint32_t* W[5]; const float* bias[5];
  const float* T[5]; const float* up[5];
  float* dst[5];
  int M[5]; int seq[5]; int rowOff[5]; int rms[5];
};

#define AW3_ 24
#define AWORDS3_ (128 * AW3_)            // 3072
#define STAGE3_ (AWORDS3_ + 2048)        // 5120 u32 = 20480 B

__global__ void __launch_bounds__(256, 2) gemm_h(GF gf, int N, int K) {
  extern __shared__ uint32_t smu[];
  const uint32_t sbase = (uint32_t)__cvta_generic_to_shared(smu);

  const int z = blockIdx.z;
  const uint32_t* __restrict__ A = gf.A[z];
  const uint32_t* __restrict__ W = gf.W[z];
  const float* __restrict__ bias = gf.bias[z];
  const int M = gf.M[z];
  const int K2 = K / 2;

  const int tid = threadIdx.x;
  const int lane = tid & 31;
  const int wid = tid >> 5;
  const int warpM = wid >> 2;
  const int warpN = wid & 3;
  const int m0 = blockIdx.y * 128;
  const int n0 = blockIdx.x * 128;
  if (m0 >= M) return;

  const int NKT = K / 32;

  auto issue = [&](int kt) {
    if (kt < NKT) {
      int k20 = kt * 16;
      uint32_t st = sbase + (uint32_t)((kt % 3) * STAGE3_) * 4u;
      // A: 128 rows x 16 u32 (4 chunks/row)
#pragma unroll
      for (int p = 0; p < 2; p++) {
        int ch = tid + p * 256;
        int r = ch >> 2, c4 = (ch & 3) << 2;
        int gr = m0 + r;
        int sz = (gr < M) ? 16 : 0;
        if (gr >= M) gr = M - 1;
        cp_async16(st + (uint32_t)(r * AW3_ + c4) * 4u,
                   A + (size_t)gr * K2 + k20 + c4, sz);
      }
      // B: 2 groups x 128 n x 8 u32 (2 chunks per (g,n))
      uint32_t stb = st + (uint32_t)AWORDS3_ * 4u;
#pragma unroll
      for (int p = 0; p < 2; p++) {
        int ch = tid + p * 256;
        int gl = ch >> 8, rem = ch & 255, n = rem >> 1, half = rem & 1;
        cp_async16(stb + (uint32_t)(gl * 1024 + n * 8 + half * 4) * 4u,
                   W + ((size_t)((k20 >> 3) + gl) * N + n0 + n) * 8 + half * 4, 16);
      }
    }
    CP_COMMIT();
  };

  float acc[4][4][4];
#pragma unroll
  for (int mt = 0; mt < 4; mt++)
#pragma unroll
    for (int nt = 0; nt < 4; nt++)
#pragma unroll
      for (int i = 0; i < 4; i++) acc[mt][nt][i] = 0.f;

  issue(0);
  issue(1);

  const int gid = lane >> 2, tig = lane & 3;

  for (int kt = 0; kt < NKT; kt++) {
    CP_WAIT1();
    __syncthreads();
    const uint32_t* sa = smu + (kt % 3) * STAGE3_;
    const uint32_t* sb = sa + AWORDS3_;
    const uint32_t* arow = sa + (warpM * 64 + gid) * AW3_ + 2 * tig;
    const uint32_t* bcol = sb + (warpN * 32 + gid) * 8 + 2 * tig;
#pragma unroll
    for (int ks2 = 0; ks2 < 2; ks2++) {
      uint32_t a[4][4];
      uint32_t b[4][2];
#pragma unroll
      for (int mt = 0; mt < 4; mt++) {
        const uint32_t* r0 = arow + mt * 16 * AW3_ + ks2 * 8;
        uint2 la = *(const uint2*)r0;              // a0 (j=tig), a2 (j=tig+4)
        uint2 lb = *(const uint2*)(r0 + 8 * AW3_); // a1, a3 (row+8)
        a[mt][0] = la.x; a[mt][1] = lb.x; a[mt][2] = la.y; a[mt][3] = lb.y;
      }
#pragma unroll
      for (int nt = 0; nt < 4; nt++) {
        uint2 bb = *(const uint2*)(bcol + ks2 * 1024 + nt * 64);
        b[nt][0] = bb.x; b[nt][1] = bb.y;
      }
#pragma unroll
      for (int mt = 0; mt < 4; mt++)
#pragma unroll
        for (int nt = 0; nt < 4; nt++) mma_f16(acc[mt][nt], a[mt], b[nt]);
    }
    issue(kt + 2);
  }
  CP_WAIT0();
  __syncthreads();

  // ---- fused epilogue (identical math order to R12) ----
  const float* Tz = gf.T[z];
  const float* upz = gf.up[z];
  float* dst = gf.dst[z];
  const int seq = gf.seq[z], rowOff = gf.rowOff[z], doRMS = gf.rms[z];

  float bb0[4], bb1[4];
#pragma unroll
  for (int nt = 0; nt < 4; nt++) {
    int col = n0 + warpN * 32 + nt * 8 + tig * 2;
    bb0[nt] = bias ? bias[col] : 0.f;
    bb1[nt] = bias ? bias[col + 1] : 0.f;
  }
#pragma unroll
  for (int mt = 0; mt < 4; mt++) {
    int gr0 = m0 + warpM * 64 + mt * 16 + gid;
#pragma unroll
    for (int nt = 0; nt < 4; nt++) {
      acc[mt][nt][0] += bb0[nt]; acc[mt][nt][1] += bb1[nt];
      acc[mt][nt][2] += bb0[nt]; acc[mt][nt][3] += bb1[nt];
    }
    if (upz) {
      int l0 = gr0 - (M - COND_);
      int l1 = l0 + 8;
      if (l1 >= 0) {
        bool h0 = (l0 >= 0);
#pragma unroll
        for (int i0 = 0; i0 < 16; i0 += 4) {
          float4 t1q = *(const float4*)(Tz + (size_t)l1 * 16 + i0);
          float4 t0q = h0 ? *(const float4*)(Tz + (size_t)l0 * 16 + i0)
                          : make_float4(0.f, 0.f, 0.f, 0.f);
          float tv0[4] = {t0q.x, t0q.y, t0q.z, t0q.w};
          float tv1[4] = {t1q.x, t1q.y, t1q.z, t1q.w};
#pragma unroll
          for (int j = 0; j < 4; j++) {
#pragma unroll
            for (int nt = 0; nt < 4; nt++) {
              int col = n0 + warpN * 32 + nt * 8 + tig * 2;
              float2 u = *(const float2*)(upz + (size_t)(i0 + j) * N + col);
              acc[mt][nt][0] = fmaf(tv0[j], u.x, acc[mt][nt][0]);
              acc[mt][nt][1] = fmaf(tv0[j], u.y, acc[mt][nt][1]);
              acc[mt][nt][2] = fmaf(tv1[j], u.x, acc[mt][nt][2]);
              acc[mt][nt][3] = fmaf(tv1[j], u.y, acc[mt][nt][3]);
            }
          }
        }
      }
    }
  }

  if (doRMS) {
    float* ssm = (float*)smu;
#pragma unroll
    for (int mt = 0; mt < 4; mt++) {
      int lr = warpM * 64 + mt * 16 + gid;
      float ss0 = 0.f, ss1 = 0.f;
#pragma unroll
      for (int nt = 0; nt < 4; nt++) {
        ss0 = fmaf(acc[mt][nt][0], acc[mt][nt][0], ss0);
        ss0 = fmaf(acc[mt][nt][1], acc[mt][nt][1], ss0);
        ss1 = fmaf(acc[mt][nt][2], acc[mt][nt][2], ss1);
        ss1 = fmaf(acc[mt][nt][3], acc[mt][nt][3], ss1);
      }
      ss0 += __shfl_xor_sync(0xffffffffu, ss0, 1);
      ss0 += __shfl_xor_sync(0xffffffffu, ss0, 2);
      ss1 += __shfl_xor_sync(0xffffffffu, ss1, 1);
      ss1 += __shfl_xor_sync(0xffffffffu, ss1, 2);
      if (tig == 0) {
        ssm[lr * 4 + warpN] = ss0;
        ssm[(lr + 8) * 4 + warpN] = ss1;
      }
    }
    __syncthreads();
#pragma unroll
    for (int mt = 0; mt < 4; mt++) {
      int lr = warpM * 64 + mt * 16 + gid;
      float4 s0 = *(const float4*)&ssm[lr * 4];
      float4 s1 = *(const float4*)&ssm[(lr + 8) * 4];
      float sc0 = rsqrtf((s0.x + s0.y + s0.z + s0.w) * (1.f / 128.f) + EPS_);
      float sc1 = rsqrtf((s1.x + s1.y + s1.z + s1.w) * (1.f / 128.f) + EPS_);
#pragma unroll
      for (int nt = 0; nt < 4; nt++) {
        acc[mt][nt][0] *= sc0; acc[mt][nt][1] *= sc0;
        acc[mt][nt][2] *= sc1; acc[mt][nt][3] *= sc1;
      }
    }
  }

  const int head = n0 >> 7;
#pragma unroll
  for (int mt = 0; mt < 4; mt++) {
    int gr0 = m0 + warpM * 64 + mt * 16 + gid;
    int gr1 = gr0 + 8;
#pragma unroll
    for (int nt = 0; nt < 4; nt++) {
      int colh = warpN * 32 + nt * 8 + tig * 2;
      float2 v0 = make_float2(acc[mt][nt][0], acc[mt][nt][1]);
      float2 v1 = make_float2(acc[mt][nt][2], acc[mt][nt][3]);
      if (seq) {
        float* bp = dst + ((size_t)head * seq + rowOff) * 128 + colh;
        if (gr0 < M) *(float2*)(bp + (size_t)gr0 * 128) = v0;
        if (gr1 < M) *(float2*)(bp + (size_t)gr1 * 128) = v1;
      } else {
        if (gr0 < M) *(float2*)(dst + (size_t)gr0 * N + n0 + colh) = v0;
        if (gr1 < M) *(float2*)(dst + (size_t)gr1 * N + n0 + colh) = v1;
      }
    }
  }
}

// ---------------- single LoRA for the output projection (unchanged) ----------------
__global__ void __launch_bounds__(256) lora_kernel(
    const float* __restrict__ A, const float* __restrict__ dn,
    const float* __restrict__ up, float* __restrict__ C) {
  __shared__ float red[8 * 16];
  __shared__ float st[16];
  const int r = blockIdx.x, tid = threadIdx.x, lane = tid & 31, wid = tid >> 5;
  const float* a = A + (size_t)r * D_;
  float p[16];
#pragma unroll
  for (int i = 0; i < 16; i++) p[i] = 0.f;
  for (int k = tid; k < D_; k += 256) {
    float av = a[k];
    float4 d0 = *(const float4*)(dn + k * 16);
    float4 d1 = *(const float4*)(dn + k * 16 + 4);
    float4 d2 = *(const float4*)(dn + k * 16 + 8);
    float4 d3 = *(const float4*)(dn + k * 16 + 12);
    p[0]  = fmaf(av, d0.x, p[0]);  p[1]  = fmaf(av, d0.y, p[1]);
    p[2]  = fmaf(av, d0.z, p[2]);  p[3]  = fmaf(av, d0.w, p[3]);
    p[4]  = fmaf(av, d1.x, p[4]);  p[5]  = fmaf(av, d1.y, p[5]);
    p[6]  = fmaf(av, d1.z, p[6]);  p[7]  = fmaf(av, d1.w, p[7]);
    p[8]  = fmaf(av, d2.x, p[8]);  p[9]  = fmaf(av, d2.y, p[9]);
    p[10] = fmaf(av, d2.z, p[10]); p[11] = fmaf(av, d2.w, p[11]);
    p[12] = fmaf(av, d3.x, p[12]); p[13] = fmaf(av, d3.y, p[13]);
    p[14] = fmaf(av, d3.z, p[14]); p[15] = fmaf(av, d3.w, p[15]);
  }
#pragma unroll
  for (int o = 16; o; o >>= 1)
#pragma unroll
    for (int i = 0; i < 16; i++) p[i] += __shfl_xor_sync(0xffffffffu, p[i], o);
  if (lane == 0)
#pragma unroll
    for (int i = 0; i < 16; i++) red[wid * 16 + i] = p[i];
  __syncthreads();
  if (tid < 16) {
    float s = 0.f;
#pragma unroll
    for (int w = 0; w < 8; w++) s += red[w * 16 + tid];
    st[tid] = s;
  }
  __syncthreads();
  float t0[16];
#pragma unroll
  for (int i = 0; i < 16; i++) t0[i] = st[i];
  float* crow = C + (size_t)r * D_;
  for (int c = tid; c < D_; c += 256) {
    float s = 0.f;
#pragma unroll
    for (int i = 0; i < 16; i++) s = fmaf(t0[i], up[(size_t)i * D_ + c], s);
    crow[c] += s;
  }
}

// ---------------- fp16 tensor-core flash attention + fused IP (R12 mainloop) ----------------
// Only the epilogue write index changes: packed outputs use the fragment-pair layout.
__global__ void __launch_bounds__(256) attn_mma_kernel(
    const float* __restrict__ Q, const float* __restrict__ K,
    const float* __restrict__ V, const float* __restrict__ KIP,
    const float* __restrict__ VIP, uint32_t* __restrict__ outE,
    uint32_t* __restrict__ outM) {
  extern __shared__ uint32_t smA[];
  uint32_t* Ks = smA;
  uint32_t* Vs = smA + 4096;
  const int tid = threadIdx.x, lane = tid & 31, w = tid >> 5;
  const int gid = lane >> 2, tig = lane & 3;
  const int h = blockIdx.y, q0 = blockIdx.x * 128;

  uint32_t qf[8][4];
  {
    const float* qr0 = Q + ((size_t)h * SL_ + q0 + w * 16 + gid) * DH_;
    const float* qr1 = qr0 + 8 * DH_;
#pragma unroll
    for (int s = 0; s < 8; s++) {
      float2 p0 = *(const float2*)(qr0 + s * 16 + 2 * tig);
      float2 p1 = *(const float2*)(qr1 + s * 16 + 2 * tig);
      float2 p2 = *(const float2*)(qr0 + s * 16 + 2 * tig + 8);
      float2 p3 = *(const float2*)(qr1 + s * 16 + 2 * tig + 8);
      qf[s][0] = pack_h2(p0.x * SCALE_, p0.y * SCALE_);
      qf[s][1] = pack_h2(p1.x * SCALE_, p1.y * SCALE_);
      qf[s][2] = pack_h2(p2.x * SCALE_, p2.y * SCALE_);
      qf[s][3] = pack_h2(p3.x * SCALE_, p3.y * SCALE_);
    }
  }

  float o[16][4];
#pragma unroll
  for (int i = 0; i < 16; i++) { o[i][0] = o[i][1] = o[i][2] = o[i][3] = 0.f; }
  float m0 = -1e30f, m1 = -1e30f, l0 = 0.f, l1 = 0.f;

  const int kc0 = 16 * (lane >> 2) + 2 * (lane & 3);
  const int cgv = 2 * (lane & 15) + (lane >> 4);
  const int ksl = lane >> 2, tgl = lane & 3;

  const int kt0 = (q0 >= SB_) ? (SB_ / 64) : 0;
  for (int kt = kt0; kt < SL_ / 64; kt++) {
    __syncthreads();
    const float* Kt = K + ((size_t)h * SL_ + kt * 64) * DH_;
    const float* Vt = V + ((size_t)h * SL_ + kt * 64) * DH_;
    float2 kf0[8], kf1[8];
    float4 vf0[4], vf1[4];
#pragma unroll
    for (int it = 0; it < 8; it++) {
      int r = w + it * 8;
      kf0[it] = *(const float2*)(Kt + r * DH_ + kc0);
      kf1[it] = *(const float2*)(Kt + r * DH_ + kc0 + 8);
    }
#pragma unroll
    for (int it = 0; it < 4; it++) {
      int m = w + it * 8;
      vf0[it] = *(const float4*)(Vt + (2 * m) * DH_ + cgv * 4);
      vf1[it] = *(const float4*)(Vt + (2 * m + 1) * DH_ + cgv * 4);
    }
#pragma unroll
    for (int it = 0; it < 8; it++) {
      int r = w + it * 8;
      int nt = r >> 3, gk = r & 7;
      uint32_t* dst = Ks + ((nt * 8 + ksl) * 32 + ((gk * 4 + tgl) ^ (ksl << 2))) * 2;
      dst[0] = pack_h2(kf0[it].x, kf0[it].y);
      dst[1] = pack_h2(kf1[it].x, kf1[it].y);
    }
    __syncthreads();

    float sa[8][4];
#pragma unroll
    for (int nt = 0; nt < 8; nt++) { sa[nt][0] = sa[nt][1] = sa[nt][2] = sa[nt][3] = 0.f; }
#pragma unroll
    for (int ks = 0; ks < 8; ks++) {
#pragma unroll
      for (int nt = 0; nt < 8; nt++) {
        uint2 b2 = *(const uint2*)(Ks + ((nt * 8 + ks) * 32 + (lane ^ (ks << 2))) * 2);
        uint32_t bb[2] = {b2.x, b2.y};
        mma_f16(sa[nt], qf[ks], bb);
      }
    }

    float rm0 = -1e30f, rm1 = -1e30f;
#pragma unroll
    for (int nt = 0; nt < 8; nt++) {
      rm0 = fmaxf(rm0, fmaxf(sa[nt][0], sa[nt][1]));
      rm1 = fmaxf(rm1, fmaxf(sa[nt][2], sa[nt][3]));
    }
#pragma unroll
    for (int off = 1; off < 4; off <<= 1) {
      rm0 = fmaxf(rm0, __shfl_xor_sync(0xffffffffu, rm0, off));
      rm1 = fmaxf(rm1, __shfl_xor_sync(0xffffffffu, rm1, off));
    }
    float mn0 = fmaxf(m0, rm0), mn1 = fmaxf(m1, rm1);
    float corr0 = __expf(m0 - mn0), corr1 = __expf(m1 - mn1);
    m0 = mn0; m1 = mn1;
    float rs0 = 0.f, rs1 = 0.f;
#pragma unroll
    for (int nt = 0; nt < 8; nt++) {
      sa[nt][0] = __expf(sa[nt][0] - mn0); rs0 += sa[nt][0];
      sa[nt][1] = __expf(sa[nt][1] - mn0); rs0 += sa[nt][1];
      sa[nt][2] = __expf(sa[nt][2] - mn1); rs1 += sa[nt][2];
      sa[nt][3] = __expf(sa[nt][3] - mn1); rs1 += sa[nt][3];
    }
#pragma unroll
    for (int off = 1; off < 4; off <<= 1) {
      rs0 += __shfl_xor_sync(0xffffffffu, rs0, off);
      rs1 += __shfl_xor_sync(0xffffffffu, rs1, off);
    }
    l0 = l0 * corr0 + rs0;
    l1 = l1 * corr1 + rs1;
#pragma unroll
    for (int i = 0; i < 16; i++) {
      o[i][0] *= corr0; o[i][1] *= corr0; o[i][2] *= corr1; o[i][3] *= corr1;
    }

#pragma unroll
    for (int it = 0; it < 4; it++) {
      int m = w + it * 8;
      int g = m >> 3, ov = m & 7, reg = ov >> 2, tvx = ov & 3;
      float v0e[4] = {vf0[it].x, vf0[it].y, vf0[it].z, vf0[it].w};
      float v1e[4] = {vf1[it].x, vf1[it].y, vf1[it].z, vf1[it].w};
#pragma unroll
      for (int e = 0; e < 4; e++) {
        int d = cgv * 4 + e;
        int ntd = d >> 3, gn = d & 7;
        Vs[((ntd * 4 + g) * 32 + ((gn * 4 + tvx) ^ ntd)) * 2 + reg] = pack_h2(v0e[e], v1e[e]);
      }
    }
    __syncthreads();

#pragma unroll
    for (int g = 0; g < 4; g++) {
      uint32_t pf[4];
      pf[0] = pack_h2(sa[2 * g][0], sa[2 * g][1]);
      pf[1] = pack_h2(sa[2 * g][2], sa[2 * g][3]);
      pf[2] = pack_h2(sa[2 * g + 1][0], sa[2 * g + 1][1]);
      pf[3] = pack_h2(sa[2 * g + 1][2], sa[2 * g + 1][3]);
#pragma unroll
      for (int ntd = 0; ntd < 16; ntd++) {
        uint2 b2 = *(const uint2*)(Vs + ((ntd * 4 + g) * 32 + (lane ^ ntd)) * 2);
        uint32_t bb[2] = {b2.x, b2.y};
        mma_f16(o[ntd], pf, bb);
      }
    }
  }

  float inv0 = 1.f / l0, inv1 = 1.f / l1;
#pragma unroll
  for (int i = 0; i < 16; i++) {
    o[i][0] *= inv0; o[i][1] *= inv0; o[i][2] *= inv1; o[i][3] *= inv1;
  }

  if (q0 >= ENC_) {
    __syncthreads();
    const float* Kt = KIP + (size_t)h * NIP_ * DH_;
    const float* Vt = VIP + (size_t)h * NIP_ * DH_;
    float2 kf0[8], kf1[8];
    float4 vf0[4], vf1[4];
#pragma unroll
    for (int it = 0; it < 8; it++) {
      int r = w + it * 8;
      kf0[it] = *(const float2*)(Kt + r * DH_ + kc0);
      kf1[it] = *(const float2*)(Kt + r * DH_ + kc0 + 8);
    }
#pragma unroll
    for (int it = 0; it < 4; it++) {
      int m = w + it * 8;
      vf0[it] = *(const float4*)(Vt + (2 * m) * DH_ + cgv * 4);
      vf1[it] = *(const float4*)(Vt + (2 * m + 1) * DH_ + cgv * 4);
    }
#pragma unroll
    for (int it = 0; it < 8; it++) {
      int r = w + it * 8;
      int nt = r >> 3, gk = r & 7;
      uint32_t* dst = Ks + ((nt * 8 + ksl) * 32 + ((gk * 4 + tgl) ^ (ksl << 2))) * 2;
      dst[0] = pack_h2(kf0[it].x, kf0[it].y);
      dst[1] = pack_h2(kf1[it].x, kf1[it].y);
    }
    __syncthreads();

    float sa[8][4];
#pragma unroll
    for (int nt = 0; nt < 8; nt++) { sa[nt][0] = sa[nt][1] = sa[nt][2] = sa[nt][3] = 0.f; }
#pragma unroll
    for (int ks = 0; ks < 8; ks++) {
#pragma unroll
      for (int nt = 0; nt < 8; nt++) {
        uint2 b2 = *(const uint2*)(Ks + ((nt * 8 + ks) * 32 + (lane ^ (ks << 2))) * 2);
        uint32_t bb[2] = {b2.x, b2.y};
        mma_f16(sa[nt], qf[ks], bb);
      }
    }
    float rm0 = -1e30f, rm1 = -1e30f;
#pragma unroll
    for (int nt = 0; nt < 8; nt++) {
      rm0 = fmaxf(rm0, fmaxf(sa[nt][0], sa[nt][1]));
      rm1 = fmaxf(rm1, fmaxf(sa[nt][2], sa[nt][3]));
    }
#pragma unroll
    for (int off = 1; off < 4; off <<= 1) {
      rm0 = fmaxf(rm0, __shfl_xor_sync(0xffffffffu, rm0, off));
      rm1 = fmaxf(rm1, __shfl_xor_sync(0xffffffffu, rm1, off));
    }
    float rs0 = 0.f, rs1 = 0.f;
#pragma unroll
    for (int nt = 0; nt < 8; nt++) {
      sa[nt][0] = __expf(sa[nt][0] - rm0); rs0 += sa[nt][0];
      sa[nt][1] = __expf(sa[nt][1] - rm0); rs0 += sa[nt][1];
      sa[nt][2] = __expf(sa[nt][2] - rm1); rs1 += sa[nt][2];
      sa[nt][3] = __expf(sa[nt][3] - rm1); rs1 += sa[nt][3];
    }
#pragma unroll
    for (int off = 1; off < 4; off <<= 1) {
      rs0 += __shfl_xor_sync(0xffffffffu, rs0, off);
      rs1 += __shfl_xor_sync(0xffffffffu, rs1, off);
    }
    float iv0 = 1.f / rs0, iv1 = 1.f / rs1;
#pragma unroll
    for (int it = 0; it < 4; it++) {
      int m = w + it * 8;
      int g = m >> 3, ov = m & 7, reg = ov >> 2, tvx = ov & 3;
      float v0e[4] = {vf0[it].x, vf0[it].y, vf0[it].z, vf0[it].w};
      float v1e[4] = {vf1[it].x, vf1[it].y, vf1[it].z, vf1[it].w};
#pragma unroll
      for (int e = 0; e < 4; e++) {
        int d = cgv * 4 + e;
        int ntd = d >> 3, gn = d & 7;
        Vs[((ntd * 4 + g) * 32 + ((gn * 4 + tvx) ^ ntd)) * 2 + reg] = pack_h2(v0e[e], v1e[e]);
      }
    }
    __syncthreads();
#pragma unroll
    for (int g = 0; g < 4; g++) {
      uint32_t pf[4];
      pf[0] = pack_h2(sa[2 * g][0] * iv0, sa[2 * g][1] * iv0);
      pf[1] = pack_h2(sa[2 * g][2] * iv1, sa[2 * g][3] * iv1);
      pf[2] = pack_h2(sa[2 * g + 1][0] * iv0, sa[2 * g + 1][1] * iv0);
      pf[3] = pack_h2(sa[2 * g + 1][2] * iv1, sa[2 * g + 1][3] * iv1);
#pragma unroll
      for (int ntd = 0; ntd < 16; ntd++) {
        uint2 b2 = *(const uint2*)(Vs + ((ntd * 4 + g) * 32 + (lane ^ ntd)) * 2);
        uint32_t bb[2] = {b2.x, b2.y};
        mma_f16(o[ntd], pf, bb);
      }
    }
  }

  // ---- epilogue: pack f16x2, scatter with fragment-pair permutation ----
  int row0 = q0 + w * 16 + gid, row1 = row0 + 8;
#pragma unroll
  for (int ntd = 0; ntd < 16; ntd++) {
    int k2 = h * 64 + ntd * 4 + tig;
    int j = k2 & 7;
    int c2 = (k2 & ~7) | (2 * (j & 3) + (j >> 2));
    uint32_t p0 = pack_h2(o[ntd][0], o[ntd][1]);
    uint32_t p1 = pack_h2(o[ntd][2], o[ntd][3]);
    if (row0 < ENC_) {
      outE[(size_t)row0 * K2_ + c2] = p0;
      outE[(size_t)row1 * K2_ + c2] = p1;
    } else {
      outM[(size_t)(row0 - ENC_) * K2_ + c2] = p0;
      outM[(size_t)(row1 - ENC_) * K2_ + c2] = p1;
    }
  }
}

// ---------------- launch ----------------
extern "C" void kernel_launch(void* const* d_in, const int* in_sizes, int n_in,
                              void* d_out, int out_size) {
  const float* hs   = (const float*)d_in[0];
  const float* ehs  = (const float*)d_in[1];
  const float* img  = (const float*)d_in[2];
  const float* Wq   = (const float*)d_in[3];  const float* bq  = (const float*)d_in[4];
  const float* Wk   = (const float*)d_in[5];  const float* bk  = (const float*)d_in[6];
  const float* Wv   = (const float*)d_in[7];  const float* bv  = (const float*)d_in[8];
  const float* Waq  = (const float*)d_in[9];  const float* baq = (const float*)d_in[10];
  const float* Wak  = (const float*)d_in[11]; const float* bak = (const float*)d_in[12];
  const float* Wav  = (const float*)d_in[13]; const float* bav = (const float*)d_in[14];
  const float* Wo   = (const float*)d_in[15]; const float* bo  = (const float*)d_in[16];
  const float* Wao  = (const float*)d_in[17]; const float* bao = (const float*)d_in[18];
  const float* Wkip = (const float*)d_in[19]; const float* Wvip = (const float*)d_in[20];
  const float* lq_dn = (const float*)d_in[21]; const float* lq_up = (const float*)d_in[22];
  const float* lk_dn = (const float*)d_in[23]; const float* lk_up = (const float*)d_in[24];
  const float* lv_dn = (const float*)d_in[25]; const float* lv_up = (const float*)d_in[26];
  const float* lp_dn = (const float*)d_in[27]; const float* lp_up = (const float*)d_in[28];
  float* out = (float*)d_out;

  float *Q, *K, *V, *KIP, *VIP, *T3;
  uint32_t *WB, *hsH, *ehsH, *imgH, *amH, *aeH;
  cudaGetSymbolAddress((void**)&Q, g_Q);
  cudaGetSymbolAddress((void**)&K, g_K);
  cudaGetSymbolAddress((void**)&V, g_V);
  cudaGetSymbolAddress((void**)&KIP, g_KIP);
  cudaGetSymbolAddress((void**)&VIP, g_VIP);
  cudaGetSymbolAddress((void**)&T3, g_T3);
  cudaGetSymbolAddress((void**)&WB, g_WB);
  cudaGetSymbolAddress((void**)&hsH, g_hsH);
  cudaGetSymbolAddress((void**)&ehsH, g_ehsH);
  cudaGetSymbolAddress((void**)&imgH, g_imgH);
  cudaGetSymbolAddress((void**)&amH, g_amH);
  cudaGetSymbolAddress((void**)&aeH, g_aeH);

  const int G_SMEM = 3 * STAGE3_ * 4;       // 61440 B
  const int ATTN_SMEM = (4096 + 4096) * 4;  // 32768 B
  cudaFuncSetAttribute(gemm_h, cudaFuncAttributeMaxDynamicSharedMemorySize, G_SMEM);
  cudaFuncSetAttribute(attn_mma_kernel, cudaFuncAttributeMaxDynamicSharedMemorySize, ATTN_SMEM);

  float* outMain = out + (size_t)ENC_ * D_;
  const float* hsC = hs + (size_t)(S_ - COND_) * D_;

  // 0. pack operands (fragment-pair layouts)
  W10 w10 = {{Wq, Wk, Wv, Waq, Wak, Wav, Wkip, Wvip, Wo, Wao}};
  cvtB_kernel<<<dim3(D_ / 32, K2_ / 32, 10), 256>>>(w10, WB);
  cvtA_kernel<<<S_ * K2_ / 256, 256>>>(hs, hsH, S_ * K2_);
  cvtA_kernel<<<ENC_ * K2_ / 256, 256>>>(ehs, ehsH, ENC_ * K2_);
  cvtA_kernel<<<NIP_ * K2_ / 256, 256>>>(img, imgH, NIP_ * K2_);

  // 1. lora-down temps
  D3 d3 = {{lq_dn, lk_dn, lv_dn}};
  lora_dn3<<<COND_ / 8, 256>>>(hsC, d3, T3);

  // 2. main QKV projections (fused epilogue)
  size_t WS = (size_t)K2_ * D_;
  GF gqkv = {
    {hsH, hsH, hsH, 0, 0}, {WB, WB + WS, WB + 2 * WS, 0, 0}, {bq, bk, bv, 0, 0},
    {T3, T3 + COND_ * 16, T3 + 2 * COND_ * 16, 0, 0}, {lq_up, lk_up, lv_up, 0, 0},
    {Q, K, V, 0, 0},
    {S_, S_, S_, 1, 1}, {SL_, SL_, SL_, 1, 1}, {ENC_, ENC_, ENC_, 0, 0}, {1, 1, 0, 0, 0}};
  gemm_h<<<dim3(24, 16, 3), 256, G_SMEM>>>(gqkv, D_, D_);

  // 3. encoder + IP projections
  GF gei = {
    {ehsH, ehsH, ehsH, imgH, imgH},
    {WB + 3 * WS, WB + 4 * WS, WB + 5 * WS, WB + 6 * WS, WB + 7 * WS},
    {baq, bak, bav, 0, 0},
    {0, 0, 0, 0, 0}, {0, 0, 0, 0, 0},
    {Q, K, V, KIP, VIP},
    {ENC_, ENC_, ENC_, NIP_, NIP_}, {SL_, SL_, SL_, NIP_, NIP_},
    {0, 0, 0, 0, 0}, {1, 1, 0, 1, 0}};
  gemm_h<<<dim3(24, 4, 5), 256, G_SMEM>>>(gei, D_, D_);

  // 4. joint attention + fused IP (writes packed, permuted amH/aeH)
  attn_mma_kernel<<<dim3(SL_ / 128, H_), 256, ATTN_SMEM>>>(Q, K, V, KIP, VIP, aeH, amH);

  // 5. output projections
  GF gout = {
    {amH, aeH, 0, 0, 0}, {WB + 8 * WS, WB + 9 * WS, 0, 0, 0}, {bo, bao, 0, 0, 0},
    {0, 0, 0, 0, 0}, {0, 0, 0, 0, 0},
    {outMain, out, 0, 0, 0},
    {S_, ENC_, 1, 1, 1}, {0, 0, 0, 0, 0}, {0, 0, 0, 0, 0}, {0, 0, 0, 0, 0}};
  gemm_h<<<dim3(24, 16, 2), 256, G_SMEM>>>(gout, D_, D_);

  // 6. output LoRA
  float* outCond = outMain + (size_t)(S_ - COND_) * D_;
  lora_kernel<<<COND_, 256>>>(outCond, lp_dn, lp_up, outCond);
}

// round 16
// speedup vs baseline: 8.7251x; 1.0215x over previous
#include <cuda_runtime.h>
#include <math.h>
#include <stdint.h>

// ---------------- problem constants ----------------
#define D_    3072
#define K2_   1536   // D/2 (packed f16x2 along k)
#define S_    2048
#define H_    24
#define DH_   128
#define ENC_  512
#define NIP_  64
#define COND_ 1024
#define SL_   2560
#define SB_   1536
#define RANK_ 16
#define EPS_  1e-5f
#define SCALE_ 0.08838834764831845f

// ---------------- scratch ----------------
__device__ uint32_t g_QH[H_ * SL_ * 64];    // Q packed f16x2 (scale folded), head-major
__device__ uint32_t g_KH[H_ * SL_ * 64];    // K packed f16x2, head-major
__device__ float    g_V[H_ * SL_ * DH_];    // V f32, head-major
__device__ uint32_t g_KIPH[H_ * NIP_ * 64];
__device__ float    g_VIP[H_ * NIP_ * DH_];
__device__ float    g_T3[3 * COND_ * RANK_];
// packed f16x2 operand buffers, fragment-pair group layout (p(j) = 2*(j&3)+(j>>2))
__device__ uint32_t g_WB[10 * K2_ * D_];
__device__ uint32_t g_hsH[S_ * K2_];
__device__ uint32_t g_ehsH[ENC_ * K2_];
__device__ uint32_t g_imgH[NIP_ * K2_];
__device__ uint32_t g_amH[S_ * K2_];
__device__ uint32_t g_aeH[ENC_ * K2_];

// ---------------- helpers ----------------
__device__ __forceinline__ uint32_t pack_h2(float lo, float hi) {
  uint32_t r;
  asm("cvt.rn.f16x2.f32 %0, %1, %2;" : "=r"(r) : "f"(hi), "f"(lo));
  return r;
}

__device__ __forceinline__ void mma_f16(float c[4], const uint32_t a[4], const uint32_t b[2]) {
  asm("mma.sync.aligned.m16n8k16.row.col.f32.f16.f16.f32 "
      "{%0,%1,%2,%3}, {%4,%5,%6,%7}, {%8,%9}, {%0,%1,%2,%3};"
      : "+f"(c[0]), "+f"(c[1]), "+f"(c[2]), "+f"(c[3])
      : "r"(a[0]), "r"(a[1]), "r"(a[2]), "r"(a[3]), "r"(b[0]), "r"(b[1]));
}

__device__ __forceinline__ void cp_async16(uint32_t smem_addr, const void* gptr, int src_bytes) {
  asm volatile("cp.async.cg.shared.global [%0], [%1], 16, %2;"
               :: "r"(smem_addr), "l"(gptr), "r"(src_bytes) : "memory");
}
#define CP_COMMIT() asm volatile("cp.async.commit_group;" ::: "memory")
#define CP_WAIT1()  asm volatile("cp.async.wait_group 1;" ::: "memory")
#define CP_WAIT0()  asm volatile("cp.async.wait_group 0;" ::: "memory")

// ---------------- conversion kernels ----------------
__global__ void cvtA_kernel(const float* __restrict__ A, uint32_t* __restrict__ AH, int n) {
  int i = blockIdx.x * 256 + threadIdx.x;
  if (i < n) {
    float2 v = *(const float2*)(A + 2 * (size_t)i);
    int j = i & 7;
    int o = (i & ~7) | (2 * (j & 3) + (j >> 2));
    AH[o] = pack_h2(v.x, v.y);
  }
}

struct W10 { const float* W[10]; };
__global__ void __launch_bounds__(256) cvtB_kernel(W10 g, uint32_t* __restrict__ WB) {
  __shared__ float sm[64 * 33];
  const int z = blockIdx.z;
  const float* W = g.W[z];
  uint32_t* dst = WB + (size_t)z * K2_ * D_;
  const int n0t = blockIdx.x * 32, k20 = blockIdx.y * 32;
  const int tid = threadIdx.x;
#pragma unroll
  for (int p = 0; p < 8; p++) {
    int i = tid + p * 256;
    int r = i >> 5, c = i & 31;
    sm[r * 33 + c] = W[(size_t)(k20 * 2 + r) * D_ + n0t + c];
  }
  __syncthreads();
#pragma unroll
  for (int p = 0; p < 4; p++) {
    int i = tid + p * 256;
    int gl = i >> 8, rem = i & 255, n = rem >> 3, jp = rem & 7;
    int j = (jp >> 1) + ((jp & 1) << 2);
    int k2l = gl * 8 + j;
    dst[((size_t)((k20 >> 3) + gl) * D_ + n0t + n) * 8 + jp] =
        pack_h2(sm[(2 * k2l) * 33 + n], sm[(2 * k2l + 1) * 33 + n]);
  }
}

// ---------------- lora-down (unchanged) ----------------
struct D3 { const float* dn[3]; };

__global__ void __launch_bounds__(256) lora_dn3(const float* __restrict__ A, D3 g,
                                                float* __restrict__ T) {
  const int tid = threadIdx.x, lane = tid & 31, w = tid >> 5;
  const int row = blockIdx.x * 8 + w;
  const float* a = A + (size_t)row * D_;
  float p[48];
#pragma unroll
  for (int i = 0; i < 48; i++) p[i] = 0.f;
  for (int k = lane; k < D_; k += 32) {
    float av = a[k];
#pragma unroll
    for (int t = 0; t < 3; t++) {
      const float* dk = g.dn[t] + k * 16;
      float4 d0 = *(const float4*)(dk);
      float4 d1 = *(const float4*)(dk + 4);
      float4 d2 = *(const float4*)(dk + 8);
      float4 d3 = *(const float4*)(dk + 12);
      float* pt = p + t * 16;
      pt[0]  = fmaf(av, d0.x, pt[0]);  pt[1]  = fmaf(av, d0.y, pt[1]);
      pt[2]  = fmaf(av, d0.z, pt[2]);  pt[3]  = fmaf(av, d0.w, pt[3]);
      pt[4]  = fmaf(av, d1.x, pt[4]);  pt[5]  = fmaf(av, d1.y, pt[5]);
      pt[6]  = fmaf(av, d1.z, pt[6]);  pt[7]  = fmaf(av, d1.w, pt[7]);
      pt[8]  = fmaf(av, d2.x, pt[8]);  pt[9]  = fmaf(av, d2.y, pt[9]);
      pt[10] = fmaf(av, d2.z, pt[10]); pt[11] = fmaf(av, d2.w, pt[11]);
      pt[12] = fmaf(av, d3.x, pt[12]); pt[13] = fmaf(av, d3.y, pt[13]);
      pt[14] = fmaf(av, d3.z, pt[14]); pt[15] = fmaf(av, d3.w, pt[15]);
    }
  }
#pragma unroll
  for (int off = 16; off; off >>= 1)
#pragma unroll
    for (int i = 0; i < 48; i++) p[i] += __shfl_xor_sync(0xffffffffu, p[i], off);
  if (lane == 0) {
#pragma unroll
    for (int t = 0; t < 3; t++) {
      float* dt = T + ((size_t)t * COND_ + row) * 16;
#pragma unroll
      for (int i = 0; i < 16; i += 4)
        *(float4*)(dt + i) = make_float4(p[t*16+i], p[t*16+i+1], p[t*16+i+2], p[t*16+i+3]);
    }
  }
}

// ---------------- fused fp16 GEMM (R14 mainloop; epilogue adds packed-f16 stores) ----------------
// pk: 0 = f32 store; 1 = packed f16x2 head-major; 2 = packed with SCALE_ folded (Q).
struct GF {
  const uint32_t* A[8]; const uint32_t* W[8]; const float* bias[8];
  const float* T[8]; const float* up[8];
  float* dst[8];
  int M[8]; int seq[8]; int rowOff[8]; int rms[8]; int pk[8];
};

#define AW3_ 24
#define AWORDS3_ (128 * AW3_)            // 3072
#define STAGE3_ (AWORDS3_ + 2048)        // 5120 u32 = 20480 B

__global__ void __launch_bounds__(256, 2) gemm_h(GF gf, int N, int K) {
  extern __shared__ uint32_t smu[];
  const uint32_t sbase = (uint32_t)__cvta_generic_to_shared(smu);

  const int z = blockIdx.z;
  const uint32_t* __restrict__ A = gf.A[z];
  const uint32_t* __restrict__ W = gf.W[z];
  const float* __restrict__ bias = gf.bias[z];
  const int M = gf.M[z];
  const int K2 = K / 2;

  const int tid = threadIdx.x;
  const int lane = tid & 31;
  const int wid = tid >> 5;
  const int warpM = wid >> 2;
  const int warpN = wid & 3;
  const int m0 = blockIdx.y * 128;
  const int n0 = blockIdx.x * 128;
  if (m0 >= M) return;

  const int NKT = K / 32;

  auto issue = [&](int kt) {
    if (kt < NKT) {
      int k20 = kt * 16;
      uint32_t st = sbase + (uint32_t)((kt % 3) * STAGE3_) * 4u;
#pragma unroll
      for (int p = 0; p < 2; p++) {
        int ch = tid + p * 256;
        int r = ch >> 2, c4 = (ch & 3) << 2;
        int gr = m0 + r;
        int sz = (gr < M) ? 16 : 0;
        if (gr >= M) gr = M - 1;
        cp_async16(st + (uint32_t)(r * AW3_ + c4) * 4u,
                   A + (size_t)gr * K2 + k20 + c4, sz);
      }
      uint32_t stb = st + (uint32_t)AWORDS3_ * 4u;
#pragma unroll
      for (int p = 0; p < 2; p++) {
        int ch = tid + p * 256;
        int gl = ch >> 8, rem = ch & 255, n = rem >> 1, half = rem & 1;
        cp_async16(stb + (uint32_t)(gl * 1024 + n * 8 + half * 4) * 4u,
                   W + ((size_t)((k20 >> 3) + gl) * N + n0 + n) * 8 + half * 4, 16);
      }
    }
    CP_COMMIT();
  };

  float acc[4][4][4];
#pragma unroll
  for (int mt = 0; mt < 4; mt++)
#pragma unroll
    for (int nt = 0; nt < 4; nt++)
#pragma unroll
      for (int i = 0; i < 4; i++) acc[mt][nt][i] = 0.f;

  issue(0);
  issue(1);

  const int gid = lane >> 2, tig = lane & 3;

  for (int kt = 0; kt < NKT; kt++) {
    CP_WAIT1();
    __syncthreads();
    const uint32_t* sa = smu + (kt % 3) * STAGE3_;
    const uint32_t* sb = sa + AWORDS3_;
    const uint32_t* arow = sa + (warpM * 64 + gid) * AW3_ + 2 * tig;
    const uint32_t* bcol = sb + (warpN * 32 + gid) * 8 + 2 * tig;
#pragma unroll
    for (int ks2 = 0; ks2 < 2; ks2++) {
      uint32_t a[4][4];
      uint32_t b[4][2];
#pragma unroll
      for (int mt = 0; mt < 4; mt++) {
        const uint32_t* r0 = arow + mt * 16 * AW3_ + ks2 * 8;
        uint2 la = *(const uint2*)r0;
        uint2 lb = *(const uint2*)(r0 + 8 * AW3_);
        a[mt][0] = la.x; a[mt][1] = lb.x; a[mt][2] = la.y; a[mt][3] = lb.y;
      }
#pragma unroll
      for (int nt = 0; nt < 4; nt++) {
        uint2 bb = *(const uint2*)(bcol + ks2 * 1024 + nt * 64);
        b[nt][0] = bb.x; b[nt][1] = bb.y;
      }
#pragma unroll
      for (int mt = 0; mt < 4; mt++)
#pragma unroll
        for (int nt = 0; nt < 4; nt++) mma_f16(acc[mt][nt], a[mt], b[nt]);
    }
    issue(kt + 2);
  }
  CP_WAIT0();
  __syncthreads();

  // ---- fused epilogue ----
  const float* Tz = gf.T[z];
  const float* upz = gf.up[z];
  float* dst = gf.dst[z];
  const int seq = gf.seq[z], rowOff = gf.rowOff[z], doRMS = gf.rms[z], pk = gf.pk[z];

  float bb0[4], bb1[4];
#pragma unroll
  for (int nt = 0; nt < 4; nt++) {
    int col = n0 + warpN * 32 + nt * 8 + tig * 2;
    bb0[nt] = bias ? bias[col] : 0.f;
    bb1[nt] = bias ? bias[col + 1] : 0.f;
  }
#pragma unroll
  for (int mt = 0; mt < 4; mt++) {
    int gr0 = m0 + warpM * 64 + mt * 16 + gid;
#pragma unroll
    for (int nt = 0; nt < 4; nt++) {
      acc[mt][nt][0] += bb0[nt]; acc[mt][nt][1] += bb1[nt];
      acc[mt][nt][2] += bb0[nt]; acc[mt][nt][3] += bb1[nt];
    }
    if (upz) {
      int l0 = gr0 - (M - COND_);
      int l1 = l0 + 8;
      if (l1 >= 0) {
        bool h0 = (l0 >= 0);
#pragma unroll
        for (int i0 = 0; i0 < 16; i0 += 4) {
          float4 t1q = *(const float4*)(Tz + (size_t)l1 * 16 + i0);
          float4 t0q = h0 ? *(const float4*)(Tz + (size_t)l0 * 16 + i0)
                          : make_float4(0.f, 0.f, 0.f, 0.f);
          float tv0[4] = {t0q.x, t0q.y, t0q.z, t0q.w};
          float tv1[4] = {t1q.x, t1q.y, t1q.z, t1q.w};
#pragma unroll
          for (int j = 0; j < 4; j++) {
#pragma unroll
            for (int nt = 0; nt < 4; nt++) {
              int col = n0 + warpN * 32 + nt * 8 + tig * 2;
              float2 u = *(const float2*)(upz + (size_t)(i0 + j) * N + col);
              acc[mt][nt][0] = fmaf(tv0[j], u.x, acc[mt][nt][0]);
              acc[mt][nt][1] = fmaf(tv0[j], u.y, acc[mt][nt][1]);
              acc[mt][nt][2] = fmaf(tv1[j], u.x, acc[mt][nt][2]);
              acc[mt][nt][3] = fmaf(tv1[j], u.y, acc[mt][nt][3]);
            }
          }
        }
      }
    }
  }

  if (doRMS) {
    float* ssm = (float*)smu;
#pragma unroll
    for (int mt = 0; mt < 4; mt++) {
      int lr = warpM * 64 + mt * 16 + gid;
      float ss0 = 0.f, ss1 = 0.f;
#pragma unroll
      for (int nt = 0; nt < 4; nt++) {
        ss0 = fmaf(acc[mt][nt][0], acc[mt][nt][0], ss0);
        ss0 = fmaf(acc[mt][nt][1], acc[mt][nt][1], ss0);
        ss1 = fmaf(acc[mt][nt][2], acc[mt][nt][2], ss1);
        ss1 = fmaf(acc[mt][nt][3], acc[mt][nt][3], ss1);
      }
      ss0 += __shfl_xor_sync(0xffffffffu, ss0, 1);
      ss0 += __shfl_xor_sync(0xffffffffu, ss0, 2);
      ss1 += __shfl_xor_sync(0xffffffffu, ss1, 1);
      ss1 += __shfl_xor_sync(0xffffffffu, ss1, 2);
      if (tig == 0) {
        ssm[lr * 4 + warpN] = ss0;
        ssm[(lr + 8) * 4 + warpN] = ss1;
      }
    }
    __syncthreads();
#pragma unroll
    for (int mt = 0; mt < 4; mt++) {
      int lr = warpM * 64 + mt * 16 + gid;
      float4 s0 = *(const float4*)&ssm[lr * 4];
      float4 s1 = *(const float4*)&ssm[(lr + 8) * 4];
      float sc0 = rsqrtf((s0.x + s0.y + s0.z + s0.w) * (1.f / 128.f) + EPS_);
      float sc1 = rsqrtf((s1.x + s1.y + s1.z + s1.w) * (1.f / 128.f) + EPS_);
#pragma unroll
      for (int nt = 0; nt < 4; nt++) {
        acc[mt][nt][0] *= sc0; acc[mt][nt][1] *= sc0;
        acc[mt][nt][2] *= sc1; acc[mt][nt][3] *= sc1;
      }
    }
  }

  const int head = n0 >> 7;
  const float fs = (pk == 2) ? SCALE_ : 1.f;
#pragma unroll
  for (int mt = 0; mt < 4; mt++) {
    int gr0 = m0 + warpM * 64 + mt * 16 + gid;
    int gr1 = gr0 + 8;
#pragma unroll
    for (int nt = 0; nt < 4; nt++) {
      int colh = warpN * 32 + nt * 8 + tig * 2;
      if (seq) {
        if (pk) {
          uint32_t* d2 = (uint32_t*)dst;
          size_t base = (size_t)head * seq + rowOff;
          int c2 = warpN * 16 + nt * 4 + tig;
          if (gr0 < M)
            d2[(base + gr0) * 64 + c2] = pack_h2(acc[mt][nt][0] * fs, acc[mt][nt][1] * fs);
          if (gr1 < M)
            d2[(base + gr1) * 64 + c2] = pack_h2(acc[mt][nt][2] * fs, acc[mt][nt][3] * fs);
        } else {
          float* bp = dst + ((size_t)head * seq + rowOff) * 128 + colh;
          if (gr0 < M) *(float2*)(bp + (size_t)gr0 * 128) =
              make_float2(acc[mt][nt][0], acc[mt][nt][1]);
          if (gr1 < M) *(float2*)(bp + (size_t)gr1 * 128) =
              make_float2(acc[mt][nt][2], acc[mt][nt][3]);
        }
      } else {
        if (gr0 < M) *(float2*)(dst + (size_t)gr0 * N + n0 + colh) =
            make_float2(acc[mt][nt][0], acc[mt][nt][1]);
        if (gr1 < M) *(float2*)(dst + (size_t)gr1 * N + n0 + colh) =
            make_float2(acc[mt][nt][2], acc[mt][nt][3]);
      }
    }
  }
}

// ---------------- single LoRA for the output projection (unchanged) ----------------
__global__ void __launch_bounds__(256) lora_kernel(
    const float* __restrict__ A, const float* __restrict__ dn,
    const float* __restrict__ up, float* __restrict__ C) {
  __shared__ float red[8 * 16];
  __shared__ float st[16];
  const int r = blockIdx.x, tid = threadIdx.x, lane = tid & 31, wid = tid >> 5;
  const float* a = A + (size_t)r * D_;
  float p[16];
#pragma unroll
  for (int i = 0; i < 16; i++) p[i] = 0.f;
  for (int k = tid; k < D_; k += 256) {
    float av = a[k];
    float4 d0 = *(const float4*)(dn + k * 16);
    float4 d1 = *(const float4*)(dn + k * 16 + 4);
    float4 d2 = *(const float4*)(dn + k * 16 + 8);
    float4 d3 = *(const float4*)(dn + k * 16 + 12);
    p[0]  = fmaf(av, d0.x, p[0]);  p[1]  = fmaf(av, d0.y, p[1]);
    p[2]  = fmaf(av, d0.z, p[2]);  p[3]  = fmaf(av, d0.w, p[3]);
    p[4]  = fmaf(av, d1.x, p[4]);  p[5]  = fmaf(av, d1.y, p[5]);
    p[6]  = fmaf(av, d1.z, p[6]);  p[7]  = fmaf(av, d1.w, p[7]);
    p[8]  = fmaf(av, d2.x, p[8]);  p[9]  = fmaf(av, d2.y, p[9]);
    p[10] = fmaf(av, d2.z, p[10]); p[11] = fmaf(av, d2.w, p[11]);
    p[12] = fmaf(av, d3.x, p[12]); p[13] = fmaf(av, d3.y, p[13]);
    p[14] = fmaf(av, d3.z, p[14]); p[15] = fmaf(av, d3.w, p[15]);
  }
#pragma unroll
  for (int o = 16; o; o >>= 1)
#pragma unroll
    for (int i = 0; i < 16; i++) p[i] += __shfl_xor_sync(0xffffffffu, p[i], o);
  if (lane == 0)
#pragma unroll
    for (int i = 0; i < 16; i++) red[wid * 16 + i] = p[i];
  __syncthreads();
  if (tid < 16) {
    float s = 0.f;
#pragma unroll
    for (int w = 0; w < 8; w++) s += red[w * 16 + tid];
    st[tid] = s;
  }
  __syncthreads();
  float t0[16];
#pragma unroll
  for (int i = 0; i < 16; i++) t0[i] = st[i];
  float* crow = C + (size_t)r * D_;
  for (int c = tid; c < D_; c += 256) {
    float s = 0.f;
#pragma unroll
    for (int i = 0; i < 16; i++) s = fmaf(t0[i], up[(size_t)i * D_ + c], s);
    crow[c] += s;
  }
}

// ---------------- fp16 flash attention + fused IP; Q/K pre-packed f16 in global ----------------
__global__ void __launch_bounds__(256) attn_mma_kernel(
    const uint32_t* __restrict__ QH, const uint32_t* __restrict__ KH,
    const float* __restrict__ V, const uint32_t* __restrict__ KIPH,
    const float* __restrict__ VIP, uint32_t* __restrict__ outE,
    uint32_t* __restrict__ outM) {
  extern __shared__ uint32_t smA[];
  uint32_t* Ks = smA;
  uint32_t* Vs = smA + 4096;
  const int tid = threadIdx.x, lane = tid & 31, w = tid >> 5;
  const int gid = lane >> 2, tig = lane & 3;
  const int h = blockIdx.y, q0 = blockIdx.x * 128;

  // Q fragments: direct u32 loads (scale already folded at pack time)
  uint32_t qf[8][4];
  {
    const uint32_t* qp = QH + ((size_t)h * SL_ + q0 + w * 16 + gid) * 64;
    const uint32_t* qp1 = qp + 8 * 64;
#pragma unroll
    for (int s = 0; s < 8; s++) {
      qf[s][0] = qp[s * 8 + tig];
      qf[s][1] = qp1[s * 8 + tig];
      qf[s][2] = qp[s * 8 + tig + 4];
      qf[s][3] = qp1[s * 8 + tig + 4];
    }
  }

  float o[16][4];
#pragma unroll
  for (int i = 0; i < 16; i++) { o[i][0] = o[i][1] = o[i][2] = o[i][3] = 0.f; }
  float m0 = -1e30f, m1 = -1e30f, l0 = 0.f, l1 = 0.f;

  const int cgv = 2 * (lane & 15) + (lane >> 4);     // V rotated col group
  const int ksl = lane >> 2, tgl = lane & 3;
  const int kofs = 8 * ksl + tgl;                    // K packed k2 column

  const int kt0 = (q0 >= SB_) ? (SB_ / 64) : 0;
  for (int kt = kt0; kt < SL_ / 64; kt++) {
    __syncthreads();
    const uint32_t* Kt = KH + ((size_t)h * SL_ + kt * 64) * 64;
    const float* Vt = V + ((size_t)h * SL_ + kt * 64) * DH_;
    uint32_t ku0[8], ku1[8];
    float4 vf0[4], vf1[4];
#pragma unroll
    for (int it = 0; it < 8; it++) {
      int r = w + it * 8;
      ku0[it] = Kt[r * 64 + kofs];
      ku1[it] = Kt[r * 64 + kofs + 4];
    }
#pragma unroll
    for (int it = 0; it < 4; it++) {
      int m = w + it * 8;
      vf0[it] = *(const float4*)(Vt + (2 * m) * DH_ + cgv * 4);
      vf1[it] = *(const float4*)(Vt + (2 * m + 1) * DH_ + cgv * 4);
    }
    // stage K (raw u32 copies, no cvts)
#pragma unroll
    for (int it = 0; it < 8; it++) {
      int r = w + it * 8;
      int nt = r >> 3, gk = r & 7;
      uint32_t* dst = Ks + ((nt * 8 + ksl) * 32 + ((gk * 4 + tgl) ^ (ksl << 2))) * 2;
      dst[0] = ku0[it];
      dst[1] = ku1[it];
    }
    __syncthreads();

    float sa[8][4];
#pragma unroll
    for (int nt = 0; nt < 8; nt++) { sa[nt][0] = sa[nt][1] = sa[nt][2] = sa[nt][3] = 0.f; }
#pragma unroll
    for (int ks = 0; ks < 8; ks++) {
#pragma unroll
      for (int nt = 0; nt < 8; nt++) {
        uint2 b2 = *(const uint2*)(Ks + ((nt * 8 + ks) * 32 + (lane ^ (ks << 2))) * 2);
        uint32_t bb[2] = {b2.x, b2.y};
        mma_f16(sa[nt], qf[ks], bb);
      }
    }

    float rm0 = -1e30f, rm1 = -1e30f;
#pragma unroll
    for (int nt = 0; nt < 8; nt++) {
      rm0 = fmaxf(rm0, fmaxf(sa[nt][0], sa[nt][1]));
      rm1 = fmaxf(rm1, fmaxf(sa[nt][2], sa[nt][3]));
    }
#pragma unroll
    for (int off = 1; off < 4; off <<= 1) {
      rm0 = fmaxf(rm0, __shfl_xor_sync(0xffffffffu, rm0, off));
      rm1 = fmaxf(rm1, __shfl_xor_sync(0xffffffffu, rm1, off));
    }
    float mn0 = fmaxf(m0, rm0), mn1 = fmaxf(m1, rm1);
    float corr0 = __expf(m0 - mn0), corr1 = __expf(m1 - mn1);
    m0 = mn0; m1 = mn1;
    float rs0 = 0.f, rs1 = 0.f;
#pragma unroll
    for (int nt = 0; nt < 8; nt++) {
      sa[nt][0] = __expf(sa[nt][0] - mn0); rs0 += sa[nt][0];
      sa[nt][1] = __expf(sa[nt][1] - mn0); rs0 += sa[nt][1];
      sa[nt][2] = __expf(sa[nt][2] - mn1); rs1 += sa[nt][2];
      sa[nt][3] = __expf(sa[nt][3] - mn1); rs1 += sa[nt][3];
    }
#pragma unroll
    for (int off = 1; off < 4; off <<= 1) {
      rs0 += __shfl_xor_sync(0xffffffffu, rs0, off);
      rs1 += __shfl_xor_sync(0xffffffffu, rs1, off);
    }
    l0 = l0 * corr0 + rs0;
    l1 = l1 * corr1 + rs1;
#pragma unroll
    for (int i = 0; i < 16; i++) {
      o[i][0] *= corr0; o[i][1] *= corr0; o[i][2] *= corr1; o[i][3] *= corr1;
    }

#pragma unroll
    for (int it = 0; it < 4; it++) {
      int m = w + it * 8;
      int g = m >> 3, ov = m & 7, reg = ov >> 2, tvx = ov & 3;
      float v0e[4] = {vf0[it].x, vf0[it].y, vf0[it].z, vf0[it].w};
      float v1e[4] = {vf1[it].x, vf1[it].y, vf1[it].z, vf1[it].w};
#pragma unroll
      for (int e = 0; e < 4; e++) {
        int d = cgv * 4 + e;
        int ntd = d >> 3, gn = d & 7;
        Vs[((ntd * 4 + g) * 32 + ((gn * 4 + tvx) ^ ntd)) * 2 + reg] = pack_h2(v0e[e], v1e[e]);
      }
    }
    __syncthreads();

#pragma unroll
    for (int g = 0; g < 4; g++) {
      uint32_t pf[4];
      pf[0] = pack_h2(sa[2 * g][0], sa[2 * g][1]);
      pf[1] = pack_h2(sa[2 * g][2], sa[2 * g][3]);
      pf[2] = pack_h2(sa[2 * g + 1][0], sa[2 * g + 1][1]);
      pf[3] = pack_h2(sa[2 * g + 1][2], sa[2 * g + 1][3]);
#pragma unroll
      for (int ntd = 0; ntd < 16; ntd++) {
        uint2 b2 = *(const uint2*)(Vs + ((ntd * 4 + g) * 32 + (lane ^ ntd)) * 2);
        uint32_t bb[2] = {b2.x, b2.y};
        mma_f16(o[ntd], pf, bb);
      }
    }
  }

  float inv0 = 1.f / l0, inv1 = 1.f / l1;
#pragma unroll
  for (int i = 0; i < 16; i++) {
    o[i][0] *= inv0; o[i][1] *= inv0; o[i][2] *= inv1; o[i][3] *= inv1;
  }

  if (q0 >= ENC_) {
    __syncthreads();
    const uint32_t* Kt = KIPH + (size_t)h * NIP_ * 64;
    const float* Vt = VIP + (size_t)h * NIP_ * DH_;
    uint32_t ku0[8], ku1[8];
    float4 vf0[4], vf1[4];
#pragma unroll
    for (int it = 0; it < 8; it++) {
      int r = w + it * 8;
      ku0[it] = Kt[r * 64 + kofs];
      ku1[it] = Kt[r * 64 + kofs + 4];
    }
#pragma unroll
    for (int it = 0; it < 4; it++) {
      int m = w + it * 8;
      vf0[it] = *(const float4*)(Vt + (2 * m) * DH_ + cgv * 4);
      vf1[it] = *(const float4*)(Vt + (2 * m + 1) * DH_ + cgv * 4);
    }
#pragma unroll
    for (int it = 0; it < 8; it++) {
      int r = w + it * 8;
      int nt = r >> 3, gk = r & 7;
      uint32_t* dst = Ks + ((nt * 8 + ksl) * 32 + ((gk * 4 + tgl) ^ (ksl << 2))) * 2;
      dst[0] = ku0[it];
      dst[1] = ku1[it];
    }
    __syncthreads();

    float sa[8][4];
#pragma unroll
    for (int nt = 0; nt < 8; nt++) { sa[nt][0] = sa[nt][1] = sa[nt][2] = sa[nt][3] = 0.f; }
#pragma unroll
    for (int ks = 0; ks < 8; ks++) {
#pragma unroll
      for (int nt = 0; nt < 8; nt++) {
        uint2 b2 = *(const uint2*)(Ks + ((nt * 8 + ks) * 32 + (lane ^ (ks << 2))) * 2);
        uint32_t bb[2] = {b2.x, b2.y};
        mma_f16(sa[nt], qf[ks], bb);
      }
    }
    float rm0 = -1e30f, rm1 = -1e30f;
#pragma unroll
    for (int nt = 0; nt < 8; nt++) {
      rm0 = fmaxf(rm0, fmaxf(sa[nt][0], sa[nt][1]));
      rm1 = fmaxf(rm1, fmaxf(sa[nt][2], sa[nt][3]));
    }
#pragma unroll
    for (int off = 1; off < 4; off <<= 1) {
      rm0 = fmaxf(rm0, __shfl_xor_sync(0xffffffffu, rm0, off));
      rm1 = fmaxf(rm1, __shfl_xor_sync(0xffffffffu, rm1, off));
    }
    float rs0 = 0.f, rs1 = 0.f;
#pragma unroll
    for (int nt = 0; nt < 8; nt++) {
      sa[nt][0] = __expf(sa[nt][0] - rm0); rs0 += sa[nt][0];
      sa[nt][1] = __expf(sa[nt][1] - rm0); rs0 += sa[nt][1];
      sa[nt][2] = __expf(sa[nt][2] - rm1); rs1 += sa[nt][2];
      sa[nt][3] = __expf(sa[nt][3] - rm1); rs1 += sa[nt][3];
    }
#pragma unroll
    for (int off = 1; off < 4; off <<= 1) {
      rs0 += __shfl_xor_sync(0xffffffffu, rs0, off);
      rs1 += __shfl_xor_sync(0xffffffffu, rs1, off);
    }
    float iv0 = 1.f / rs0, iv1 = 1.f / rs1;
#pragma unroll
    for (int it = 0; it < 4; it++) {
      int m = w + it * 8;
      int g = m >> 3, ov = m & 7, reg = ov >> 2, tvx = ov & 3;
      float v0e[4] = {vf0[it].x, vf0[it].y, vf0[it].z, vf0[it].w};
      float v1e[4] = {vf1[it].x, vf1[it].y, vf1[it].z, vf1[it].w};
#pragma unroll
      for (int e = 0; e < 4; e++) {
        int d = cgv * 4 + e;
        int ntd = d >> 3, gn = d & 7;
        Vs[((ntd * 4 + g) * 32 + ((gn * 4 + tvx) ^ ntd)) * 2 + reg] = pack_h2(v0e[e], v1e[e]);
      }
    }
    __syncthreads();
#pragma unroll
    for (int g = 0; g < 4; g++) {
      uint32_t pf[4];
      pf[0] = pack_h2(sa[2 * g][0] * iv0, sa[2 * g][1] * iv0);
      pf[1] = pack_h2(sa[2 * g][2] * iv1, sa[2 * g][3] * iv1);
      pf[2] = pack_h2(sa[2 * g + 1][0] * iv0, sa[2 * g + 1][1] * iv0);
      pf[3] = pack_h2(sa[2 * g + 1][2] * iv1, sa[2 * g + 1][3] * iv1);
#pragma unroll
      for (int ntd = 0; ntd < 16; ntd++) {
        uint2 b2 = *(const uint2*)(Vs + ((ntd * 4 + g) * 32 + (lane ^ ntd)) * 2);
        uint32_t bb[2] = {b2.x, b2.y};
        mma_f16(o[ntd], pf, bb);
      }
    }
  }

  // ---- epilogue: pack f16x2, scatter with fragment-pair permutation ----
  int row0 = q0 + w * 16 + gid, row1 = row0 + 8;
#pragma unroll
  for (int ntd = 0; ntd < 16; ntd++) {
    int k2 = h * 64 + ntd * 4 + tig;
    int j = k2 & 7;
    int c2 = (k2 & ~7) | (2 * (j & 3) + (j >> 2));
    uint32_t p0 = pack_h2(o[ntd][0], o[ntd][1]);
    uint32_t p1 = pack_h2(o[ntd][2], o[ntd][3]);
    if (row0 < ENC_) {
      outE[(size_t)row0 * K2_ + c2] = p0;
      outE[(size_t)row1 * K2_ + c2] = p1;
    } else {
      outM[(size_t)(row0 - ENC_) * K2_ + c2] = p0;
      outM[(size_t)(row1 - ENC_) * K2_ + c2] = p1;
    }
  }
}

// ---------------- launch ----------------
extern "C" void kernel_launch(void* const* d_in, const int* in_sizes, int n_in,
                              void* d_out, int out_size) {
  const float* hs   = (const float*)d_in[0];
  const float* ehs  = (const float*)d_in[1];
  const float* img  = (const float*)d_in[2];
  const float* Wq   = (const float*)d_in[3];  const float* bq  = (const float*)d_in[4];
  const float* Wk   = (const float*)d_in[5];  const float* bk  = (const float*)d_in[6];
  const float* Wv   = (const float*)d_in[7];  const float* bv  = (const float*)d_in[8];
  const float* Waq  = (const float*)d_in[9];  const float* baq = (const float*)d_in[10];
  const float* Wak  = (const float*)d_in[11]; const float* bak = (const float*)d_in[12];
  const float* Wav  = (const float*)d_in[13]; const float* bav = (const float*)d_in[14];
  const float* Wo   = (const float*)d_in[15]; const float* bo  = (const float*)d_in[16];
  const float* Wao  = (const float*)d_in[17]; const float* bao = (const float*)d_in[18];
  const float* Wkip = (const float*)d_in[19]; const float* Wvip = (const float*)d_in[20];
  const float* lq_dn = (const float*)d_in[21]; const float* lq_up = (const float*)d_in[22];
  const float* lk_dn = (const float*)d_in[23]; const float* lk_up = (const float*)d_in[24];
  const float* lv_dn = (const float*)d_in[25]; const float* lv_up = (const float*)d_in[26];
  const float* lp_dn = (const float*)d_in[27]; const float* lp_up = (const float*)d_in[28];
  float* out = (float*)d_out;

  float *V, *VIP, *T3;
  uint32_t *QH, *KH, *KIPH, *WB, *hsH, *ehsH, *imgH, *amH, *aeH;
  cudaGetSymbolAddress((void**)&QH, g_QH);
  cudaGetSymbolAddress((void**)&KH, g_KH);
  cudaGetSymbolAddress((void**)&V, g_V);
  cudaGetSymbolAddress((void**)&KIPH, g_KIPH);
  cudaGetSymbolAddress((void**)&VIP, g_VIP);
  cudaGetSymbolAddress((void**)&T3, g_T3);
  cudaGetSymbolAddress((void**)&WB, g_WB);
  cudaGetSymbolAddress((void**)&hsH, g_hsH);
  cudaGetSymbolAddress((void**)&ehsH, g_ehsH);
  cudaGetSymbolAddress((void**)&imgH, g_imgH);
  cudaGetSymbolAddress((void**)&amH, g_amH);
  cudaGetSymbolAddress((void**)&aeH, g_aeH);

  const int G_SMEM = 3 * STAGE3_ * 4;       // 61440 B
  const int ATTN_SMEM = (4096 + 4096) * 4;  // 32768 B
  cudaFuncSetAttribute(gemm_h, cudaFuncAttributeMaxDynamicSharedMemorySize, G_SMEM);
  cudaFuncSetAttribute(attn_mma_kernel, cudaFuncAttributeMaxDynamicSharedMemorySize, ATTN_SMEM);

  float* outMain = out + (size_t)ENC_ * D_;
  const float* hsC = hs + (size_t)(S_ - COND_) * D_;

  // 0. pack operands (fragment-pair layouts)
  W10 w10 = {{Wq, Wk, Wv, Waq, Wak, Wav, Wkip, Wvip, Wo, Wao}};
  cvtB_kernel<<<dim3(D_ / 32, K2_ / 32, 10), 256>>>(w10, WB);
  cvtA_kernel<<<S_ * K2_ / 256, 256>>>(hs, hsH, S_ * K2_);
  cvtA_kernel<<<ENC_ * K2_ / 256, 256>>>(ehs, ehsH, ENC_ * K2_);
  cvtA_kernel<<<NIP_ * K2_ / 256, 256>>>(img, imgH, NIP_ * K2_);

  // 1. lora-down temps
  D3 d3 = {{lq_dn, lk_dn, lv_dn}};
  lora_dn3<<<COND_ / 8, 256>>>(hsC, d3, T3);

  // 2. ALL projections in ONE launch (z=0..7); Q/K/KIP written packed f16
  size_t WS = (size_t)K2_ * D_;
  GF gall = {
    {hsH, hsH, hsH, ehsH, ehsH, ehsH, imgH, imgH},
    {WB, WB + WS, WB + 2 * WS, WB + 3 * WS, WB + 4 * WS, WB + 5 * WS, WB + 6 * WS, WB + 7 * WS},
    {bq, bk, bv, baq, bak, bav, 0, 0},
    {T3, T3 + COND_ * 16, T3 + 2 * COND_ * 16, 0, 0, 0, 0, 0},
    {lq_up, lk_up, lv_up, 0, 0, 0, 0, 0},
    {(float*)QH, (float*)KH, V, (float*)QH, (float*)KH, V, (float*)KIPH, VIP},
    {S_, S_, S_, ENC_, ENC_, ENC_, NIP_, NIP_},
    {SL_, SL_, SL_, SL_, SL_, SL_, NIP_, NIP_},
    {ENC_, ENC_, ENC_, 0, 0, 0, 0, 0},
    {1, 1, 0, 1, 1, 0, 1, 0},
    {2, 1, 0, 2, 1, 0, 1, 0}};
  gemm_h<<<dim3(24, 16, 8), 256, G_SMEM>>>(gall, D_, D_);

  // 3. joint attention + fused IP (reads packed Q/K; writes packed amH/aeH)
  attn_mma_kernel<<<dim3(SL_ / 128, H_), 256, ATTN_SMEM>>>(QH, KH, V, KIPH, VIP, aeH, amH);

  // 4. output projections
  GF gout = {
    {amH, aeH, 0, 0, 0, 0, 0, 0},
    {WB + 8 * WS, WB + 9 * WS, 0, 0, 0, 0, 0, 0},
    {bo, bao, 0, 0, 0, 0, 0, 0},
    {0, 0, 0, 0, 0, 0, 0, 0}, {0, 0, 0, 0, 0, 0, 0, 0},
    {outMain, out, 0, 0, 0, 0, 0, 0},
    {S_, ENC_, 1, 1, 1, 1, 1, 1},
    {0, 0, 0, 0, 0, 0, 0, 0},
    {0, 0, 0, 0, 0, 0, 0, 0},
    {0, 0, 0, 0, 0, 0, 0, 0},
    {0, 0, 0, 0, 0, 0, 0, 0}};
  gemm_h<<<dim3(24, 16, 2), 256, G_SMEM>>>(gout, D_, D_);

  // 5. output LoRA
  float* outCond = outMain + (size_t)(S_ - COND_) * D_;
  lora_kernel<<<COND_, 256>>>(outCond, lp_dn, lp_up, outCond);
}

// round 17
// speedup vs baseline: 8.8985x; 1.0199x over previous
#include <cuda_runtime.h>
#include <math.h>
#include <stdint.h>

// ---------------- problem constants ----------------
#define D_    3072
#define K2_   1536   // D/2 (packed f16x2 along k)
#define S_    2048
#define H_    24
#define DH_   128
#define ENC_  512
#define NIP_  64
#define COND_ 1024
#define SL_   2560
#define SB_   1536
#define RANK_ 16
#define EPS_  1e-5f
#define SCALE_ 0.08838834764831845f

// ---------------- scratch ----------------
__device__ uint32_t g_QH[H_ * SL_ * 64];    // Q packed f16x2 (scale folded), head-major
__device__ uint32_t g_KH[H_ * SL_ * 64];    // K packed f16x2, head-major
__device__ float    g_V[H_ * SL_ * DH_];    // V f32, head-major
__device__ uint32_t g_KIPH[H_ * NIP_ * 64];
__device__ float    g_VIP[H_ * NIP_ * DH_];
__device__ float    g_T3[3 * COND_ * RANK_];
// packed f16x2 operand buffers, fragment-pair group layout (p(j) = 2*(j&3)+(j>>2))
__device__ uint32_t g_WB[10 * K2_ * D_];
__device__ uint32_t g_hsH[S_ * K2_];
__device__ uint32_t g_ehsH[ENC_ * K2_];
__device__ uint32_t g_imgH[NIP_ * K2_];
__device__ uint32_t g_amH[S_ * K2_];
__device__ uint32_t g_aeH[ENC_ * K2_];

// ---------------- helpers ----------------
__device__ __forceinline__ uint32_t pack_h2(float lo, float hi) {
  uint32_t r;
  asm("cvt.rn.f16x2.f32 %0, %1, %2;" : "=r"(r) : "f"(hi), "f"(lo));
  return r;
}

__device__ __forceinline__ void mma_f16(float c[4], const uint32_t a[4], const uint32_t b[2]) {
  asm("mma.sync.aligned.m16n8k16.row.col.f32.f16.f16.f32 "
      "{%0,%1,%2,%3}, {%4,%5,%6,%7}, {%8,%9}, {%0,%1,%2,%3};"
      : "+f"(c[0]), "+f"(c[1]), "+f"(c[2]), "+f"(c[3])
      : "r"(a[0]), "r"(a[1]), "r"(a[2]), "r"(a[3]), "r"(b[0]), "r"(b[1]));
}

__device__ __forceinline__ void cp_async16(uint32_t smem_addr, const void* gptr, int src_bytes) {
  asm volatile("cp.async.cg.shared.global [%0], [%1], 16, %2;"
               :: "r"(smem_addr), "l"(gptr), "r"(src_bytes) : "memory");
}
#define CP_COMMIT() asm volatile("cp.async.commit_group;" ::: "memory")
#define CP_WAIT1()  asm volatile("cp.async.wait_group 1;" ::: "memory")
#define CP_WAIT0()  asm volatile("cp.async.wait_group 0;" ::: "memory")

// ---------------- conversion kernels ----------------
__global__ void cvtA_kernel(const float* __restrict__ A, uint32_t* __restrict__ AH, int n) {
  int i = blockIdx.x * 256 + threadIdx.x;
  if (i < n) {
    float2 v = *(const float2*)(A + 2 * (size_t)i);
    int j = i & 7;
    int o = (i & ~7) | (2 * (j & 3) + (j >> 2));
    AH[o] = pack_h2(v.x, v.y);
  }
}

struct W10 { const float* W[10]; };
__global__ void __launch_bounds__(256) cvtB_kernel(W10 g, uint32_t* __restrict__ WB) {
  __shared__ float sm[64 * 33];
  const int z = blockIdx.z;
  const float* W = g.W[z];
  uint32_t* dst = WB + (size_t)z * K2_ * D_;
  const int n0t = blockIdx.x * 32, k20 = blockIdx.y * 32;
  const int tid = threadIdx.x;
#pragma unroll
  for (int p = 0; p < 8; p++) {
    int i = tid + p * 256;
    int r = i >> 5, c = i & 31;
    sm[r * 33 + c] = W[(size_t)(k20 * 2 + r) * D_ + n0t + c];
  }
  __syncthreads();
#pragma unroll
  for (int p = 0; p < 4; p++) {
    int i = tid + p * 256;
    int gl = i >> 8, rem = i & 255, n = rem >> 3, jp = rem & 7;
    int j = (jp >> 1) + ((jp & 1) << 2);
    int k2l = gl * 8 + j;
    dst[((size_t)((k20 >> 3) + gl) * D_ + n0t + n) * 8 + jp] =
        pack_h2(sm[(2 * k2l) * 33 + n], sm[(2 * k2l + 1) * 33 + n]);
  }
}

// ---------------- lora-down (unchanged) ----------------
struct D3 { const float* dn[3]; };

__global__ void __launch_bounds__(256) lora_dn3(const float* __restrict__ A, D3 g,
                                                float* __restrict__ T) {
  const int tid = threadIdx.x, lane = tid & 31, w = tid >> 5;
  const int row = blockIdx.x * 8 + w;
  const float* a = A + (size_t)row * D_;
  float p[48];
#pragma unroll
  for (int i = 0; i < 48; i++) p[i] = 0.f;
  for (int k = lane; k < D_; k += 32) {
    float av = a[k];
#pragma unroll
    for (int t = 0; t < 3; t++) {
      const float* dk = g.dn[t] + k * 16;
      float4 d0 = *(const float4*)(dk);
      float4 d1 = *(const float4*)(dk + 4);
      float4 d2 = *(const float4*)(dk + 8);
      float4 d3 = *(const float4*)(dk + 12);
      float* pt = p + t * 16;
      pt[0]  = fmaf(av, d0.x, pt[0]);  pt[1]  = fmaf(av, d0.y, pt[1]);
      pt[2]  = fmaf(av, d0.z, pt[2]);  pt[3]  = fmaf(av, d0.w, pt[3]);
      pt[4]  = fmaf(av, d1.x, pt[4]);  pt[5]  = fmaf(av, d1.y, pt[5]);
      pt[6]  = fmaf(av, d1.z, pt[6]);  pt[7]  = fmaf(av, d1.w, pt[7]);
      pt[8]  = fmaf(av, d2.x, pt[8]);  pt[9]  = fmaf(av, d2.y, pt[9]);
      pt[10] = fmaf(av, d2.z, pt[10]); pt[11] = fmaf(av, d2.w, pt[11]);
      pt[12] = fmaf(av, d3.x, pt[12]); pt[13] = fmaf(av, d3.y, pt[13]);
      pt[14] = fmaf(av, d3.z, pt[14]); pt[15] = fmaf(av, d3.w, pt[15]);
    }
  }
#pragma unroll
  for (int off = 16; off; off >>= 1)
#pragma unroll
    for (int i = 0; i < 48; i++) p[i] += __shfl_xor_sync(0xffffffffu, p[i], off);
  if (lane == 0) {
#pragma unroll
    for (int t = 0; t < 3; t++) {
      float* dt = T + ((size_t)t * COND_ + row) * 16;
#pragma unroll
      for (int i = 0; i < 16; i += 4)
        *(float4*)(dt + i) = make_float4(p[t*16+i], p[t*16+i+1], p[t*16+i+2], p[t*16+i+3]);
    }
  }
}

// ---------------- fused fp16 GEMM (unchanged R15) ----------------
struct GF {
  const uint32_t* A[8]; const uint32_t* W[8]; const float* bias[8];
  const float* T[8]; const float* up[8];
  float* dst[8];
  int M[8]; int seq[8]; int rowOff[8]; int rms[8]; int pk[8];
};

#define AW3_ 24
#define AWORDS3_ (128 * AW3_)            // 3072
#define STAGE3_ (AWORDS3_ + 2048)        // 5120 u32 = 20480 B

__global__ void __launch_bounds__(256, 2) gemm_h(GF gf, int N, int K) {
  extern __shared__ uint32_t smu[];
  const uint32_t sbase = (uint32_t)__cvta_generic_to_shared(smu);

  const int z = blockIdx.z;
  const uint32_t* __restrict__ A = gf.A[z];
  const uint32_t* __restrict__ W = gf.W[z];
  const float* __restrict__ bias = gf.bias[z];
  const int M = gf.M[z];
  const int K2 = K / 2;

  const int tid = threadIdx.x;
  const int lane = tid & 31;
  const int wid = tid >> 5;
  const int warpM = wid >> 2;
  const int warpN = wid & 3;
  const int m0 = blockIdx.y * 128;
  const int n0 = blockIdx.x * 128;
  if (m0 >= M) return;

  const int NKT = K / 32;

  auto issue = [&](int kt) {
    if (kt < NKT) {
      int k20 = kt * 16;
      uint32_t st = sbase + (uint32_t)((kt % 3) * STAGE3_) * 4u;
#pragma unroll
      for (int p = 0; p < 2; p++) {
        int ch = tid + p * 256;
        int r = ch >> 2, c4 = (ch & 3) << 2;
        int gr = m0 + r;
        int sz = (gr < M) ? 16 : 0;
        if (gr >= M) gr = M - 1;
        cp_async16(st + (uint32_t)(r * AW3_ + c4) * 4u,
                   A + (size_t)gr * K2 + k20 + c4, sz);
      }
      uint32_t stb = st + (uint32_t)AWORDS3_ * 4u;
#pragma unroll
      for (int p = 0; p < 2; p++) {
        int ch = tid + p * 256;
        int gl = ch >> 8, rem = ch & 255, n = rem >> 1, half = rem & 1;
        cp_async16(stb + (uint32_t)(gl * 1024 + n * 8 + half * 4) * 4u,
                   W + ((size_t)((k20 >> 3) + gl) * N + n0 + n) * 8 + half * 4, 16);
      }
    }
    CP_COMMIT();
  };

  float acc[4][4][4];
#pragma unroll
  for (int mt = 0; mt < 4; mt++)
#pragma unroll
    for (int nt = 0; nt < 4; nt++)
#pragma unroll
      for (int i = 0; i < 4; i++) acc[mt][nt][i] = 0.f;

  issue(0);
  issue(1);

  const int gid = lane >> 2, tig = lane & 3;

  for (int kt = 0; kt < NKT; kt++) {
    CP_WAIT1();
    __syncthreads();
    const uint32_t* sa = smu + (kt % 3) * STAGE3_;
    const uint32_t* sb = sa + AWORDS3_;
    const uint32_t* arow = sa + (warpM * 64 + gid) * AW3_ + 2 * tig;
    const uint32_t* bcol = sb + (warpN * 32 + gid) * 8 + 2 * tig;
#pragma unroll
    for (int ks2 = 0; ks2 < 2; ks2++) {
      uint32_t a[4][4];
      uint32_t b[4][2];
#pragma unroll
      for (int mt = 0; mt < 4; mt++) {
        const uint32_t* r0 = arow + mt * 16 * AW3_ + ks2 * 8;
        uint2 la = *(const uint2*)r0;
        uint2 lb = *(const uint2*)(r0 + 8 * AW3_);
        a[mt][0] = la.x; a[mt][1] = lb.x; a[mt][2] = la.y; a[mt][3] = lb.y;
      }
#pragma unroll
      for (int nt = 0; nt < 4; nt++) {
        uint2 bb = *(const uint2*)(bcol + ks2 * 1024 + nt * 64);
        b[nt][0] = bb.x; b[nt][1] = bb.y;
      }
#pragma unroll
      for (int mt = 0; mt < 4; mt++)
#pragma unroll
        for (int nt = 0; nt < 4; nt++) mma_f16(acc[mt][nt], a[mt], b[nt]);
    }
    issue(kt + 2);
  }
  CP_WAIT0();
  __syncthreads();

  // ---- fused epilogue ----
  const float* Tz = gf.T[z];
  const float* upz = gf.up[z];
  float* dst = gf.dst[z];
  const int seq = gf.seq[z], rowOff = gf.rowOff[z], doRMS = gf.rms[z], pk = gf.pk[z];

  float bb0[4], bb1[4];
#pragma unroll
  for (int nt = 0; nt < 4; nt++) {
    int col = n0 + warpN * 32 + nt * 8 + tig * 2;
    bb0[nt] = bias ? bias[col] : 0.f;
    bb1[nt] = bias ? bias[col + 1] : 0.f;
  }
#pragma unroll
  for (int mt = 0; mt < 4; mt++) {
    int gr0 = m0 + warpM * 64 + mt * 16 + gid;
#pragma unroll
    for (int nt = 0; nt < 4; nt++) {
      acc[mt][nt][0] += bb0[nt]; acc[mt][nt][1] += bb1[nt];
      acc[mt][nt][2] += bb0[nt]; acc[mt][nt][3] += bb1[nt];
    }
    if (upz) {
      int l0 = gr0 - (M - COND_);
      int l1 = l0 + 8;
      if (l1 >= 0) {
        bool h0 = (l0 >= 0);
#pragma unroll
        for (int i0 = 0; i0 < 16; i0 += 4) {
          float4 t1q = *(const float4*)(Tz + (size_t)l1 * 16 + i0);
          float4 t0q = h0 ? *(const float4*)(Tz + (size_t)l0 * 16 + i0)
                          : make_float4(0.f, 0.f, 0.f, 0.f);
          float tv0[4] = {t0q.x, t0q.y, t0q.z, t0q.w};
          float tv1[4] = {t1q.x, t1q.y, t1q.z, t1q.w};
#pragma unroll
          for (int j = 0; j < 4; j++) {
#pragma unroll
            for (int nt = 0; nt < 4; nt++) {
              int col = n0 + warpN * 32 + nt * 8 + tig * 2;
              float2 u = *(const float2*)(upz + (size_t)(i0 + j) * N + col);
              acc[mt][nt][0] = fmaf(tv0[j], u.x, acc[mt][nt][0]);
              acc[mt][nt][1] = fmaf(tv0[j], u.y, acc[mt][nt][1]);
              acc[mt][nt][2] = fmaf(tv1[j], u.x, acc[mt][nt][2]);
              acc[mt][nt][3] = fmaf(tv1[j], u.y, acc[mt][nt][3]);
            }
          }
        }
      }
    }
  }

  if (doRMS) {
    float* ssm = (float*)smu;
#pragma unroll
    for (int mt = 0; mt < 4; mt++) {
      int lr = warpM * 64 + mt * 16 + gid;
      float ss0 = 0.f, ss1 = 0.f;
#pragma unroll
      for (int nt = 0; nt < 4; nt++) {
        ss0 = fmaf(acc[mt][nt][0], acc[mt][nt][0], ss0);
        ss0 = fmaf(acc[mt][nt][1], acc[mt][nt][1], ss0);
        ss1 = fmaf(acc[mt][nt][2], acc[mt][nt][2], ss1);
        ss1 = fmaf(acc[mt][nt][3], acc[mt][nt][3], ss1);
      }
      ss0 += __shfl_xor_sync(0xffffffffu, ss0, 1);
      ss0 += __shfl_xor_sync(0xffffffffu, ss0, 2);
      ss1 += __shfl_xor_sync(0xffffffffu, ss1, 1);
      ss1 += __shfl_xor_sync(0xffffffffu, ss1, 2);
      if (tig == 0) {
        ssm[lr * 4 + warpN] = ss0;
        ssm[(lr + 8) * 4 + warpN] = ss1;
      }
    }
    __syncthreads();
#pragma unroll
    for (int mt = 0; mt < 4; mt++) {
      int lr = warpM * 64 + mt * 16 + gid;
      float4 s0 = *(const float4*)&ssm[lr * 4];
      float4 s1 = *(const float4*)&ssm[(lr + 8) * 4];
      float sc0 = rsqrtf((s0.x + s0.y + s0.z + s0.w) * (1.f / 128.f) + EPS_);
      float sc1 = rsqrtf((s1.x + s1.y + s1.z + s1.w) * (1.f / 128.f) + EPS_);
#pragma unroll
      for (int nt = 0; nt < 4; nt++) {
        acc[mt][nt][0] *= sc0; acc[mt][nt][1] *= sc0;
        acc[mt][nt][2] *= sc1; acc[mt][nt][3] *= sc1;
      }
    }
  }

  const int head = n0 >> 7;
  const float fs = (pk == 2) ? SCALE_ : 1.f;
#pragma unroll
  for (int mt = 0; mt < 4; mt++) {
    int gr0 = m0 + warpM * 64 + mt * 16 + gid;
    int gr1 = gr0 + 8;
#pragma unroll
    for (int nt = 0; nt < 4; nt++) {
      int colh = warpN * 32 + nt * 8 + tig * 2;
      if (seq) {
        if (pk) {
          uint32_t* d2 = (uint32_t*)dst;
          size_t base = (size_t)head * seq + rowOff;
          int c2 = warpN * 16 + nt * 4 + tig;
          if (gr0 < M)
            d2[(base + gr0) * 64 + c2] = pack_h2(acc[mt][nt][0] * fs, acc[mt][nt][1] * fs);
          if (gr1 < M)
            d2[(base + gr1) * 64 + c2] = pack_h2(acc[mt][nt][2] * fs, acc[mt][nt][3] * fs);
        } else {
          float* bp = dst + ((size_t)head * seq + rowOff) * 128 + colh;
          if (gr0 < M) *(float2*)(bp + (size_t)gr0 * 128) =
              make_float2(acc[mt][nt][0], acc[mt][nt][1]);
          if (gr1 < M) *(float2*)(bp + (size_t)gr1 * 128) =
              make_float2(acc[mt][nt][2], acc[mt][nt][3]);
        }
      } else {
        if (gr0 < M) *(float2*)(dst + (size_t)gr0 * N + n0 + colh) =
            make_float2(acc[mt][nt][0], acc[mt][nt][1]);
        if (gr1 < M) *(float2*)(dst + (size_t)gr1 * N + n0 + colh) =
            make_float2(acc[mt][nt][2], acc[mt][nt][3]);
      }
    }
  }
}

// ---------------- single LoRA for the output projection (unchanged) ----------------
__global__ void __launch_bounds__(256) lora_kernel(
    const float* __restrict__ A, const float* __restrict__ dn,
    const float* __restrict__ up, float* __restrict__ C) {
  __shared__ float red[8 * 16];
  __shared__ float st[16];
  const int r = blockIdx.x, tid = threadIdx.x, lane = tid & 31, wid = tid >> 5;
  const float* a = A + (size_t)r * D_;
  float p[16];
#pragma unroll
  for (int i = 0; i < 16; i++) p[i] = 0.f;
  for (int k = tid; k < D_; k += 256) {
    float av = a[k];
    float4 d0 = *(const float4*)(dn + k * 16);
    float4 d1 = *(const float4*)(dn + k * 16 + 4);
    float4 d2 = *(const float4*)(dn + k * 16 + 8);
    float4 d3 = *(const float4*)(dn + k * 16 + 12);
    p[0]  = fmaf(av, d0.x, p[0]);  p[1]  = fmaf(av, d0.y, p[1]);
    p[2]  = fmaf(av, d0.z, p[2]);  p[3]  = fmaf(av, d0.w, p[3]);
    p[4]  = fmaf(av, d1.x, p[4]);  p[5]  = fmaf(av, d1.y, p[5]);
    p[6]  = fmaf(av, d1.z, p[6]);  p[7]  = fmaf(av, d1.w, p[7]);
    p[8]  = fmaf(av, d2.x, p[8]);  p[9]  = fmaf(av, d2.y, p[9]);
    p[10] = fmaf(av, d2.z, p[10]); p[11] = fmaf(av, d2.w, p[11]);
    p[12] = fmaf(av, d3.x, p[12]); p[13] = fmaf(av, d3.y, p[13]);
    p[14] = fmaf(av, d3.z, p[14]); p[15] = fmaf(av, d3.w, p[15]);
  }
#pragma unroll
  for (int o = 16; o; o >>= 1)
#pragma unroll
    for (int i = 0; i < 16; i++) p[i] += __shfl_xor_sync(0xffffffffu, p[i], o);
  if (lane == 0)
#pragma unroll
    for (int i = 0; i < 16; i++) red[wid * 16 + i] = p[i];
  __syncthreads();
  if (tid < 16) {
    float s = 0.f;
#pragma unroll
    for (int w = 0; w < 8; w++) s += red[w * 16 + tid];
    st[tid] = s;
  }
  __syncthreads();
  float t0[16];
#pragma unroll
  for (int i = 0; i < 16; i++) t0[i] = st[i];
  float* crow = C + (size_t)r * D_;
  for (int c = tid; c < D_; c += 256) {
    float s = 0.f;
#pragma unroll
    for (int i = 0; i < 16; i++) s = fmaf(t0[i], up[(size_t)i * D_ + c], s);
    crow[c] += s;
  }
}

// ---------------- fp16 flash attention + fused IP ----------------
// Double-buffered Ks/Vs (2 syncs/tile instead of 3) + register prefetch of the
// next tile's K and V (LDGs issued under the previous tile's MMAs). Numerics
// identical to R15 (pure scheduling change).
__global__ void __launch_bounds__(256) attn_mma_kernel(
    const uint32_t* __restrict__ QH, const uint32_t* __restrict__ KH,
    const float* __restrict__ V, const uint32_t* __restrict__ KIPH,
    const float* __restrict__ VIP, uint32_t* __restrict__ outE,
    uint32_t* __restrict__ outM) {
  extern __shared__ uint32_t smA[];   // Ks[2]: 0..8191, Vs[2]: 8192..16383
  const int tid = threadIdx.x, lane = tid & 31, w = tid >> 5;
  const int gid = lane >> 2, tig = lane & 3;
  const int h = blockIdx.y, q0 = blockIdx.x * 128;

  uint32_t qf[8][4];
  {
    const uint32_t* qp = QH + ((size_t)h * SL_ + q0 + w * 16 + gid) * 64;
    const uint32_t* qp1 = qp + 8 * 64;
#pragma unroll
    for (int s = 0; s < 8; s++) {
      qf[s][0] = qp[s * 8 + tig];
      qf[s][1] = qp1[s * 8 + tig];
      qf[s][2] = qp[s * 8 + tig + 4];
      qf[s][3] = qp1[s * 8 + tig + 4];
    }
  }

  float o[16][4];
#pragma unroll
  for (int i = 0; i < 16; i++) { o[i][0] = o[i][1] = o[i][2] = o[i][3] = 0.f; }
  float m0 = -1e30f, m1 = -1e30f, l0 = 0.f, l1 = 0.f;

  const int cgv = 2 * (lane & 15) + (lane >> 4);
  const int ksl = lane >> 2, tgl = lane & 3;
  const int kofs = 8 * ksl + tgl;

  const int NT = SL_ / 64;
  const int kt0 = (q0 >= SB_) ? (SB_ / 64) : 0;

  uint32_t ku0[8], ku1[8];
  float4 vf0[4], vf1[4];
  {  // prologue: load tile kt0 into registers
    const uint32_t* Kt = KH + ((size_t)h * SL_ + kt0 * 64) * 64;
    const float* Vt = V + ((size_t)h * SL_ + kt0 * 64) * DH_;
#pragma unroll
    for (int it = 0; it < 8; it++) {
      int r = w + it * 8;
      ku0[it] = Kt[r * 64 + kofs];
      ku1[it] = Kt[r * 64 + kofs + 4];
    }
#pragma unroll
    for (int it = 0; it < 4; it++) {
      int m = w + it * 8;
      vf0[it] = *(const float4*)(Vt + (2 * m) * DH_ + cgv * 4);
      vf1[it] = *(const float4*)(Vt + (2 * m + 1) * DH_ + cgv * 4);
    }
  }

  for (int kt = kt0; kt < NT; kt++) {
    const int b = kt & 1;
    uint32_t* Ks = smA + b * 4096;
    uint32_t* Vs = smA + 8192 + b * 4096;
    // stage K (safe: last reads of this buffer finished before sync#2 of kt-1)
#pragma unroll
    for (int it = 0; it < 8; it++) {
      int r = w + it * 8;
      int nt = r >> 3, gk = r & 7;
      uint32_t* dst = Ks + ((nt * 8 + ksl) * 32 + ((gk * 4 + tgl) ^ (ksl << 2))) * 2;
      dst[0] = ku0[it];
      dst[1] = ku1[it];
    }
    // prefetch next K (hidden under S-mma + softmax + PV)
    if (kt + 1 < NT) {
      const uint32_t* Kt = KH + ((size_t)h * SL_ + (kt + 1) * 64) * 64;
#pragma unroll
      for (int it = 0; it < 8; it++) {
        int r = w + it * 8;
        ku0[it] = Kt[r * 64 + kofs];
        ku1[it] = Kt[r * 64 + kofs + 4];
      }
    }
    __syncthreads();  // sync#1: K staged

    float sa[8][4];
#pragma unroll
    for (int nt = 0; nt < 8; nt++) { sa[nt][0] = sa[nt][1] = sa[nt][2] = sa[nt][3] = 0.f; }
#pragma unroll
    for (int ks = 0; ks < 8; ks++) {
#pragma unroll
      for (int nt = 0; nt < 8; nt++) {
        uint2 b2 = *(const uint2*)(Ks + ((nt * 8 + ks) * 32 + (lane ^ (ks << 2))) * 2);
        uint32_t bb[2] = {b2.x, b2.y};
        mma_f16(sa[nt], qf[ks], bb);
      }
    }

    float rm0 = -1e30f, rm1 = -1e30f;
#pragma unroll
    for (int nt = 0; nt < 8; nt++) {
      rm0 = fmaxf(rm0, fmaxf(sa[nt][0], sa[nt][1]));
      rm1 = fmaxf(rm1, fmaxf(sa[nt][2], sa[nt][3]));
    }
#pragma unroll
    for (int off = 1; off < 4; off <<= 1) {
      rm0 = fmaxf(rm0, __shfl_xor_sync(0xffffffffu, rm0, off));
      rm1 = fmaxf(rm1, __shfl_xor_sync(0xffffffffu, rm1, off));
    }
    float mn0 = fmaxf(m0, rm0), mn1 = fmaxf(m1, rm1);
    float corr0 = __expf(m0 - mn0), corr1 = __expf(m1 - mn1);
    m0 = mn0; m1 = mn1;
    float rs0 = 0.f, rs1 = 0.f;
#pragma unroll
    for (int nt = 0; nt < 8; nt++) {
      sa[nt][0] = __expf(sa[nt][0] - mn0); rs0 += sa[nt][0];
      sa[nt][1] = __expf(sa[nt][1] - mn0); rs0 += sa[nt][1];
      sa[nt][2] = __expf(sa[nt][2] - mn1); rs1 += sa[nt][2];
      sa[nt][3] = __expf(sa[nt][3] - mn1); rs1 += sa[nt][3];
    }
#pragma unroll
    for (int off = 1; off < 4; off <<= 1) {
      rs0 += __shfl_xor_sync(0xffffffffu, rs0, off);
      rs1 += __shfl_xor_sync(0xffffffffu, rs1, off);
    }
    l0 = l0 * corr0 + rs0;
    l1 = l1 * corr1 + rs1;
#pragma unroll
    for (int i = 0; i < 16; i++) {
      o[i][0] *= corr0; o[i][1] *= corr0; o[i][2] *= corr1; o[i][3] *= corr1;
    }

    // stage V (safe: last PV reads of this buffer finished before sync#1 of kt)
#pragma unroll
    for (int it = 0; it < 4; it++) {
      int m = w + it * 8;
      int g = m >> 3, ov = m & 7, reg = ov >> 2, tvx = ov & 3;
      float v0e[4] = {vf0[it].x, vf0[it].y, vf0[it].z, vf0[it].w};
      float v1e[4] = {vf1[it].x, vf1[it].y, vf1[it].z, vf1[it].w};
#pragma unroll
      for (int e = 0; e < 4; e++) {
        int d = cgv * 4 + e;
        int ntd = d >> 3, gn = d & 7;
        Vs[((ntd * 4 + g) * 32 + ((gn * 4 + tvx) ^ ntd)) * 2 + reg] = pack_h2(v0e[e], v1e[e]);
      }
    }
    // prefetch next V
    if (kt + 1 < NT) {
      const float* Vt = V + ((size_t)h * SL_ + (kt + 1) * 64) * DH_;
#pragma unroll
      for (int it = 0; it < 4; it++) {
        int m = w + it * 8;
        vf0[it] = *(const float4*)(Vt + (2 * m) * DH_ + cgv * 4);
        vf1[it] = *(const float4*)(Vt + (2 * m + 1) * DH_ + cgv * 4);
      }
    }
    __syncthreads();  // sync#2: V staged

#pragma unroll
    for (int g = 0; g < 4; g++) {
      uint32_t pf[4];
      pf[0] = pack_h2(sa[2 * g][0], sa[2 * g][1]);
      pf[1] = pack_h2(sa[2 * g][2], sa[2 * g][3]);
      pf[2] = pack_h2(sa[2 * g + 1][0], sa[2 * g + 1][1]);
      pf[3] = pack_h2(sa[2 * g + 1][2], sa[2 * g + 1][3]);
#pragma unroll
      for (int ntd = 0; ntd < 16; ntd++) {
        uint2 b2 = *(const uint2*)(Vs + ((ntd * 4 + g) * 32 + (lane ^ ntd)) * 2);
        uint32_t bb[2] = {b2.x, b2.y};
        mma_f16(o[ntd], pf, bb);
      }
    }
  }

  float inv0 = 1.f / l0, inv1 = 1.f / l1;
#pragma unroll
  for (int i = 0; i < 16; i++) {
    o[i][0] *= inv0; o[i][1] *= inv0; o[i][2] *= inv1; o[i][3] *= inv1;
  }

  if (q0 >= ENC_) {
    __syncthreads();  // all warps out of main loop before reusing buffer 0
    uint32_t* Ks = smA;
    uint32_t* Vs = smA + 8192;
    const uint32_t* Kt = KIPH + (size_t)h * NIP_ * 64;
    const float* Vt = VIP + (size_t)h * NIP_ * DH_;
#pragma unroll
    for (int it = 0; it < 8; it++) {
      int r = w + it * 8;
      ku0[it] = Kt[r * 64 + kofs];
      ku1[it] = Kt[r * 64 + kofs + 4];
    }
#pragma unroll
    for (int it = 0; it < 4; it++) {
      int m = w + it * 8;
      vf0[it] = *(const float4*)(Vt + (2 * m) * DH_ + cgv * 4);
      vf1[it] = *(const float4*)(Vt + (2 * m + 1) * DH_ + cgv * 4);
    }
#pragma unroll
    for (int it = 0; it < 8; it++) {
      int r = w + it * 8;
      int nt = r >> 3, gk = r & 7;
      uint32_t* dst = Ks + ((nt * 8 + ksl) * 32 + ((gk * 4 + tgl) ^ (ksl << 2))) * 2;
      dst[0] = ku0[it];
      dst[1] = ku1[it];
    }
    __syncthreads();

    float sa[8][4];
#pragma unroll
    for (int nt = 0; nt < 8; nt++) { sa[nt][0] = sa[nt][1] = sa[nt][2] = sa[nt][3] = 0.f; }
#pragma unroll
    for (int ks = 0; ks < 8; ks++) {
#pragma unroll
      for (int nt = 0; nt < 8; nt++) {
        uint2 b2 = *(const uint2*)(Ks + ((nt * 8 + ks) * 32 + (lane ^ (ks << 2))) * 2);
        uint32_t bb[2] = {b2.x, b2.y};
        mma_f16(sa[nt], qf[ks], bb);
      }
    }
    float rm0 = -1e30f, rm1 = -1e30f;
#pragma unroll
    for (int nt = 0; nt < 8; nt++) {
      rm0 = fmaxf(rm0, fmaxf(sa[nt][0], sa[nt][1]));
      rm1 = fmaxf(rm1, fmaxf(sa[nt][2], sa[nt][3]));
    }
#pragma unroll
    for (int off = 1; off < 4; off <<= 1) {
      rm0 = fmaxf(rm0, __shfl_xor_sync(0xffffffffu, rm0, off));
      rm1 = fmaxf(rm1, __shfl_xor_sync(0xffffffffu, rm1, off));
    }
    float rs0 = 0.f, rs1 = 0.f;
#pragma unroll
    for (int nt = 0; nt < 8; nt++) {
      sa[nt][0] = __expf(sa[nt][0] - rm0); rs0 += sa[nt][0];
      sa[nt][1] = __expf(sa[nt][1] - rm0); rs0 += sa[nt][1];
      sa[nt][2] = __expf(sa[nt][2] - rm1); rs1 += sa[nt][2];
      sa[nt][3] = __expf(sa[nt][3] - rm1); rs1 += sa[nt][3];
    }
#pragma unroll
    for (int off = 1; off < 4; off <<= 1) {
      rs0 += __shfl_xor_sync(0xffffffffu, rs0, off);
      rs1 += __shfl_xor_sync(0xffffffffu, rs1, off);
    }
    float iv0 = 1.f / rs0, iv1 = 1.f / rs1;
#pragma unroll
    for (int it = 0; it < 4; it++) {
      int m = w + it * 8;
      int g = m >> 3, ov = m & 7, reg = ov >> 2, tvx = ov & 3;
      float v0e[4] = {vf0[it].x, vf0[it].y, vf0[it].z, vf0[it].w};
      float v1e[4] = {vf1[it].x, vf1[it].y, vf1[it].z, vf1[it].w};
#pragma unroll
      for (int e = 0; e < 4; e++) {
        int d = cgv * 4 + e;
        int ntd = d >> 3, gn = d & 7;
        Vs[((ntd * 4 + g) * 32 + ((gn * 4 + tvx) ^ ntd)) * 2 + reg] = pack_h2(v0e[e], v1e[e]);
      }
    }
    __syncthreads();
#pragma unroll
    for (int g = 0; g < 4; g++) {
      uint32_t pf[4];
      pf[0] = pack_h2(sa[2 * g][0] * iv0, sa[2 * g][1] * iv0);
      pf[1] = pack_h2(sa[2 * g][2] * iv1, sa[2 * g][3] * iv1);
      pf[2] = pack_h2(sa[2 * g + 1][0] * iv0, sa[2 * g + 1][1] * iv0);
      pf[3] = pack_h2(sa[2 * g + 1][2] * iv1, sa[2 * g + 1][3] * iv1);
#pragma unroll
      for (int ntd = 0; ntd < 16; ntd++) {
        uint2 b2 = *(const uint2*)(Vs + ((ntd * 4 + g) * 32 + (lane ^ ntd)) * 2);
        uint32_t bb[2] = {b2.x, b2.y};
        mma_f16(o[ntd], pf, bb);
      }
    }
  }

  // ---- epilogue: pack f16x2, scatter with fragment-pair permutation ----
  int row0 = q0 + w * 16 + gid, row1 = row0 + 8;
#pragma unroll
  for (int ntd = 0; ntd < 16; ntd++) {
    int k2 = h * 64 + ntd * 4 + tig;
    int j = k2 & 7;
    int c2 = (k2 & ~7) | (2 * (j & 3) + (j >> 2));
    uint32_t p0 = pack_h2(o[ntd][0], o[ntd][1]);
    uint32_t p1 = pack_h2(o[ntd][2], o[ntd][3]);
    if (row0 < ENC_) {
      outE[(size_t)row0 * K2_ + c2] = p0;
      outE[(size_t)row1 * K2_ + c2] = p1;
    } else {
      outM[(size_t)(row0 - ENC_) * K2_ + c2] = p0;
      outM[(size_t)(row1 - ENC_) * K2_ + c2] = p1;
    }
  }
}

// ---------------- launch ----------------
extern "C" void kernel_launch(void* const* d_in, const int* in_sizes, int n_in,
                              void* d_out, int out_size) {
  const float* hs   = (const float*)d_in[0];
  const float* ehs  = (const float*)d_in[1];
  const float* img  = (const float*)d_in[2];
  const float* Wq   = (const float*)d_in[3];  const float* bq  = (const float*)d_in[4];
  const float* Wk   = (const float*)d_in[5];  const float* bk  = (const float*)d_in[6];
  const float* Wv   = (const float*)d_in[7];  const float* bv  = (const float*)d_in[8];
  const float* Waq  = (const float*)d_in[9];  const float* baq = (const float*)d_in[10];
  const float* Wak  = (const float*)d_in[11]; const float* bak = (const float*)d_in[12];
  const float* Wav  = (const float*)d_in[13]; const float* bav = (const float*)d_in[14];
  const float* Wo   = (const float*)d_in[15]; const float* bo  = (const float*)d_in[16];
  const float* Wao  = (const float*)d_in[17]; const float* bao = (const float*)d_in[18];
  const float* Wkip = (const float*)d_in[19]; const float* Wvip = (const float*)d_in[20];
  const float* lq_dn = (const float*)d_in[21]; const float* lq_up = (const float*)d_in[22];
  const float* lk_dn = (const float*)d_in[23]; const float* lk_up = (const float*)d_in[24];
  const float* lv_dn = (const float*)d_in[25]; const float* lv_up = (const float*)d_in[26];
  const float* lp_dn = (const float*)d_in[27]; const float* lp_up = (const float*)d_in[28];
  float* out = (float*)d_out;

  float *V, *VIP, *T3;
  uint32_t *QH, *KH, *KIPH, *WB, *hsH, *ehsH, *imgH, *amH, *aeH;
  cudaGetSymbolAddress((void**)&QH, g_QH);
  cudaGetSymbolAddress((void**)&KH, g_KH);
  cudaGetSymbolAddress((void**)&V, g_V);
  cudaGetSymbolAddress((void**)&KIPH, g_KIPH);
  cudaGetSymbolAddress((void**)&VIP, g_VIP);
  cudaGetSymbolAddress((void**)&T3, g_T3);
  cudaGetSymbolAddress((void**)&WB, g_WB);
  cudaGetSymbolAddress((void**)&hsH, g_hsH);
  cudaGetSymbolAddress((void**)&ehsH, g_ehsH);
  cudaGetSymbolAddress((void**)&imgH, g_imgH);
  cudaGetSymbolAddress((void**)&amH, g_amH);
  cudaGetSymbolAddress((void**)&aeH, g_aeH);

  const int G_SMEM = 3 * STAGE3_ * 4;       // 61440 B
  const int ATTN_SMEM = 16384 * 4;          // 65536 B (double-buffered Ks/Vs)
  cudaFuncSetAttribute(gemm_h, cudaFuncAttributeMaxDynamicSharedMemorySize, G_SMEM);
  cudaFuncSetAttribute(attn_mma_kernel, cudaFuncAttributeMaxDynamicSharedMemorySize, ATTN_SMEM);

  float* outMain = out + (size_t)ENC_ * D_;
  const float* hsC = hs + (size_t)(S_ - COND_) * D_;

  // 0. pack operands (fragment-pair layouts)
  W10 w10 = {{Wq, Wk, Wv, Waq, Wak, Wav, Wkip, Wvip, Wo, Wao}};
  cvtB_kernel<<<dim3(D_ / 32, K2_ / 32, 10), 256>>>(w10, WB);
  cvtA_kernel<<<S_ * K2_ / 256, 256>>>(hs, hsH, S_ * K2_);
  cvtA_kernel<<<ENC_ * K2_ / 256, 256>>>(ehs, ehsH, ENC_ * K2_);
  cvtA_kernel<<<NIP_ * K2_ / 256, 256>>>(img, imgH, NIP_ * K2_);

  // 1. lora-down temps
  D3 d3 = {{lq_dn, lk_dn, lv_dn}};
  lora_dn3<<<COND_ / 8, 256>>>(hsC, d3, T3);

  // 2. ALL projections in ONE launch (z=0..7); Q/K/KIP written packed f16
  size_t WS = (size_t)K2_ * D_;
  GF gall = {
    {hsH, hsH, hsH, ehsH, ehsH, ehsH, imgH, imgH},
    {WB, WB + WS, WB + 2 * WS, WB + 3 * WS, WB + 4 * WS, WB + 5 * WS, WB + 6 * WS, WB + 7 * WS},
    {bq, bk, bv, baq, bak, bav, 0, 0},
    {T3, T3 + COND_ * 16, T3 + 2 * COND_ * 16, 0, 0, 0, 0, 0},
    {lq_up, lk_up, lv_up, 0, 0, 0, 0, 0},
    {(float*)QH, (float*)KH, V, (float*)QH, (float*)KH, V, (float*)KIPH, VIP},
    {S_, S_, S_, ENC_, ENC_, ENC_, NIP_, NIP_},
    {SL_, SL_, SL_, SL_, SL_, SL_, NIP_, NIP_},
    {ENC_, ENC_, ENC_, 0, 0, 0, 0, 0},
    {1, 1, 0, 1, 1, 0, 1, 0},
    {2, 1, 0, 2, 1, 0, 1, 0}};
  gemm_h<<<dim3(24, 16, 8), 256, G_SMEM>>>(gall, D_, D_);

  // 3. joint attention + fused IP (reads packed Q/K; writes packed amH/aeH)
  attn_mma_kernel<<<dim3(SL_ / 128, H_), 256, ATTN_SMEM>>>(QH, KH, V, KIPH, VIP, aeH, amH);

  // 4. output projections
  GF gout = {
    {amH, aeH, 0, 0, 0, 0, 0, 0},
    {WB + 8 * WS, WB + 9 * WS, 0, 0, 0, 0, 0, 0},
    {bo, bao, 0, 0, 0, 0, 0, 0},
    {0, 0, 0, 0, 0, 0, 0, 0}, {0, 0, 0, 0, 0, 0, 0, 0},
    {outMain, out, 0, 0, 0, 0, 0, 0},
    {S_, ENC_, 1, 1, 1, 1, 1, 1},
    {0, 0, 0, 0, 0, 0, 0, 0},
    {0, 0, 0, 0, 0, 0, 0, 0},
    {0, 0, 0, 0, 0, 0, 0, 0},
    {0, 0, 0, 0, 0, 0, 0, 0}};
  gemm_h<<<dim3(24, 16, 2), 256, G_SMEM>>>(gout, D_, D_);

  // 5. output LoRA
  float* outCond = outMain + (size_t)(S_ - COND_) * D_;
  lora_kernel<<<COND_, 256>>>(outCond, lp_dn, lp_up, outCond);
}